// round 1
// baseline (speedup 1.0000x reference)
#include <cuda_runtime.h>
#include <math.h>

#define B_   2
#define S_   2048
#define D_   4096
#define HQ   32
#define HKV  8
#define HD   128
#define GRP  4
#define MROWS (B_*S_)   // 4096

// Scratch (module-load allocated; no runtime allocs)
__device__ float g_q[(size_t)B_*S_*HQ*HD];      // 67 MB
__device__ float g_k[(size_t)B_*S_*HKV*HD];     // 16.8 MB
__device__ float g_v[(size_t)B_*S_*HKV*HD];     // 16.8 MB
__device__ float g_p[(size_t)B_*HQ*S_*S_];      // 1.07 GB score/prob buffer
__device__ float g_ao[(size_t)B_*S_*D_];        // 67 MB attention output

// ---------------------------------------------------------------------------
// Generic fp32 SIMT GEMM: C = alpha * A@B (+bias), optional batched heads.
//   BT      : B source is stored [N,K] (i.e., compute A @ B^T)
//   HAS_BIAS: add bias[n]
//   CSKIP   : skip blocks strictly above diagonal (causal scores)
//   CKLIM   : limit K loop to m0+BM (causal PV: P[:, j>=m0+128] is zero)
// Batching: z -> (b = z/H, h = z%H); per-matrix offsets b*s?b + (h or h/Gdiv)*s?h
// ---------------------------------------------------------------------------
template<bool BT, bool HAS_BIAS, bool CSKIP, bool CKLIM>
__global__ __launch_bounds__(256, 2)
void sgemm_k(const float* __restrict__ Ag, const float* __restrict__ Bg,
             const float* __restrict__ bias, float* __restrict__ Cg,
             int M, int N, int K, int lda, int ldb, int ldc,
             int H, int Gdiv,
             long sAb, long sAh, long sBb, long sBh, long sCb, long sCh,
             float alpha)
{
    const int BM = 128, BN = 128, BK = 8;
    __shared__ float As[BK][BM];
    __shared__ float Bs[BK][BN];

    int m0 = blockIdx.y * BM;
    int n0 = blockIdx.x * BN;
    if (CSKIP && n0 > m0 + (BM - 1)) return;   // fully-masked score block

    int z = blockIdx.z;
    int b = z / H;
    int h = z - b * H;
    const float* A  = Ag + b * sAb + (long)h * sAh;
    const float* Bp = Bg + b * sBb + (long)(h / Gdiv) * sBh;
    float*       C  = Cg + b * sCb + (long)h * sCh;

    int tid = threadIdx.x;
    int tx = tid & 15, ty = tid >> 4;

    float acc[8][8];
    #pragma unroll
    for (int i = 0; i < 8; i++)
        #pragma unroll
        for (int j = 0; j < 8; j++) acc[i][j] = 0.f;

    int kEnd = K;
    if (CKLIM) { int ke = m0 + BM; kEnd = ke < K ? ke : K; }

    int arow = tid >> 1;           // 0..127
    int acol = (tid & 1) << 2;     // 0 or 4
    int brow = tid >> 5;           // 0..7
    int bcol = (tid & 31) << 2;    // 0..124

    for (int k0 = 0; k0 < kEnd; k0 += BK) {
        float4 av = *reinterpret_cast<const float4*>(A + (long)(m0 + arow) * lda + (k0 + acol));
        As[acol + 0][arow] = av.x; As[acol + 1][arow] = av.y;
        As[acol + 2][arow] = av.z; As[acol + 3][arow] = av.w;
        if (BT) {
            float4 bv = *reinterpret_cast<const float4*>(Bp + (long)(n0 + arow) * ldb + (k0 + acol));
            Bs[acol + 0][arow] = bv.x; Bs[acol + 1][arow] = bv.y;
            Bs[acol + 2][arow] = bv.z; Bs[acol + 3][arow] = bv.w;
        } else {
            float4 bv = *reinterpret_cast<const float4*>(Bp + (long)(k0 + brow) * ldb + (n0 + bcol));
            *reinterpret_cast<float4*>(&Bs[brow][bcol]) = bv;
        }
        __syncthreads();
        #pragma unroll
        for (int kk = 0; kk < BK; kk++) {
            float a[8], bb[8];
            *(float4*)&a[0]  = *(const float4*)&As[kk][ty * 8];
            *(float4*)&a[4]  = *(const float4*)&As[kk][ty * 8 + 4];
            *(float4*)&bb[0] = *(const float4*)&Bs[kk][tx * 8];
            *(float4*)&bb[4] = *(const float4*)&Bs[kk][tx * 8 + 4];
            #pragma unroll
            for (int i = 0; i < 8; i++)
                #pragma unroll
                for (int j = 0; j < 8; j++)
                    acc[i][j] = fmaf(a[i], bb[j], acc[i][j]);
        }
        __syncthreads();
    }

    #pragma unroll
    for (int i = 0; i < 8; i++) {
        long row = m0 + ty * 8 + i;
        #pragma unroll
        for (int j = 0; j < 8; j += 4) {
            int col = n0 + tx * 8 + j;
            float4 o;
            o.x = acc[i][j + 0] * alpha;
            o.y = acc[i][j + 1] * alpha;
            o.z = acc[i][j + 2] * alpha;
            o.w = acc[i][j + 3] * alpha;
            if (HAS_BIAS) {
                o.x += bias[col + 0]; o.y += bias[col + 1];
                o.z += bias[col + 2]; o.w += bias[col + 3];
            }
            *reinterpret_cast<float4*>(C + row * ldc + col) = o;
        }
    }
}

// ---------------------------------------------------------------------------
// RoPE (interleaved pairs: (2i, 2i+1) rotated by angle[s, i])
// ---------------------------------------------------------------------------
__global__ void rope_k(float* __restrict__ t, const float* __restrict__ cosb,
                       const float* __restrict__ sinb, const int* __restrict__ start_pos,
                       int heads, long total)
{
    long idx = blockIdx.x * (long)blockDim.x + threadIdx.x;
    if (idx >= total) return;
    int i = (int)(idx & 63);
    long tmp = idx >> 6;
    int h = (int)(tmp % heads);
    long row = tmp / heads;                 // b*S + s
    int s = (int)(row % S_) + *start_pos;
    float c  = cosb[s * 64 + i];
    float sn = sinb[s * 64 + i];
    long base = row * (long)(heads * HD) + (long)h * HD + 2 * i;
    float x0 = t[base], x1 = t[base + 1];
    t[base]     = x0 * c - x1 * sn;
    t[base + 1] = x0 * sn + x1 * c;
}

// ---------------------------------------------------------------------------
// Causal row softmax on g_p. One block per row. Writes zeros up to the next
// 128 boundary so the causal-K-limited PV GEMM never reads stale data.
// ---------------------------------------------------------------------------
__global__ __launch_bounds__(256) void softmax_k(float* __restrict__ P)
{
    long r = blockIdx.x;                    // 0 .. B*HQ*S-1
    int i = (int)(r % S_);
    float* row = P + r * (long)S_;
    int L = i + 1;
    int wlim = ((i >> 7) + 1) << 7;
    int tid = threadIdx.x;
    __shared__ float red[256];

    float m = -1e30f;
    for (int j = tid; j < L; j += 256) m = fmaxf(m, row[j]);
    red[tid] = m; __syncthreads();
    for (int s = 128; s > 0; s >>= 1) {
        if (tid < s) red[tid] = fmaxf(red[tid], red[tid + s]);
        __syncthreads();
    }
    float gmax = red[0]; __syncthreads();

    float sum = 0.f;
    for (int j = tid; j < L; j += 256) {
        float e = __expf(row[j] - gmax);
        row[j] = e;
        sum += e;
    }
    red[tid] = sum; __syncthreads();
    for (int s = 128; s > 0; s >>= 1) {
        if (tid < s) red[tid] += red[tid + s];
        __syncthreads();
    }
    float inv = 1.0f / red[0];
    for (int j = tid; j < L; j += 256) row[j] *= inv;
    for (int j = L + tid; j < wlim; j += 256) row[j] = 0.f;
}

// ---------------------------------------------------------------------------
extern "C" void kernel_launch(void* const* d_in, const int* in_sizes, int n_in,
                              void* d_out, int out_size)
{
    const float* x  = (const float*)d_in[0];
    const float* fc = (const float*)d_in[1];
    const float* fs = (const float*)d_in[2];
    const float* qw = (const float*)d_in[3];
    const float* qb = (const float*)d_in[4];
    const float* kw = (const float*)d_in[5];
    const float* kb = (const float*)d_in[6];
    const float* vw = (const float*)d_in[7];
    const float* vb = (const float*)d_in[8];
    const float* ow = (const float*)d_in[9];
    const int*   sp = (const int*)d_in[10];
    float* out = (float*)d_out;

    float *q, *k, *v, *p, *ao;
    cudaGetSymbolAddress((void**)&q,  g_q);
    cudaGetSymbolAddress((void**)&k,  g_k);
    cudaGetSymbolAddress((void**)&v,  g_v);
    cudaGetSymbolAddress((void**)&p,  g_p);
    cudaGetSymbolAddress((void**)&ao, g_ao);

    dim3 blk(256);

    // 1) Projections (fused bias)
    sgemm_k<false, true, false, false><<<dim3(D_/128, MROWS/128, 1), blk>>>(
        x, qw, qb, q, MROWS, D_, D_, D_, D_, D_,
        1, 1, 0, 0, 0, 0, 0, 0, 1.0f);
    sgemm_k<false, true, false, false><<<dim3((HKV*HD)/128, MROWS/128, 1), blk>>>(
        x, kw, kb, k, MROWS, HKV*HD, D_, D_, HKV*HD, HKV*HD,
        1, 1, 0, 0, 0, 0, 0, 0, 1.0f);
    sgemm_k<false, true, false, false><<<dim3((HKV*HD)/128, MROWS/128, 1), blk>>>(
        x, vw, vb, v, MROWS, HKV*HD, D_, D_, HKV*HD, HKV*HD,
        1, 1, 0, 0, 0, 0, 0, 0, 1.0f);

    // 2) RoPE
    long tq = (long)MROWS * HQ * 64;
    rope_k<<<(unsigned)((tq + 255) / 256), 256>>>(q, fc, fs, sp, HQ, tq);
    long tk = (long)MROWS * HKV * 64;
    rope_k<<<(unsigned)((tk + 255) / 256), 256>>>(k, fc, fs, sp, HKV, tk);

    // 3) scores = (1/sqrt(hd)) * Q @ K^T  (causal block skip)
    sgemm_k<true, false, true, false><<<dim3(S_/128, S_/128, B_*HQ), blk>>>(
        q, k, nullptr, p, S_, S_, HD, HQ*HD, HKV*HD, S_,
        HQ, GRP,
        (long)S_*HQ*HD, (long)HD,
        (long)S_*HKV*HD, (long)HD,
        (long)HQ*S_*S_, (long)S_*S_,
        0.08838834764831845f);

    // 4) causal softmax (in place)
    softmax_k<<<(unsigned)((long)B_*HQ*S_), 256>>>(p);

    // 5) O_head = P @ V  (causal K limit), written directly as [b, s, h*128+d]
    sgemm_k<false, false, false, true><<<dim3(HD/128, S_/128, B_*HQ), blk>>>(
        p, v, nullptr, ao, S_, HD, S_, S_, HKV*HD, D_,
        HQ, GRP,
        (long)HQ*S_*S_, (long)S_*S_,
        (long)S_*HKV*HD, (long)HD,
        (long)S_*D_, (long)HD,
        1.0f);

    // 6) out = AO @ ow
    sgemm_k<false, false, false, false><<<dim3(D_/128, MROWS/128, 1), blk>>>(
        ao, ow, nullptr, out, MROWS, D_, D_, D_, D_, D_,
        1, 1, 0, 0, 0, 0, 0, 0, 1.0f);
}

// round 2
// speedup vs baseline: 1.7164x; 1.7164x over previous
#include <cuda_runtime.h>
#include <cuda_bf16.h>

typedef unsigned short u16;
typedef unsigned int   u32;

#define B_   2
#define S_   2048
#define D_   4096
#define HQ   32
#define HKV  8
#define HD   128
#define GRP  4
#define MR   (B_*S_)   // 4096

// ---------------- scratch (__device__ globals; no runtime allocation) -------
__device__ float g_q[(size_t)MR*D_];                 // fp32 Q (pre-rope)
__device__ float g_k[(size_t)MR*HKV*HD];             // fp32 K (pre-rope)
__device__ float g_v[(size_t)MR*HKV*HD];             // fp32 V
__device__ float g_p[(size_t)B_*HQ*S_*S_];           // fp32 scores (1.07 GB)

__device__ u16 g_xh[(size_t)MR*D_],        g_xl[(size_t)MR*D_];
__device__ u16 g_qwt_h[(size_t)D_*D_],     g_qwt_l[(size_t)D_*D_];        // [N,K]
__device__ u16 g_kwt_h[(size_t)1024*D_],   g_kwt_l[(size_t)1024*D_];
__device__ u16 g_vwt_h[(size_t)1024*D_],   g_vwt_l[(size_t)1024*D_];
__device__ u16 g_owt_h[(size_t)D_*D_],     g_owt_l[(size_t)D_*D_];
__device__ u16 g_qh[(size_t)MR*D_],        g_ql[(size_t)MR*D_];           // post-rope Q
__device__ u16 g_kh[(size_t)MR*HKV*HD],    g_kl[(size_t)MR*HKV*HD];       // post-rope K
__device__ u16 g_vth[(size_t)B_*HKV*HD*S_],g_vtl[(size_t)B_*HKV*HD*S_];   // V^T [b,h,d,s]
__device__ u16 g_ph[(size_t)B_*HQ*S_*S_],  g_pl[(size_t)B_*HQ*S_*S_];     // split P
__device__ u16 g_aoh[(size_t)MR*D_],       g_aol[(size_t)MR*D_];          // split attn out

// ---------------------------------------------------------------------------
__device__ __forceinline__ void split2(float v, u16& h, u16& l) {
    __nv_bfloat16 hb = __float2bfloat16(v);
    float r = v - __bfloat162float(hb);
    h = __bfloat16_as_ushort(hb);
    l = __bfloat16_as_ushort(__float2bfloat16(r));
}

__device__ __forceinline__ void mma16816(float* d, const u32* a, const u32* b) {
    asm volatile(
        "mma.sync.aligned.m16n8k16.row.col.f32.bf16.bf16.f32 "
        "{%0,%1,%2,%3}, {%4,%5,%6,%7}, {%8,%9}, {%0,%1,%2,%3};\n"
        : "+f"(d[0]), "+f"(d[1]), "+f"(d[2]), "+f"(d[3])
        : "r"(a[0]), "r"(a[1]), "r"(a[2]), "r"(a[3]), "r"(b[0]), "r"(b[1]));
}

// ---------------------------------------------------------------------------
// Split-bf16 tensor-core GEMM: C = alpha * A @ B^T (+bias)
// A: [M,K] row-major split bf16 (hi/lo). B: [N,K] row-major split bf16 (all
// weights / V / K pre-transposed to K-major). 128x128x32 CTA tile, 256 thr,
// warp tile 64x32, mma.sync m16n8k16 bf16, 3-term compensated product.
//   CSKIP: skip blocks strictly above the causal diagonal (scores)
//   CKLIM: K-loop limit m0+128 (PV; softmax zero-fills to that boundary)
//   SOUT : write split bf16 output (Ch/Cl) instead of fp32
// ---------------------------------------------------------------------------
template<bool BIAS, bool CSKIP, bool CKLIM, bool SOUT>
__global__ __launch_bounds__(256, 1)
void mgemm(const u16* __restrict__ Agh, const u16* __restrict__ Agl,
           const u16* __restrict__ Bgh, const u16* __restrict__ Bgl,
           const float* __restrict__ bias,
           float* __restrict__ Cf, u16* __restrict__ Ch, u16* __restrict__ Cl,
           int M, int N, int K, int lda, int ldb, int ldc,
           int H, int Gdiv,
           long sAb, long sAh, long sBb, long sBh, long sCb, long sCh,
           float alpha)
{
    const int BKP = 40;   // 32 + 8 pad: 80B rows -> conflict-free frag LDS
    __shared__ __align__(16) u16 Ah[128*BKP], Al[128*BKP], Bh[128*BKP], Bl[128*BKP];

    int m0 = blockIdx.y * 128, n0 = blockIdx.x * 128;
    if (CSKIP && n0 > m0 + 127) return;

    int z = blockIdx.z, b = z / H, h = z - b * H;
    const u16* Aph = Agh + b * sAb + (long)h * sAh;
    const u16* Apl = Agl + b * sAb + (long)h * sAh;
    const u16* Bph = Bgh + b * sBb + (long)(h / Gdiv) * sBh;
    const u16* Bpl = Bgl + b * sBb + (long)(h / Gdiv) * sBh;

    int tid = threadIdx.x;
    int w = tid >> 5, lane = tid & 31;
    int wx = w & 3, wy = w >> 2;           // 4 warps along N, 2 along M
    int g = lane >> 2, tg = lane & 3;

    float d[4][4][4];
    #pragma unroll
    for (int i = 0; i < 4; i++)
        #pragma unroll
        for (int j = 0; j < 4; j++)
            #pragma unroll
            for (int q = 0; q < 4; q++) d[i][j][q] = 0.f;

    int kEnd = K;
    if (CKLIM) { int ke = m0 + 128; kEnd = ke < K ? ke : K; }

    int lr = tid >> 1;           // smem fill row 0..127
    int lq = (tid & 1) * 2;      // uint4 index 0 or 2

    for (int k0 = 0; k0 < kEnd; k0 += 32) {
        {
            const u16* pa_h = Aph + (long)(m0 + lr) * lda + k0 + lq * 8;
            const u16* pa_l = Apl + (long)(m0 + lr) * lda + k0 + lq * 8;
            const u16* pb_h = Bph + (long)(n0 + lr) * ldb + k0 + lq * 8;
            const u16* pb_l = Bpl + (long)(n0 + lr) * ldb + k0 + lq * 8;
            int so = lr * BKP + lq * 8;
            *(uint4*)&Ah[so]     = *(const uint4*)pa_h;
            *(uint4*)&Ah[so + 8] = *(const uint4*)(pa_h + 8);
            *(uint4*)&Al[so]     = *(const uint4*)pa_l;
            *(uint4*)&Al[so + 8] = *(const uint4*)(pa_l + 8);
            *(uint4*)&Bh[so]     = *(const uint4*)pb_h;
            *(uint4*)&Bh[so + 8] = *(const uint4*)(pb_h + 8);
            *(uint4*)&Bl[so]     = *(const uint4*)pb_l;
            *(uint4*)&Bl[so + 8] = *(const uint4*)(pb_l + 8);
        }
        __syncthreads();

        #pragma unroll
        for (int kk = 0; kk < 2; kk++) {
            int kb = kk * 16 + tg * 2;
            u32 ah[4][4], al[4][4], bh[4][2], bl[4][2];
            #pragma unroll
            for (int mi = 0; mi < 4; mi++) {
                int r = (wy * 64 + mi * 16 + g) * BKP + kb;
                ah[mi][0] = *(const u32*)&Ah[r];
                ah[mi][1] = *(const u32*)&Ah[r + 8 * BKP];
                ah[mi][2] = *(const u32*)&Ah[r + 8];
                ah[mi][3] = *(const u32*)&Ah[r + 8 * BKP + 8];
                al[mi][0] = *(const u32*)&Al[r];
                al[mi][1] = *(const u32*)&Al[r + 8 * BKP];
                al[mi][2] = *(const u32*)&Al[r + 8];
                al[mi][3] = *(const u32*)&Al[r + 8 * BKP + 8];
            }
            #pragma unroll
            for (int nj = 0; nj < 4; nj++) {
                int r = (wx * 32 + nj * 8 + g) * BKP + kb;
                bh[nj][0] = *(const u32*)&Bh[r];
                bh[nj][1] = *(const u32*)&Bh[r + 8];
                bl[nj][0] = *(const u32*)&Bl[r];
                bl[nj][1] = *(const u32*)&Bl[r + 8];
            }
            // 3 compensated terms; 16 independent accumulator chains each
            #pragma unroll
            for (int nj = 0; nj < 4; nj++)
                #pragma unroll
                for (int mi = 0; mi < 4; mi++)
                    mma16816(d[mi][nj], ah[mi], bh[nj]);
            #pragma unroll
            for (int nj = 0; nj < 4; nj++)
                #pragma unroll
                for (int mi = 0; mi < 4; mi++)
                    mma16816(d[mi][nj], ah[mi], bl[nj]);
            #pragma unroll
            for (int nj = 0; nj < 4; nj++)
                #pragma unroll
                for (int mi = 0; mi < 4; mi++)
                    mma16816(d[mi][nj], al[mi], bh[nj]);
        }
        __syncthreads();
    }

    // epilogue
    #pragma unroll
    for (int mi = 0; mi < 4; mi++) {
        #pragma unroll
        for (int nj = 0; nj < 4; nj++) {
            int r = m0 + wy * 64 + mi * 16 + g;
            int c = n0 + wx * 32 + nj * 8 + tg * 2;
            float v0 = d[mi][nj][0] * alpha, v1 = d[mi][nj][1] * alpha;
            float v2 = d[mi][nj][2] * alpha, v3 = d[mi][nj][3] * alpha;
            if (BIAS) {
                float b0 = bias[c], b1 = bias[c + 1];
                v0 += b0; v1 += b1; v2 += b0; v3 += b1;
            }
            long o0 = b * sCb + (long)h * sCh + (long)r * ldc + c;
            long o1 = o0 + 8L * ldc;
            if (SOUT) {
                u16 h0, l0, h1, l1;
                split2(v0, h0, l0); split2(v1, h1, l1);
                *(u32*)&Ch[o0] = (u32)h0 | ((u32)h1 << 16);
                *(u32*)&Cl[o0] = (u32)l0 | ((u32)l1 << 16);
                split2(v2, h0, l0); split2(v3, h1, l1);
                *(u32*)&Ch[o1] = (u32)h0 | ((u32)h1 << 16);
                *(u32*)&Cl[o1] = (u32)l0 | ((u32)l1 << 16);
            } else {
                float2 p0 = make_float2(v0, v1);
                float2 p1 = make_float2(v2, v3);
                *(float2*)&Cf[o0] = p0;
                *(float2*)&Cf[o1] = p1;
            }
        }
    }
}

// ---------------------------------------------------------------------------
// fp32 -> split bf16, elementwise
__global__ void conv_split(const float* __restrict__ in, u16* __restrict__ oh,
                           u16* __restrict__ ol, long n)
{
    long i = blockIdx.x * 256L + threadIdx.x;
    if (i < n) split2(in[i], oh[i], ol[i]);
}

// fp32 [R,C] (optionally batched) -> transposed split bf16 [C,R]
__global__ void tsplit(const float* __restrict__ in, u16* __restrict__ oh,
                       u16* __restrict__ ol, int ldin, int ldout,
                       long sInB, long sInH, long sOutZ, int Hc)
{
    __shared__ float t[32][33];
    int z = blockIdx.z, bb = z / Hc, hh = z - bb * Hc;
    const float* ip = in + bb * sInB + (long)hh * sInH;
    int c0 = blockIdx.x * 32, r0 = blockIdx.y * 32;
    #pragma unroll
    for (int i = 0; i < 4; i++)
        t[threadIdx.y + i * 8][threadIdx.x] =
            ip[(long)(r0 + threadIdx.y + i * 8) * ldin + c0 + threadIdx.x];
    __syncthreads();
    #pragma unroll
    for (int i = 0; i < 4; i++) {
        int orow = c0 + threadIdx.y + i * 8;
        int oc = r0 + threadIdx.x;
        float v = t[threadIdx.x][threadIdx.y + i * 8];
        long o = z * sOutZ + (long)orow * ldout + oc;
        split2(v, oh[o], ol[o]);
    }
}

// RoPE on fp32 input, writes split bf16 (interleaved-pair convention)
__global__ void rope_split(const float* __restrict__ t, u16* __restrict__ oh,
                           u16* __restrict__ ol, const float* __restrict__ cosb,
                           const float* __restrict__ sinb,
                           const int* __restrict__ start_pos, int heads, long total)
{
    long idx = blockIdx.x * 256L + threadIdx.x;
    if (idx >= total) return;
    int i = (int)(idx & 63);
    long tmp = idx >> 6;
    int h = (int)(tmp % heads);
    long row = tmp / heads;
    int s = (int)(row % S_) + *start_pos;
    float c = cosb[s * 64 + i];
    float sn = sinb[s * 64 + i];
    long base = row * (long)(heads * HD) + (long)h * HD + 2 * i;
    float x0 = t[base], x1 = t[base + 1];
    float o0 = x0 * c - x1 * sn;
    float o1 = x0 * sn + x1 * c;
    split2(o0, oh[base], ol[base]);
    split2(o1, oh[base + 1], ol[base + 1]);
}

// causal softmax: fp32 scores in, split bf16 probs out, zero-fill to 128-align
__global__ __launch_bounds__(256) void softmax_split(const float* __restrict__ P,
                                                     u16* __restrict__ Ph,
                                                     u16* __restrict__ Pl)
{
    long r = blockIdx.x;
    int i = (int)(r % S_);
    const float* row = P + r * (long)S_;
    u16* rh = Ph + r * (long)S_;
    u16* rl = Pl + r * (long)S_;
    int L = i + 1;
    int wlim = ((i >> 7) + 1) << 7;
    int tid = threadIdx.x;
    __shared__ float red[256];
    __shared__ float tmp_unused; (void)tmp_unused;

    float m = -1e30f;
    for (int j = tid; j < L; j += 256) m = fmaxf(m, row[j]);
    red[tid] = m; __syncthreads();
    for (int s = 128; s > 0; s >>= 1) {
        if (tid < s) red[tid] = fmaxf(red[tid], red[tid + s]);
        __syncthreads();
    }
    float gmax = red[0]; __syncthreads();

    float sum = 0.f;
    for (int j = tid; j < L; j += 256) sum += __expf(row[j] - gmax);
    red[tid] = sum; __syncthreads();
    for (int s = 128; s > 0; s >>= 1) {
        if (tid < s) red[tid] += red[tid + s];
        __syncthreads();
    }
    float inv = 1.0f / red[0];

    for (int j = tid; j < L; j += 256) {
        float w = __expf(row[j] - gmax) * inv;
        split2(w, rh[j], rl[j]);
    }
    for (int j = L + tid; j < wlim; j += 256) { rh[j] = 0; rl[j] = 0; }
}

// ---------------------------------------------------------------------------
extern "C" void kernel_launch(void* const* d_in, const int* in_sizes, int n_in,
                              void* d_out, int out_size)
{
    const float* x  = (const float*)d_in[0];
    const float* fc = (const float*)d_in[1];
    const float* fs = (const float*)d_in[2];
    const float* qw = (const float*)d_in[3];
    const float* qb = (const float*)d_in[4];
    const float* kw = (const float*)d_in[5];
    const float* kb = (const float*)d_in[6];
    const float* vw = (const float*)d_in[7];
    const float* vb = (const float*)d_in[8];
    const float* ow = (const float*)d_in[9];
    const int*   sp = (const int*)d_in[10];
    float* out = (float*)d_out;

    float *q, *k, *v, *p;
    u16 *xh, *xl, *qwth, *qwtl, *kwth, *kwtl, *vwth, *vwtl, *owth, *owtl;
    u16 *qh, *ql, *kh, *kl, *vth, *vtl, *ph, *pl, *aoh, *aol;
    cudaGetSymbolAddress((void**)&q, g_q);
    cudaGetSymbolAddress((void**)&k, g_k);
    cudaGetSymbolAddress((void**)&v, g_v);
    cudaGetSymbolAddress((void**)&p, g_p);
    cudaGetSymbolAddress((void**)&xh, g_xh);   cudaGetSymbolAddress((void**)&xl, g_xl);
    cudaGetSymbolAddress((void**)&qwth, g_qwt_h); cudaGetSymbolAddress((void**)&qwtl, g_qwt_l);
    cudaGetSymbolAddress((void**)&kwth, g_kwt_h); cudaGetSymbolAddress((void**)&kwtl, g_kwt_l);
    cudaGetSymbolAddress((void**)&vwth, g_vwt_h); cudaGetSymbolAddress((void**)&vwtl, g_vwt_l);
    cudaGetSymbolAddress((void**)&owth, g_owt_h); cudaGetSymbolAddress((void**)&owtl, g_owt_l);
    cudaGetSymbolAddress((void**)&qh, g_qh);   cudaGetSymbolAddress((void**)&ql, g_ql);
    cudaGetSymbolAddress((void**)&kh, g_kh);   cudaGetSymbolAddress((void**)&kl, g_kl);
    cudaGetSymbolAddress((void**)&vth, g_vth); cudaGetSymbolAddress((void**)&vtl, g_vtl);
    cudaGetSymbolAddress((void**)&ph, g_ph);   cudaGetSymbolAddress((void**)&pl, g_pl);
    cudaGetSymbolAddress((void**)&aoh, g_aoh); cudaGetSymbolAddress((void**)&aol, g_aol);

    // 1) split-convert activations and weights (weights transposed to [N,K])
    conv_split<<<(unsigned)(((long)MR * D_ + 255) / 256), 256>>>(x, xh, xl, (long)MR * D_);
    dim3 tb(32, 8);
    tsplit<<<dim3(128, 128, 1), tb>>>(qw, qwth, qwtl, D_, D_, 0, 0, 0, 1);
    tsplit<<<dim3(32, 128, 1), tb>>>(kw, kwth, kwtl, 1024, D_, 0, 0, 0, 1);
    tsplit<<<dim3(32, 128, 1), tb>>>(vw, vwth, vwtl, 1024, D_, 0, 0, 0, 1);
    tsplit<<<dim3(128, 128, 1), tb>>>(ow, owth, owtl, D_, D_, 0, 0, 0, 1);

    // 2) projections (tensor-core, fused bias) -> fp32 q/k/v
    mgemm<true, false, false, false><<<dim3(32, 32, 1), 256>>>(
        xh, xl, qwth, qwtl, qb, q, nullptr, nullptr,
        MR, D_, D_, D_, D_, D_, 1, 1, 0, 0, 0, 0, 0, 0, 1.0f);
    mgemm<true, false, false, false><<<dim3(8, 32, 1), 256>>>(
        xh, xl, kwth, kwtl, kb, k, nullptr, nullptr,
        MR, 1024, D_, D_, D_, 1024, 1, 1, 0, 0, 0, 0, 0, 0, 1.0f);
    mgemm<true, false, false, false><<<dim3(8, 32, 1), 256>>>(
        xh, xl, vwth, vwtl, vb, v, nullptr, nullptr,
        MR, 1024, D_, D_, D_, 1024, 1, 1, 0, 0, 0, 0, 0, 0, 1.0f);

    // 3) RoPE + split-convert q,k ; transpose+split v -> [b,h,d,s]
    long tq = (long)MR * HQ * 64;
    rope_split<<<(unsigned)((tq + 255) / 256), 256>>>(q, qh, ql, fc, fs, sp, HQ, tq);
    long tk = (long)MR * HKV * 64;
    rope_split<<<(unsigned)((tk + 255) / 256), 256>>>(k, kh, kl, fc, fs, sp, HKV, tk);
    tsplit<<<dim3(4, 64, B_ * HKV), tb>>>(v, vth, vtl, 1024, S_,
        (long)S_ * 1024, (long)HD, (long)HD * S_, HKV);

    // 4) scores = (1/sqrt(128)) * Q @ K^T  (causal block skip) -> fp32 p
    mgemm<false, true, false, false><<<dim3(16, 16, B_ * HQ), 256>>>(
        qh, ql, kh, kl, nullptr, p, nullptr, nullptr,
        S_, S_, HD, D_, 1024, S_, HQ, GRP,
        (long)S_ * D_, (long)HD,
        (long)S_ * 1024, (long)HD,
        (long)HQ * S_ * S_, (long)S_ * S_,
        0.08838834764831845f);

    // 5) softmax -> split bf16 P (zero-filled to 128-boundary)
    softmax_split<<<(unsigned)((long)B_ * HQ * S_), 256>>>(p, ph, pl);

    // 6) AO = P @ V (causal K limit), split-bf16 output in [b,s,h*128+d]
    mgemm<false, false, true, true><<<dim3(1, 16, B_ * HQ), 256>>>(
        ph, pl, vth, vtl, nullptr, nullptr, aoh, aol,
        S_, HD, S_, S_, S_, D_, HQ, GRP,
        (long)HQ * S_ * S_, (long)S_ * S_,
        (long)HKV * HD * S_, (long)HD * S_,
        (long)S_ * D_, (long)HD,
        1.0f);

    // 7) out = AO @ ow
    mgemm<false, false, false, false><<<dim3(32, 32, 1), 256>>>(
        aoh, aol, owth, owtl, nullptr, out, nullptr, nullptr,
        MR, D_, D_, D_, D_, D_, 1, 1, 0, 0, 0, 0, 0, 0, 1.0f);
}

// round 4
// speedup vs baseline: 2.6801x; 1.5615x over previous
#include <cuda_runtime.h>
#include <cuda_bf16.h>

typedef unsigned short u16;
typedef unsigned int   u32;

#define B_   2
#define S_   2048
#define D_   4096
#define HQ   32
#define HKV  8
#define HD   128
#define GRP  4
#define MR   (B_*S_)   // 4096

// ---------------- scratch (__device__ globals; no runtime allocation) -------
__device__ float g_q[(size_t)MR*D_];
__device__ float g_k[(size_t)MR*HKV*HD];
__device__ float g_v[(size_t)MR*HKV*HD];
__device__ float g_p[(size_t)B_*HQ*S_*S_];

__device__ u16 g_xh[(size_t)MR*D_],        g_xl[(size_t)MR*D_];
__device__ u16 g_qwt_h[(size_t)D_*D_],     g_qwt_l[(size_t)D_*D_];
__device__ u16 g_kwt_h[(size_t)1024*D_],   g_kwt_l[(size_t)1024*D_];
__device__ u16 g_vwt_h[(size_t)1024*D_],   g_vwt_l[(size_t)1024*D_];
__device__ u16 g_owt_h[(size_t)D_*D_],     g_owt_l[(size_t)D_*D_];
__device__ u16 g_qh[(size_t)MR*D_],        g_ql[(size_t)MR*D_];
__device__ u16 g_kh[(size_t)MR*HKV*HD],    g_kl[(size_t)MR*HKV*HD];
__device__ u16 g_vth[(size_t)B_*HKV*HD*S_],g_vtl[(size_t)B_*HKV*HD*S_];
__device__ u16 g_ph[(size_t)B_*HQ*S_*S_],  g_pl[(size_t)B_*HQ*S_*S_];
__device__ u16 g_aoh[(size_t)MR*D_],       g_aol[(size_t)MR*D_];

// ---------------------------------------------------------------------------
__device__ __forceinline__ void split2(float v, u16& h, u16& l) {
    __nv_bfloat16 hb = __float2bfloat16(v);
    float r = v - __bfloat162float(hb);
    h = __bfloat16_as_ushort(hb);
    l = __bfloat16_as_ushort(__float2bfloat16(r));
}

__device__ __forceinline__ u32 smem_u32(const void* p) {
    u32 a;
    asm("{ .reg .u64 t; cvta.to.shared.u64 t, %1; cvt.u32.u64 %0, t; }" : "=r"(a) : "l"(p));
    return a;
}

__device__ __forceinline__ void cp16(u32 sdst, const void* gsrc) {
    asm volatile("cp.async.cg.shared.global [%0], [%1], 16;\n" :: "r"(sdst), "l"(gsrc));
}
#define CP_COMMIT()  asm volatile("cp.async.commit_group;" ::: "memory")
#define CP_WAIT1()   asm volatile("cp.async.wait_group 1;" ::: "memory")
#define CP_WAIT0()   asm volatile("cp.async.wait_group 0;" ::: "memory")

__device__ __forceinline__ void ldsm4(u32* r, u32 addr) {
    asm volatile("ldmatrix.sync.aligned.m8n8.x4.shared.b16 {%0,%1,%2,%3}, [%4];"
        : "=r"(r[0]), "=r"(r[1]), "=r"(r[2]), "=r"(r[3]) : "r"(addr));
}

__device__ __forceinline__ void mma16816(float* d, const u32* a, const u32* b) {
    asm volatile(
        "mma.sync.aligned.m16n8k16.row.col.f32.bf16.bf16.f32 "
        "{%0,%1,%2,%3}, {%4,%5,%6,%7}, {%8,%9}, {%0,%1,%2,%3};\n"
        : "+f"(d[0]), "+f"(d[1]), "+f"(d[2]), "+f"(d[3])
        : "r"(a[0]), "r"(a[1]), "r"(a[2]), "r"(a[3]), "r"(b[0]), "r"(b[1]));
}

// ---------------------------------------------------------------------------
// Split-bf16 tensor GEMM: C = alpha * A @ B^T (+bias)
// A:[M,K] split bf16 row-major; B:[N,K] split bf16 row-major.
// 128x128 CTA tile, BK=64, double-buffered cp.async, ldmatrix fragments,
// 3-term compensated product (Ah*Bh + Al*Bh + Ah*Bl). 256 threads.
// Smem rows padded to 144B -> conflict-free for cp fill and ldmatrix.
// ---------------------------------------------------------------------------
#define ROWB 144          // bytes per smem row (128 data + 16 pad)
#define ARRB (128*ROWB)   // one operand array: 18432 B
#define STGB (4*ARRB)     // stage: Ah,Al,Bh,Bl = 73728 B
#define SMEMB (2*STGB)    // 147456 B

template<bool BIAS, bool CSKIP, bool CKLIM, bool SOUT>
__global__ __launch_bounds__(256, 1)
void mgemm(const u16* __restrict__ Agh, const u16* __restrict__ Agl,
           const u16* __restrict__ Bgh, const u16* __restrict__ Bgl,
           const float* __restrict__ bias,
           float* __restrict__ Cf, u16* __restrict__ Ch, u16* __restrict__ Cl,
           int K, int lda, int ldb, int ldc,
           int H, int Gdiv,
           long sAb, long sAh, long sBb, long sBh, long sCb, long sCh,
           float alpha)
{
    extern __shared__ __align__(16) char dsm[];

    int m0 = blockIdx.y * 128, n0 = blockIdx.x * 128;
    if (CSKIP && n0 > m0 + 127) return;

    int z = blockIdx.z, b = z / H, h = z - b * H;
    const u16* Aph = Agh + b * sAb + (long)h * sAh;
    const u16* Apl = Agl + b * sAb + (long)h * sAh;
    const u16* Bph = Bgh + b * sBb + (long)(h / Gdiv) * sBh;
    const u16* Bpl = Bgl + b * sBb + (long)(h / Gdiv) * sBh;

    int tid = threadIdx.x, wid = tid >> 5, lane = tid & 31;
    int wx = wid & 3, wy = wid >> 2;
    int g = lane >> 2, tg = lane & 3;

    u32 sbase = smem_u32(dsm);

    // fragment smem offsets (bytes, within array)
    int aRow = ((lane >> 3) & 1) * 8 + (lane & 7);
    int aK   = (lane >> 4) * 16;
    u32 aOff[4];
    #pragma unroll
    for (int mi = 0; mi < 4; mi++)
        aOff[mi] = (u32)((wy * 64 + mi * 16 + aRow) * ROWB + aK);
    int bRow = (lane >> 4) * 8 + (lane & 7);
    int bK   = ((lane >> 3) & 1) * 16;
    u32 bOff[2];
    #pragma unroll
    for (int p = 0; p < 2; p++)
        bOff[p] = (u32)((wx * 32 + p * 16 + bRow) * ROWB + bK);

    float d[4][4][4];
    #pragma unroll
    for (int i = 0; i < 4; i++)
        #pragma unroll
        for (int j = 0; j < 4; j++)
            #pragma unroll
            for (int q = 0; q < 4; q++) d[i][j][q] = 0.f;

    int kEnd = K;
    if (CKLIM) { int ke = m0 + 128; kEnd = ke < K ? ke : K; }
    int nch = kEnd >> 6;

    // ---- async loader: one 64-wide K chunk into stage s ----
    auto prefetch = [&](int c, int s) {
        u32 st = sbase + s * STGB;
        int k0 = c << 6;
        #pragma unroll
        for (int i = 0; i < 16; i++) {
            int arr = i >> 2;                      // 0:Ah 1:Al 2:Bh 3:Bl
            int rem = (i & 3) * 256 + tid;         // 0..1023
            int row = rem >> 3, ch = rem & 7;
            u32 so = st + arr * ARRB + row * ROWB + ch * 16;
            long ke = (long)(k0 + ch * 8);
            const u16* gp;
            if (arr == 0)      gp = Aph + (long)(m0 + row) * lda + ke;
            else if (arr == 1) gp = Apl + (long)(m0 + row) * lda + ke;
            else if (arr == 2) gp = Bph + (long)(n0 + row) * ldb + ke;
            else               gp = Bpl + (long)(n0 + row) * ldb + ke;
            cp16(so, gp);
        }
    };

    prefetch(0, 0);
    CP_COMMIT();

    for (int c = 0; c < nch; c++) {
        if (c + 1 < nch) { prefetch(c + 1, (c + 1) & 1); CP_COMMIT(); CP_WAIT1(); }
        else             { CP_WAIT0(); }
        __syncthreads();

        u32 st = sbase + (c & 1) * STGB;
        u32 sAh_ = st, sAl_ = st + ARRB, sBh_ = st + 2 * ARRB, sBl_ = st + 3 * ARRB;

        #pragma unroll
        for (int kk = 0; kk < 4; kk++) {
            u32 ko = kk * 32;
            u32 ah[4][4], xa[4][4], xb[2][4];
            #pragma unroll
            for (int mi = 0; mi < 4; mi++) ldsm4(ah[mi], sAh_ + aOff[mi] + ko);
            #pragma unroll
            for (int p = 0; p < 2; p++)    ldsm4(xb[p], sBh_ + bOff[p] + ko);
            #pragma unroll
            for (int mi = 0; mi < 4; mi++)
                #pragma unroll
                for (int nj = 0; nj < 4; nj++)
                    mma16816(d[mi][nj], ah[mi], &xb[nj >> 1][(nj & 1) * 2]);
            #pragma unroll
            for (int mi = 0; mi < 4; mi++) ldsm4(xa[mi], sAl_ + aOff[mi] + ko);
            #pragma unroll
            for (int mi = 0; mi < 4; mi++)
                #pragma unroll
                for (int nj = 0; nj < 4; nj++)
                    mma16816(d[mi][nj], xa[mi], &xb[nj >> 1][(nj & 1) * 2]);
            #pragma unroll
            for (int p = 0; p < 2; p++)    ldsm4(xb[p], sBl_ + bOff[p] + ko);
            #pragma unroll
            for (int mi = 0; mi < 4; mi++)
                #pragma unroll
                for (int nj = 0; nj < 4; nj++)
                    mma16816(d[mi][nj], ah[mi], &xb[nj >> 1][(nj & 1) * 2]);
        }
        __syncthreads();
    }

    // epilogue
    #pragma unroll
    for (int mi = 0; mi < 4; mi++) {
        #pragma unroll
        for (int nj = 0; nj < 4; nj++) {
            int r = m0 + wy * 64 + mi * 16 + g;
            int c = n0 + wx * 32 + nj * 8 + tg * 2;
            float v0 = d[mi][nj][0] * alpha, v1 = d[mi][nj][1] * alpha;
            float v2 = d[mi][nj][2] * alpha, v3 = d[mi][nj][3] * alpha;
            if (BIAS) {
                float b0 = bias[c], b1 = bias[c + 1];
                v0 += b0; v1 += b1; v2 += b0; v3 += b1;
            }
            long o0 = b * sCb + (long)h * sCh + (long)r * ldc + c;
            long o1 = o0 + 8L * ldc;
            if (SOUT) {
                u16 h0, l0, h1, l1;
                split2(v0, h0, l0); split2(v1, h1, l1);
                *(u32*)&Ch[o0] = (u32)h0 | ((u32)h1 << 16);
                *(u32*)&Cl[o0] = (u32)l0 | ((u32)l1 << 16);
                split2(v2, h0, l0); split2(v3, h1, l1);
                *(u32*)&Ch[o1] = (u32)h0 | ((u32)h1 << 16);
                *(u32*)&Cl[o1] = (u32)l0 | ((u32)l1 << 16);
            } else {
                *(float2*)&Cf[o0] = make_float2(v0, v1);
                *(float2*)&Cf[o1] = make_float2(v2, v3);
            }
        }
    }
}

// ---------------------------------------------------------------------------
__global__ void conv_split(const float* __restrict__ in, u16* __restrict__ oh,
                           u16* __restrict__ ol, long n)
{
    long i = blockIdx.x * 256L + threadIdx.x;
    if (i < n) split2(in[i], oh[i], ol[i]);
}

__global__ void tsplit(const float* __restrict__ in, u16* __restrict__ oh,
                       u16* __restrict__ ol, int ldin, int ldout,
                       long sInB, long sInH, long sOutZ, int Hc)
{
    __shared__ float t[32][33];
    int z = blockIdx.z, bb = z / Hc, hh = z - bb * Hc;
    const float* ip = in + bb * sInB + (long)hh * sInH;
    int c0 = blockIdx.x * 32, r0 = blockIdx.y * 32;
    #pragma unroll
    for (int i = 0; i < 4; i++)
        t[threadIdx.y + i * 8][threadIdx.x] =
            ip[(long)(r0 + threadIdx.y + i * 8) * ldin + c0 + threadIdx.x];
    __syncthreads();
    #pragma unroll
    for (int i = 0; i < 4; i++) {
        int orow = c0 + threadIdx.y + i * 8;
        int oc = r0 + threadIdx.x;
        float v = t[threadIdx.x][threadIdx.y + i * 8];
        long o = z * sOutZ + (long)orow * ldout + oc;
        split2(v, oh[o], ol[o]);
    }
}

__global__ void rope_split(const float* __restrict__ t, u16* __restrict__ oh,
                           u16* __restrict__ ol, const float* __restrict__ cosb,
                           const float* __restrict__ sinb,
                           const int* __restrict__ start_pos, int heads, long total)
{
    long idx = blockIdx.x * 256L + threadIdx.x;
    if (idx >= total) return;
    int i = (int)(idx & 63);
    long tmp = idx >> 6;
    int h = (int)(tmp % heads);
    long row = tmp / heads;
    int s = (int)(row % S_) + *start_pos;
    float c = cosb[s * 64 + i];
    float sn = sinb[s * 64 + i];
    long base = row * (long)(heads * HD) + (long)h * HD + 2 * i;
    float x0 = t[base], x1 = t[base + 1];
    float o0 = x0 * c - x1 * sn;
    float o1 = x0 * sn + x1 * c;
    split2(o0, oh[base], ol[base]);
    split2(o1, oh[base + 1], ol[base + 1]);
}

// causal softmax, single exp pass (values cached in registers)
__global__ __launch_bounds__(256) void softmax_split(const float* __restrict__ P,
                                                     u16* __restrict__ Ph,
                                                     u16* __restrict__ Pl)
{
    long r = blockIdx.x;
    int i = (int)(r % S_);
    const float* row = P + r * (long)S_;
    u16* rh = Ph + r * (long)S_;
    u16* rl = Pl + r * (long)S_;
    int L = i + 1;
    int wlim = ((i >> 7) + 1) << 7;
    int tid = threadIdx.x;
    __shared__ float red[256];

    float m = -1e30f;
    float xv[8];
    int cnt = 0;
    for (int j = tid; j < L; j += 256) {
        float v = row[j];
        xv[cnt++] = v;
        m = fmaxf(m, v);
    }
    red[tid] = m; __syncthreads();
    for (int s = 128; s > 0; s >>= 1) {
        if (tid < s) red[tid] = fmaxf(red[tid], red[tid + s]);
        __syncthreads();
    }
    float gmax = red[0]; __syncthreads();

    float sum = 0.f;
    #pragma unroll
    for (int t = 0; t < 8; t++) {
        if (t < cnt) {
            float e = __expf(xv[t] - gmax);
            xv[t] = e;
            sum += e;
        }
    }
    red[tid] = sum; __syncthreads();
    for (int s = 128; s > 0; s >>= 1) {
        if (tid < s) red[tid] += red[tid + s];
        __syncthreads();
    }
    float inv = 1.0f / red[0];

    int cnt2 = 0;
    for (int j = tid; j < L; j += 256) {
        float w = xv[cnt2++] * inv;
        split2(w, rh[j], rl[j]);
    }
    for (int j = L + tid; j < wlim; j += 256) { rh[j] = 0; rl[j] = 0; }
}

// ---------------------------------------------------------------------------
extern "C" void kernel_launch(void* const* d_in, const int* in_sizes, int n_in,
                              void* d_out, int out_size)
{
    const float* x  = (const float*)d_in[0];
    const float* fc = (const float*)d_in[1];
    const float* fs = (const float*)d_in[2];
    const float* qw = (const float*)d_in[3];
    const float* qb = (const float*)d_in[4];
    const float* kw = (const float*)d_in[5];
    const float* kb = (const float*)d_in[6];
    const float* vw = (const float*)d_in[7];
    const float* vb = (const float*)d_in[8];
    const float* ow = (const float*)d_in[9];
    const int*   sp = (const int*)d_in[10];
    float* out = (float*)d_out;

    float *q, *k, *v, *p;
    u16 *xh, *xl, *qwth, *qwtl, *kwth, *kwtl, *vwth, *vwtl, *owth, *owtl;
    u16 *qh, *ql, *kh, *kl, *vth, *vtl, *ph, *pl, *aoh, *aol;
    cudaGetSymbolAddress((void**)&q, g_q);
    cudaGetSymbolAddress((void**)&k, g_k);
    cudaGetSymbolAddress((void**)&v, g_v);
    cudaGetSymbolAddress((void**)&p, g_p);
    cudaGetSymbolAddress((void**)&xh, g_xh);   cudaGetSymbolAddress((void**)&xl, g_xl);
    cudaGetSymbolAddress((void**)&qwth, g_qwt_h); cudaGetSymbolAddress((void**)&qwtl, g_qwt_l);
    cudaGetSymbolAddress((void**)&kwth, g_kwt_h); cudaGetSymbolAddress((void**)&kwtl, g_kwt_l);
    cudaGetSymbolAddress((void**)&vwth, g_vwt_h); cudaGetSymbolAddress((void**)&vwtl, g_vwt_l);
    cudaGetSymbolAddress((void**)&owth, g_owt_h); cudaGetSymbolAddress((void**)&owtl, g_owt_l);
    cudaGetSymbolAddress((void**)&qh, g_qh);   cudaGetSymbolAddress((void**)&ql, g_ql);
    cudaGetSymbolAddress((void**)&kh, g_kh);   cudaGetSymbolAddress((void**)&kl, g_kl);
    cudaGetSymbolAddress((void**)&vth, g_vth); cudaGetSymbolAddress((void**)&vtl, g_vtl);
    cudaGetSymbolAddress((void**)&ph, g_ph);   cudaGetSymbolAddress((void**)&pl, g_pl);
    cudaGetSymbolAddress((void**)&aoh, g_aoh); cudaGetSymbolAddress((void**)&aol, g_aol);

    cudaFuncSetAttribute((const void*)mgemm<true,  false, false, false>,
                         cudaFuncAttributeMaxDynamicSharedMemorySize, SMEMB);
    cudaFuncSetAttribute((const void*)mgemm<false, true,  false, false>,
                         cudaFuncAttributeMaxDynamicSharedMemorySize, SMEMB);
    cudaFuncSetAttribute((const void*)mgemm<false, false, true,  true>,
                         cudaFuncAttributeMaxDynamicSharedMemorySize, SMEMB);
    cudaFuncSetAttribute((const void*)mgemm<false, false, false, false>,
                         cudaFuncAttributeMaxDynamicSharedMemorySize, SMEMB);

    // 1) split-convert activations and weights (weights transposed to [N,K])
    conv_split<<<(unsigned)(((long)MR * D_ + 255) / 256), 256>>>(x, xh, xl, (long)MR * D_);
    dim3 tb(32, 8);
    tsplit<<<dim3(128, 128, 1), tb>>>(qw, qwth, qwtl, D_, D_, 0, 0, 0, 1);
    tsplit<<<dim3(32, 128, 1), tb>>>(kw, kwth, kwtl, 1024, D_, 0, 0, 0, 1);
    tsplit<<<dim3(32, 128, 1), tb>>>(vw, vwth, vwtl, 1024, D_, 0, 0, 0, 1);
    tsplit<<<dim3(128, 128, 1), tb>>>(ow, owth, owtl, D_, D_, 0, 0, 0, 1);

    // 2) projections (tensor-core, fused bias) -> fp32 q/k/v
    mgemm<true, false, false, false><<<dim3(32, 32, 1), 256, SMEMB>>>(
        xh, xl, qwth, qwtl, qb, q, nullptr, nullptr,
        D_, D_, D_, D_, 1, 1, 0, 0, 0, 0, 0, 0, 1.0f);
    mgemm<true, false, false, false><<<dim3(8, 32, 1), 256, SMEMB>>>(
        xh, xl, kwth, kwtl, kb, k, nullptr, nullptr,
        D_, D_, D_, 1024, 1, 1, 0, 0, 0, 0, 0, 0, 1.0f);
    mgemm<true, false, false, false><<<dim3(8, 32, 1), 256, SMEMB>>>(
        xh, xl, vwth, vwtl, vb, v, nullptr, nullptr,
        D_, D_, D_, 1024, 1, 1, 0, 0, 0, 0, 0, 0, 1.0f);

    // 3) RoPE + split-convert q,k ; transpose+split v -> [b,h,d,s]
    long tq = (long)MR * HQ * 64;
    rope_split<<<(unsigned)((tq + 255) / 256), 256>>>(q, qh, ql, fc, fs, sp, HQ, tq);
    long tk = (long)MR * HKV * 64;
    rope_split<<<(unsigned)((tk + 255) / 256), 256>>>(k, kh, kl, fc, fs, sp, HKV, tk);
    tsplit<<<dim3(4, 64, B_ * HKV), tb>>>(v, vth, vtl, 1024, S_,
        (long)S_ * 1024, (long)HD, (long)HD * S_, HKV);

    // 4) scores = (1/sqrt(128)) * Q @ K^T  (causal block skip) -> fp32 p
    mgemm<false, true, false, false><<<dim3(16, 16, B_ * HQ), 256, SMEMB>>>(
        qh, ql, kh, kl, nullptr, p, nullptr, nullptr,
        HD, D_, 1024, S_, HQ, GRP,
        (long)S_ * D_, (long)HD,
        (long)S_ * 1024, (long)HD,
        (long)HQ * S_ * S_, (long)S_ * S_,
        0.08838834764831845f);

    // 5) softmax -> split bf16 P (zero-filled to 128-boundary)
    softmax_split<<<(unsigned)((long)B_ * HQ * S_), 256>>>(p, ph, pl);

    // 6) AO = P @ V (causal K limit), split-bf16 output in [b,s,h*128+d]
    mgemm<false, false, true, true><<<dim3(1, 16, B_ * HQ), 256, SMEMB>>>(
        ph, pl, vth, vtl, nullptr, nullptr, aoh, aol,
        S_, S_, S_, D_, HQ, GRP,
        (long)HQ * S_ * S_, (long)S_ * S_,
        (long)HKV * HD * S_, (long)HD * S_,
        (long)S_ * D_, (long)HD,
        1.0f);

    // 7) out = AO @ ow
    mgemm<false, false, false, false><<<dim3(32, 32, 1), 256, SMEMB>>>(
        aoh, aol, owth, owtl, nullptr, out, nullptr, nullptr,
        D_, D_, D_, D_, 1, 1, 0, 0, 0, 0, 0, 0, 1.0f);
}

// round 5
// speedup vs baseline: 3.0000x; 1.1194x over previous
#include <cuda_runtime.h>
#include <cuda_bf16.h>

typedef unsigned short u16;
typedef unsigned int   u32;

#define B_   2
#define S_   2048
#define D_   4096
#define HQ   32
#define HKV  8
#define HD   128
#define GRP  4
#define MR   (B_*S_)   // 4096

// ---------------- scratch (__device__ globals; no runtime allocation) -------
__device__ float g_q[(size_t)MR*D_];
__device__ float g_k[(size_t)MR*HKV*HD];
__device__ float g_v[(size_t)MR*HKV*HD];
__device__ float g_p[(size_t)B_*HQ*S_*S_];

__device__ u16 g_xh[(size_t)MR*D_],        g_xl[(size_t)MR*D_];
__device__ u16 g_qwt_h[(size_t)D_*D_],     g_qwt_l[(size_t)D_*D_];
__device__ u16 g_kwt_h[(size_t)1024*D_],   g_kwt_l[(size_t)1024*D_];
__device__ u16 g_vwt_h[(size_t)1024*D_],   g_vwt_l[(size_t)1024*D_];
__device__ u16 g_owt_h[(size_t)D_*D_],     g_owt_l[(size_t)D_*D_];
__device__ u16 g_qh[(size_t)MR*D_],        g_ql[(size_t)MR*D_];
__device__ u16 g_kh[(size_t)MR*HKV*HD],    g_kl[(size_t)MR*HKV*HD];
__device__ u16 g_vth[(size_t)B_*HKV*HD*S_],g_vtl[(size_t)B_*HKV*HD*S_];
__device__ u16 g_ph[(size_t)B_*HQ*S_*S_],  g_pl[(size_t)B_*HQ*S_*S_];
__device__ u16 g_aoh[(size_t)MR*D_],       g_aol[(size_t)MR*D_];

// ---------------------------------------------------------------------------
__device__ __forceinline__ void split2(float v, u16& h, u16& l) {
    __nv_bfloat16 hb = __float2bfloat16(v);
    float r = v - __bfloat162float(hb);
    h = __bfloat16_as_ushort(hb);
    l = __bfloat16_as_ushort(__float2bfloat16(r));
}

__device__ __forceinline__ u32 smem_u32(const void* p) {
    u32 a;
    asm("{ .reg .u64 t; cvta.to.shared.u64 t, %1; cvt.u32.u64 %0, t; }" : "=r"(a) : "l"(p));
    return a;
}

__device__ __forceinline__ void cp16(u32 sdst, const void* gsrc) {
    asm volatile("cp.async.cg.shared.global [%0], [%1], 16;\n" :: "r"(sdst), "l"(gsrc));
}
#define CP_COMMIT()  asm volatile("cp.async.commit_group;" ::: "memory")
#define CP_WAIT1()   asm volatile("cp.async.wait_group 1;" ::: "memory")
#define CP_WAIT0()   asm volatile("cp.async.wait_group 0;" ::: "memory")

__device__ __forceinline__ void ldsm4(u32* r, u32 addr) {
    asm volatile("ldmatrix.sync.aligned.m8n8.x4.shared.b16 {%0,%1,%2,%3}, [%4];"
        : "=r"(r[0]), "=r"(r[1]), "=r"(r[2]), "=r"(r[3]) : "r"(addr));
}

__device__ __forceinline__ void mma16816(float* d, const u32* a, const u32* b) {
    asm volatile(
        "mma.sync.aligned.m16n8k16.row.col.f32.bf16.bf16.f32 "
        "{%0,%1,%2,%3}, {%4,%5,%6,%7}, {%8,%9}, {%0,%1,%2,%3};\n"
        : "+f"(d[0]), "+f"(d[1]), "+f"(d[2]), "+f"(d[3])
        : "r"(a[0]), "r"(a[1]), "r"(a[2]), "r"(a[3]), "r"(b[0]), "r"(b[1]));
}

// ---------------------------------------------------------------------------
// Split-bf16 tensor GEMM: C = alpha * A @ B^T (+bias)
// A:[M,K] split bf16 row-major; B:[N,K] split bf16 row-major.
// CTA tile 128 x NT (NT=256 or 128), BK=64, double-buffered cp.async,
// SW128 XOR-swizzled smem (128B rows, no padding), ldmatrix fragments,
// 3-term compensated product (Ah*Bh + Al*Bh + Ah*Bl). 256 threads,
// warp tile 64 x (NT/4).
// ---------------------------------------------------------------------------
template<int NT, bool BIAS, bool CSKIP, bool CKLIM, bool SOUT>
__global__ __launch_bounds__(256, 1)
void mgemm(const u16* __restrict__ Agh, const u16* __restrict__ Agl,
           const u16* __restrict__ Bgh, const u16* __restrict__ Bgl,
           const float* __restrict__ bias,
           float* __restrict__ Cf, u16* __restrict__ Ch, u16* __restrict__ Cl,
           int K, int lda, int ldb, int ldc,
           int H, int Gdiv,
           long sAb, long sAh, long sBb, long sBh, long sCb, long sCh,
           float alpha)
{
    constexpr int NJ  = NT / 32;           // n-tiles per warp (8 or 4)
    constexpr int STG = 32768 + 2 * NT * 128;
    extern __shared__ __align__(16) char dsm[];

    int m0 = blockIdx.y * 128, n0 = blockIdx.x * NT;
    if (CSKIP && n0 > m0 + 127) return;

    int z = blockIdx.z, b = z / H, h = z - b * H;
    const u16* Aph = Agh + b * sAb + (long)h * sAh;
    const u16* Apl = Agl + b * sAb + (long)h * sAh;
    const u16* Bph = Bgh + b * sBb + (long)(h / Gdiv) * sBh;
    const u16* Bpl = Bgl + b * sBb + (long)(h / Gdiv) * sBh;

    int tid = threadIdx.x, wid = tid >> 5, lane = tid & 31;
    int wx = wid & 3, wy = wid >> 2;
    int g = lane >> 2, tg = lane & 3;

    u32 sbase = smem_u32(dsm);

    // fragment row bases + swizzle keys
    int aRow = ((lane >> 3) & 1) * 8 + (lane & 7);
    int aKu  = lane >> 4;                  // 16B-unit offset within 32B kk step
    u32 aBase[4]; int aSw[4];
    #pragma unroll
    for (int mi = 0; mi < 4; mi++) {
        int r = wy * 64 + mi * 16 + aRow;
        aBase[mi] = (u32)(r * 128); aSw[mi] = r & 7;
    }
    int bRow = (lane >> 4) * 8 + (lane & 7);
    int bKu  = (lane >> 3) & 1;
    u32 bBase[NJ / 2]; int bSw[NJ / 2];
    #pragma unroll
    for (int p = 0; p < NJ / 2; p++) {
        int r = wx * (NT / 4) + p * 16 + bRow;
        bBase[p] = (u32)(r * 128); bSw[p] = r & 7;
    }

    float d[4][NJ][4];
    #pragma unroll
    for (int i = 0; i < 4; i++)
        #pragma unroll
        for (int j = 0; j < NJ; j++)
            #pragma unroll
            for (int q = 0; q < 4; q++) d[i][j][q] = 0.f;

    int kEnd = K;
    if (CKLIM) { int ke = m0 + 128; kEnd = ke < K ? ke : K; }
    int nch = kEnd >> 6;

    // ---- async loader: one 64-wide K chunk into stage s (SW128 layout) ----
    auto prefetch = [&](int c, int s) {
        u32 st = sbase + s * STG;
        int k0 = c << 6;
        constexpr int TOT = (256 + 2 * NT) * 8;
        #pragma unroll
        for (int u0 = 0; u0 < TOT; u0 += 256) {
            int u = u0 + tid;
            int row, c16;
            const u16* gp;
            u32 abase;
            if (u0 < 2048) {                       // A (hi then lo)
                row = (u >> 3) & 127; c16 = u & 7;
                bool lo = u >= 1024;
                gp = (lo ? Apl : Aph) + (long)(m0 + row) * lda + k0 + c16 * 8;
                abase = st + (lo ? 16384u : 0u);
            } else {                               // B (hi then lo)
                int v = u - 2048;
                row = (v >> 3) & (NT - 1); c16 = v & 7;
                bool lo = v >= NT * 8;
                gp = (lo ? Bpl : Bph) + (long)(n0 + row) * ldb + k0 + c16 * 8;
                abase = st + 32768u + (lo ? (u32)(NT * 128) : 0u);
            }
            u32 so = abase + (u32)(row * 128) + ((u32)(c16 ^ (row & 7)) << 4);
            cp16(so, gp);
        }
    };

    prefetch(0, 0);
    CP_COMMIT();

    for (int c = 0; c < nch; c++) {
        if (c + 1 < nch) { prefetch(c + 1, (c + 1) & 1); CP_COMMIT(); CP_WAIT1(); }
        else             { CP_WAIT0(); }
        __syncthreads();

        u32 st = sbase + (c & 1) * STG;
        u32 sAh_ = st, sAl_ = st + 16384, sBh_ = st + 32768, sBl_ = st + 32768 + NT * 128;

        #pragma unroll
        for (int kk = 0; kk < 4; kk++) {
            int kuA = kk * 2 + aKu;
            int kuB = kk * 2 + bKu;
            u32 ah[4][4], xa[4][4], xb[NJ / 2][4];
            #pragma unroll
            for (int mi = 0; mi < 4; mi++)
                ldsm4(ah[mi], sAh_ + aBase[mi] + ((u32)(kuA ^ aSw[mi]) << 4));
            #pragma unroll
            for (int p = 0; p < NJ / 2; p++)
                ldsm4(xb[p], sBh_ + bBase[p] + ((u32)(kuB ^ bSw[p]) << 4));
            #pragma unroll
            for (int mi = 0; mi < 4; mi++)
                #pragma unroll
                for (int nj = 0; nj < NJ; nj++)
                    mma16816(d[mi][nj], ah[mi], &xb[nj >> 1][(nj & 1) * 2]);
            #pragma unroll
            for (int mi = 0; mi < 4; mi++)
                ldsm4(xa[mi], sAl_ + aBase[mi] + ((u32)(kuA ^ aSw[mi]) << 4));
            #pragma unroll
            for (int mi = 0; mi < 4; mi++)
                #pragma unroll
                for (int nj = 0; nj < NJ; nj++)
                    mma16816(d[mi][nj], xa[mi], &xb[nj >> 1][(nj & 1) * 2]);
            #pragma unroll
            for (int p = 0; p < NJ / 2; p++)
                ldsm4(xb[p], sBl_ + bBase[p] + ((u32)(kuB ^ bSw[p]) << 4));
            #pragma unroll
            for (int mi = 0; mi < 4; mi++)
                #pragma unroll
                for (int nj = 0; nj < NJ; nj++)
                    mma16816(d[mi][nj], ah[mi], &xb[nj >> 1][(nj & 1) * 2]);
        }
        __syncthreads();
    }

    // epilogue
    #pragma unroll
    for (int mi = 0; mi < 4; mi++) {
        #pragma unroll
        for (int nj = 0; nj < NJ; nj++) {
            int r = m0 + wy * 64 + mi * 16 + g;
            int c = n0 + wx * (NT / 4) + nj * 8 + tg * 2;
            float v0 = d[mi][nj][0] * alpha, v1 = d[mi][nj][1] * alpha;
            float v2 = d[mi][nj][2] * alpha, v3 = d[mi][nj][3] * alpha;
            if (BIAS) {
                float b0 = bias[c], b1 = bias[c + 1];
                v0 += b0; v1 += b1; v2 += b0; v3 += b1;
            }
            long o0 = b * sCb + (long)h * sCh + (long)r * ldc + c;
            long o1 = o0 + 8L * ldc;
            if (SOUT) {
                u16 h0, l0, h1, l1;
                split2(v0, h0, l0); split2(v1, h1, l1);
                *(u32*)&Ch[o0] = (u32)h0 | ((u32)h1 << 16);
                *(u32*)&Cl[o0] = (u32)l0 | ((u32)l1 << 16);
                split2(v2, h0, l0); split2(v3, h1, l1);
                *(u32*)&Ch[o1] = (u32)h0 | ((u32)h1 << 16);
                *(u32*)&Cl[o1] = (u32)l0 | ((u32)l1 << 16);
            } else {
                *(float2*)&Cf[o0] = make_float2(v0, v1);
                *(float2*)&Cf[o1] = make_float2(v2, v3);
            }
        }
    }
}

// ---------------------------------------------------------------------------
__global__ void conv_split(const float* __restrict__ in, u16* __restrict__ oh,
                           u16* __restrict__ ol, long n)
{
    long i = blockIdx.x * 256L + threadIdx.x;
    if (i < n) split2(in[i], oh[i], ol[i]);
}

__global__ void tsplit(const float* __restrict__ in, u16* __restrict__ oh,
                       u16* __restrict__ ol, int ldin, int ldout,
                       long sInB, long sInH, long sOutZ, int Hc)
{
    __shared__ float t[32][33];
    int z = blockIdx.z, bb = z / Hc, hh = z - bb * Hc;
    const float* ip = in + bb * sInB + (long)hh * sInH;
    int c0 = blockIdx.x * 32, r0 = blockIdx.y * 32;
    #pragma unroll
    for (int i = 0; i < 4; i++)
        t[threadIdx.y + i * 8][threadIdx.x] =
            ip[(long)(r0 + threadIdx.y + i * 8) * ldin + c0 + threadIdx.x];
    __syncthreads();
    #pragma unroll
    for (int i = 0; i < 4; i++) {
        int orow = c0 + threadIdx.y + i * 8;
        int oc = r0 + threadIdx.x;
        float v = t[threadIdx.x][threadIdx.y + i * 8];
        long o = z * sOutZ + (long)orow * ldout + oc;
        split2(v, oh[o], ol[o]);
    }
}

__global__ void rope_split(const float* __restrict__ t, u16* __restrict__ oh,
                           u16* __restrict__ ol, const float* __restrict__ cosb,
                           const float* __restrict__ sinb,
                           const int* __restrict__ start_pos, int heads, long total)
{
    long idx = blockIdx.x * 256L + threadIdx.x;
    if (idx >= total) return;
    int i = (int)(idx & 63);
    long tmp = idx >> 6;
    int h = (int)(tmp % heads);
    long row = tmp / heads;
    int s = (int)(row % S_) + *start_pos;
    float c = cosb[s * 64 + i];
    float sn = sinb[s * 64 + i];
    long base = row * (long)(heads * HD) + (long)h * HD + 2 * i;
    float x0 = t[base], x1 = t[base + 1];
    float o0 = x0 * c - x1 * sn;
    float o1 = x0 * sn + x1 * c;
    split2(o0, oh[base], ol[base]);
    split2(o1, oh[base + 1], ol[base + 1]);
}

// causal softmax, single exp pass (values cached in registers)
__global__ __launch_bounds__(256) void softmax_split(const float* __restrict__ P,
                                                     u16* __restrict__ Ph,
                                                     u16* __restrict__ Pl)
{
    long r = blockIdx.x;
    int i = (int)(r % S_);
    const float* row = P + r * (long)S_;
    u16* rh = Ph + r * (long)S_;
    u16* rl = Pl + r * (long)S_;
    int L = i + 1;
    int wlim = ((i >> 7) + 1) << 7;
    int tid = threadIdx.x;
    __shared__ float red[256];

    float m = -1e30f;
    float xv[8];
    int cnt = 0;
    for (int j = tid; j < L; j += 256) {
        float v = row[j];
        xv[cnt++] = v;
        m = fmaxf(m, v);
    }
    red[tid] = m; __syncthreads();
    for (int s = 128; s > 0; s >>= 1) {
        if (tid < s) red[tid] = fmaxf(red[tid], red[tid + s]);
        __syncthreads();
    }
    float gmax = red[0]; __syncthreads();

    float sum = 0.f;
    #pragma unroll
    for (int t = 0; t < 8; t++) {
        if (t < cnt) {
            float e = __expf(xv[t] - gmax);
            xv[t] = e;
            sum += e;
        }
    }
    red[tid] = sum; __syncthreads();
    for (int s = 128; s > 0; s >>= 1) {
        if (tid < s) red[tid] += red[tid + s];
        __syncthreads();
    }
    float inv = 1.0f / red[0];

    int cnt2 = 0;
    for (int j = tid; j < L; j += 256) {
        float w = xv[cnt2++] * inv;
        split2(w, rh[j], rl[j]);
    }
    for (int j = L + tid; j < wlim; j += 256) { rh[j] = 0; rl[j] = 0; }
}

// ---------------------------------------------------------------------------
extern "C" void kernel_launch(void* const* d_in, const int* in_sizes, int n_in,
                              void* d_out, int out_size)
{
    const float* x  = (const float*)d_in[0];
    const float* fc = (const float*)d_in[1];
    const float* fs = (const float*)d_in[2];
    const float* qw = (const float*)d_in[3];
    const float* qb = (const float*)d_in[4];
    const float* kw = (const float*)d_in[5];
    const float* kb = (const float*)d_in[6];
    const float* vw = (const float*)d_in[7];
    const float* vb = (const float*)d_in[8];
    const float* ow = (const float*)d_in[9];
    const int*   sp = (const int*)d_in[10];
    float* out = (float*)d_out;

    float *q, *k, *v, *p;
    u16 *xh, *xl, *qwth, *qwtl, *kwth, *kwtl, *vwth, *vwtl, *owth, *owtl;
    u16 *qh, *ql, *kh, *kl, *vth, *vtl, *ph, *pl, *aoh, *aol;
    cudaGetSymbolAddress((void**)&q, g_q);
    cudaGetSymbolAddress((void**)&k, g_k);
    cudaGetSymbolAddress((void**)&v, g_v);
    cudaGetSymbolAddress((void**)&p, g_p);
    cudaGetSymbolAddress((void**)&xh, g_xh);   cudaGetSymbolAddress((void**)&xl, g_xl);
    cudaGetSymbolAddress((void**)&qwth, g_qwt_h); cudaGetSymbolAddress((void**)&qwtl, g_qwt_l);
    cudaGetSymbolAddress((void**)&kwth, g_kwt_h); cudaGetSymbolAddress((void**)&kwtl, g_kwt_l);
    cudaGetSymbolAddress((void**)&vwth, g_vwt_h); cudaGetSymbolAddress((void**)&vwtl, g_vwt_l);
    cudaGetSymbolAddress((void**)&owth, g_owt_h); cudaGetSymbolAddress((void**)&owtl, g_owt_l);
    cudaGetSymbolAddress((void**)&qh, g_qh);   cudaGetSymbolAddress((void**)&ql, g_ql);
    cudaGetSymbolAddress((void**)&kh, g_kh);   cudaGetSymbolAddress((void**)&kl, g_kl);
    cudaGetSymbolAddress((void**)&vth, g_vth); cudaGetSymbolAddress((void**)&vtl, g_vtl);
    cudaGetSymbolAddress((void**)&ph, g_ph);   cudaGetSymbolAddress((void**)&pl, g_pl);
    cudaGetSymbolAddress((void**)&aoh, g_aoh); cudaGetSymbolAddress((void**)&aol, g_aol);

    const int SM256 = 2 * (32768 + 2 * 256 * 128);   // 196608
    const int SM128 = 2 * (32768 + 2 * 128 * 128);   // 131072
    cudaFuncSetAttribute((const void*)mgemm<256, true,  false, false, false>,
                         cudaFuncAttributeMaxDynamicSharedMemorySize, SM256);
    cudaFuncSetAttribute((const void*)mgemm<256, false, true,  false, false>,
                         cudaFuncAttributeMaxDynamicSharedMemorySize, SM256);
    cudaFuncSetAttribute((const void*)mgemm<128, false, false, true,  true>,
                         cudaFuncAttributeMaxDynamicSharedMemorySize, SM128);
    cudaFuncSetAttribute((const void*)mgemm<256, false, false, false, false>,
                         cudaFuncAttributeMaxDynamicSharedMemorySize, SM256);

    // 1) split-convert activations and weights (weights transposed to [N,K])
    conv_split<<<(unsigned)(((long)MR * D_ + 255) / 256), 256>>>(x, xh, xl, (long)MR * D_);
    dim3 tb(32, 8);
    tsplit<<<dim3(128, 128, 1), tb>>>(qw, qwth, qwtl, D_, D_, 0, 0, 0, 1);
    tsplit<<<dim3(32, 128, 1), tb>>>(kw, kwth, kwtl, 1024, D_, 0, 0, 0, 1);
    tsplit<<<dim3(32, 128, 1), tb>>>(vw, vwth, vwtl, 1024, D_, 0, 0, 0, 1);
    tsplit<<<dim3(128, 128, 1), tb>>>(ow, owth, owtl, D_, D_, 0, 0, 0, 1);

    // 2) projections (tensor-core, fused bias) -> fp32 q/k/v
    mgemm<256, true, false, false, false><<<dim3(16, 32, 1), 256, SM256>>>(
        xh, xl, qwth, qwtl, qb, q, nullptr, nullptr,
        D_, D_, D_, D_, 1, 1, 0, 0, 0, 0, 0, 0, 1.0f);
    mgemm<256, true, false, false, false><<<dim3(4, 32, 1), 256, SM256>>>(
        xh, xl, kwth, kwtl, kb, k, nullptr, nullptr,
        D_, D_, D_, 1024, 1, 1, 0, 0, 0, 0, 0, 0, 1.0f);
    mgemm<256, true, false, false, false><<<dim3(4, 32, 1), 256, SM256>>>(
        xh, xl, vwth, vwtl, vb, v, nullptr, nullptr,
        D_, D_, D_, 1024, 1, 1, 0, 0, 0, 0, 0, 0, 1.0f);

    // 3) RoPE + split-convert q,k ; transpose+split v -> [b,h,d,s]
    long tq = (long)MR * HQ * 64;
    rope_split<<<(unsigned)((tq + 255) / 256), 256>>>(q, qh, ql, fc, fs, sp, HQ, tq);
    long tk = (long)MR * HKV * 64;
    rope_split<<<(unsigned)((tk + 255) / 256), 256>>>(k, kh, kl, fc, fs, sp, HKV, tk);
    tsplit<<<dim3(4, 64, B_ * HKV), tb>>>(v, vth, vtl, 1024, S_,
        (long)S_ * 1024, (long)HD, (long)HD * S_, HKV);

    // 4) scores = (1/sqrt(128)) * Q @ K^T  (causal block skip) -> fp32 p
    mgemm<256, false, true, false, false><<<dim3(8, 16, B_ * HQ), 256, SM256>>>(
        qh, ql, kh, kl, nullptr, p, nullptr, nullptr,
        HD, D_, 1024, S_, HQ, GRP,
        (long)S_ * D_, (long)HD,
        (long)S_ * 1024, (long)HD,
        (long)HQ * S_ * S_, (long)S_ * S_,
        0.08838834764831845f);

    // 5) softmax -> split bf16 P (zero-filled to 128-boundary)
    softmax_split<<<(unsigned)((long)B_ * HQ * S_), 256>>>(p, ph, pl);

    // 6) AO = P @ V (causal K limit), split-bf16 output in [b,s,h*128+d]
    mgemm<128, false, false, true, true><<<dim3(1, 16, B_ * HQ), 256, SM128>>>(
        ph, pl, vth, vtl, nullptr, nullptr, aoh, aol,
        S_, S_, S_, D_, HQ, GRP,
        (long)HQ * S_ * S_, (long)S_ * S_,
        (long)HKV * HD * S_, (long)HD * S_,
        (long)S_ * D_, (long)HD,
        1.0f);

    // 7) out = AO @ ow
    mgemm<256, false, false, false, false><<<dim3(16, 32, 1), 256, SM256>>>(
        aoh, aol, owth, owtl, nullptr, out, nullptr, nullptr,
        D_, D_, D_, D_, 1, 1, 0, 0, 0, 0, 0, 0, 1.0f);
}

// round 6
// speedup vs baseline: 3.2018x; 1.0673x over previous
#include <cuda_runtime.h>
#include <cuda_bf16.h>

typedef unsigned short u16;
typedef unsigned int   u32;

#define B_   2
#define S_   2048
#define D_   4096
#define HQ   32
#define HKV  8
#define HD   128
#define GRP  4
#define MR   (B_*S_)   // 4096

// ---------------- scratch (__device__ globals; no runtime allocation) -------
__device__ float g_v[(size_t)MR*HKV*HD];             // fp32 V (pre-transpose)
__device__ float g_p[(size_t)B_*HQ*S_*S_];           // fp32 scores

__device__ u16 g_xh[(size_t)MR*D_],        g_xl[(size_t)MR*D_];
__device__ u16 g_qwt_h[(size_t)D_*D_],     g_qwt_l[(size_t)D_*D_];
__device__ u16 g_kwt_h[(size_t)1024*D_],   g_kwt_l[(size_t)1024*D_];
__device__ u16 g_vwt_h[(size_t)1024*D_],   g_vwt_l[(size_t)1024*D_];
__device__ u16 g_owt_h[(size_t)D_*D_],     g_owt_l[(size_t)D_*D_];
__device__ u16 g_qh[(size_t)MR*D_],        g_ql[(size_t)MR*D_];           // rope'd Q
__device__ u16 g_kh[(size_t)MR*HKV*HD],    g_kl[(size_t)MR*HKV*HD];       // rope'd K
__device__ u16 g_vth[(size_t)B_*HKV*HD*S_],g_vtl[(size_t)B_*HKV*HD*S_];   // V^T [b,h,d,s]
__device__ u16 g_aoh[(size_t)MR*D_],       g_aol[(size_t)MR*D_];          // attn out

// ---------------------------------------------------------------------------
__device__ __forceinline__ void split2(float v, u16& h, u16& l) {
    __nv_bfloat16 hb = __float2bfloat16(v);
    float r = v - __bfloat162float(hb);
    h = __bfloat16_as_ushort(hb);
    l = __bfloat16_as_ushort(__float2bfloat16(r));
}

__device__ __forceinline__ u32 smem_u32(const void* p) {
    u32 a;
    asm("{ .reg .u64 t; cvta.to.shared.u64 t, %1; cvt.u32.u64 %0, t; }" : "=r"(a) : "l"(p));
    return a;
}

__device__ __forceinline__ void cp16(u32 sdst, const void* gsrc) {
    asm volatile("cp.async.cg.shared.global [%0], [%1], 16;\n" :: "r"(sdst), "l"(gsrc));
}
#define CP_COMMIT()  asm volatile("cp.async.commit_group;" ::: "memory")
#define CP_WAIT1()   asm volatile("cp.async.wait_group 1;" ::: "memory")
#define CP_WAIT0()   asm volatile("cp.async.wait_group 0;" ::: "memory")

__device__ __forceinline__ void ldsm4(u32* r, u32 addr) {
    asm volatile("ldmatrix.sync.aligned.m8n8.x4.shared.b16 {%0,%1,%2,%3}, [%4];"
        : "=r"(r[0]), "=r"(r[1]), "=r"(r[2]), "=r"(r[3]) : "r"(addr));
}

__device__ __forceinline__ void mma16816(float* d, const u32* a, const u32* b) {
    asm volatile(
        "mma.sync.aligned.m16n8k16.row.col.f32.bf16.bf16.f32 "
        "{%0,%1,%2,%3}, {%4,%5,%6,%7}, {%8,%9}, {%0,%1,%2,%3};\n"
        : "+f"(d[0]), "+f"(d[1]), "+f"(d[2]), "+f"(d[3])
        : "r"(a[0]), "r"(a[1]), "r"(a[2]), "r"(a[3]), "r"(b[0]), "r"(b[1]));
}

// ---------------------------------------------------------------------------
// Split-bf16 tensor GEMM: C = alpha * A @ B^T (+bias) [+RoPE on output pairs]
// 128 x NT CTA tile, BK=64, 2-stage cp.async, SW128 swizzle, ldmatrix,
// 3-term compensated product. ROPE => rope applied then split bf16 output.
// ---------------------------------------------------------------------------
template<int NT, bool BIAS, bool CSKIP, bool ROPE>
__global__ __launch_bounds__(256, 1)
void mgemm(const u16* __restrict__ Agh, const u16* __restrict__ Agl,
           const u16* __restrict__ Bgh, const u16* __restrict__ Bgl,
           const float* __restrict__ bias,
           float* __restrict__ Cf, u16* __restrict__ Ch, u16* __restrict__ Cl,
           int K, int lda, int ldb, int ldc,
           int H, int Gdiv,
           long sAb, long sAh, long sBb, long sBh, long sCb, long sCh,
           float alpha,
           const float* __restrict__ fc, const float* __restrict__ fs,
           const int* __restrict__ sp)
{
    constexpr int NJ  = NT / 32;
    constexpr int STG = 32768 + 2 * NT * 128;
    extern __shared__ __align__(16) char dsm[];

    int m0 = blockIdx.y * 128, n0 = blockIdx.x * NT;
    if (CSKIP && n0 > m0 + 127) return;

    int z = blockIdx.z, b = z / H, h = z - b * H;
    const u16* Aph = Agh + b * sAb + (long)h * sAh;
    const u16* Apl = Agl + b * sAb + (long)h * sAh;
    const u16* Bph = Bgh + b * sBb + (long)(h / Gdiv) * sBh;
    const u16* Bpl = Bgl + b * sBb + (long)(h / Gdiv) * sBh;

    int tid = threadIdx.x, wid = tid >> 5, lane = tid & 31;
    int wx = wid & 3, wy = wid >> 2;
    int g = lane >> 2, tg = lane & 3;

    u32 sbase = smem_u32(dsm);

    int aRow = ((lane >> 3) & 1) * 8 + (lane & 7);
    int aKu  = lane >> 4;
    u32 aBase[4]; int aSw[4];
    #pragma unroll
    for (int mi = 0; mi < 4; mi++) {
        int r = wy * 64 + mi * 16 + aRow;
        aBase[mi] = (u32)(r * 128); aSw[mi] = r & 7;
    }
    int bRow = (lane >> 4) * 8 + (lane & 7);
    int bKu  = (lane >> 3) & 1;
    u32 bBase[NJ / 2]; int bSw[NJ / 2];
    #pragma unroll
    for (int p = 0; p < NJ / 2; p++) {
        int r = wx * (NT / 4) + p * 16 + bRow;
        bBase[p] = (u32)(r * 128); bSw[p] = r & 7;
    }

    float d[4][NJ][4];
    #pragma unroll
    for (int i = 0; i < 4; i++)
        #pragma unroll
        for (int j = 0; j < NJ; j++)
            #pragma unroll
            for (int q = 0; q < 4; q++) d[i][j][q] = 0.f;

    int nch = K >> 6;

    auto prefetch = [&](int c, int s) {
        u32 st = sbase + s * STG;
        int k0 = c << 6;
        constexpr int TOT = (256 + 2 * NT) * 8;
        #pragma unroll
        for (int u0 = 0; u0 < TOT; u0 += 256) {
            int u = u0 + tid;
            int row, c16;
            const u16* gp;
            u32 abase;
            if (u0 < 2048) {
                row = (u >> 3) & 127; c16 = u & 7;
                bool lo = u >= 1024;
                gp = (lo ? Apl : Aph) + (long)(m0 + row) * lda + k0 + c16 * 8;
                abase = st + (lo ? 16384u : 0u);
            } else {
                int v = u - 2048;
                row = (v >> 3) & (NT - 1); c16 = v & 7;
                bool lo = v >= NT * 8;
                gp = (lo ? Bpl : Bph) + (long)(n0 + row) * ldb + k0 + c16 * 8;
                abase = st + 32768u + (lo ? (u32)(NT * 128) : 0u);
            }
            u32 so = abase + (u32)(row * 128) + ((u32)(c16 ^ (row & 7)) << 4);
            cp16(so, gp);
        }
    };

    prefetch(0, 0);
    CP_COMMIT();

    for (int c = 0; c < nch; c++) {
        if (c + 1 < nch) { prefetch(c + 1, (c + 1) & 1); CP_COMMIT(); CP_WAIT1(); }
        else             { CP_WAIT0(); }
        __syncthreads();

        u32 st = sbase + (c & 1) * STG;
        u32 sAh_ = st, sAl_ = st + 16384, sBh_ = st + 32768, sBl_ = st + 32768 + NT * 128;

        #pragma unroll
        for (int kk = 0; kk < 4; kk++) {
            int kuA = kk * 2 + aKu;
            int kuB = kk * 2 + bKu;
            u32 ah[4][4], xa[4][4], xb[NJ / 2][4];
            #pragma unroll
            for (int mi = 0; mi < 4; mi++)
                ldsm4(ah[mi], sAh_ + aBase[mi] + ((u32)(kuA ^ aSw[mi]) << 4));
            #pragma unroll
            for (int p = 0; p < NJ / 2; p++)
                ldsm4(xb[p], sBh_ + bBase[p] + ((u32)(kuB ^ bSw[p]) << 4));
            #pragma unroll
            for (int mi = 0; mi < 4; mi++)
                #pragma unroll
                for (int nj = 0; nj < NJ; nj++)
                    mma16816(d[mi][nj], ah[mi], &xb[nj >> 1][(nj & 1) * 2]);
            #pragma unroll
            for (int mi = 0; mi < 4; mi++)
                ldsm4(xa[mi], sAl_ + aBase[mi] + ((u32)(kuA ^ aSw[mi]) << 4));
            #pragma unroll
            for (int mi = 0; mi < 4; mi++)
                #pragma unroll
                for (int nj = 0; nj < NJ; nj++)
                    mma16816(d[mi][nj], xa[mi], &xb[nj >> 1][(nj & 1) * 2]);
            #pragma unroll
            for (int p = 0; p < NJ / 2; p++)
                ldsm4(xb[p], sBl_ + bBase[p] + ((u32)(kuB ^ bSw[p]) << 4));
            #pragma unroll
            for (int mi = 0; mi < 4; mi++)
                #pragma unroll
                for (int nj = 0; nj < NJ; nj++)
                    mma16816(d[mi][nj], ah[mi], &xb[nj >> 1][(nj & 1) * 2]);
        }
        __syncthreads();
    }

    int sp0 = ROPE ? *sp : 0;

    #pragma unroll
    for (int mi = 0; mi < 4; mi++) {
        #pragma unroll
        for (int nj = 0; nj < NJ; nj++) {
            int r = m0 + wy * 64 + mi * 16 + g;
            int c = n0 + wx * (NT / 4) + nj * 8 + tg * 2;
            float v0 = d[mi][nj][0] * alpha, v1 = d[mi][nj][1] * alpha;
            float v2 = d[mi][nj][2] * alpha, v3 = d[mi][nj][3] * alpha;
            if (BIAS) {
                float b0 = bias[c], b1 = bias[c + 1];
                v0 += b0; v1 += b1; v2 += b0; v3 += b1;
            }
            long o0 = b * sCb + (long)h * sCh + (long)r * ldc + c;
            long o1 = o0 + 8L * ldc;
            if (ROPE) {
                int i_ = (c & 127) >> 1;
                int s0 = (r & (S_ - 1)) + sp0;
                int s8 = ((r + 8) & (S_ - 1)) + sp0;
                float c0f = fc[s0 * 64 + i_], s0f = fs[s0 * 64 + i_];
                float c8f = fc[s8 * 64 + i_], s8f = fs[s8 * 64 + i_];
                float r0 = v0 * c0f - v1 * s0f, r1 = v0 * s0f + v1 * c0f;
                float r2 = v2 * c8f - v3 * s8f, r3 = v2 * s8f + v3 * c8f;
                u16 h0, l0, h1, l1;
                split2(r0, h0, l0); split2(r1, h1, l1);
                *(u32*)&Ch[o0] = (u32)h0 | ((u32)h1 << 16);
                *(u32*)&Cl[o0] = (u32)l0 | ((u32)l1 << 16);
                split2(r2, h0, l0); split2(r3, h1, l1);
                *(u32*)&Ch[o1] = (u32)h0 | ((u32)h1 << 16);
                *(u32*)&Cl[o1] = (u32)l0 | ((u32)l1 << 16);
            } else {
                *(float2*)&Cf[o0] = make_float2(v0, v1);
                *(float2*)&Cf[o1] = make_float2(v2, v3);
            }
        }
    }
}

// ---------------------------------------------------------------------------
// Fused online-softmax + PV. One CTA per (m-tile, b, h). Reads fp32 scores
// (alpha already applied) + split V^T; writes split-bf16 attention output.
// Smem: P(hi/lo) 32KB single-buffered, V stages 2x32KB, stats 1.5KB.
// ---------------------------------------------------------------------------
#define PV_PH    0
#define PV_PL    16384
#define PV_V     32768          // + s*32768 ; lo at +16384
#define PV_STATS 98304
#define PV_SMEM  (98304 + 1536)

__global__ __launch_bounds__(256, 1)
void pv_fused(const float* __restrict__ Pg,
              const u16* __restrict__ Vth, const u16* __restrict__ Vtl,
              u16* __restrict__ Oh, u16* __restrict__ Ol)
{
    extern __shared__ __align__(16) char dsm[];
    u32 sbase = smem_u32(dsm);
    float* m_run = (float*)(dsm + PV_STATS);
    float* l_run = m_run + 128;
    float* fch   = m_run + 256;

    int m0 = (int)(gridDim.x - 1 - blockIdx.x) * 128;     // heavy tiles first
    int z = blockIdx.y, b = z / HQ, h = z - b * HQ;

    const float* Sp = Pg + (long)b * HQ * S_ * S_ + (long)h * S_ * S_;
    const u16* Vph = Vth + ((long)b * HKV + (h / GRP)) * (long)HD * S_;
    const u16* Vpl = Vtl + ((long)b * HKV + (h / GRP)) * (long)HD * S_;

    int tid = threadIdx.x, wid = tid >> 5, lane = tid & 31;
    int wx = wid & 3, wy = wid >> 2;
    int g = lane >> 2, tg = lane & 3;

    // stats row ownership: r = tid>>1, half = tid&1 scans 32 cols
    int r_own = tid >> 1, half = tid & 1;
    int gr = m0 + r_own;
    const float* rowp = Sp + (long)gr * S_;
    int ch0 = half * 32;

    if (tid < 128) { m_run[tid] = -1e30f; l_run[tid] = 0.f; }
    __syncthreads();

    // fragment offsets (same pattern as mgemm, NT=128)
    int aRow = ((lane >> 3) & 1) * 8 + (lane & 7);
    int aKu  = lane >> 4;
    u32 aBase[4]; int aSw[4];
    #pragma unroll
    for (int mi = 0; mi < 4; mi++) {
        int rr = wy * 64 + mi * 16 + aRow;
        aBase[mi] = (u32)(rr * 128); aSw[mi] = rr & 7;
    }
    int bRow = (lane >> 4) * 8 + (lane & 7);
    int bKu  = (lane >> 3) & 1;
    u32 bBase[2]; int bSw[2];
    #pragma unroll
    for (int p = 0; p < 2; p++) {
        int rr = wx * 32 + p * 16 + bRow;
        bBase[p] = (u32)(rr * 128); bSw[p] = rr & 7;
    }

    float d[4][4][4];
    #pragma unroll
    for (int i = 0; i < 4; i++)
        #pragma unroll
        for (int j = 0; j < 4; j++)
            #pragma unroll
            for (int q = 0; q < 4; q++) d[i][j][q] = 0.f;

    int nch = (m0 + 128) >> 6;

    auto vfetch = [&](int c, int s) {
        int k0 = c << 6;
        #pragma unroll
        for (int u0 = 0; u0 < 2048; u0 += 256) {
            int u = u0 + tid;
            bool lo = u >= 1024;
            int v = u & 1023;
            int row = v >> 3, c16 = v & 7;
            const u16* gp = (lo ? Vpl : Vph) + (long)row * S_ + k0 + c16 * 8;
            u32 so = sbase + PV_V + s * 32768 + (lo ? 16384u : 0u)
                   + (u32)(row * 128) + ((u32)(c16 ^ (row & 7)) << 4);
            cp16(so, gp);
        }
    };

    // score prefetch for chunk 0
    float4 scv[8];
    {
        const float4* sp4 = reinterpret_cast<const float4*>(rowp + ch0);
        #pragma unroll
        for (int j = 0; j < 8; j++) scv[j] = sp4[j];
    }
    vfetch(0, 0);
    CP_COMMIT();

    for (int c = 0; c < nch; c++) {
        int k0 = c << 6;
        if (c + 1 < nch) { vfetch(c + 1, (c + 1) & 1); CP_COMMIT(); }

        // chunk max (masked)
        float mx = -1e30f;
        #pragma unroll
        for (int j = 0; j < 8; j++) {
            int cb = k0 + ch0 + j * 4;
            if (cb + 0 <= gr) mx = fmaxf(mx, scv[j].x);
            if (cb + 1 <= gr) mx = fmaxf(mx, scv[j].y);
            if (cb + 2 <= gr) mx = fmaxf(mx, scv[j].z);
            if (cb + 3 <= gr) mx = fmaxf(mx, scv[j].w);
        }
        mx = fmaxf(mx, __shfl_xor_sync(0xffffffffu, mx, 1));
        if (half == 0) {
            float mo = m_run[r_own];
            float mn = fmaxf(mo, mx);
            fch[r_own] = __expf(mo - mn);
            m_run[r_own] = mn;
        }
        __syncthreads();

        // rescale accumulators
        #pragma unroll
        for (int mi = 0; mi < 4; mi++) {
            int rl = wy * 64 + mi * 16 + g;
            float f0 = fch[rl], f8 = fch[rl + 8];
            #pragma unroll
            for (int nj = 0; nj < 4; nj++) {
                d[mi][nj][0] *= f0; d[mi][nj][1] *= f0;
                d[mi][nj][2] *= f8; d[mi][nj][3] *= f8;
            }
        }

        // transform: P = exp(S - m), masked; write split bf16 to swizzled smem
        {
            float mrow = m_run[r_own];
            float sum = 0.f;
            #pragma unroll
            for (int j = 0; j < 8; j++) {
                int cb = k0 + ch0 + j * 4;
                float p0 = (cb + 0 <= gr) ? __expf(scv[j].x - mrow) : 0.f;
                float p1 = (cb + 1 <= gr) ? __expf(scv[j].y - mrow) : 0.f;
                float p2 = (cb + 2 <= gr) ? __expf(scv[j].z - mrow) : 0.f;
                float p3 = (cb + 3 <= gr) ? __expf(scv[j].w - mrow) : 0.f;
                sum += (p0 + p1) + (p2 + p3);
                int cc = ch0 + j * 4;
                u32 unit = (u32)((cc >> 3) ^ (r_own & 7));
                u32 off = (u32)(r_own * 128) + (unit << 4) + (u32)((cc & 7) * 2);
                u16 h0, l0, h1, l1;
                split2(p0, h0, l0); split2(p1, h1, l1);
                *(u32*)(dsm + PV_PH + off) = (u32)h0 | ((u32)h1 << 16);
                *(u32*)(dsm + PV_PL + off) = (u32)l0 | ((u32)l1 << 16);
                split2(p2, h0, l0); split2(p3, h1, l1);
                *(u32*)(dsm + PV_PH + off + 4) = (u32)h0 | ((u32)h1 << 16);
                *(u32*)(dsm + PV_PL + off + 4) = (u32)l0 | ((u32)l1 << 16);
            }
            sum += __shfl_xor_sync(0xffffffffu, sum, 1);
            if (half == 0) l_run[r_own] = l_run[r_own] * fch[r_own] + sum;
        }

        // prefetch scores for next chunk
        if (c + 1 < nch) {
            const float4* sp4 = reinterpret_cast<const float4*>(rowp + (k0 + 64) + ch0);
            #pragma unroll
            for (int j = 0; j < 8; j++) scv[j] = sp4[j];
        }

        if (c + 1 < nch) CP_WAIT1(); else CP_WAIT0();
        __syncthreads();

        // MMA: 3-term P @ V
        u32 sPh = sbase + PV_PH, sPl = sbase + PV_PL;
        u32 sVh = sbase + PV_V + (c & 1) * 32768, sVl = sVh + 16384;
        #pragma unroll
        for (int kk = 0; kk < 4; kk++) {
            int kuA = kk * 2 + aKu;
            int kuB = kk * 2 + bKu;
            u32 ah[4][4], xa[4][4], xb[2][4];
            #pragma unroll
            for (int mi = 0; mi < 4; mi++)
                ldsm4(ah[mi], sPh + aBase[mi] + ((u32)(kuA ^ aSw[mi]) << 4));
            #pragma unroll
            for (int p = 0; p < 2; p++)
                ldsm4(xb[p], sVh + bBase[p] + ((u32)(kuB ^ bSw[p]) << 4));
            #pragma unroll
            for (int mi = 0; mi < 4; mi++)
                #pragma unroll
                for (int nj = 0; nj < 4; nj++)
                    mma16816(d[mi][nj], ah[mi], &xb[nj >> 1][(nj & 1) * 2]);
            #pragma unroll
            for (int mi = 0; mi < 4; mi++)
                ldsm4(xa[mi], sPl + aBase[mi] + ((u32)(kuA ^ aSw[mi]) << 4));
            #pragma unroll
            for (int mi = 0; mi < 4; mi++)
                #pragma unroll
                for (int nj = 0; nj < 4; nj++)
                    mma16816(d[mi][nj], xa[mi], &xb[nj >> 1][(nj & 1) * 2]);
            #pragma unroll
            for (int p = 0; p < 2; p++)
                ldsm4(xb[p], sVl + bBase[p] + ((u32)(kuB ^ bSw[p]) << 4));
            #pragma unroll
            for (int mi = 0; mi < 4; mi++)
                #pragma unroll
                for (int nj = 0; nj < 4; nj++)
                    mma16816(d[mi][nj], ah[mi], &xb[nj >> 1][(nj & 1) * 2]);
        }
        __syncthreads();
    }

    // epilogue: divide by l, split, store [b, s, h*128 + col]
    #pragma unroll
    for (int mi = 0; mi < 4; mi++) {
        int rl = wy * 64 + mi * 16 + g;
        float i0 = 1.0f / l_run[rl];
        float i8 = 1.0f / l_run[rl + 8];
        #pragma unroll
        for (int nj = 0; nj < 4; nj++) {
            int cc = wx * 32 + nj * 8 + tg * 2;
            long o0 = ((long)b * S_ + m0 + rl) * D_ + h * HD + cc;
            long o1 = o0 + 8L * D_;
            float v0 = d[mi][nj][0] * i0, v1 = d[mi][nj][1] * i0;
            float v2 = d[mi][nj][2] * i8, v3 = d[mi][nj][3] * i8;
            u16 h0, l0, h1, l1;
            split2(v0, h0, l0); split2(v1, h1, l1);
            *(u32*)&Oh[o0] = (u32)h0 | ((u32)h1 << 16);
            *(u32*)&Ol[o0] = (u32)l0 | ((u32)l1 << 16);
            split2(v2, h0, l0); split2(v3, h1, l1);
            *(u32*)&Oh[o1] = (u32)h0 | ((u32)h1 << 16);
            *(u32*)&Ol[o1] = (u32)l0 | ((u32)l1 << 16);
        }
    }
}

// ---------------------------------------------------------------------------
__global__ void conv_split(const float* __restrict__ in, u16* __restrict__ oh,
                           u16* __restrict__ ol, long n)
{
    long i = blockIdx.x * 256L + threadIdx.x;
    if (i < n) split2(in[i], oh[i], ol[i]);
}

__global__ void tsplit(const float* __restrict__ in, u16* __restrict__ oh,
                       u16* __restrict__ ol, int ldin, int ldout,
                       long sInB, long sInH, long sOutZ, int Hc)
{
    __shared__ float t[32][33];
    int z = blockIdx.z, bb = z / Hc, hh = z - bb * Hc;
    const float* ip = in + bb * sInB + (long)hh * sInH;
    int c0 = blockIdx.x * 32, r0 = blockIdx.y * 32;
    #pragma unroll
    for (int i = 0; i < 4; i++)
        t[threadIdx.y + i * 8][threadIdx.x] =
            ip[(long)(r0 + threadIdx.y + i * 8) * ldin + c0 + threadIdx.x];
    __syncthreads();
    #pragma unroll
    for (int i = 0; i < 4; i++) {
        int orow = c0 + threadIdx.y + i * 8;
        int oc = r0 + threadIdx.x;
        float v = t[threadIdx.x][threadIdx.y + i * 8];
        long o = z * sOutZ + (long)orow * ldout + oc;
        split2(v, oh[o], ol[o]);
    }
}

// ---------------------------------------------------------------------------
extern "C" void kernel_launch(void* const* d_in, const int* in_sizes, int n_in,
                              void* d_out, int out_size)
{
    const float* x  = (const float*)d_in[0];
    const float* fc = (const float*)d_in[1];
    const float* fs = (const float*)d_in[2];
    const float* qw = (const float*)d_in[3];
    const float* qb = (const float*)d_in[4];
    const float* kw = (const float*)d_in[5];
    const float* kb = (const float*)d_in[6];
    const float* vw = (const float*)d_in[7];
    const float* vb = (const float*)d_in[8];
    const float* ow = (const float*)d_in[9];
    const int*   sp = (const int*)d_in[10];
    float* out = (float*)d_out;

    float *v, *p;
    u16 *xh, *xl, *qwth, *qwtl, *kwth, *kwtl, *vwth, *vwtl, *owth, *owtl;
    u16 *qh, *ql, *kh, *kl, *vth, *vtl, *aoh, *aol;
    cudaGetSymbolAddress((void**)&v, g_v);
    cudaGetSymbolAddress((void**)&p, g_p);
    cudaGetSymbolAddress((void**)&xh, g_xh);   cudaGetSymbolAddress((void**)&xl, g_xl);
    cudaGetSymbolAddress((void**)&qwth, g_qwt_h); cudaGetSymbolAddress((void**)&qwtl, g_qwt_l);
    cudaGetSymbolAddress((void**)&kwth, g_kwt_h); cudaGetSymbolAddress((void**)&kwtl, g_kwt_l);
    cudaGetSymbolAddress((void**)&vwth, g_vwt_h); cudaGetSymbolAddress((void**)&vwtl, g_vwt_l);
    cudaGetSymbolAddress((void**)&owth, g_owt_h); cudaGetSymbolAddress((void**)&owtl, g_owt_l);
    cudaGetSymbolAddress((void**)&qh, g_qh);   cudaGetSymbolAddress((void**)&ql, g_ql);
    cudaGetSymbolAddress((void**)&kh, g_kh);   cudaGetSymbolAddress((void**)&kl, g_kl);
    cudaGetSymbolAddress((void**)&vth, g_vth); cudaGetSymbolAddress((void**)&vtl, g_vtl);
    cudaGetSymbolAddress((void**)&aoh, g_aoh); cudaGetSymbolAddress((void**)&aol, g_aol);

    const int SM256 = 2 * (32768 + 2 * 256 * 128);   // 196608
    cudaFuncSetAttribute((const void*)mgemm<256, true,  false, true>,
                         cudaFuncAttributeMaxDynamicSharedMemorySize, SM256);
    cudaFuncSetAttribute((const void*)mgemm<256, true,  false, false>,
                         cudaFuncAttributeMaxDynamicSharedMemorySize, SM256);
    cudaFuncSetAttribute((const void*)mgemm<256, false, true,  false>,
                         cudaFuncAttributeMaxDynamicSharedMemorySize, SM256);
    cudaFuncSetAttribute((const void*)mgemm<256, false, false, false>,
                         cudaFuncAttributeMaxDynamicSharedMemorySize, SM256);
    cudaFuncSetAttribute((const void*)pv_fused,
                         cudaFuncAttributeMaxDynamicSharedMemorySize, PV_SMEM);

    // 1) split-convert activations and weights (weights transposed to [N,K])
    conv_split<<<(unsigned)(((long)MR * D_ + 255) / 256), 256>>>(x, xh, xl, (long)MR * D_);
    dim3 tb(32, 8);
    tsplit<<<dim3(128, 128, 1), tb>>>(qw, qwth, qwtl, D_, D_, 0, 0, 0, 1);
    tsplit<<<dim3(32, 128, 1), tb>>>(kw, kwth, kwtl, 1024, D_, 0, 0, 0, 1);
    tsplit<<<dim3(32, 128, 1), tb>>>(vw, vwth, vwtl, 1024, D_, 0, 0, 0, 1);
    tsplit<<<dim3(128, 128, 1), tb>>>(ow, owth, owtl, D_, D_, 0, 0, 0, 1);

    // 2) Q/K projections with fused bias + RoPE + split output
    mgemm<256, true, false, true><<<dim3(16, 32, 1), 256, SM256>>>(
        xh, xl, qwth, qwtl, qb, nullptr, qh, ql,
        D_, D_, D_, D_, 1, 1, 0, 0, 0, 0, 0, 0, 1.0f, fc, fs, sp);
    mgemm<256, true, false, true><<<dim3(4, 32, 1), 256, SM256>>>(
        xh, xl, kwth, kwtl, kb, nullptr, kh, kl,
        D_, D_, D_, 1024, 1, 1, 0, 0, 0, 0, 0, 0, 1.0f, fc, fs, sp);
    // V projection (fp32 out) then transpose+split to [b,h,d,s]
    mgemm<256, true, false, false><<<dim3(4, 32, 1), 256, SM256>>>(
        xh, xl, vwth, vwtl, vb, v, nullptr, nullptr,
        D_, D_, D_, 1024, 1, 1, 0, 0, 0, 0, 0, 0, 1.0f, nullptr, nullptr, nullptr);
    tsplit<<<dim3(4, 64, B_ * HKV), tb>>>(v, vth, vtl, 1024, S_,
        (long)S_ * 1024, (long)HD, (long)HD * S_, HKV);

    // 3) scores = (1/sqrt(128)) * Q @ K^T  (causal block skip) -> fp32 p
    mgemm<256, false, true, false><<<dim3(8, 16, B_ * HQ), 256, SM256>>>(
        qh, ql, kh, kl, nullptr, p, nullptr, nullptr,
        HD, D_, 1024, S_, HQ, GRP,
        (long)S_ * D_, (long)HD,
        (long)S_ * 1024, (long)HD,
        (long)HQ * S_ * S_, (long)S_ * S_,
        0.08838834764831845f, nullptr, nullptr, nullptr);

    // 4) fused online-softmax + P@V -> split bf16 AO in [b,s,h*128+d]
    pv_fused<<<dim3(16, B_ * HQ), 256, PV_SMEM>>>(p, vth, vtl, aoh, aol);

    // 5) out = AO @ ow
    mgemm<256, false, false, false><<<dim3(16, 32, 1), 256, SM256>>>(
        aoh, aol, owth, owtl, nullptr, out, nullptr, nullptr,
        D_, D_, D_, D_, 1, 1, 0, 0, 0, 0, 0, 0, 1.0f, nullptr, nullptr, nullptr);
}

// round 7
// speedup vs baseline: 3.4091x; 1.0647x over previous
#include <cuda_runtime.h>
#include <cuda_bf16.h>

typedef unsigned short u16;
typedef unsigned int   u32;

#define B_   2
#define S_   2048
#define D_   4096
#define HQ   32
#define HKV  8
#define HD   128
#define GRP  4
#define MR   (B_*S_)   // 4096

// ---------------- scratch (__device__ globals; no runtime allocation) -------
__device__ float g_v[(size_t)MR*HKV*HD];             // fp32 V (pre-transpose)

__device__ u16 g_xh[(size_t)MR*D_],        g_xl[(size_t)MR*D_];
__device__ u16 g_qwt_h[(size_t)D_*D_],     g_qwt_l[(size_t)D_*D_];
__device__ u16 g_kwt_h[(size_t)1024*D_],   g_kwt_l[(size_t)1024*D_];
__device__ u16 g_vwt_h[(size_t)1024*D_],   g_vwt_l[(size_t)1024*D_];
__device__ u16 g_owt_h[(size_t)D_*D_],     g_owt_l[(size_t)D_*D_];
__device__ u16 g_qh[(size_t)MR*D_],        g_ql[(size_t)MR*D_];           // rope'd Q
__device__ u16 g_kh[(size_t)MR*HKV*HD],    g_kl[(size_t)MR*HKV*HD];       // rope'd K
__device__ u16 g_vth[(size_t)B_*HKV*HD*S_],g_vtl[(size_t)B_*HKV*HD*S_];   // V^T [b,h,d,s]
__device__ u16 g_aoh[(size_t)MR*D_],       g_aol[(size_t)MR*D_];          // attn out

// ---------------------------------------------------------------------------
__device__ __forceinline__ void split2(float v, u16& h, u16& l) {
    __nv_bfloat16 hb = __float2bfloat16(v);
    float r = v - __bfloat162float(hb);
    h = __bfloat16_as_ushort(hb);
    l = __bfloat16_as_ushort(__float2bfloat16(r));
}

__device__ __forceinline__ u32 smem_u32(const void* p) {
    u32 a;
    asm("{ .reg .u64 t; cvta.to.shared.u64 t, %1; cvt.u32.u64 %0, t; }" : "=r"(a) : "l"(p));
    return a;
}

__device__ __forceinline__ void cp16(u32 sdst, const void* gsrc) {
    asm volatile("cp.async.cg.shared.global [%0], [%1], 16;\n" :: "r"(sdst), "l"(gsrc));
}
#define CP_COMMIT()  asm volatile("cp.async.commit_group;" ::: "memory")
#define CP_WAIT2()   asm volatile("cp.async.wait_group 2;" ::: "memory")
#define CP_WAIT1()   asm volatile("cp.async.wait_group 1;" ::: "memory")
#define CP_WAIT0()   asm volatile("cp.async.wait_group 0;" ::: "memory")

__device__ __forceinline__ void ldsm4(u32* r, u32 addr) {
    asm volatile("ldmatrix.sync.aligned.m8n8.x4.shared.b16 {%0,%1,%2,%3}, [%4];"
        : "=r"(r[0]), "=r"(r[1]), "=r"(r[2]), "=r"(r[3]) : "r"(addr));
}

__device__ __forceinline__ void mma16816(float* d, const u32* a, const u32* b) {
    asm volatile(
        "mma.sync.aligned.m16n8k16.row.col.f32.bf16.bf16.f32 "
        "{%0,%1,%2,%3}, {%4,%5,%6,%7}, {%8,%9}, {%0,%1,%2,%3};\n"
        : "+f"(d[0]), "+f"(d[1]), "+f"(d[2]), "+f"(d[3])
        : "r"(a[0]), "r"(a[1]), "r"(a[2]), "r"(a[3]), "r"(b[0]), "r"(b[1]));
}

// ---------------------------------------------------------------------------
// Split-bf16 tensor GEMM: C = alpha * A @ B^T (+bias) [+RoPE on output pairs]
// 128 x NT CTA tile, BK=64, 2-stage cp.async, SW128 swizzle, ldmatrix,
// 3-term compensated product.
// ---------------------------------------------------------------------------
template<int NT, bool BIAS, bool ROPE>
__global__ __launch_bounds__(256, 1)
void mgemm(const u16* __restrict__ Agh, const u16* __restrict__ Agl,
           const u16* __restrict__ Bgh, const u16* __restrict__ Bgl,
           const float* __restrict__ bias,
           float* __restrict__ Cf, u16* __restrict__ Ch, u16* __restrict__ Cl,
           int K, int lda, int ldb, int ldc,
           float alpha,
           const float* __restrict__ fc, const float* __restrict__ fs,
           const int* __restrict__ sp)
{
    constexpr int NJ  = NT / 32;
    constexpr int STG = 32768 + 2 * NT * 128;
    extern __shared__ __align__(16) char dsm[];

    int m0 = blockIdx.y * 128, n0 = blockIdx.x * NT;

    const u16* Aph = Agh;
    const u16* Apl = Agl;
    const u16* Bph = Bgh;
    const u16* Bpl = Bgl;

    int tid = threadIdx.x, wid = tid >> 5, lane = tid & 31;
    int wx = wid & 3, wy = wid >> 2;
    int g = lane >> 2, tg = lane & 3;

    u32 sbase = smem_u32(dsm);

    int aRow = ((lane >> 3) & 1) * 8 + (lane & 7);
    int aKu  = lane >> 4;
    u32 aBase[4]; int aSw[4];
    #pragma unroll
    for (int mi = 0; mi < 4; mi++) {
        int r = wy * 64 + mi * 16 + aRow;
        aBase[mi] = (u32)(r * 128); aSw[mi] = r & 7;
    }
    int bRow = (lane >> 4) * 8 + (lane & 7);
    int bKu  = (lane >> 3) & 1;
    u32 bBase[NJ / 2]; int bSw[NJ / 2];
    #pragma unroll
    for (int p = 0; p < NJ / 2; p++) {
        int r = wx * (NT / 4) + p * 16 + bRow;
        bBase[p] = (u32)(r * 128); bSw[p] = r & 7;
    }

    float d[4][NJ][4];
    #pragma unroll
    for (int i = 0; i < 4; i++)
        #pragma unroll
        for (int j = 0; j < NJ; j++)
            #pragma unroll
            for (int q = 0; q < 4; q++) d[i][j][q] = 0.f;

    int nch = K >> 6;

    auto prefetch = [&](int c, int s) {
        u32 st = sbase + s * STG;
        int k0 = c << 6;
        constexpr int TOT = (256 + 2 * NT) * 8;
        #pragma unroll
        for (int u0 = 0; u0 < TOT; u0 += 256) {
            int u = u0 + tid;
            int row, c16;
            const u16* gp;
            u32 abase;
            if (u0 < 2048) {
                row = (u >> 3) & 127; c16 = u & 7;
                bool lo = u >= 1024;
                gp = (lo ? Apl : Aph) + (long)(m0 + row) * lda + k0 + c16 * 8;
                abase = st + (lo ? 16384u : 0u);
            } else {
                int v = u - 2048;
                row = (v >> 3) & (NT - 1); c16 = v & 7;
                bool lo = v >= NT * 8;
                gp = (lo ? Bpl : Bph) + (long)(n0 + row) * ldb + k0 + c16 * 8;
                abase = st + 32768u + (lo ? (u32)(NT * 128) : 0u);
            }
            u32 so = abase + (u32)(row * 128) + ((u32)(c16 ^ (row & 7)) << 4);
            cp16(so, gp);
        }
    };

    prefetch(0, 0);
    CP_COMMIT();

    for (int c = 0; c < nch; c++) {
        if (c + 1 < nch) { prefetch(c + 1, (c + 1) & 1); CP_COMMIT(); CP_WAIT1(); }
        else             { CP_WAIT0(); }
        __syncthreads();

        u32 st = sbase + (c & 1) * STG;
        u32 sAh_ = st, sAl_ = st + 16384, sBh_ = st + 32768, sBl_ = st + 32768 + NT * 128;

        #pragma unroll
        for (int kk = 0; kk < 4; kk++) {
            int kuA = kk * 2 + aKu;
            int kuB = kk * 2 + bKu;
            u32 ah[4][4], xa[4][4], xb[NJ / 2][4];
            #pragma unroll
            for (int mi = 0; mi < 4; mi++)
                ldsm4(ah[mi], sAh_ + aBase[mi] + ((u32)(kuA ^ aSw[mi]) << 4));
            #pragma unroll
            for (int p = 0; p < NJ / 2; p++)
                ldsm4(xb[p], sBh_ + bBase[p] + ((u32)(kuB ^ bSw[p]) << 4));
            #pragma unroll
            for (int mi = 0; mi < 4; mi++)
                #pragma unroll
                for (int nj = 0; nj < NJ; nj++)
                    mma16816(d[mi][nj], ah[mi], &xb[nj >> 1][(nj & 1) * 2]);
            #pragma unroll
            for (int mi = 0; mi < 4; mi++)
                ldsm4(xa[mi], sAl_ + aBase[mi] + ((u32)(kuA ^ aSw[mi]) << 4));
            #pragma unroll
            for (int mi = 0; mi < 4; mi++)
                #pragma unroll
                for (int nj = 0; nj < NJ; nj++)
                    mma16816(d[mi][nj], xa[mi], &xb[nj >> 1][(nj & 1) * 2]);
            #pragma unroll
            for (int p = 0; p < NJ / 2; p++)
                ldsm4(xb[p], sBl_ + bBase[p] + ((u32)(kuB ^ bSw[p]) << 4));
            #pragma unroll
            for (int mi = 0; mi < 4; mi++)
                #pragma unroll
                for (int nj = 0; nj < NJ; nj++)
                    mma16816(d[mi][nj], ah[mi], &xb[nj >> 1][(nj & 1) * 2]);
        }
        __syncthreads();
    }

    int sp0 = ROPE ? *sp : 0;

    #pragma unroll
    for (int mi = 0; mi < 4; mi++) {
        #pragma unroll
        for (int nj = 0; nj < NJ; nj++) {
            int r = m0 + wy * 64 + mi * 16 + g;
            int c = n0 + wx * (NT / 4) + nj * 8 + tg * 2;
            float v0 = d[mi][nj][0] * alpha, v1 = d[mi][nj][1] * alpha;
            float v2 = d[mi][nj][2] * alpha, v3 = d[mi][nj][3] * alpha;
            if (BIAS) {
                float b0 = bias[c], b1 = bias[c + 1];
                v0 += b0; v1 += b1; v2 += b0; v3 += b1;
            }
            long o0 = (long)r * ldc + c;
            long o1 = o0 + 8L * ldc;
            if (ROPE) {
                int i_ = (c & 127) >> 1;
                int s0 = (r & (S_ - 1)) + sp0;
                int s8 = ((r + 8) & (S_ - 1)) + sp0;
                float c0f = fc[s0 * 64 + i_], s0f = fs[s0 * 64 + i_];
                float c8f = fc[s8 * 64 + i_], s8f = fs[s8 * 64 + i_];
                float r0 = v0 * c0f - v1 * s0f, r1 = v0 * s0f + v1 * c0f;
                float r2 = v2 * c8f - v3 * s8f, r3 = v2 * s8f + v3 * c8f;
                u16 h0, l0, h1, l1;
                split2(r0, h0, l0); split2(r1, h1, l1);
                *(u32*)&Ch[o0] = (u32)h0 | ((u32)h1 << 16);
                *(u32*)&Cl[o0] = (u32)l0 | ((u32)l1 << 16);
                split2(r2, h0, l0); split2(r3, h1, l1);
                *(u32*)&Ch[o1] = (u32)h0 | ((u32)h1 << 16);
                *(u32*)&Cl[o1] = (u32)l0 | ((u32)l1 << 16);
            } else {
                *(float2*)&Cf[o0] = make_float2(v0, v1);
                *(float2*)&Cf[o1] = make_float2(v2, v3);
            }
        }
    }
}

// ---------------------------------------------------------------------------
// Fused FlashAttention: S = alpha*Q@K^T (3-term), online softmax, O = P@V.
// One CTA per (m-tile, b, h). Q tile resident; K double-buffered; V single.
// ---------------------------------------------------------------------------
#define FA_QH   0
#define FA_QL   32768
#define FA_K    65536       // + stage*32768 ; [KHcc0 8K][KHcc1][KLcc0][KLcc1]
#define FA_V    131072      // VH 16K, VL 16K
#define FA_P    163840      // PH 16K, PL 16K
#define FA_ST   196608
#define FA_SMEM (196608 + 5632)

__global__ __launch_bounds__(256, 1)
void fa_fused(const u16* __restrict__ Qh, const u16* __restrict__ Ql,
              const u16* __restrict__ Kh, const u16* __restrict__ Kl,
              const u16* __restrict__ Vth, const u16* __restrict__ Vtl,
              u16* __restrict__ Oh, u16* __restrict__ Ol, float alpha)
{
    extern __shared__ __align__(16) char dsm[];
    u32 sbase = smem_u32(dsm);
    float* m_run = (float*)(dsm + FA_ST);
    float* l_run = m_run + 128;
    float* fch   = m_run + 256;
    float* mpart = m_run + 384;   // [4][128]
    float* lpart = m_run + 896;   // [4][128]

    int m0 = (int)(gridDim.x - 1 - blockIdx.x) * 128;     // heavy tiles first
    int z = blockIdx.y, b = z / HQ, h = z - b * HQ;

    const u16* Qph = Qh + ((long)b * S_ + m0) * D_ + h * HD;
    const u16* Qpl = Ql + ((long)b * S_ + m0) * D_ + h * HD;
    const u16* Kph = Kh + (long)b * S_ * 1024 + (h / GRP) * HD;
    const u16* Kpl = Kl + (long)b * S_ * 1024 + (h / GRP) * HD;
    const u16* Vph = Vth + ((long)b * HKV + (h / GRP)) * (long)HD * S_;
    const u16* Vpl = Vtl + ((long)b * HKV + (h / GRP)) * (long)HD * S_;

    int tid = threadIdx.x, wid = tid >> 5, lane = tid & 31;
    int wx = wid & 3, wy = wid >> 2;
    int g = lane >> 2, tg = lane & 3;

    if (tid < 128) { m_run[tid] = -1e30f; l_run[tid] = 0.f; }

    // fragment offset precompute
    int aRow = ((lane >> 3) & 1) * 8 + (lane & 7);
    int aKu  = lane >> 4;
    u32 aBase[4]; int aSw[4];
    #pragma unroll
    for (int mi = 0; mi < 4; mi++) {
        int rr = wy * 64 + mi * 16 + aRow;
        aBase[mi] = (u32)(rr * 128); aSw[mi] = rr & 7;
    }
    int bRow = (lane >> 4) * 8 + (lane & 7);
    int bKu  = (lane >> 3) & 1;
    // S-phase B (16-row tile)
    u32 bBaseS = (u32)((wx * 16 + bRow) * 128); int bSwS = bRow & 7;
    // PV-phase B (32-row tiles)
    u32 bBaseV[2]; int bSwV[2];
    #pragma unroll
    for (int p = 0; p < 2; p++) {
        int rr = wx * 32 + p * 16 + bRow;
        bBaseV[p] = (u32)(rr * 128); bSwV[p] = rr & 7;
    }

    float d_o[4][4][4];
    #pragma unroll
    for (int i = 0; i < 4; i++)
        #pragma unroll
        for (int j = 0; j < 4; j++)
            #pragma unroll
            for (int q = 0; q < 4; q++) d_o[i][j][q] = 0.f;

    int nch = (m0 + 128) >> 6;

    // ---- loaders ----
    auto qfetch = [&]() {
        #pragma unroll
        for (int u0 = 0; u0 < 4096; u0 += 256) {
            int u = u0 + tid;
            int cc = u >> 11, rest = u & 2047;
            bool lo = rest >= 1024;
            int v = rest & 1023, row = v >> 3, c16 = v & 7;
            const u16* gp = (lo ? Qpl : Qph) + (long)row * D_ + cc * 64 + c16 * 8;
            u32 so = sbase + FA_QH + (u32)cc * 16384 + (lo ? 32768u : 0u)
                   + (u32)(row * 128) + ((u32)(c16 ^ (row & 7)) << 4);
            cp16(so, gp);
        }
    };
    auto kfetch = [&](int c, int s) {
        int j0 = c << 6;
        #pragma unroll
        for (int u0 = 0; u0 < 2048; u0 += 256) {
            int u = u0 + tid;
            int cc = u >> 10, rest = u & 1023;
            bool lo = rest >= 512;
            int v = rest & 511, row = v >> 3, c16 = v & 7;
            const u16* gp = (lo ? Kpl : Kph) + (long)(j0 + row) * 1024 + cc * 64 + c16 * 8;
            u32 so = sbase + FA_K + (u32)s * 32768 + (u32)cc * 8192 + (lo ? 16384u : 0u)
                   + (u32)(row * 128) + ((u32)(c16 ^ (row & 7)) << 4);
            cp16(so, gp);
        }
    };
    auto vfetch = [&](int c) {
        int j0 = c << 6;
        #pragma unroll
        for (int u0 = 0; u0 < 2048; u0 += 256) {
            int u = u0 + tid;
            bool lo = u >= 1024;
            int v = u & 1023, row = v >> 3, c16 = v & 7;
            const u16* gp = (lo ? Vpl : Vph) + (long)row * S_ + j0 + c16 * 8;
            u32 so = sbase + FA_V + (lo ? 16384u : 0u)
                   + (u32)(row * 128) + ((u32)(c16 ^ (row & 7)) << 4);
            cp16(so, gp);
        }
    };

    qfetch();
    CP_COMMIT();
    kfetch(0, 0);
    CP_COMMIT();

    for (int c = 0; c < nch; c++) {
        int j0 = c << 6;
        bool hasNext = (c + 1 < nch);

        vfetch(c); CP_COMMIT();
        if (hasNext) { kfetch(c + 1, (c + 1) & 1); CP_COMMIT(); }

        if (hasNext) CP_WAIT2(); else CP_WAIT1();   // K(c) (and Q) ready
        __syncthreads();

        // ---- S = Q @ K^T (3 terms) ----
        float d_s[4][2][4];
        #pragma unroll
        for (int i = 0; i < 4; i++)
            #pragma unroll
            for (int j = 0; j < 2; j++)
                #pragma unroll
                for (int q = 0; q < 4; q++) d_s[i][j][q] = 0.f;

        u32 kst = sbase + FA_K + (u32)(c & 1) * 32768;
        #pragma unroll
        for (int cc = 0; cc < 2; cc++) {
            u32 sQh_ = sbase + FA_QH + (u32)cc * 16384;
            u32 sQl_ = sQh_ + 32768;
            u32 sKh_ = kst + (u32)cc * 8192;
            u32 sKl_ = sKh_ + 16384;
            #pragma unroll
            for (int kk = 0; kk < 4; kk++) {
                int kuA = kk * 2 + aKu;
                int kuB = kk * 2 + bKu;
                u32 ah[4][4], xa[4][4], xb[4];
                #pragma unroll
                for (int mi = 0; mi < 4; mi++)
                    ldsm4(ah[mi], sQh_ + aBase[mi] + ((u32)(kuA ^ aSw[mi]) << 4));
                ldsm4(xb, sKh_ + bBaseS + ((u32)(kuB ^ bSwS) << 4));
                #pragma unroll
                for (int mi = 0; mi < 4; mi++)
                    #pragma unroll
                    for (int nj = 0; nj < 2; nj++)
                        mma16816(d_s[mi][nj], ah[mi], &xb[nj * 2]);
                #pragma unroll
                for (int mi = 0; mi < 4; mi++)
                    ldsm4(xa[mi], sQl_ + aBase[mi] + ((u32)(kuA ^ aSw[mi]) << 4));
                #pragma unroll
                for (int mi = 0; mi < 4; mi++)
                    #pragma unroll
                    for (int nj = 0; nj < 2; nj++)
                        mma16816(d_s[mi][nj], xa[mi], &xb[nj * 2]);
                ldsm4(xb, sKl_ + bBaseS + ((u32)(kuB ^ bSwS) << 4));
                #pragma unroll
                for (int mi = 0; mi < 4; mi++)
                    #pragma unroll
                    for (int nj = 0; nj < 2; nj++)
                        mma16816(d_s[mi][nj], ah[mi], &xb[nj * 2]);
            }
        }

        // ---- mask + alpha + chunk row-max ----
        bool domask = (c >= nch - 2);
        #pragma unroll
        for (int mi = 0; mi < 4; mi++) {
            int rl0 = wy * 64 + mi * 16 + g;
            int grow0 = m0 + rl0, grow8 = grow0 + 8;
            float mx0 = -1e30f, mx8 = -1e30f;
            #pragma unroll
            for (int nj = 0; nj < 2; nj++) {
                #pragma unroll
                for (int e = 0; e < 2; e++) {
                    int gc = j0 + wx * 16 + nj * 8 + tg * 2 + e;
                    float v0 = d_s[mi][nj][e] * alpha;
                    float v8 = d_s[mi][nj][2 + e] * alpha;
                    if (domask) {
                        if (gc > grow0) v0 = -1e30f;
                        if (gc > grow8) v8 = -1e30f;
                    }
                    d_s[mi][nj][e] = v0; d_s[mi][nj][2 + e] = v8;
                    mx0 = fmaxf(mx0, v0); mx8 = fmaxf(mx8, v8);
                }
            }
            mx0 = fmaxf(mx0, __shfl_xor_sync(0xffffffffu, mx0, 1));
            mx0 = fmaxf(mx0, __shfl_xor_sync(0xffffffffu, mx0, 2));
            mx8 = fmaxf(mx8, __shfl_xor_sync(0xffffffffu, mx8, 1));
            mx8 = fmaxf(mx8, __shfl_xor_sync(0xffffffffu, mx8, 2));
            if (tg == 0) {
                mpart[wx * 128 + rl0] = mx0;
                mpart[wx * 128 + rl0 + 8] = mx8;
            }
        }
        __syncthreads();

        if (tid < 128) {
            float mc = fmaxf(fmaxf(mpart[tid], mpart[128 + tid]),
                             fmaxf(mpart[256 + tid], mpart[384 + tid]));
            float mo = m_run[tid];
            float mn = fmaxf(mo, mc);
            fch[tid] = __expf(mo - mn);
            m_run[tid] = mn;
        }
        __syncthreads();

        // ---- rescale O accumulators ----
        #pragma unroll
        for (int mi = 0; mi < 4; mi++) {
            int rl = wy * 64 + mi * 16 + g;
            float f0 = fch[rl], f8 = fch[rl + 8];
            #pragma unroll
            for (int nj = 0; nj < 4; nj++) {
                d_o[mi][nj][0] *= f0; d_o[mi][nj][1] *= f0;
                d_o[mi][nj][2] *= f8; d_o[mi][nj][3] *= f8;
            }
        }

        // ---- P = exp(S - m), split to smem; partial row sums ----
        #pragma unroll
        for (int mi = 0; mi < 4; mi++) {
            int rl0 = wy * 64 + mi * 16 + g;
            float mrow0 = m_run[rl0], mrow8 = m_run[rl0 + 8];
            float s0 = 0.f, s8 = 0.f;
            #pragma unroll
            for (int nj = 0; nj < 2; nj++) {
                float p00 = __expf(d_s[mi][nj][0] - mrow0);
                float p01 = __expf(d_s[mi][nj][1] - mrow0);
                float p80 = __expf(d_s[mi][nj][2] - mrow8);
                float p81 = __expf(d_s[mi][nj][3] - mrow8);
                s0 += p00 + p01; s8 += p80 + p81;
                int cl = wx * 16 + nj * 8 + tg * 2;
                u32 u0 = (u32)(((cl >> 3) ^ (rl0 & 7)) << 4) + (u32)((cl & 7) * 2);
                u32 u8 = (u32)(((cl >> 3) ^ ((rl0 + 8) & 7)) << 4) + (u32)((cl & 7) * 2);
                u16 hh, ll, h1, l1;
                split2(p00, hh, ll); split2(p01, h1, l1);
                *(u32*)(dsm + FA_P + rl0 * 128 + u0) = (u32)hh | ((u32)h1 << 16);
                *(u32*)(dsm + FA_P + 16384 + rl0 * 128 + u0) = (u32)ll | ((u32)l1 << 16);
                split2(p80, hh, ll); split2(p81, h1, l1);
                *(u32*)(dsm + FA_P + (rl0 + 8) * 128 + u8) = (u32)hh | ((u32)h1 << 16);
                *(u32*)(dsm + FA_P + 16384 + (rl0 + 8) * 128 + u8) = (u32)ll | ((u32)l1 << 16);
            }
            s0 += __shfl_xor_sync(0xffffffffu, s0, 1);
            s0 += __shfl_xor_sync(0xffffffffu, s0, 2);
            s8 += __shfl_xor_sync(0xffffffffu, s8, 1);
            s8 += __shfl_xor_sync(0xffffffffu, s8, 2);
            if (tg == 0) {
                lpart[wx * 128 + rl0] = s0;
                lpart[wx * 128 + rl0 + 8] = s8;
            }
        }

        if (hasNext) CP_WAIT1(); else CP_WAIT0();    // V(c) ready
        __syncthreads();

        if (tid < 128) {
            float sum = lpart[tid] + lpart[128 + tid] + lpart[256 + tid] + lpart[384 + tid];
            l_run[tid] = l_run[tid] * fch[tid] + sum;
        }

        // ---- O += P @ V (3 terms) ----
        u32 sPh = sbase + FA_P, sPl = sPh + 16384;
        u32 sVh = sbase + FA_V, sVl = sVh + 16384;
        #pragma unroll
        for (int kk = 0; kk < 4; kk++) {
            int kuA = kk * 2 + aKu;
            int kuB = kk * 2 + bKu;
            u32 ah[4][4], xa[4][4], xb[2][4];
            #pragma unroll
            for (int mi = 0; mi < 4; mi++)
                ldsm4(ah[mi], sPh + aBase[mi] + ((u32)(kuA ^ aSw[mi]) << 4));
            #pragma unroll
            for (int p = 0; p < 2; p++)
                ldsm4(xb[p], sVh + bBaseV[p] + ((u32)(kuB ^ bSwV[p]) << 4));
            #pragma unroll
            for (int mi = 0; mi < 4; mi++)
                #pragma unroll
                for (int nj = 0; nj < 4; nj++)
                    mma16816(d_o[mi][nj], ah[mi], &xb[nj >> 1][(nj & 1) * 2]);
            #pragma unroll
            for (int mi = 0; mi < 4; mi++)
                ldsm4(xa[mi], sPl + aBase[mi] + ((u32)(kuA ^ aSw[mi]) << 4));
            #pragma unroll
            for (int mi = 0; mi < 4; mi++)
                #pragma unroll
                for (int nj = 0; nj < 4; nj++)
                    mma16816(d_o[mi][nj], xa[mi], &xb[nj >> 1][(nj & 1) * 2]);
            #pragma unroll
            for (int p = 0; p < 2; p++)
                ldsm4(xb[p], sVl + bBaseV[p] + ((u32)(kuB ^ bSwV[p]) << 4));
            #pragma unroll
            for (int mi = 0; mi < 4; mi++)
                #pragma unroll
                for (int nj = 0; nj < 4; nj++)
                    mma16816(d_o[mi][nj], ah[mi], &xb[nj >> 1][(nj & 1) * 2]);
        }
        __syncthreads();   // guard SV / P overwrite next iteration
    }

    // ---- epilogue: divide by l, split, store [b, s, h*128 + col] ----
    #pragma unroll
    for (int mi = 0; mi < 4; mi++) {
        int rl = wy * 64 + mi * 16 + g;
        float i0 = 1.0f / l_run[rl];
        float i8 = 1.0f / l_run[rl + 8];
        #pragma unroll
        for (int nj = 0; nj < 4; nj++) {
            int cc = wx * 32 + nj * 8 + tg * 2;
            long o0 = ((long)b * S_ + m0 + rl) * D_ + h * HD + cc;
            long o1 = o0 + 8L * D_;
            float v0 = d_o[mi][nj][0] * i0, v1 = d_o[mi][nj][1] * i0;
            float v2 = d_o[mi][nj][2] * i8, v3 = d_o[mi][nj][3] * i8;
            u16 h0, l0, h1, l1;
            split2(v0, h0, l0); split2(v1, h1, l1);
            *(u32*)&Oh[o0] = (u32)h0 | ((u32)h1 << 16);
            *(u32*)&Ol[o0] = (u32)l0 | ((u32)l1 << 16);
            split2(v2, h0, l0); split2(v3, h1, l1);
            *(u32*)&Oh[o1] = (u32)h0 | ((u32)h1 << 16);
            *(u32*)&Ol[o1] = (u32)l0 | ((u32)l1 << 16);
        }
    }
}

// ---------------------------------------------------------------------------
__global__ void conv_split(const float* __restrict__ in, u16* __restrict__ oh,
                           u16* __restrict__ ol, long n)
{
    long i = blockIdx.x * 256L + threadIdx.x;
    if (i < n) split2(in[i], oh[i], ol[i]);
}

__global__ void tsplit(const float* __restrict__ in, u16* __restrict__ oh,
                       u16* __restrict__ ol, int ldin, int ldout,
                       long sInB, long sInH, long sOutZ, int Hc)
{
    __shared__ float t[32][33];
    int z = blockIdx.z, bb = z / Hc, hh = z - bb * Hc;
    const float* ip = in + bb * sInB + (long)hh * sInH;
    int c0 = blockIdx.x * 32, r0 = blockIdx.y * 32;
    #pragma unroll
    for (int i = 0; i < 4; i++)
        t[threadIdx.y + i * 8][threadIdx.x] =
            ip[(long)(r0 + threadIdx.y + i * 8) * ldin + c0 + threadIdx.x];
    __syncthreads();
    #pragma unroll
    for (int i = 0; i < 4; i++) {
        int orow = c0 + threadIdx.y + i * 8;
        int oc = r0 + threadIdx.x;
        float v = t[threadIdx.x][threadIdx.y + i * 8];
        long o = z * sOutZ + (long)orow * ldout + oc;
        split2(v, oh[o], ol[o]);
    }
}

// ---------------------------------------------------------------------------
extern "C" void kernel_launch(void* const* d_in, const int* in_sizes, int n_in,
                              void* d_out, int out_size)
{
    const float* x  = (const float*)d_in[0];
    const float* fc = (const float*)d_in[1];
    const float* fs = (const float*)d_in[2];
    const float* qw = (const float*)d_in[3];
    const float* qb = (const float*)d_in[4];
    const float* kw = (const float*)d_in[5];
    const float* kb = (const float*)d_in[6];
    const float* vw = (const float*)d_in[7];
    const float* vb = (const float*)d_in[8];
    const float* ow = (const float*)d_in[9];
    const int*   sp = (const int*)d_in[10];
    float* out = (float*)d_out;

    float *v;
    u16 *xh, *xl, *qwth, *qwtl, *kwth, *kwtl, *vwth, *vwtl, *owth, *owtl;
    u16 *qh, *ql, *kh, *kl, *vth, *vtl, *aoh, *aol;
    cudaGetSymbolAddress((void**)&v, g_v);
    cudaGetSymbolAddress((void**)&xh, g_xh);   cudaGetSymbolAddress((void**)&xl, g_xl);
    cudaGetSymbolAddress((void**)&qwth, g_qwt_h); cudaGetSymbolAddress((void**)&qwtl, g_qwt_l);
    cudaGetSymbolAddress((void**)&kwth, g_kwt_h); cudaGetSymbolAddress((void**)&kwtl, g_kwt_l);
    cudaGetSymbolAddress((void**)&vwth, g_vwt_h); cudaGetSymbolAddress((void**)&vwtl, g_vwt_l);
    cudaGetSymbolAddress((void**)&owth, g_owt_h); cudaGetSymbolAddress((void**)&owtl, g_owt_l);
    cudaGetSymbolAddress((void**)&qh, g_qh);   cudaGetSymbolAddress((void**)&ql, g_ql);
    cudaGetSymbolAddress((void**)&kh, g_kh);   cudaGetSymbolAddress((void**)&kl, g_kl);
    cudaGetSymbolAddress((void**)&vth, g_vth); cudaGetSymbolAddress((void**)&vtl, g_vtl);
    cudaGetSymbolAddress((void**)&aoh, g_aoh); cudaGetSymbolAddress((void**)&aol, g_aol);

    const int SM256 = 2 * (32768 + 2 * 256 * 128);   // 196608
    cudaFuncSetAttribute((const void*)mgemm<256, true,  true>,
                         cudaFuncAttributeMaxDynamicSharedMemorySize, SM256);
    cudaFuncSetAttribute((const void*)mgemm<256, true,  false>,
                         cudaFuncAttributeMaxDynamicSharedMemorySize, SM256);
    cudaFuncSetAttribute((const void*)mgemm<256, false, false>,
                         cudaFuncAttributeMaxDynamicSharedMemorySize, SM256);
    cudaFuncSetAttribute((const void*)fa_fused,
                         cudaFuncAttributeMaxDynamicSharedMemorySize, FA_SMEM);

    // 1) split-convert activations and weights (weights transposed to [N,K])
    conv_split<<<(unsigned)(((long)MR * D_ + 255) / 256), 256>>>(x, xh, xl, (long)MR * D_);
    dim3 tb(32, 8);
    tsplit<<<dim3(128, 128, 1), tb>>>(qw, qwth, qwtl, D_, D_, 0, 0, 0, 1);
    tsplit<<<dim3(32, 128, 1), tb>>>(kw, kwth, kwtl, 1024, D_, 0, 0, 0, 1);
    tsplit<<<dim3(32, 128, 1), tb>>>(vw, vwth, vwtl, 1024, D_, 0, 0, 0, 1);
    tsplit<<<dim3(128, 128, 1), tb>>>(ow, owth, owtl, D_, D_, 0, 0, 0, 1);

    // 2) Q/K projections with fused bias + RoPE + split output
    mgemm<256, true, true><<<dim3(16, 32, 1), 256, SM256>>>(
        xh, xl, qwth, qwtl, qb, nullptr, qh, ql,
        D_, D_, D_, D_, 1.0f, fc, fs, sp);
    mgemm<256, true, true><<<dim3(4, 32, 1), 256, SM256>>>(
        xh, xl, kwth, kwtl, kb, nullptr, kh, kl,
        D_, D_, D_, 1024, 1.0f, fc, fs, sp);
    // V projection (fp32 out) then transpose+split to [b,h,d,s]
    mgemm<256, true, false><<<dim3(4, 32, 1), 256, SM256>>>(
        xh, xl, vwth, vwtl, vb, v, nullptr, nullptr,
        D_, D_, D_, 1024, 1.0f, nullptr, nullptr, nullptr);
    tsplit<<<dim3(4, 64, B_ * HKV), tb>>>(v, vth, vtl, 1024, S_,
        (long)S_ * 1024, (long)HD, (long)HD * S_, HKV);

    // 3) fused attention -> split bf16 AO in [b,s,h*128+d]
    fa_fused<<<dim3(16, B_ * HQ), 256, FA_SMEM>>>(
        qh, ql, kh, kl, vth, vtl, aoh, aol, 0.08838834764831845f);

    // 4) out = AO @ ow
    mgemm<256, false, false><<<dim3(16, 32, 1), 256, SM256>>>(
        aoh, aol, owth, owtl, nullptr, out, nullptr, nullptr,
        D_, D_, D_, D_, 1.0f, nullptr, nullptr, nullptr);
}

// round 8
// speedup vs baseline: 3.4221x; 1.0038x over previous
#include <cuda_runtime.h>
#include <cuda_bf16.h>

typedef unsigned short u16;
typedef unsigned int   u32;

#define B_   2
#define S_   2048
#define D_   4096
#define HQ   32
#define HKV  8
#define HD   128
#define GRP  4
#define MR   (B_*S_)   // 4096

// ---------------- scratch (__device__ globals; no runtime allocation) -------
__device__ float g_v[(size_t)MR*HKV*HD];             // fp32 V (pre-transpose)

__device__ u16 g_xh[(size_t)MR*D_],        g_xl[(size_t)MR*D_];
__device__ u16 g_qwt_h[(size_t)D_*D_],     g_qwt_l[(size_t)D_*D_];
__device__ u16 g_kwt_h[(size_t)1024*D_],   g_kwt_l[(size_t)1024*D_];
__device__ u16 g_vwt_h[(size_t)1024*D_],   g_vwt_l[(size_t)1024*D_];
__device__ u16 g_owt_h[(size_t)D_*D_],     g_owt_l[(size_t)D_*D_];
__device__ u16 g_qh[(size_t)MR*D_],        g_ql[(size_t)MR*D_];           // rope'd Q
__device__ u16 g_kh[(size_t)MR*HKV*HD],    g_kl[(size_t)MR*HKV*HD];       // rope'd K
__device__ u16 g_vth[(size_t)B_*HKV*HD*S_],g_vtl[(size_t)B_*HKV*HD*S_];   // V^T [b,h,d,s]
__device__ u16 g_aoh[(size_t)MR*D_],       g_aol[(size_t)MR*D_];          // attn out

// ---------------------------------------------------------------------------
__device__ __forceinline__ void split2(float v, u16& h, u16& l) {
    __nv_bfloat16 hb = __float2bfloat16(v);
    float r = v - __bfloat162float(hb);
    h = __bfloat16_as_ushort(hb);
    l = __bfloat16_as_ushort(__float2bfloat16(r));
}

__device__ __forceinline__ u32 smem_u32(const void* p) {
    u32 a;
    asm("{ .reg .u64 t; cvta.to.shared.u64 t, %1; cvt.u32.u64 %0, t; }" : "=r"(a) : "l"(p));
    return a;
}

__device__ __forceinline__ void cp16(u32 sdst, const void* gsrc) {
    asm volatile("cp.async.cg.shared.global [%0], [%1], 16;\n" :: "r"(sdst), "l"(gsrc));
}
#define CP_COMMIT()  asm volatile("cp.async.commit_group;" ::: "memory")
#define CP_WAIT2()   asm volatile("cp.async.wait_group 2;" ::: "memory")
#define CP_WAIT1()   asm volatile("cp.async.wait_group 1;" ::: "memory")
#define CP_WAIT0()   asm volatile("cp.async.wait_group 0;" ::: "memory")

__device__ __forceinline__ void ldsm4(u32* r, u32 addr) {
    asm volatile("ldmatrix.sync.aligned.m8n8.x4.shared.b16 {%0,%1,%2,%3}, [%4];"
        : "=r"(r[0]), "=r"(r[1]), "=r"(r[2]), "=r"(r[3]) : "r"(addr));
}

__device__ __forceinline__ void mma16816(float* d, const u32* a, const u32* b) {
    asm volatile(
        "mma.sync.aligned.m16n8k16.row.col.f32.bf16.bf16.f32 "
        "{%0,%1,%2,%3}, {%4,%5,%6,%7}, {%8,%9}, {%0,%1,%2,%3};\n"
        : "+f"(d[0]), "+f"(d[1]), "+f"(d[2]), "+f"(d[3])
        : "r"(a[0]), "r"(a[1]), "r"(a[2]), "r"(a[3]), "r"(b[0]), "r"(b[1]));
}

// ---------------------------------------------------------------------------
// Shared GEMM mainloop: d += A @ B^T (3-term split bf16).
// 128 x NT CTA tile, BK=64, 2-stage cp.async, SW128 swizzle, ldmatrix.
// LDSM hoisted ahead of MMA blocks to cover shared-load latency.
// ---------------------------------------------------------------------------
template<int NT>
__device__ __forceinline__ void gemm_core(
    u32 sbase,
    const u16* __restrict__ Aph, const u16* __restrict__ Apl,
    const u16* __restrict__ Bph, const u16* __restrict__ Bpl,
    int lda, int ldb, int m0, int n0, int K,
    float (&d)[4][NT / 32][4])
{
    constexpr int NJ  = NT / 32;
    constexpr int STG = 32768 + 2 * NT * 128;

    int tid = threadIdx.x, wid = tid >> 5, lane = tid & 31;
    int wx = wid & 3, wy = wid >> 2;

    int aRow = ((lane >> 3) & 1) * 8 + (lane & 7);
    int aKu  = lane >> 4;
    u32 aBase[4]; int aSw[4];
    #pragma unroll
    for (int mi = 0; mi < 4; mi++) {
        int r = wy * 64 + mi * 16 + aRow;
        aBase[mi] = (u32)(r * 128); aSw[mi] = r & 7;
    }
    int bRow = (lane >> 4) * 8 + (lane & 7);
    int bKu  = (lane >> 3) & 1;
    u32 bBase[NJ / 2]; int bSw[NJ / 2];
    #pragma unroll
    for (int p = 0; p < NJ / 2; p++) {
        int r = wx * (NT / 4) + p * 16 + bRow;
        bBase[p] = (u32)(r * 128); bSw[p] = r & 7;
    }

    int nch = K >> 6;

    auto prefetch = [&](int c, int s) {
        u32 st = sbase + s * STG;
        int k0 = c << 6;
        constexpr int TOT = (256 + 2 * NT) * 8;
        #pragma unroll
        for (int u0 = 0; u0 < TOT; u0 += 256) {
            int u = u0 + tid;
            int row, c16;
            const u16* gp;
            u32 abase;
            if (u0 < 2048) {
                row = (u >> 3) & 127; c16 = u & 7;
                bool lo = u >= 1024;
                gp = (lo ? Apl : Aph) + (long)(m0 + row) * lda + k0 + c16 * 8;
                abase = st + (lo ? 16384u : 0u);
            } else {
                int v = u - 2048;
                row = (v >> 3) & (NT - 1); c16 = v & 7;
                bool lo = v >= NT * 8;
                gp = (lo ? Bpl : Bph) + (long)(n0 + row) * ldb + k0 + c16 * 8;
                abase = st + 32768u + (lo ? (u32)(NT * 128) : 0u);
            }
            u32 so = abase + (u32)(row * 128) + ((u32)(c16 ^ (row & 7)) << 4);
            cp16(so, gp);
        }
    };

    prefetch(0, 0);
    CP_COMMIT();

    for (int c = 0; c < nch; c++) {
        if (c + 1 < nch) { prefetch(c + 1, (c + 1) & 1); CP_COMMIT(); CP_WAIT1(); }
        else             { CP_WAIT0(); }
        __syncthreads();

        u32 st = sbase + (c & 1) * STG;
        u32 sAh_ = st, sAl_ = st + 16384, sBh_ = st + 32768, sBl_ = st + 32768 + NT * 128;

        #pragma unroll
        for (int kk = 0; kk < 4; kk++) {
            int kuA = kk * 2 + aKu;
            int kuB = kk * 2 + bKu;
            u32 ah[4][4], xa[4][4], xbh[NJ / 2][4], xbl[NJ / 2][4];
            // hoisted loads: A-hi, B-hi, B-lo in flight before first MMA
            #pragma unroll
            for (int mi = 0; mi < 4; mi++)
                ldsm4(ah[mi], sAh_ + aBase[mi] + ((u32)(kuA ^ aSw[mi]) << 4));
            #pragma unroll
            for (int p = 0; p < NJ / 2; p++)
                ldsm4(xbh[p], sBh_ + bBase[p] + ((u32)(kuB ^ bSw[p]) << 4));
            #pragma unroll
            for (int p = 0; p < NJ / 2; p++)
                ldsm4(xbl[p], sBl_ + bBase[p] + ((u32)(kuB ^ bSw[p]) << 4));
            #pragma unroll
            for (int mi = 0; mi < 4; mi++)
                #pragma unroll
                for (int nj = 0; nj < NJ; nj++)
                    mma16816(d[mi][nj], ah[mi], &xbh[nj >> 1][(nj & 1) * 2]);
            #pragma unroll
            for (int mi = 0; mi < 4; mi++)
                ldsm4(xa[mi], sAl_ + aBase[mi] + ((u32)(kuA ^ aSw[mi]) << 4));
            #pragma unroll
            for (int mi = 0; mi < 4; mi++)
                #pragma unroll
                for (int nj = 0; nj < NJ; nj++)
                    mma16816(d[mi][nj], ah[mi], &xbl[nj >> 1][(nj & 1) * 2]);
            #pragma unroll
            for (int mi = 0; mi < 4; mi++)
                #pragma unroll
                for (int nj = 0; nj < NJ; nj++)
                    mma16816(d[mi][nj], xa[mi], &xbh[nj >> 1][(nj & 1) * 2]);
        }
        __syncthreads();
    }
}

// ---------------------------------------------------------------------------
// Merged Q/K/V projection: grid.x = 24 n-tiles (16 Q, 4 K, 4 V), grid.y = m.
// Q/K: bias + RoPE + split-bf16 out. V: bias + fp32 out.
// ---------------------------------------------------------------------------
__global__ __launch_bounds__(256, 1)
void qkv_gemm(const u16* __restrict__ xh, const u16* __restrict__ xl,
              const u16* __restrict__ qwth, const u16* __restrict__ qwtl, const float* __restrict__ qb,
              const u16* __restrict__ kwth, const u16* __restrict__ kwtl, const float* __restrict__ kb,
              const u16* __restrict__ vwth, const u16* __restrict__ vwtl, const float* __restrict__ vb,
              u16* __restrict__ qh, u16* __restrict__ ql,
              u16* __restrict__ kh, u16* __restrict__ kl,
              float* __restrict__ vf,
              const float* __restrict__ fc, const float* __restrict__ fs,
              const int* __restrict__ sp)
{
    extern __shared__ __align__(16) char dsm[];
    int nt = blockIdx.x, m0 = blockIdx.y * 128;

    const u16 *Bph, *Bpl; const float* bias;
    u16 *Ch = nullptr, *Cl = nullptr; float* Cf = nullptr;
    int ldc, n0;
    if (nt < 16)      { Bph = qwth; Bpl = qwtl; bias = qb; Ch = qh; Cl = ql; ldc = 4096; n0 = nt * 256; }
    else if (nt < 20) { Bph = kwth; Bpl = kwtl; bias = kb; Ch = kh; Cl = kl; ldc = 1024; n0 = (nt - 16) * 256; }
    else              { Bph = vwth; Bpl = vwtl; bias = vb; Cf = vf;          ldc = 1024; n0 = (nt - 20) * 256; }

    float d[4][8][4];
    #pragma unroll
    for (int i = 0; i < 4; i++)
        #pragma unroll
        for (int j = 0; j < 8; j++)
            #pragma unroll
            for (int q = 0; q < 4; q++) d[i][j][q] = 0.f;

    gemm_core<256>(smem_u32(dsm), xh, xl, Bph, Bpl, D_, D_, m0, n0, D_, d);

    int tid = threadIdx.x, wid = tid >> 5, lane = tid & 31;
    int wx = wid & 3, wy = wid >> 2;
    int g = lane >> 2, tg = lane & 3;
    int sp0 = *sp;

    #pragma unroll
    for (int mi = 0; mi < 4; mi++) {
        #pragma unroll
        for (int nj = 0; nj < 8; nj++) {
            int r = m0 + wy * 64 + mi * 16 + g;
            int c = n0 + wx * 64 + nj * 8 + tg * 2;
            float b0 = bias[c], b1 = bias[c + 1];
            float v0 = d[mi][nj][0] + b0, v1 = d[mi][nj][1] + b1;
            float v2 = d[mi][nj][2] + b0, v3 = d[mi][nj][3] + b1;
            long o0 = (long)r * ldc + c;
            long o1 = o0 + 8L * ldc;
            if (Cf) {
                *(float2*)&Cf[o0] = make_float2(v0, v1);
                *(float2*)&Cf[o1] = make_float2(v2, v3);
            } else {
                int i_ = (c & 127) >> 1;
                int s0 = (r & (S_ - 1)) + sp0;
                int s8 = ((r + 8) & (S_ - 1)) + sp0;
                float c0f = fc[s0 * 64 + i_], s0f = fs[s0 * 64 + i_];
                float c8f = fc[s8 * 64 + i_], s8f = fs[s8 * 64 + i_];
                float r0 = v0 * c0f - v1 * s0f, r1 = v0 * s0f + v1 * c0f;
                float r2 = v2 * c8f - v3 * s8f, r3 = v2 * s8f + v3 * c8f;
                u16 h0, l0, h1, l1;
                split2(r0, h0, l0); split2(r1, h1, l1);
                *(u32*)&Ch[o0] = (u32)h0 | ((u32)h1 << 16);
                *(u32*)&Cl[o0] = (u32)l0 | ((u32)l1 << 16);
                split2(r2, h0, l0); split2(r3, h1, l1);
                *(u32*)&Ch[o1] = (u32)h0 | ((u32)h1 << 16);
                *(u32*)&Cl[o1] = (u32)l0 | ((u32)l1 << 16);
            }
        }
    }
}

// ---------------------------------------------------------------------------
// Output projection: out = AO @ ow^T (fp32 out, no bias).
// ---------------------------------------------------------------------------
__global__ __launch_bounds__(256, 1)
void oproj_gemm(const u16* __restrict__ Agh, const u16* __restrict__ Agl,
                const u16* __restrict__ Bgh, const u16* __restrict__ Bgl,
                float* __restrict__ Cf)
{
    extern __shared__ __align__(16) char dsm[];
    int m0 = blockIdx.y * 128, n0 = blockIdx.x * 256;

    float d[4][8][4];
    #pragma unroll
    for (int i = 0; i < 4; i++)
        #pragma unroll
        for (int j = 0; j < 8; j++)
            #pragma unroll
            for (int q = 0; q < 4; q++) d[i][j][q] = 0.f;

    gemm_core<256>(smem_u32(dsm), Agh, Agl, Bgh, Bgl, D_, D_, m0, n0, D_, d);

    int tid = threadIdx.x, wid = tid >> 5, lane = tid & 31;
    int wx = wid & 3, wy = wid >> 2;
    int g = lane >> 2, tg = lane & 3;

    #pragma unroll
    for (int mi = 0; mi < 4; mi++) {
        #pragma unroll
        for (int nj = 0; nj < 8; nj++) {
            int r = m0 + wy * 64 + mi * 16 + g;
            int c = n0 + wx * 64 + nj * 8 + tg * 2;
            long o0 = (long)r * D_ + c;
            long o1 = o0 + 8L * D_;
            *(float2*)&Cf[o0] = make_float2(d[mi][nj][0], d[mi][nj][1]);
            *(float2*)&Cf[o1] = make_float2(d[mi][nj][2], d[mi][nj][3]);
        }
    }
}

// ---------------------------------------------------------------------------
// Fused FlashAttention: S = alpha*Q@K^T (3-term), online softmax, O = P@V.
// ---------------------------------------------------------------------------
#define FA_QH   0
#define FA_QL   32768
#define FA_K    65536
#define FA_V    131072
#define FA_P    163840
#define FA_ST   196608
#define FA_SMEM (196608 + 5632)

__global__ __launch_bounds__(256, 1)
void fa_fused(const u16* __restrict__ Qh, const u16* __restrict__ Ql,
              const u16* __restrict__ Kh, const u16* __restrict__ Kl,
              const u16* __restrict__ Vth, const u16* __restrict__ Vtl,
              u16* __restrict__ Oh, u16* __restrict__ Ol, float alpha)
{
    extern __shared__ __align__(16) char dsm[];
    u32 sbase = smem_u32(dsm);
    float* m_run = (float*)(dsm + FA_ST);
    float* l_run = m_run + 128;
    float* fch   = m_run + 256;
    float* mpart = m_run + 384;
    float* lpart = m_run + 896;

    int m0 = (int)(gridDim.x - 1 - blockIdx.x) * 128;
    int z = blockIdx.y, b = z / HQ, h = z - b * HQ;

    const u16* Qph = Qh + ((long)b * S_ + m0) * D_ + h * HD;
    const u16* Qpl = Ql + ((long)b * S_ + m0) * D_ + h * HD;
    const u16* Kph = Kh + (long)b * S_ * 1024 + (h / GRP) * HD;
    const u16* Kpl = Kl + (long)b * S_ * 1024 + (h / GRP) * HD;
    const u16* Vph = Vth + ((long)b * HKV + (h / GRP)) * (long)HD * S_;
    const u16* Vpl = Vtl + ((long)b * HKV + (h / GRP)) * (long)HD * S_;

    int tid = threadIdx.x, wid = tid >> 5, lane = tid & 31;
    int wx = wid & 3, wy = wid >> 2;
    int g = lane >> 2, tg = lane & 3;

    if (tid < 128) { m_run[tid] = -1e30f; l_run[tid] = 0.f; }

    int aRow = ((lane >> 3) & 1) * 8 + (lane & 7);
    int aKu  = lane >> 4;
    u32 aBase[4]; int aSw[4];
    #pragma unroll
    for (int mi = 0; mi < 4; mi++) {
        int rr = wy * 64 + mi * 16 + aRow;
        aBase[mi] = (u32)(rr * 128); aSw[mi] = rr & 7;
    }
    int bRow = (lane >> 4) * 8 + (lane & 7);
    int bKu  = (lane >> 3) & 1;
    u32 bBaseS = (u32)((wx * 16 + bRow) * 128); int bSwS = bRow & 7;
    u32 bBaseV[2]; int bSwV[2];
    #pragma unroll
    for (int p = 0; p < 2; p++) {
        int rr = wx * 32 + p * 16 + bRow;
        bBaseV[p] = (u32)(rr * 128); bSwV[p] = rr & 7;
    }

    float d_o[4][4][4];
    #pragma unroll
    for (int i = 0; i < 4; i++)
        #pragma unroll
        for (int j = 0; j < 4; j++)
            #pragma unroll
            for (int q = 0; q < 4; q++) d_o[i][j][q] = 0.f;

    int nch = (m0 + 128) >> 6;

    auto qfetch = [&]() {
        #pragma unroll
        for (int u0 = 0; u0 < 4096; u0 += 256) {
            int u = u0 + tid;
            int cc = u >> 11, rest = u & 2047;
            bool lo = rest >= 1024;
            int v = rest & 1023, row = v >> 3, c16 = v & 7;
            const u16* gp = (lo ? Qpl : Qph) + (long)row * D_ + cc * 64 + c16 * 8;
            u32 so = sbase + FA_QH + (u32)cc * 16384 + (lo ? 32768u : 0u)
                   + (u32)(row * 128) + ((u32)(c16 ^ (row & 7)) << 4);
            cp16(so, gp);
        }
    };
    auto kfetch = [&](int c, int s) {
        int j0 = c << 6;
        #pragma unroll
        for (int u0 = 0; u0 < 2048; u0 += 256) {
            int u = u0 + tid;
            int cc = u >> 10, rest = u & 1023;
            bool lo = rest >= 512;
            int v = rest & 511, row = v >> 3, c16 = v & 7;
            const u16* gp = (lo ? Kpl : Kph) + (long)(j0 + row) * 1024 + cc * 64 + c16 * 8;
            u32 so = sbase + FA_K + (u32)s * 32768 + (u32)cc * 8192 + (lo ? 16384u : 0u)
                   + (u32)(row * 128) + ((u32)(c16 ^ (row & 7)) << 4);
            cp16(so, gp);
        }
    };
    auto vfetch = [&](int c) {
        int j0 = c << 6;
        #pragma unroll
        for (int u0 = 0; u0 < 2048; u0 += 256) {
            int u = u0 + tid;
            bool lo = u >= 1024;
            int v = u & 1023, row = v >> 3, c16 = v & 7;
            const u16* gp = (lo ? Vpl : Vph) + (long)row * S_ + j0 + c16 * 8;
            u32 so = sbase + FA_V + (lo ? 16384u : 0u)
                   + (u32)(row * 128) + ((u32)(c16 ^ (row & 7)) << 4);
            cp16(so, gp);
        }
    };

    qfetch();
    CP_COMMIT();
    kfetch(0, 0);
    CP_COMMIT();

    for (int c = 0; c < nch; c++) {
        int j0 = c << 6;
        bool hasNext = (c + 1 < nch);

        vfetch(c); CP_COMMIT();
        if (hasNext) { kfetch(c + 1, (c + 1) & 1); CP_COMMIT(); }

        if (hasNext) CP_WAIT2(); else CP_WAIT1();
        __syncthreads();

        // ---- S = Q @ K^T (3 terms, hoisted LDSM) ----
        float d_s[4][2][4];
        #pragma unroll
        for (int i = 0; i < 4; i++)
            #pragma unroll
            for (int j = 0; j < 2; j++)
                #pragma unroll
                for (int q = 0; q < 4; q++) d_s[i][j][q] = 0.f;

        u32 kst = sbase + FA_K + (u32)(c & 1) * 32768;
        #pragma unroll
        for (int cc = 0; cc < 2; cc++) {
            u32 sQh_ = sbase + FA_QH + (u32)cc * 16384;
            u32 sQl_ = sQh_ + 32768;
            u32 sKh_ = kst + (u32)cc * 8192;
            u32 sKl_ = sKh_ + 16384;
            #pragma unroll
            for (int kk = 0; kk < 4; kk++) {
                int kuA = kk * 2 + aKu;
                int kuB = kk * 2 + bKu;
                u32 ah[4][4], xa[4][4], xbh[4], xbl[4];
                #pragma unroll
                for (int mi = 0; mi < 4; mi++)
                    ldsm4(ah[mi], sQh_ + aBase[mi] + ((u32)(kuA ^ aSw[mi]) << 4));
                ldsm4(xbh, sKh_ + bBaseS + ((u32)(kuB ^ bSwS) << 4));
                ldsm4(xbl, sKl_ + bBaseS + ((u32)(kuB ^ bSwS) << 4));
                #pragma unroll
                for (int mi = 0; mi < 4; mi++)
                    #pragma unroll
                    for (int nj = 0; nj < 2; nj++)
                        mma16816(d_s[mi][nj], ah[mi], &xbh[nj * 2]);
                #pragma unroll
                for (int mi = 0; mi < 4; mi++)
                    ldsm4(xa[mi], sQl_ + aBase[mi] + ((u32)(kuA ^ aSw[mi]) << 4));
                #pragma unroll
                for (int mi = 0; mi < 4; mi++)
                    #pragma unroll
                    for (int nj = 0; nj < 2; nj++)
                        mma16816(d_s[mi][nj], ah[mi], &xbl[nj * 2]);
                #pragma unroll
                for (int mi = 0; mi < 4; mi++)
                    #pragma unroll
                    for (int nj = 0; nj < 2; nj++)
                        mma16816(d_s[mi][nj], xa[mi], &xbh[nj * 2]);
            }
        }

        // ---- mask + alpha + chunk row-max ----
        bool domask = (c >= nch - 2);
        #pragma unroll
        for (int mi = 0; mi < 4; mi++) {
            int rl0 = wy * 64 + mi * 16 + g;
            int grow0 = m0 + rl0, grow8 = grow0 + 8;
            float mx0 = -1e30f, mx8 = -1e30f;
            #pragma unroll
            for (int nj = 0; nj < 2; nj++) {
                #pragma unroll
                for (int e = 0; e < 2; e++) {
                    int gc = j0 + wx * 16 + nj * 8 + tg * 2 + e;
                    float v0 = d_s[mi][nj][e] * alpha;
                    float v8 = d_s[mi][nj][2 + e] * alpha;
                    if (domask) {
                        if (gc > grow0) v0 = -1e30f;
                        if (gc > grow8) v8 = -1e30f;
                    }
                    d_s[mi][nj][e] = v0; d_s[mi][nj][2 + e] = v8;
                    mx0 = fmaxf(mx0, v0); mx8 = fmaxf(mx8, v8);
                }
            }
            mx0 = fmaxf(mx0, __shfl_xor_sync(0xffffffffu, mx0, 1));
            mx0 = fmaxf(mx0, __shfl_xor_sync(0xffffffffu, mx0, 2));
            mx8 = fmaxf(mx8, __shfl_xor_sync(0xffffffffu, mx8, 1));
            mx8 = fmaxf(mx8, __shfl_xor_sync(0xffffffffu, mx8, 2));
            if (tg == 0) {
                mpart[wx * 128 + rl0] = mx0;
                mpart[wx * 128 + rl0 + 8] = mx8;
            }
        }
        __syncthreads();

        if (tid < 128) {
            float mc = fmaxf(fmaxf(mpart[tid], mpart[128 + tid]),
                             fmaxf(mpart[256 + tid], mpart[384 + tid]));
            float mo = m_run[tid];
            float mn = fmaxf(mo, mc);
            fch[tid] = __expf(mo - mn);
            m_run[tid] = mn;
        }
        __syncthreads();

        #pragma unroll
        for (int mi = 0; mi < 4; mi++) {
            int rl = wy * 64 + mi * 16 + g;
            float f0 = fch[rl], f8 = fch[rl + 8];
            #pragma unroll
            for (int nj = 0; nj < 4; nj++) {
                d_o[mi][nj][0] *= f0; d_o[mi][nj][1] *= f0;
                d_o[mi][nj][2] *= f8; d_o[mi][nj][3] *= f8;
            }
        }

        #pragma unroll
        for (int mi = 0; mi < 4; mi++) {
            int rl0 = wy * 64 + mi * 16 + g;
            float mrow0 = m_run[rl0], mrow8 = m_run[rl0 + 8];
            float s0 = 0.f, s8 = 0.f;
            #pragma unroll
            for (int nj = 0; nj < 2; nj++) {
                float p00 = __expf(d_s[mi][nj][0] - mrow0);
                float p01 = __expf(d_s[mi][nj][1] - mrow0);
                float p80 = __expf(d_s[mi][nj][2] - mrow8);
                float p81 = __expf(d_s[mi][nj][3] - mrow8);
                s0 += p00 + p01; s8 += p80 + p81;
                int cl = wx * 16 + nj * 8 + tg * 2;
                u32 u0 = (u32)(((cl >> 3) ^ (rl0 & 7)) << 4) + (u32)((cl & 7) * 2);
                u32 u8 = (u32)(((cl >> 3) ^ ((rl0 + 8) & 7)) << 4) + (u32)((cl & 7) * 2);
                u16 hh, ll, h1, l1;
                split2(p00, hh, ll); split2(p01, h1, l1);
                *(u32*)(dsm + FA_P + rl0 * 128 + u0) = (u32)hh | ((u32)h1 << 16);
                *(u32*)(dsm + FA_P + 16384 + rl0 * 128 + u0) = (u32)ll | ((u32)l1 << 16);
                split2(p80, hh, ll); split2(p81, h1, l1);
                *(u32*)(dsm + FA_P + (rl0 + 8) * 128 + u8) = (u32)hh | ((u32)h1 << 16);
                *(u32*)(dsm + FA_P + 16384 + (rl0 + 8) * 128 + u8) = (u32)ll | ((u32)l1 << 16);
            }
            s0 += __shfl_xor_sync(0xffffffffu, s0, 1);
            s0 += __shfl_xor_sync(0xffffffffu, s0, 2);
            s8 += __shfl_xor_sync(0xffffffffu, s8, 1);
            s8 += __shfl_xor_sync(0xffffffffu, s8, 2);
            if (tg == 0) {
                lpart[wx * 128 + rl0] = s0;
                lpart[wx * 128 + rl0 + 8] = s8;
            }
        }

        if (hasNext) CP_WAIT1(); else CP_WAIT0();
        __syncthreads();

        if (tid < 128) {
            float sum = lpart[tid] + lpart[128 + tid] + lpart[256 + tid] + lpart[384 + tid];
            l_run[tid] = l_run[tid] * fch[tid] + sum;
        }

        // ---- O += P @ V (3 terms, hoisted LDSM) ----
        u32 sPh = sbase + FA_P, sPl = sPh + 16384;
        u32 sVh = sbase + FA_V, sVl = sVh + 16384;
        #pragma unroll
        for (int kk = 0; kk < 4; kk++) {
            int kuA = kk * 2 + aKu;
            int kuB = kk * 2 + bKu;
            u32 ah[4][4], xa[4][4], xbh[2][4], xbl[2][4];
            #pragma unroll
            for (int mi = 0; mi < 4; mi++)
                ldsm4(ah[mi], sPh + aBase[mi] + ((u32)(kuA ^ aSw[mi]) << 4));
            #pragma unroll
            for (int p = 0; p < 2; p++)
                ldsm4(xbh[p], sVh + bBaseV[p] + ((u32)(kuB ^ bSwV[p]) << 4));
            #pragma unroll
            for (int p = 0; p < 2; p++)
                ldsm4(xbl[p], sVl + bBaseV[p] + ((u32)(kuB ^ bSwV[p]) << 4));
            #pragma unroll
            for (int mi = 0; mi < 4; mi++)
                #pragma unroll
                for (int nj = 0; nj < 4; nj++)
                    mma16816(d_o[mi][nj], ah[mi], &xbh[nj >> 1][(nj & 1) * 2]);
            #pragma unroll
            for (int mi = 0; mi < 4; mi++)
                ldsm4(xa[mi], sPl + aBase[mi] + ((u32)(kuA ^ aSw[mi]) << 4));
            #pragma unroll
            for (int mi = 0; mi < 4; mi++)
                #pragma unroll
                for (int nj = 0; nj < 4; nj++)
                    mma16816(d_o[mi][nj], ah[mi], &xbl[nj >> 1][(nj & 1) * 2]);
            #pragma unroll
            for (int mi = 0; mi < 4; mi++)
                #pragma unroll
                for (int nj = 0; nj < 4; nj++)
                    mma16816(d_o[mi][nj], xa[mi], &xbh[nj >> 1][(nj & 1) * 2]);
        }
        __syncthreads();
    }

    #pragma unroll
    for (int mi = 0; mi < 4; mi++) {
        int rl = wy * 64 + mi * 16 + g;
        float i0 = 1.0f / l_run[rl];
        float i8 = 1.0f / l_run[rl + 8];
        #pragma unroll
        for (int nj = 0; nj < 4; nj++) {
            int cc = wx * 32 + nj * 8 + tg * 2;
            long o0 = ((long)b * S_ + m0 + rl) * D_ + h * HD + cc;
            long o1 = o0 + 8L * D_;
            float v0 = d_o[mi][nj][0] * i0, v1 = d_o[mi][nj][1] * i0;
            float v2 = d_o[mi][nj][2] * i8, v3 = d_o[mi][nj][3] * i8;
            u16 h0, l0, h1, l1;
            split2(v0, h0, l0); split2(v1, h1, l1);
            *(u32*)&Oh[o0] = (u32)h0 | ((u32)h1 << 16);
            *(u32*)&Ol[o0] = (u32)l0 | ((u32)l1 << 16);
            split2(v2, h0, l0); split2(v3, h1, l1);
            *(u32*)&Oh[o1] = (u32)h0 | ((u32)h1 << 16);
            *(u32*)&Ol[o1] = (u32)l0 | ((u32)l1 << 16);
        }
    }
}

// ---------------------------------------------------------------------------
__global__ void conv_split(const float* __restrict__ in, u16* __restrict__ oh,
                           u16* __restrict__ ol, long n)
{
    long i = blockIdx.x * 256L + threadIdx.x;
    if (i < n) split2(in[i], oh[i], ol[i]);
}

__global__ void tsplit(const float* __restrict__ in, u16* __restrict__ oh,
                       u16* __restrict__ ol, int ldin, int ldout,
                       long sInB, long sInH, long sOutZ, int Hc)
{
    __shared__ float t[32][33];
    int z = blockIdx.z, bb = z / Hc, hh = z - bb * Hc;
    const float* ip = in + bb * sInB + (long)hh * sInH;
    int c0 = blockIdx.x * 32, r0 = blockIdx.y * 32;
    #pragma unroll
    for (int i = 0; i < 4; i++)
        t[threadIdx.y + i * 8][threadIdx.x] =
            ip[(long)(r0 + threadIdx.y + i * 8) * ldin + c0 + threadIdx.x];
    __syncthreads();
    #pragma unroll
    for (int i = 0; i < 4; i++) {
        int orow = c0 + threadIdx.y + i * 8;
        int oc = r0 + threadIdx.x;
        float v = t[threadIdx.x][threadIdx.y + i * 8];
        long o = z * sOutZ + (long)orow * ldout + oc;
        split2(v, oh[o], ol[o]);
    }
}

// ---------------------------------------------------------------------------
extern "C" void kernel_launch(void* const* d_in, const int* in_sizes, int n_in,
                              void* d_out, int out_size)
{
    const float* x  = (const float*)d_in[0];
    const float* fc = (const float*)d_in[1];
    const float* fs = (const float*)d_in[2];
    const float* qw = (const float*)d_in[3];
    const float* qb = (const float*)d_in[4];
    const float* kw = (const float*)d_in[5];
    const float* kb = (const float*)d_in[6];
    const float* vw = (const float*)d_in[7];
    const float* vb = (const float*)d_in[8];
    const float* ow = (const float*)d_in[9];
    const int*   sp = (const int*)d_in[10];
    float* out = (float*)d_out;

    float *v;
    u16 *xh, *xl, *qwth, *qwtl, *kwth, *kwtl, *vwth, *vwtl, *owth, *owtl;
    u16 *qh, *ql, *kh, *kl, *vth, *vtl, *aoh, *aol;
    cudaGetSymbolAddress((void**)&v, g_v);
    cudaGetSymbolAddress((void**)&xh, g_xh);   cudaGetSymbolAddress((void**)&xl, g_xl);
    cudaGetSymbolAddress((void**)&qwth, g_qwt_h); cudaGetSymbolAddress((void**)&qwtl, g_qwt_l);
    cudaGetSymbolAddress((void**)&kwth, g_kwt_h); cudaGetSymbolAddress((void**)&kwtl, g_kwt_l);
    cudaGetSymbolAddress((void**)&vwth, g_vwt_h); cudaGetSymbolAddress((void**)&vwtl, g_vwt_l);
    cudaGetSymbolAddress((void**)&owth, g_owt_h); cudaGetSymbolAddress((void**)&owtl, g_owt_l);
    cudaGetSymbolAddress((void**)&qh, g_qh);   cudaGetSymbolAddress((void**)&ql, g_ql);
    cudaGetSymbolAddress((void**)&kh, g_kh);   cudaGetSymbolAddress((void**)&kl, g_kl);
    cudaGetSymbolAddress((void**)&vth, g_vth); cudaGetSymbolAddress((void**)&vtl, g_vtl);
    cudaGetSymbolAddress((void**)&aoh, g_aoh); cudaGetSymbolAddress((void**)&aol, g_aol);

    const int SM256 = 2 * (32768 + 2 * 256 * 128);   // 196608
    cudaFuncSetAttribute((const void*)qkv_gemm,
                         cudaFuncAttributeMaxDynamicSharedMemorySize, SM256);
    cudaFuncSetAttribute((const void*)oproj_gemm,
                         cudaFuncAttributeMaxDynamicSharedMemorySize, SM256);
    cudaFuncSetAttribute((const void*)fa_fused,
                         cudaFuncAttributeMaxDynamicSharedMemorySize, FA_SMEM);

    // 1) split-convert activations and weights (weights transposed to [N,K])
    conv_split<<<(unsigned)(((long)MR * D_ + 255) / 256), 256>>>(x, xh, xl, (long)MR * D_);
    dim3 tb(32, 8);
    tsplit<<<dim3(128, 128, 1), tb>>>(qw, qwth, qwtl, D_, D_, 0, 0, 0, 1);
    tsplit<<<dim3(32, 128, 1), tb>>>(kw, kwth, kwtl, 1024, D_, 0, 0, 0, 1);
    tsplit<<<dim3(32, 128, 1), tb>>>(vw, vwth, vwtl, 1024, D_, 0, 0, 0, 1);
    tsplit<<<dim3(128, 128, 1), tb>>>(ow, owth, owtl, D_, D_, 0, 0, 0, 1);

    // 2) merged Q/K/V projections (bias; RoPE+split for Q/K, fp32 for V)
    qkv_gemm<<<dim3(24, 32), 256, SM256>>>(
        xh, xl, qwth, qwtl, qb, kwth, kwtl, kb, vwth, vwtl, vb,
        qh, ql, kh, kl, v, fc, fs, sp);
    // transpose+split V -> [b,h,d,s]
    tsplit<<<dim3(4, 64, B_ * HKV), tb>>>(v, vth, vtl, 1024, S_,
        (long)S_ * 1024, (long)HD, (long)HD * S_, HKV);

    // 3) fused attention -> split bf16 AO in [b,s,h*128+d]
    fa_fused<<<dim3(16, B_ * HQ), 256, FA_SMEM>>>(
        qh, ql, kh, kl, vth, vtl, aoh, aol, 0.08838834764831845f);

    // 4) out = AO @ ow
    oproj_gemm<<<dim3(16, 32), 256, SM256>>>(aoh, aol, owth, owtl, out);
}

// round 9
// speedup vs baseline: 4.1674x; 1.2178x over previous
#include <cuda_runtime.h>
#include <cuda_fp16.h>

typedef unsigned short u16;
typedef unsigned int   u32;

#define B_   2
#define S_   2048
#define D_   4096
#define HQ   32
#define HKV  8
#define HD   128
#define GRP  4
#define MR   (B_*S_)   // 4096

// ---------------- scratch (__device__ globals; no runtime allocation) -------
__device__ float g_v[(size_t)MR*HKV*HD];             // fp32 V (pre-transpose)

__device__ u16 g_xh[(size_t)MR*D_],        g_xl[(size_t)MR*D_];
__device__ u16 g_qwt_h[(size_t)D_*D_],     g_qwt_l[(size_t)D_*D_];
__device__ u16 g_kwt_h[(size_t)1024*D_],   g_kwt_l[(size_t)1024*D_];
__device__ u16 g_vwt_h[(size_t)1024*D_],   g_vwt_l[(size_t)1024*D_];
__device__ u16 g_owt_h[(size_t)D_*D_],     g_owt_l[(size_t)D_*D_];
__device__ u16 g_qh[(size_t)MR*D_],        g_ql[(size_t)MR*D_];           // rope'd Q
__device__ u16 g_kh[(size_t)MR*HKV*HD],    g_kl[(size_t)MR*HKV*HD];       // rope'd K
__device__ u16 g_vth[(size_t)B_*HKV*HD*S_],g_vtl[(size_t)B_*HKV*HD*S_];   // V^T [b,h,d,s]
__device__ u16 g_ao[(size_t)MR*D_];                                       // fp16 attn out

// ---------------------------------------------------------------------------
// fp16 split: v = hi + lo, hi = rn(v), lo = rn(v - hi)
__device__ __forceinline__ void split2(float v, u16& h, u16& l) {
    __half hb = __float2half_rn(v);
    float r = v - __half2float(hb);
    h = __half_as_ushort(hb);
    l = __half_as_ushort(__float2half_rn(r));
}
__device__ __forceinline__ u16 h16(float v) {
    return __half_as_ushort(__float2half_rn(v));
}

__device__ __forceinline__ u32 smem_u32(const void* p) {
    u32 a;
    asm("{ .reg .u64 t; cvta.to.shared.u64 t, %1; cvt.u32.u64 %0, t; }" : "=r"(a) : "l"(p));
    return a;
}

__device__ __forceinline__ void cp16(u32 sdst, const void* gsrc) {
    asm volatile("cp.async.cg.shared.global [%0], [%1], 16;\n" :: "r"(sdst), "l"(gsrc));
}
#define CP_COMMIT()  asm volatile("cp.async.commit_group;" ::: "memory")
#define CP_WAIT2()   asm volatile("cp.async.wait_group 2;" ::: "memory")
#define CP_WAIT1()   asm volatile("cp.async.wait_group 1;" ::: "memory")
#define CP_WAIT0()   asm volatile("cp.async.wait_group 0;" ::: "memory")

__device__ __forceinline__ void ldsm4(u32* r, u32 addr) {
    asm volatile("ldmatrix.sync.aligned.m8n8.x4.shared.b16 {%0,%1,%2,%3}, [%4];"
        : "=r"(r[0]), "=r"(r[1]), "=r"(r[2]), "=r"(r[3]) : "r"(addr));
}

__device__ __forceinline__ void mma16816(float* d, const u32* a, const u32* b) {
    asm volatile(
        "mma.sync.aligned.m16n8k16.row.col.f32.f16.f16.f32 "
        "{%0,%1,%2,%3}, {%4,%5,%6,%7}, {%8,%9}, {%0,%1,%2,%3};\n"
        : "+f"(d[0]), "+f"(d[1]), "+f"(d[2]), "+f"(d[3])
        : "r"(a[0]), "r"(a[1]), "r"(a[2]), "r"(a[3]), "r"(b[0]), "r"(b[1]));
}

// ---------------------------------------------------------------------------
// GEMM mainloop (3-term layout): d += A @ B^T.
// third=true : Ah*Bh + Ah*Bl + Al*Bh ; third=false : Ah*Bh + Ah*Bl.
// 128 x 256 CTA tile, BK=64, 2-stage cp.async, SW128 swizzle.
// ---------------------------------------------------------------------------
__device__ __forceinline__ void gemm_core3(
    u32 sbase,
    const u16* __restrict__ Aph, const u16* __restrict__ Apl,
    const u16* __restrict__ Bph, const u16* __restrict__ Bpl,
    int lda, int ldb, int m0, int n0, int K, bool third,
    float (&d)[4][8][4])
{
    constexpr int NT = 256, NJ = 8;
    constexpr int STG = 32768 + 2 * NT * 128;

    int tid = threadIdx.x, wid = tid >> 5, lane = tid & 31;
    int wx = wid & 3, wy = wid >> 2;

    int aRow = ((lane >> 3) & 1) * 8 + (lane & 7);
    int aKu  = lane >> 4;
    u32 aBase[4]; int aSw[4];
    #pragma unroll
    for (int mi = 0; mi < 4; mi++) {
        int r = wy * 64 + mi * 16 + aRow;
        aBase[mi] = (u32)(r * 128); aSw[mi] = r & 7;
    }
    int bRow = (lane >> 4) * 8 + (lane & 7);
    int bKu  = (lane >> 3) & 1;
    u32 bBase[NJ / 2]; int bSw[NJ / 2];
    #pragma unroll
    for (int p = 0; p < NJ / 2; p++) {
        int r = wx * 64 + p * 16 + bRow;
        bBase[p] = (u32)(r * 128); bSw[p] = r & 7;
    }

    int nch = K >> 6;

    auto prefetch = [&](int c, int s) {
        u32 st = sbase + s * STG;
        int k0 = c << 6;
        constexpr int TOT = (256 + 2 * NT) * 8;
        #pragma unroll
        for (int u0 = 0; u0 < TOT; u0 += 256) {
            int u = u0 + tid;
            int row, c16;
            const u16* gp;
            u32 abase;
            if (u0 < 2048) {
                row = (u >> 3) & 127; c16 = u & 7;
                bool lo = u >= 1024;
                gp = (lo ? Apl : Aph) + (long)(m0 + row) * lda + k0 + c16 * 8;
                abase = st + (lo ? 16384u : 0u);
            } else {
                int v = u - 2048;
                row = (v >> 3) & (NT - 1); c16 = v & 7;
                bool lo = v >= NT * 8;
                gp = (lo ? Bpl : Bph) + (long)(n0 + row) * ldb + k0 + c16 * 8;
                abase = st + 32768u + (lo ? (u32)(NT * 128) : 0u);
            }
            u32 so = abase + (u32)(row * 128) + ((u32)(c16 ^ (row & 7)) << 4);
            cp16(so, gp);
        }
    };

    prefetch(0, 0);
    CP_COMMIT();

    for (int c = 0; c < nch; c++) {
        if (c + 1 < nch) { prefetch(c + 1, (c + 1) & 1); CP_COMMIT(); CP_WAIT1(); }
        else             { CP_WAIT0(); }
        __syncthreads();

        u32 st = sbase + (c & 1) * STG;
        u32 sAh_ = st, sAl_ = st + 16384, sBh_ = st + 32768, sBl_ = st + 32768 + NT * 128;

        #pragma unroll
        for (int kk = 0; kk < 4; kk++) {
            int kuA = kk * 2 + aKu;
            int kuB = kk * 2 + bKu;
            u32 ah[4][4], xbh[NJ / 2][4], xbl[NJ / 2][4];
            #pragma unroll
            for (int mi = 0; mi < 4; mi++)
                ldsm4(ah[mi], sAh_ + aBase[mi] + ((u32)(kuA ^ aSw[mi]) << 4));
            #pragma unroll
            for (int p = 0; p < NJ / 2; p++)
                ldsm4(xbh[p], sBh_ + bBase[p] + ((u32)(kuB ^ bSw[p]) << 4));
            #pragma unroll
            for (int p = 0; p < NJ / 2; p++)
                ldsm4(xbl[p], sBl_ + bBase[p] + ((u32)(kuB ^ bSw[p]) << 4));
            #pragma unroll
            for (int mi = 0; mi < 4; mi++)
                #pragma unroll
                for (int nj = 0; nj < NJ; nj++)
                    mma16816(d[mi][nj], ah[mi], &xbh[nj >> 1][(nj & 1) * 2]);
            #pragma unroll
            for (int mi = 0; mi < 4; mi++)
                #pragma unroll
                for (int nj = 0; nj < NJ; nj++)
                    mma16816(d[mi][nj], ah[mi], &xbl[nj >> 1][(nj & 1) * 2]);
            if (third) {
                u32 xa[4][4];
                #pragma unroll
                for (int mi = 0; mi < 4; mi++)
                    ldsm4(xa[mi], sAl_ + aBase[mi] + ((u32)(kuA ^ aSw[mi]) << 4));
                #pragma unroll
                for (int mi = 0; mi < 4; mi++)
                    #pragma unroll
                    for (int nj = 0; nj < NJ; nj++)
                        mma16816(d[mi][nj], xa[mi], &xbh[nj >> 1][(nj & 1) * 2]);
            }
        }
        __syncthreads();
    }
}

// ---------------------------------------------------------------------------
// 2-term GEMM mainloop, A single-array fp16 (no lo): d += A @ (Bh+Bl)^T.
// ---------------------------------------------------------------------------
__device__ __forceinline__ void gemm_core2(
    u32 sbase,
    const u16* __restrict__ Ap,
    const u16* __restrict__ Bph, const u16* __restrict__ Bpl,
    int lda, int ldb, int m0, int n0, int K,
    float (&d)[4][8][4])
{
    constexpr int NT = 256, NJ = 8;
    constexpr int STG = 16384 + 2 * NT * 128;   // 81920

    int tid = threadIdx.x, wid = tid >> 5, lane = tid & 31;
    int wx = wid & 3, wy = wid >> 2;

    int aRow = ((lane >> 3) & 1) * 8 + (lane & 7);
    int aKu  = lane >> 4;
    u32 aBase[4]; int aSw[4];
    #pragma unroll
    for (int mi = 0; mi < 4; mi++) {
        int r = wy * 64 + mi * 16 + aRow;
        aBase[mi] = (u32)(r * 128); aSw[mi] = r & 7;
    }
    int bRow = (lane >> 4) * 8 + (lane & 7);
    int bKu  = (lane >> 3) & 1;
    u32 bBase[NJ / 2]; int bSw[NJ / 2];
    #pragma unroll
    for (int p = 0; p < NJ / 2; p++) {
        int r = wx * 64 + p * 16 + bRow;
        bBase[p] = (u32)(r * 128); bSw[p] = r & 7;
    }

    int nch = K >> 6;

    auto prefetch = [&](int c, int s) {
        u32 st = sbase + s * STG;
        int k0 = c << 6;
        constexpr int TOT = (128 + 2 * NT) * 8;   // 5120
        #pragma unroll
        for (int u0 = 0; u0 < TOT; u0 += 256) {
            int u = u0 + tid;
            int row, c16;
            const u16* gp;
            u32 abase;
            if (u0 < 1024) {
                row = (u >> 3) & 127; c16 = u & 7;
                gp = Ap + (long)(m0 + row) * lda + k0 + c16 * 8;
                abase = st;
            } else {
                int v = u - 1024;
                row = (v >> 3) & (NT - 1); c16 = v & 7;
                bool lo = v >= NT * 8;
                gp = (lo ? Bpl : Bph) + (long)(n0 + row) * ldb + k0 + c16 * 8;
                abase = st + 16384u + (lo ? (u32)(NT * 128) : 0u);
            }
            u32 so = abase + (u32)(row * 128) + ((u32)(c16 ^ (row & 7)) << 4);
            cp16(so, gp);
        }
    };

    prefetch(0, 0);
    CP_COMMIT();

    for (int c = 0; c < nch; c++) {
        if (c + 1 < nch) { prefetch(c + 1, (c + 1) & 1); CP_COMMIT(); CP_WAIT1(); }
        else             { CP_WAIT0(); }
        __syncthreads();

        u32 st = sbase + (c & 1) * STG;
        u32 sA_ = st, sBh_ = st + 16384, sBl_ = st + 16384 + NT * 128;

        #pragma unroll
        for (int kk = 0; kk < 4; kk++) {
            int kuA = kk * 2 + aKu;
            int kuB = kk * 2 + bKu;
            u32 ah[4][4], xbh[NJ / 2][4], xbl[NJ / 2][4];
            #pragma unroll
            for (int mi = 0; mi < 4; mi++)
                ldsm4(ah[mi], sA_ + aBase[mi] + ((u32)(kuA ^ aSw[mi]) << 4));
            #pragma unroll
            for (int p = 0; p < NJ / 2; p++)
                ldsm4(xbh[p], sBh_ + bBase[p] + ((u32)(kuB ^ bSw[p]) << 4));
            #pragma unroll
            for (int p = 0; p < NJ / 2; p++)
                ldsm4(xbl[p], sBl_ + bBase[p] + ((u32)(kuB ^ bSw[p]) << 4));
            #pragma unroll
            for (int mi = 0; mi < 4; mi++)
                #pragma unroll
                for (int nj = 0; nj < NJ; nj++)
                    mma16816(d[mi][nj], ah[mi], &xbh[nj >> 1][(nj & 1) * 2]);
            #pragma unroll
            for (int mi = 0; mi < 4; mi++)
                #pragma unroll
                for (int nj = 0; nj < NJ; nj++)
                    mma16816(d[mi][nj], ah[mi], &xbl[nj >> 1][(nj & 1) * 2]);
        }
        __syncthreads();
    }
}

// ---------------------------------------------------------------------------
// Merged Q/K/V projection. Q tiles: 2-term (x-hi only). K/V: 3-term.
// Q/K: bias + RoPE + split-fp16 out. V: bias + fp32 out.
// ---------------------------------------------------------------------------
__global__ __launch_bounds__(256, 1)
void qkv_gemm(const u16* __restrict__ xh, const u16* __restrict__ xl,
              const u16* __restrict__ qwth, const u16* __restrict__ qwtl, const float* __restrict__ qb,
              const u16* __restrict__ kwth, const u16* __restrict__ kwtl, const float* __restrict__ kb,
              const u16* __restrict__ vwth, const u16* __restrict__ vwtl, const float* __restrict__ vb,
              u16* __restrict__ qh, u16* __restrict__ ql,
              u16* __restrict__ kh, u16* __restrict__ kl,
              float* __restrict__ vf,
              const float* __restrict__ fc, const float* __restrict__ fs,
              const int* __restrict__ sp)
{
    extern __shared__ __align__(16) char dsm[];
    int nt = blockIdx.x, m0 = blockIdx.y * 128;

    const u16 *Bph, *Bpl; const float* bias;
    u16 *Ch = nullptr, *Cl = nullptr; float* Cf = nullptr;
    int ldc, n0; bool three;
    if (nt < 16)      { Bph = qwth; Bpl = qwtl; bias = qb; Ch = qh; Cl = ql; ldc = 4096; n0 = nt * 256; three = false; }
    else if (nt < 20) { Bph = kwth; Bpl = kwtl; bias = kb; Ch = kh; Cl = kl; ldc = 1024; n0 = (nt - 16) * 256; three = true; }
    else              { Bph = vwth; Bpl = vwtl; bias = vb; Cf = vf;          ldc = 1024; n0 = (nt - 20) * 256; three = true; }

    float d[4][8][4];
    #pragma unroll
    for (int i = 0; i < 4; i++)
        #pragma unroll
        for (int j = 0; j < 8; j++)
            #pragma unroll
            for (int q = 0; q < 4; q++) d[i][j][q] = 0.f;

    gemm_core3(smem_u32(dsm), xh, xl, Bph, Bpl, D_, D_, m0, n0, D_, three, d);

    int tid = threadIdx.x, wid = tid >> 5, lane = tid & 31;
    int wx = wid & 3, wy = wid >> 2;
    int g = lane >> 2, tg = lane & 3;
    int sp0 = *sp;

    #pragma unroll
    for (int mi = 0; mi < 4; mi++) {
        #pragma unroll
        for (int nj = 0; nj < 8; nj++) {
            int r = m0 + wy * 64 + mi * 16 + g;
            int c = n0 + wx * 64 + nj * 8 + tg * 2;
            float b0 = bias[c], b1 = bias[c + 1];
            float v0 = d[mi][nj][0] + b0, v1 = d[mi][nj][1] + b1;
            float v2 = d[mi][nj][2] + b0, v3 = d[mi][nj][3] + b1;
            long o0 = (long)r * ldc + c;
            long o1 = o0 + 8L * ldc;
            if (Cf) {
                *(float2*)&Cf[o0] = make_float2(v0, v1);
                *(float2*)&Cf[o1] = make_float2(v2, v3);
            } else {
                int i_ = (c & 127) >> 1;
                int s0 = (r & (S_ - 1)) + sp0;
                int s8 = ((r + 8) & (S_ - 1)) + sp0;
                float c0f = fc[s0 * 64 + i_], s0f = fs[s0 * 64 + i_];
                float c8f = fc[s8 * 64 + i_], s8f = fs[s8 * 64 + i_];
                float r0 = v0 * c0f - v1 * s0f, r1 = v0 * s0f + v1 * c0f;
                float r2 = v2 * c8f - v3 * s8f, r3 = v2 * s8f + v3 * c8f;
                u16 h0, l0, h1, l1;
                split2(r0, h0, l0); split2(r1, h1, l1);
                *(u32*)&Ch[o0] = (u32)h0 | ((u32)h1 << 16);
                *(u32*)&Cl[o0] = (u32)l0 | ((u32)l1 << 16);
                split2(r2, h0, l0); split2(r3, h1, l1);
                *(u32*)&Ch[o1] = (u32)h0 | ((u32)h1 << 16);
                *(u32*)&Cl[o1] = (u32)l0 | ((u32)l1 << 16);
            }
        }
    }
}

// ---------------------------------------------------------------------------
// Output projection: out = AO(fp16) @ (owh+owl)^T, 2-term. fp32 out.
// ---------------------------------------------------------------------------
__global__ __launch_bounds__(256, 1)
void oproj_gemm(const u16* __restrict__ Ap,
                const u16* __restrict__ Bgh, const u16* __restrict__ Bgl,
                float* __restrict__ Cf)
{
    extern __shared__ __align__(16) char dsm[];
    int m0 = blockIdx.y * 128, n0 = blockIdx.x * 256;

    float d[4][8][4];
    #pragma unroll
    for (int i = 0; i < 4; i++)
        #pragma unroll
        for (int j = 0; j < 8; j++)
            #pragma unroll
            for (int q = 0; q < 4; q++) d[i][j][q] = 0.f;

    gemm_core2(smem_u32(dsm), Ap, Bgh, Bgl, D_, D_, m0, n0, D_, d);

    int tid = threadIdx.x, wid = tid >> 5, lane = tid & 31;
    int wx = wid & 3, wy = wid >> 2;
    int g = lane >> 2, tg = lane & 3;

    #pragma unroll
    for (int mi = 0; mi < 4; mi++) {
        #pragma unroll
        for (int nj = 0; nj < 8; nj++) {
            int r = m0 + wy * 64 + mi * 16 + g;
            int c = n0 + wx * 64 + nj * 8 + tg * 2;
            long o0 = (long)r * D_ + c;
            long o1 = o0 + 8L * D_;
            *(float2*)&Cf[o0] = make_float2(d[mi][nj][0], d[mi][nj][1]);
            *(float2*)&Cf[o1] = make_float2(d[mi][nj][2], d[mi][nj][3]);
        }
    }
}

// ---------------------------------------------------------------------------
// Fused FlashAttention (3-term fp16): S = alpha*Q@K^T, online softmax, O=P@V.
// Epilogue writes single fp16 AO (2-term O-projection consumes it).
// ---------------------------------------------------------------------------
#define FA_QH   0
#define FA_QL   32768
#define FA_K    65536
#define FA_V    131072
#define FA_P    163840
#define FA_ST   196608
#define FA_SMEM (196608 + 5632)

__global__ __launch_bounds__(256, 1)
void fa_fused(const u16* __restrict__ Qh, const u16* __restrict__ Ql,
              const u16* __restrict__ Kh, const u16* __restrict__ Kl,
              const u16* __restrict__ Vth, const u16* __restrict__ Vtl,
              u16* __restrict__ Ao, float alpha)
{
    extern __shared__ __align__(16) char dsm[];
    u32 sbase = smem_u32(dsm);
    float* m_run = (float*)(dsm + FA_ST);
    float* l_run = m_run + 128;
    float* fch   = m_run + 256;
    float* mpart = m_run + 384;
    float* lpart = m_run + 896;

    int m0 = (int)(gridDim.x - 1 - blockIdx.x) * 128;
    int z = blockIdx.y, b = z / HQ, h = z - b * HQ;

    const u16* Qph = Qh + ((long)b * S_ + m0) * D_ + h * HD;
    const u16* Qpl = Ql + ((long)b * S_ + m0) * D_ + h * HD;
    const u16* Kph = Kh + (long)b * S_ * 1024 + (h / GRP) * HD;
    const u16* Kpl = Kl + (long)b * S_ * 1024 + (h / GRP) * HD;
    const u16* Vph = Vth + ((long)b * HKV + (h / GRP)) * (long)HD * S_;
    const u16* Vpl = Vtl + ((long)b * HKV + (h / GRP)) * (long)HD * S_;

    int tid = threadIdx.x, wid = tid >> 5, lane = tid & 31;
    int wx = wid & 3, wy = wid >> 2;
    int g = lane >> 2, tg = lane & 3;

    if (tid < 128) { m_run[tid] = -1e30f; l_run[tid] = 0.f; }

    int aRow = ((lane >> 3) & 1) * 8 + (lane & 7);
    int aKu  = lane >> 4;
    u32 aBase[4]; int aSw[4];
    #pragma unroll
    for (int mi = 0; mi < 4; mi++) {
        int rr = wy * 64 + mi * 16 + aRow;
        aBase[mi] = (u32)(rr * 128); aSw[mi] = rr & 7;
    }
    int bRow = (lane >> 4) * 8 + (lane & 7);
    int bKu  = (lane >> 3) & 1;
    u32 bBaseS = (u32)((wx * 16 + bRow) * 128); int bSwS = bRow & 7;
    u32 bBaseV[2]; int bSwV[2];
    #pragma unroll
    for (int p = 0; p < 2; p++) {
        int rr = wx * 32 + p * 16 + bRow;
        bBaseV[p] = (u32)(rr * 128); bSwV[p] = rr & 7;
    }

    float d_o[4][4][4];
    #pragma unroll
    for (int i = 0; i < 4; i++)
        #pragma unroll
        for (int j = 0; j < 4; j++)
            #pragma unroll
            for (int q = 0; q < 4; q++) d_o[i][j][q] = 0.f;

    int nch = (m0 + 128) >> 6;

    auto qfetch = [&]() {
        #pragma unroll
        for (int u0 = 0; u0 < 4096; u0 += 256) {
            int u = u0 + tid;
            int cc = u >> 11, rest = u & 2047;
            bool lo = rest >= 1024;
            int v = rest & 1023, row = v >> 3, c16 = v & 7;
            const u16* gp = (lo ? Qpl : Qph) + (long)row * D_ + cc * 64 + c16 * 8;
            u32 so = sbase + FA_QH + (u32)cc * 16384 + (lo ? 32768u : 0u)
                   + (u32)(row * 128) + ((u32)(c16 ^ (row & 7)) << 4);
            cp16(so, gp);
        }
    };
    auto kfetch = [&](int c, int s) {
        int j0 = c << 6;
        #pragma unroll
        for (int u0 = 0; u0 < 2048; u0 += 256) {
            int u = u0 + tid;
            int cc = u >> 10, rest = u & 1023;
            bool lo = rest >= 512;
            int v = rest & 511, row = v >> 3, c16 = v & 7;
            const u16* gp = (lo ? Kpl : Kph) + (long)(j0 + row) * 1024 + cc * 64 + c16 * 8;
            u32 so = sbase + FA_K + (u32)s * 32768 + (u32)cc * 8192 + (lo ? 16384u : 0u)
                   + (u32)(row * 128) + ((u32)(c16 ^ (row & 7)) << 4);
            cp16(so, gp);
        }
    };
    auto vfetch = [&](int c) {
        int j0 = c << 6;
        #pragma unroll
        for (int u0 = 0; u0 < 2048; u0 += 256) {
            int u = u0 + tid;
            bool lo = u >= 1024;
            int v = u & 1023, row = v >> 3, c16 = v & 7;
            const u16* gp = (lo ? Vpl : Vph) + (long)row * S_ + j0 + c16 * 8;
            u32 so = sbase + FA_V + (lo ? 16384u : 0u)
                   + (u32)(row * 128) + ((u32)(c16 ^ (row & 7)) << 4);
            cp16(so, gp);
        }
    };

    qfetch();
    CP_COMMIT();
    kfetch(0, 0);
    CP_COMMIT();

    for (int c = 0; c < nch; c++) {
        int j0 = c << 6;
        bool hasNext = (c + 1 < nch);

        vfetch(c); CP_COMMIT();
        if (hasNext) { kfetch(c + 1, (c + 1) & 1); CP_COMMIT(); }

        if (hasNext) CP_WAIT2(); else CP_WAIT1();
        __syncthreads();

        // ---- S = Q @ K^T (3 terms) ----
        float d_s[4][2][4];
        #pragma unroll
        for (int i = 0; i < 4; i++)
            #pragma unroll
            for (int j = 0; j < 2; j++)
                #pragma unroll
                for (int q = 0; q < 4; q++) d_s[i][j][q] = 0.f;

        u32 kst = sbase + FA_K + (u32)(c & 1) * 32768;
        #pragma unroll
        for (int cc = 0; cc < 2; cc++) {
            u32 sQh_ = sbase + FA_QH + (u32)cc * 16384;
            u32 sQl_ = sQh_ + 32768;
            u32 sKh_ = kst + (u32)cc * 8192;
            u32 sKl_ = sKh_ + 16384;
            #pragma unroll
            for (int kk = 0; kk < 4; kk++) {
                int kuA = kk * 2 + aKu;
                int kuB = kk * 2 + bKu;
                u32 ah[4][4], xa[4][4], xbh[4], xbl[4];
                #pragma unroll
                for (int mi = 0; mi < 4; mi++)
                    ldsm4(ah[mi], sQh_ + aBase[mi] + ((u32)(kuA ^ aSw[mi]) << 4));
                ldsm4(xbh, sKh_ + bBaseS + ((u32)(kuB ^ bSwS) << 4));
                ldsm4(xbl, sKl_ + bBaseS + ((u32)(kuB ^ bSwS) << 4));
                #pragma unroll
                for (int mi = 0; mi < 4; mi++)
                    #pragma unroll
                    for (int nj = 0; nj < 2; nj++)
                        mma16816(d_s[mi][nj], ah[mi], &xbh[nj * 2]);
                #pragma unroll
                for (int mi = 0; mi < 4; mi++)
                    ldsm4(xa[mi], sQl_ + aBase[mi] + ((u32)(kuA ^ aSw[mi]) << 4));
                #pragma unroll
                for (int mi = 0; mi < 4; mi++)
                    #pragma unroll
                    for (int nj = 0; nj < 2; nj++)
                        mma16816(d_s[mi][nj], ah[mi], &xbl[nj * 2]);
                #pragma unroll
                for (int mi = 0; mi < 4; mi++)
                    #pragma unroll
                    for (int nj = 0; nj < 2; nj++)
                        mma16816(d_s[mi][nj], xa[mi], &xbh[nj * 2]);
            }
        }

        // ---- mask + alpha + chunk row-max ----
        bool domask = (c >= nch - 2);
        #pragma unroll
        for (int mi = 0; mi < 4; mi++) {
            int rl0 = wy * 64 + mi * 16 + g;
            int grow0 = m0 + rl0, grow8 = grow0 + 8;
            float mx0 = -1e30f, mx8 = -1e30f;
            #pragma unroll
            for (int nj = 0; nj < 2; nj++) {
                #pragma unroll
                for (int e = 0; e < 2; e++) {
                    int gc = j0 + wx * 16 + nj * 8 + tg * 2 + e;
                    float v0 = d_s[mi][nj][e] * alpha;
                    float v8 = d_s[mi][nj][2 + e] * alpha;
                    if (domask) {
                        if (gc > grow0) v0 = -1e30f;
                        if (gc > grow8) v8 = -1e30f;
                    }
                    d_s[mi][nj][e] = v0; d_s[mi][nj][2 + e] = v8;
                    mx0 = fmaxf(mx0, v0); mx8 = fmaxf(mx8, v8);
                }
            }
            mx0 = fmaxf(mx0, __shfl_xor_sync(0xffffffffu, mx0, 1));
            mx0 = fmaxf(mx0, __shfl_xor_sync(0xffffffffu, mx0, 2));
            mx8 = fmaxf(mx8, __shfl_xor_sync(0xffffffffu, mx8, 1));
            mx8 = fmaxf(mx8, __shfl_xor_sync(0xffffffffu, mx8, 2));
            if (tg == 0) {
                mpart[wx * 128 + rl0] = mx0;
                mpart[wx * 128 + rl0 + 8] = mx8;
            }
        }
        __syncthreads();

        if (tid < 128) {
            float mc = fmaxf(fmaxf(mpart[tid], mpart[128 + tid]),
                             fmaxf(mpart[256 + tid], mpart[384 + tid]));
            float mo = m_run[tid];
            float mn = fmaxf(mo, mc);
            fch[tid] = __expf(mo - mn);
            m_run[tid] = mn;
        }
        __syncthreads();

        #pragma unroll
        for (int mi = 0; mi < 4; mi++) {
            int rl = wy * 64 + mi * 16 + g;
            float f0 = fch[rl], f8 = fch[rl + 8];
            #pragma unroll
            for (int nj = 0; nj < 4; nj++) {
                d_o[mi][nj][0] *= f0; d_o[mi][nj][1] *= f0;
                d_o[mi][nj][2] *= f8; d_o[mi][nj][3] *= f8;
            }
        }

        #pragma unroll
        for (int mi = 0; mi < 4; mi++) {
            int rl0 = wy * 64 + mi * 16 + g;
            float mrow0 = m_run[rl0], mrow8 = m_run[rl0 + 8];
            float s0 = 0.f, s8 = 0.f;
            #pragma unroll
            for (int nj = 0; nj < 2; nj++) {
                float p00 = __expf(d_s[mi][nj][0] - mrow0);
                float p01 = __expf(d_s[mi][nj][1] - mrow0);
                float p80 = __expf(d_s[mi][nj][2] - mrow8);
                float p81 = __expf(d_s[mi][nj][3] - mrow8);
                s0 += p00 + p01; s8 += p80 + p81;
                int cl = wx * 16 + nj * 8 + tg * 2;
                u32 u0 = (u32)(((cl >> 3) ^ (rl0 & 7)) << 4) + (u32)((cl & 7) * 2);
                u32 u8 = (u32)(((cl >> 3) ^ ((rl0 + 8) & 7)) << 4) + (u32)((cl & 7) * 2);
                u16 hh, ll, h1, l1;
                split2(p00, hh, ll); split2(p01, h1, l1);
                *(u32*)(dsm + FA_P + rl0 * 128 + u0) = (u32)hh | ((u32)h1 << 16);
                *(u32*)(dsm + FA_P + 16384 + rl0 * 128 + u0) = (u32)ll | ((u32)l1 << 16);
                split2(p80, hh, ll); split2(p81, h1, l1);
                *(u32*)(dsm + FA_P + (rl0 + 8) * 128 + u8) = (u32)hh | ((u32)h1 << 16);
                *(u32*)(dsm + FA_P + 16384 + (rl0 + 8) * 128 + u8) = (u32)ll | ((u32)l1 << 16);
            }
            s0 += __shfl_xor_sync(0xffffffffu, s0, 1);
            s0 += __shfl_xor_sync(0xffffffffu, s0, 2);
            s8 += __shfl_xor_sync(0xffffffffu, s8, 1);
            s8 += __shfl_xor_sync(0xffffffffu, s8, 2);
            if (tg == 0) {
                lpart[wx * 128 + rl0] = s0;
                lpart[wx * 128 + rl0 + 8] = s8;
            }
        }

        if (hasNext) CP_WAIT1(); else CP_WAIT0();
        __syncthreads();

        if (tid < 128) {
            float sum = lpart[tid] + lpart[128 + tid] + lpart[256 + tid] + lpart[384 + tid];
            l_run[tid] = l_run[tid] * fch[tid] + sum;
        }

        // ---- O += P @ V (3 terms) ----
        u32 sPh = sbase + FA_P, sPl = sPh + 16384;
        u32 sVh = sbase + FA_V, sVl = sVh + 16384;
        #pragma unroll
        for (int kk = 0; kk < 4; kk++) {
            int kuA = kk * 2 + aKu;
            int kuB = kk * 2 + bKu;
            u32 ah[4][4], xa[4][4], xbh[2][4], xbl[2][4];
            #pragma unroll
            for (int mi = 0; mi < 4; mi++)
                ldsm4(ah[mi], sPh + aBase[mi] + ((u32)(kuA ^ aSw[mi]) << 4));
            #pragma unroll
            for (int p = 0; p < 2; p++)
                ldsm4(xbh[p], sVh + bBaseV[p] + ((u32)(kuB ^ bSwV[p]) << 4));
            #pragma unroll
            for (int p = 0; p < 2; p++)
                ldsm4(xbl[p], sVl + bBaseV[p] + ((u32)(kuB ^ bSwV[p]) << 4));
            #pragma unroll
            for (int mi = 0; mi < 4; mi++)
                #pragma unroll
                for (int nj = 0; nj < 4; nj++)
                    mma16816(d_o[mi][nj], ah[mi], &xbh[nj >> 1][(nj & 1) * 2]);
            #pragma unroll
            for (int mi = 0; mi < 4; mi++)
                ldsm4(xa[mi], sPl + aBase[mi] + ((u32)(kuA ^ aSw[mi]) << 4));
            #pragma unroll
            for (int mi = 0; mi < 4; mi++)
                #pragma unroll
                for (int nj = 0; nj < 4; nj++)
                    mma16816(d_o[mi][nj], ah[mi], &xbl[nj >> 1][(nj & 1) * 2]);
            #pragma unroll
            for (int mi = 0; mi < 4; mi++)
                #pragma unroll
                for (int nj = 0; nj < 4; nj++)
                    mma16816(d_o[mi][nj], xa[mi], &xbh[nj >> 1][(nj & 1) * 2]);
        }
        __syncthreads();
    }

    // epilogue: divide by l, fp16-truncate, store single AO array
    #pragma unroll
    for (int mi = 0; mi < 4; mi++) {
        int rl = wy * 64 + mi * 16 + g;
        float i0 = 1.0f / l_run[rl];
        float i8 = 1.0f / l_run[rl + 8];
        #pragma unroll
        for (int nj = 0; nj < 4; nj++) {
            int cc = wx * 32 + nj * 8 + tg * 2;
            long o0 = ((long)b * S_ + m0 + rl) * D_ + h * HD + cc;
            long o1 = o0 + 8L * D_;
            u16 a0 = h16(d_o[mi][nj][0] * i0), a1 = h16(d_o[mi][nj][1] * i0);
            u16 a2 = h16(d_o[mi][nj][2] * i8), a3 = h16(d_o[mi][nj][3] * i8);
            *(u32*)&Ao[o0] = (u32)a0 | ((u32)a1 << 16);
            *(u32*)&Ao[o1] = (u32)a2 | ((u32)a3 << 16);
        }
    }
}

// ---------------------------------------------------------------------------
__global__ void conv_split(const float* __restrict__ in, u16* __restrict__ oh,
                           u16* __restrict__ ol, long n)
{
    long i = blockIdx.x * 256L + threadIdx.x;
    if (i < n) split2(in[i], oh[i], ol[i]);
}

__global__ void tsplit(const float* __restrict__ in, u16* __restrict__ oh,
                       u16* __restrict__ ol, int ldin, int ldout,
                       long sInB, long sInH, long sOutZ, int Hc)
{
    __shared__ float t[32][33];
    int z = blockIdx.z, bb = z / Hc, hh = z - bb * Hc;
    const float* ip = in + bb * sInB + (long)hh * sInH;
    int c0 = blockIdx.x * 32, r0 = blockIdx.y * 32;
    #pragma unroll
    for (int i = 0; i < 4; i++)
        t[threadIdx.y + i * 8][threadIdx.x] =
            ip[(long)(r0 + threadIdx.y + i * 8) * ldin + c0 + threadIdx.x];
    __syncthreads();
    #pragma unroll
    for (int i = 0; i < 4; i++) {
        int orow = c0 + threadIdx.y + i * 8;
        int oc = r0 + threadIdx.x;
        float v = t[threadIdx.x][threadIdx.y + i * 8];
        long o = z * sOutZ + (long)orow * ldout + oc;
        split2(v, oh[o], ol[o]);
    }
}

// ---------------------------------------------------------------------------
extern "C" void kernel_launch(void* const* d_in, const int* in_sizes, int n_in,
                              void* d_out, int out_size)
{
    const float* x  = (const float*)d_in[0];
    const float* fc = (const float*)d_in[1];
    const float* fs = (const float*)d_in[2];
    const float* qw = (const float*)d_in[3];
    const float* qb = (const float*)d_in[4];
    const float* kw = (const float*)d_in[5];
    const float* kb = (const float*)d_in[6];
    const float* vw = (const float*)d_in[7];
    const float* vb = (const float*)d_in[8];
    const float* ow = (const float*)d_in[9];
    const int*   sp = (const int*)d_in[10];
    float* out = (float*)d_out;

    float *v;
    u16 *xh, *xl, *qwth, *qwtl, *kwth, *kwtl, *vwth, *vwtl, *owth, *owtl;
    u16 *qh, *ql, *kh, *kl, *vth, *vtl, *ao;
    cudaGetSymbolAddress((void**)&v, g_v);
    cudaGetSymbolAddress((void**)&xh, g_xh);   cudaGetSymbolAddress((void**)&xl, g_xl);
    cudaGetSymbolAddress((void**)&qwth, g_qwt_h); cudaGetSymbolAddress((void**)&qwtl, g_qwt_l);
    cudaGetSymbolAddress((void**)&kwth, g_kwt_h); cudaGetSymbolAddress((void**)&kwtl, g_kwt_l);
    cudaGetSymbolAddress((void**)&vwth, g_vwt_h); cudaGetSymbolAddress((void**)&vwtl, g_vwt_l);
    cudaGetSymbolAddress((void**)&owth, g_owt_h); cudaGetSymbolAddress((void**)&owtl, g_owt_l);
    cudaGetSymbolAddress((void**)&qh, g_qh);   cudaGetSymbolAddress((void**)&ql, g_ql);
    cudaGetSymbolAddress((void**)&kh, g_kh);   cudaGetSymbolAddress((void**)&kl, g_kl);
    cudaGetSymbolAddress((void**)&vth, g_vth); cudaGetSymbolAddress((void**)&vtl, g_vtl);
    cudaGetSymbolAddress((void**)&ao, g_ao);

    const int SM3 = 2 * (32768 + 2 * 256 * 128);   // 196608
    const int SM2 = 2 * (16384 + 2 * 256 * 128);   // 163840
    cudaFuncSetAttribute((const void*)qkv_gemm,
                         cudaFuncAttributeMaxDynamicSharedMemorySize, SM3);
    cudaFuncSetAttribute((const void*)oproj_gemm,
                         cudaFuncAttributeMaxDynamicSharedMemorySize, SM2);
    cudaFuncSetAttribute((const void*)fa_fused,
                         cudaFuncAttributeMaxDynamicSharedMemorySize, FA_SMEM);

    // 1) split-convert activations and weights (weights transposed to [N,K])
    conv_split<<<(unsigned)(((long)MR * D_ + 255) / 256), 256>>>(x, xh, xl, (long)MR * D_);
    dim3 tb(32, 8);
    tsplit<<<dim3(128, 128, 1), tb>>>(qw, qwth, qwtl, D_, D_, 0, 0, 0, 1);
    tsplit<<<dim3(32, 128, 1), tb>>>(kw, kwth, kwtl, 1024, D_, 0, 0, 0, 1);
    tsplit<<<dim3(32, 128, 1), tb>>>(vw, vwth, vwtl, 1024, D_, 0, 0, 0, 1);
    tsplit<<<dim3(128, 128, 1), tb>>>(ow, owth, owtl, D_, D_, 0, 0, 0, 1);

    // 2) merged Q/K/V projections (Q 2-term; K/V 3-term; RoPE for Q/K)
    qkv_gemm<<<dim3(24, 32), 256, SM3>>>(
        xh, xl, qwth, qwtl, qb, kwth, kwtl, kb, vwth, vwtl, vb,
        qh, ql, kh, kl, v, fc, fs, sp);
    // transpose+split V -> [b,h,d,s]
    tsplit<<<dim3(4, 64, B_ * HKV), tb>>>(v, vth, vtl, 1024, S_,
        (long)S_ * 1024, (long)HD, (long)HD * S_, HKV);

    // 3) fused attention (3-term fp16) -> single fp16 AO in [b,s,h*128+d]
    fa_fused<<<dim3(16, B_ * HQ), 256, FA_SMEM>>>(
        qh, ql, kh, kl, vth, vtl, ao, 0.08838834764831845f);

    // 4) out = AO @ ow (2-term)
    oproj_gemm<<<dim3(16, 32), 256, SM2>>>(ao, owth, owtl, out);
}

// round 10
// speedup vs baseline: 4.5031x; 1.0806x over previous
#include <cuda_runtime.h>
#include <cuda_fp16.h>

typedef unsigned short u16;
typedef unsigned int   u32;

#define B_   2
#define S_   2048
#define D_   4096
#define HQ   32
#define HKV  8
#define HD   128
#define GRP  4
#define MR   (B_*S_)   // 4096

// ---------------- scratch (__device__ globals; no runtime allocation) -------
__device__ float g_v[(size_t)MR*HKV*HD];             // fp32 V (pre-transpose)

__device__ u16 g_xh[(size_t)MR*D_],        g_xl[(size_t)MR*D_];
__device__ u16 g_qwt_h[(size_t)D_*D_],     g_qwt_l[(size_t)D_*D_];
__device__ u16 g_kwt_h[(size_t)1024*D_],   g_kwt_l[(size_t)1024*D_];
__device__ u16 g_vwt_h[(size_t)1024*D_],   g_vwt_l[(size_t)1024*D_];
__device__ u16 g_owt_h[(size_t)D_*D_],     g_owt_l[(size_t)D_*D_];
__device__ u16 g_qh[(size_t)MR*D_];                                       // rope'd Q (hi only)
__device__ u16 g_kh[(size_t)MR*HKV*HD],    g_kl[(size_t)MR*HKV*HD];       // rope'd K (split)
__device__ u16 g_vth[(size_t)B_*HKV*HD*S_],g_vtl[(size_t)B_*HKV*HD*S_];   // V^T [b,h,d,s]
__device__ u16 g_ao[(size_t)MR*D_];                                       // fp16 attn out

// ---------------------------------------------------------------------------
__device__ __forceinline__ void split2(float v, u16& h, u16& l) {
    __half hb = __float2half_rn(v);
    float r = v - __half2float(hb);
    h = __half_as_ushort(hb);
    l = __half_as_ushort(__float2half_rn(r));
}
__device__ __forceinline__ u16 h16(float v) {
    return __half_as_ushort(__float2half_rn(v));
}

__device__ __forceinline__ u32 smem_u32(const void* p) {
    u32 a;
    asm("{ .reg .u64 t; cvta.to.shared.u64 t, %1; cvt.u32.u64 %0, t; }" : "=r"(a) : "l"(p));
    return a;
}

__device__ __forceinline__ void cp16(u32 sdst, const void* gsrc) {
    asm volatile("cp.async.cg.shared.global [%0], [%1], 16;\n" :: "r"(sdst), "l"(gsrc));
}
#define CP_COMMIT()  asm volatile("cp.async.commit_group;" ::: "memory")
#define CP_WAIT2()   asm volatile("cp.async.wait_group 2;" ::: "memory")
#define CP_WAIT1()   asm volatile("cp.async.wait_group 1;" ::: "memory")
#define CP_WAIT0()   asm volatile("cp.async.wait_group 0;" ::: "memory")

__device__ __forceinline__ void ldsm4(u32* r, u32 addr) {
    asm volatile("ldmatrix.sync.aligned.m8n8.x4.shared.b16 {%0,%1,%2,%3}, [%4];"
        : "=r"(r[0]), "=r"(r[1]), "=r"(r[2]), "=r"(r[3]) : "r"(addr));
}

__device__ __forceinline__ void mma16816(float* d, const u32* a, const u32* b) {
    asm volatile(
        "mma.sync.aligned.m16n8k16.row.col.f32.f16.f16.f32 "
        "{%0,%1,%2,%3}, {%4,%5,%6,%7}, {%8,%9}, {%0,%1,%2,%3};\n"
        : "+f"(d[0]), "+f"(d[1]), "+f"(d[2]), "+f"(d[3])
        : "r"(a[0]), "r"(a[1]), "r"(a[2]), "r"(a[3]), "r"(b[0]), "r"(b[1]));
}

// ---------------------------------------------------------------------------
// GEMM mainloop: d += A @ B^T.
// third=true : Ah*Bh + Ah*Bl + Al*Bh ; third=false : Ah*Bh + Ah*Bl.
// 128 x 256 CTA tile, BK=64, 2-stage cp.async, SW128 swizzle.
// ---------------------------------------------------------------------------
__device__ __forceinline__ void gemm_core3(
    u32 sbase,
    const u16* __restrict__ Aph, const u16* __restrict__ Apl,
    const u16* __restrict__ Bph, const u16* __restrict__ Bpl,
    int lda, int ldb, int m0, int n0, int K, bool third,
    float (&d)[4][8][4])
{
    constexpr int NT = 256, NJ = 8;
    constexpr int STG = 32768 + 2 * NT * 128;

    int tid = threadIdx.x, wid = tid >> 5, lane = tid & 31;
    int wx = wid & 3, wy = wid >> 2;

    int aRow = ((lane >> 3) & 1) * 8 + (lane & 7);
    int aKu  = lane >> 4;
    u32 aBase[4]; int aSw[4];
    #pragma unroll
    for (int mi = 0; mi < 4; mi++) {
        int r = wy * 64 + mi * 16 + aRow;
        aBase[mi] = (u32)(r * 128); aSw[mi] = r & 7;
    }
    int bRow = (lane >> 4) * 8 + (lane & 7);
    int bKu  = (lane >> 3) & 1;
    u32 bBase[NJ / 2]; int bSw[NJ / 2];
    #pragma unroll
    for (int p = 0; p < NJ / 2; p++) {
        int r = wx * 64 + p * 16 + bRow;
        bBase[p] = (u32)(r * 128); bSw[p] = r & 7;
    }

    int nch = K >> 6;

    auto prefetch = [&](int c, int s) {
        u32 st = sbase + s * STG;
        int k0 = c << 6;
        constexpr int TOT = (256 + 2 * NT) * 8;
        #pragma unroll
        for (int u0 = 0; u0 < TOT; u0 += 256) {
            int u = u0 + tid;
            int row, c16;
            const u16* gp;
            u32 abase;
            if (u0 < 2048) {
                row = (u >> 3) & 127; c16 = u & 7;
                bool lo = u >= 1024;
                gp = (lo ? Apl : Aph) + (long)(m0 + row) * lda + k0 + c16 * 8;
                abase = st + (lo ? 16384u : 0u);
            } else {
                int v = u - 2048;
                row = (v >> 3) & (NT - 1); c16 = v & 7;
                bool lo = v >= NT * 8;
                gp = (lo ? Bpl : Bph) + (long)(n0 + row) * ldb + k0 + c16 * 8;
                abase = st + 32768u + (lo ? (u32)(NT * 128) : 0u);
            }
            u32 so = abase + (u32)(row * 128) + ((u32)(c16 ^ (row & 7)) << 4);
            cp16(so, gp);
        }
    };

    prefetch(0, 0);
    CP_COMMIT();

    for (int c = 0; c < nch; c++) {
        if (c + 1 < nch) { prefetch(c + 1, (c + 1) & 1); CP_COMMIT(); CP_WAIT1(); }
        else             { CP_WAIT0(); }
        __syncthreads();

        u32 st = sbase + (c & 1) * STG;
        u32 sAh_ = st, sAl_ = st + 16384, sBh_ = st + 32768, sBl_ = st + 32768 + NT * 128;

        #pragma unroll
        for (int kk = 0; kk < 4; kk++) {
            int kuA = kk * 2 + aKu;
            int kuB = kk * 2 + bKu;
            u32 ah[4][4], xbh[NJ / 2][4], xbl[NJ / 2][4];
            #pragma unroll
            for (int mi = 0; mi < 4; mi++)
                ldsm4(ah[mi], sAh_ + aBase[mi] + ((u32)(kuA ^ aSw[mi]) << 4));
            #pragma unroll
            for (int p = 0; p < NJ / 2; p++)
                ldsm4(xbh[p], sBh_ + bBase[p] + ((u32)(kuB ^ bSw[p]) << 4));
            #pragma unroll
            for (int p = 0; p < NJ / 2; p++)
                ldsm4(xbl[p], sBl_ + bBase[p] + ((u32)(kuB ^ bSw[p]) << 4));
            #pragma unroll
            for (int mi = 0; mi < 4; mi++)
                #pragma unroll
                for (int nj = 0; nj < NJ; nj++)
                    mma16816(d[mi][nj], ah[mi], &xbh[nj >> 1][(nj & 1) * 2]);
            #pragma unroll
            for (int mi = 0; mi < 4; mi++)
                #pragma unroll
                for (int nj = 0; nj < NJ; nj++)
                    mma16816(d[mi][nj], ah[mi], &xbl[nj >> 1][(nj & 1) * 2]);
            if (third) {
                u32 xa[4][4];
                #pragma unroll
                for (int mi = 0; mi < 4; mi++)
                    ldsm4(xa[mi], sAl_ + aBase[mi] + ((u32)(kuA ^ aSw[mi]) << 4));
                #pragma unroll
                for (int mi = 0; mi < 4; mi++)
                    #pragma unroll
                    for (int nj = 0; nj < NJ; nj++)
                        mma16816(d[mi][nj], xa[mi], &xbh[nj >> 1][(nj & 1) * 2]);
            }
        }
        __syncthreads();
    }
}

// ---------------------------------------------------------------------------
// 2-term GEMM mainloop, A single-array fp16: d += A @ (Bh+Bl)^T.
// ---------------------------------------------------------------------------
__device__ __forceinline__ void gemm_core2(
    u32 sbase,
    const u16* __restrict__ Ap,
    const u16* __restrict__ Bph, const u16* __restrict__ Bpl,
    int lda, int ldb, int m0, int n0, int K,
    float (&d)[4][8][4])
{
    constexpr int NT = 256, NJ = 8;
    constexpr int STG = 16384 + 2 * NT * 128;   // 81920

    int tid = threadIdx.x, wid = tid >> 5, lane = tid & 31;
    int wx = wid & 3, wy = wid >> 2;

    int aRow = ((lane >> 3) & 1) * 8 + (lane & 7);
    int aKu  = lane >> 4;
    u32 aBase[4]; int aSw[4];
    #pragma unroll
    for (int mi = 0; mi < 4; mi++) {
        int r = wy * 64 + mi * 16 + aRow;
        aBase[mi] = (u32)(r * 128); aSw[mi] = r & 7;
    }
    int bRow = (lane >> 4) * 8 + (lane & 7);
    int bKu  = (lane >> 3) & 1;
    u32 bBase[NJ / 2]; int bSw[NJ / 2];
    #pragma unroll
    for (int p = 0; p < NJ / 2; p++) {
        int r = wx * 64 + p * 16 + bRow;
        bBase[p] = (u32)(r * 128); bSw[p] = r & 7;
    }

    int nch = K >> 6;

    auto prefetch = [&](int c, int s) {
        u32 st = sbase + s * STG;
        int k0 = c << 6;
        constexpr int TOT = (128 + 2 * NT) * 8;   // 5120
        #pragma unroll
        for (int u0 = 0; u0 < TOT; u0 += 256) {
            int u = u0 + tid;
            int row, c16;
            const u16* gp;
            u32 abase;
            if (u0 < 1024) {
                row = (u >> 3) & 127; c16 = u & 7;
                gp = Ap + (long)(m0 + row) * lda + k0 + c16 * 8;
                abase = st;
            } else {
                int v = u - 1024;
                row = (v >> 3) & (NT - 1); c16 = v & 7;
                bool lo = v >= NT * 8;
                gp = (lo ? Bpl : Bph) + (long)(n0 + row) * ldb + k0 + c16 * 8;
                abase = st + 16384u + (lo ? (u32)(NT * 128) : 0u);
            }
            u32 so = abase + (u32)(row * 128) + ((u32)(c16 ^ (row & 7)) << 4);
            cp16(so, gp);
        }
    };

    prefetch(0, 0);
    CP_COMMIT();

    for (int c = 0; c < nch; c++) {
        if (c + 1 < nch) { prefetch(c + 1, (c + 1) & 1); CP_COMMIT(); CP_WAIT1(); }
        else             { CP_WAIT0(); }
        __syncthreads();

        u32 st = sbase + (c & 1) * STG;
        u32 sA_ = st, sBh_ = st + 16384, sBl_ = st + 16384 + NT * 128;

        #pragma unroll
        for (int kk = 0; kk < 4; kk++) {
            int kuA = kk * 2 + aKu;
            int kuB = kk * 2 + bKu;
            u32 ah[4][4], xbh[NJ / 2][4], xbl[NJ / 2][4];
            #pragma unroll
            for (int mi = 0; mi < 4; mi++)
                ldsm4(ah[mi], sA_ + aBase[mi] + ((u32)(kuA ^ aSw[mi]) << 4));
            #pragma unroll
            for (int p = 0; p < NJ / 2; p++)
                ldsm4(xbh[p], sBh_ + bBase[p] + ((u32)(kuB ^ bSw[p]) << 4));
            #pragma unroll
            for (int p = 0; p < NJ / 2; p++)
                ldsm4(xbl[p], sBl_ + bBase[p] + ((u32)(kuB ^ bSw[p]) << 4));
            #pragma unroll
            for (int mi = 0; mi < 4; mi++)
                #pragma unroll
                for (int nj = 0; nj < NJ; nj++)
                    mma16816(d[mi][nj], ah[mi], &xbh[nj >> 1][(nj & 1) * 2]);
            #pragma unroll
            for (int mi = 0; mi < 4; mi++)
                #pragma unroll
                for (int nj = 0; nj < NJ; nj++)
                    mma16816(d[mi][nj], ah[mi], &xbl[nj >> 1][(nj & 1) * 2]);
        }
        __syncthreads();
    }
}

// ---------------------------------------------------------------------------
// Merged Q/K/V projection. Q: 2-term, RoPE, hi-only out. K: 3-term, RoPE,
// split out. V: 2-term, fp32 out.
// ---------------------------------------------------------------------------
__global__ __launch_bounds__(256, 1)
void qkv_gemm(const u16* __restrict__ xh, const u16* __restrict__ xl,
              const u16* __restrict__ qwth, const u16* __restrict__ qwtl, const float* __restrict__ qb,
              const u16* __restrict__ kwth, const u16* __restrict__ kwtl, const float* __restrict__ kb,
              const u16* __restrict__ vwth, const u16* __restrict__ vwtl, const float* __restrict__ vb,
              u16* __restrict__ qh,
              u16* __restrict__ kh, u16* __restrict__ kl,
              float* __restrict__ vf,
              const float* __restrict__ fc, const float* __restrict__ fs,
              const int* __restrict__ sp)
{
    extern __shared__ __align__(16) char dsm[];
    int nt = blockIdx.x, m0 = blockIdx.y * 128;

    const u16 *Bph, *Bpl; const float* bias;
    u16 *Ch = nullptr, *Cl = nullptr; float* Cf = nullptr;
    int ldc, n0; bool three;
    if (nt < 16)      { Bph = qwth; Bpl = qwtl; bias = qb; Ch = qh;          ldc = 4096; n0 = nt * 256; three = false; }
    else if (nt < 20) { Bph = kwth; Bpl = kwtl; bias = kb; Ch = kh; Cl = kl; ldc = 1024; n0 = (nt - 16) * 256; three = true; }
    else              { Bph = vwth; Bpl = vwtl; bias = vb; Cf = vf;          ldc = 1024; n0 = (nt - 20) * 256; three = false; }

    float d[4][8][4];
    #pragma unroll
    for (int i = 0; i < 4; i++)
        #pragma unroll
        for (int j = 0; j < 8; j++)
            #pragma unroll
            for (int q = 0; q < 4; q++) d[i][j][q] = 0.f;

    gemm_core3(smem_u32(dsm), xh, xl, Bph, Bpl, D_, D_, m0, n0, D_, three, d);

    int tid = threadIdx.x, wid = tid >> 5, lane = tid & 31;
    int wx = wid & 3, wy = wid >> 2;
    int g = lane >> 2, tg = lane & 3;
    int sp0 = *sp;

    #pragma unroll
    for (int mi = 0; mi < 4; mi++) {
        #pragma unroll
        for (int nj = 0; nj < 8; nj++) {
            int r = m0 + wy * 64 + mi * 16 + g;
            int c = n0 + wx * 64 + nj * 8 + tg * 2;
            float b0 = bias[c], b1 = bias[c + 1];
            float v0 = d[mi][nj][0] + b0, v1 = d[mi][nj][1] + b1;
            float v2 = d[mi][nj][2] + b0, v3 = d[mi][nj][3] + b1;
            long o0 = (long)r * ldc + c;
            long o1 = o0 + 8L * ldc;
            if (Cf) {
                *(float2*)&Cf[o0] = make_float2(v0, v1);
                *(float2*)&Cf[o1] = make_float2(v2, v3);
            } else {
                int i_ = (c & 127) >> 1;
                int s0 = (r & (S_ - 1)) + sp0;
                int s8 = ((r + 8) & (S_ - 1)) + sp0;
                float c0f = fc[s0 * 64 + i_], s0f = fs[s0 * 64 + i_];
                float c8f = fc[s8 * 64 + i_], s8f = fs[s8 * 64 + i_];
                float r0 = v0 * c0f - v1 * s0f, r1 = v0 * s0f + v1 * c0f;
                float r2 = v2 * c8f - v3 * s8f, r3 = v2 * s8f + v3 * c8f;
                if (Cl) {        // K: split store
                    u16 h0, l0, h1, l1;
                    split2(r0, h0, l0); split2(r1, h1, l1);
                    *(u32*)&Ch[o0] = (u32)h0 | ((u32)h1 << 16);
                    *(u32*)&Cl[o0] = (u32)l0 | ((u32)l1 << 16);
                    split2(r2, h0, l0); split2(r3, h1, l1);
                    *(u32*)&Ch[o1] = (u32)h0 | ((u32)h1 << 16);
                    *(u32*)&Cl[o1] = (u32)l0 | ((u32)l1 << 16);
                } else {         // Q: hi only
                    *(u32*)&Ch[o0] = (u32)h16(r0) | ((u32)h16(r1) << 16);
                    *(u32*)&Ch[o1] = (u32)h16(r2) | ((u32)h16(r3) << 16);
                }
            }
        }
    }
}

// ---------------------------------------------------------------------------
// Output projection: out = AO(fp16) @ (owh+owl)^T, 2-term. fp32 out.
// ---------------------------------------------------------------------------
__global__ __launch_bounds__(256, 1)
void oproj_gemm(const u16* __restrict__ Ap,
                const u16* __restrict__ Bgh, const u16* __restrict__ Bgl,
                float* __restrict__ Cf)
{
    extern __shared__ __align__(16) char dsm[];
    int m0 = blockIdx.y * 128, n0 = blockIdx.x * 256;

    float d[4][8][4];
    #pragma unroll
    for (int i = 0; i < 4; i++)
        #pragma unroll
        for (int j = 0; j < 8; j++)
            #pragma unroll
            for (int q = 0; q < 4; q++) d[i][j][q] = 0.f;

    gemm_core2(smem_u32(dsm), Ap, Bgh, Bgl, D_, D_, m0, n0, D_, d);

    int tid = threadIdx.x, wid = tid >> 5, lane = tid & 31;
    int wx = wid & 3, wy = wid >> 2;
    int g = lane >> 2, tg = lane & 3;

    #pragma unroll
    for (int mi = 0; mi < 4; mi++) {
        #pragma unroll
        for (int nj = 0; nj < 8; nj++) {
            int r = m0 + wy * 64 + mi * 16 + g;
            int c = n0 + wx * 64 + nj * 8 + tg * 2;
            long o0 = (long)r * D_ + c;
            long o1 = o0 + 8L * D_;
            *(float2*)&Cf[o0] = make_float2(d[mi][nj][0], d[mi][nj][1]);
            *(float2*)&Cf[o1] = make_float2(d[mi][nj][2], d[mi][nj][3]);
        }
    }
}

// ---------------------------------------------------------------------------
// Fused FlashAttention: S = alpha*Qh@(Kh+Kl)^T (2-term), online softmax,
// O = Ph@(Vh+Vl) (2-term). Q hi-only resident; P hi-only.
// ---------------------------------------------------------------------------
#define FA_Q    0                   // 32 KB (hi only, 2 cc x 16 KB)
#define FA_K    32768               // 2 stages x 32 KB
#define FA_V    98304               // VH 16K, VL 16K
#define FA_P    131072              // PH 16K
#define FA_ST   147456
#define FA_SMEM (147456 + 5632)

__global__ __launch_bounds__(256, 1)
void fa_fused(const u16* __restrict__ Qh,
              const u16* __restrict__ Kh, const u16* __restrict__ Kl,
              const u16* __restrict__ Vth, const u16* __restrict__ Vtl,
              u16* __restrict__ Ao, float alpha)
{
    extern __shared__ __align__(16) char dsm[];
    u32 sbase = smem_u32(dsm);
    float* m_run = (float*)(dsm + FA_ST);
    float* l_run = m_run + 128;
    float* fch   = m_run + 256;
    float* mpart = m_run + 384;
    float* lpart = m_run + 896;

    int m0 = (int)(gridDim.x - 1 - blockIdx.x) * 128;
    int z = blockIdx.y, b = z / HQ, h = z - b * HQ;

    const u16* Qph = Qh + ((long)b * S_ + m0) * D_ + h * HD;
    const u16* Kph = Kh + (long)b * S_ * 1024 + (h / GRP) * HD;
    const u16* Kpl = Kl + (long)b * S_ * 1024 + (h / GRP) * HD;
    const u16* Vph = Vth + ((long)b * HKV + (h / GRP)) * (long)HD * S_;
    const u16* Vpl = Vtl + ((long)b * HKV + (h / GRP)) * (long)HD * S_;

    int tid = threadIdx.x, wid = tid >> 5, lane = tid & 31;
    int wx = wid & 3, wy = wid >> 2;
    int g = lane >> 2, tg = lane & 3;

    if (tid < 128) { m_run[tid] = -1e30f; l_run[tid] = 0.f; }

    int aRow = ((lane >> 3) & 1) * 8 + (lane & 7);
    int aKu  = lane >> 4;
    u32 aBase[4]; int aSw[4];
    #pragma unroll
    for (int mi = 0; mi < 4; mi++) {
        int rr = wy * 64 + mi * 16 + aRow;
        aBase[mi] = (u32)(rr * 128); aSw[mi] = rr & 7;
    }
    int bRow = (lane >> 4) * 8 + (lane & 7);
    int bKu  = (lane >> 3) & 1;
    u32 bBaseS = (u32)((wx * 16 + bRow) * 128); int bSwS = bRow & 7;
    u32 bBaseV[2]; int bSwV[2];
    #pragma unroll
    for (int p = 0; p < 2; p++) {
        int rr = wx * 32 + p * 16 + bRow;
        bBaseV[p] = (u32)(rr * 128); bSwV[p] = rr & 7;
    }

    float d_o[4][4][4];
    #pragma unroll
    for (int i = 0; i < 4; i++)
        #pragma unroll
        for (int j = 0; j < 4; j++)
            #pragma unroll
            for (int q = 0; q < 4; q++) d_o[i][j][q] = 0.f;

    int nch = (m0 + 128) >> 6;

    auto qfetch = [&]() {
        #pragma unroll
        for (int u0 = 0; u0 < 2048; u0 += 256) {
            int u = u0 + tid;
            int cc = u >> 10, v = u & 1023;
            int row = v >> 3, c16 = v & 7;
            const u16* gp = Qph + (long)row * D_ + cc * 64 + c16 * 8;
            u32 so = sbase + FA_Q + (u32)cc * 16384
                   + (u32)(row * 128) + ((u32)(c16 ^ (row & 7)) << 4);
            cp16(so, gp);
        }
    };
    auto kfetch = [&](int c, int s) {
        int j0 = c << 6;
        #pragma unroll
        for (int u0 = 0; u0 < 2048; u0 += 256) {
            int u = u0 + tid;
            int cc = u >> 10, rest = u & 1023;
            bool lo = rest >= 512;
            int v = rest & 511, row = v >> 3, c16 = v & 7;
            const u16* gp = (lo ? Kpl : Kph) + (long)(j0 + row) * 1024 + cc * 64 + c16 * 8;
            u32 so = sbase + FA_K + (u32)s * 32768 + (u32)cc * 8192 + (lo ? 16384u : 0u)
                   + (u32)(row * 128) + ((u32)(c16 ^ (row & 7)) << 4);
            cp16(so, gp);
        }
    };
    auto vfetch = [&](int c) {
        int j0 = c << 6;
        #pragma unroll
        for (int u0 = 0; u0 < 2048; u0 += 256) {
            int u = u0 + tid;
            bool lo = u >= 1024;
            int v = u & 1023, row = v >> 3, c16 = v & 7;
            const u16* gp = (lo ? Vpl : Vph) + (long)row * S_ + j0 + c16 * 8;
            u32 so = sbase + FA_V + (lo ? 16384u : 0u)
                   + (u32)(row * 128) + ((u32)(c16 ^ (row & 7)) << 4);
            cp16(so, gp);
        }
    };

    qfetch();
    CP_COMMIT();
    kfetch(0, 0);
    CP_COMMIT();

    for (int c = 0; c < nch; c++) {
        int j0 = c << 6;
        bool hasNext = (c + 1 < nch);

        vfetch(c); CP_COMMIT();
        if (hasNext) { kfetch(c + 1, (c + 1) & 1); CP_COMMIT(); }

        if (hasNext) CP_WAIT2(); else CP_WAIT1();
        __syncthreads();

        // ---- S = Qh @ (Kh+Kl)^T (2 terms) ----
        float d_s[4][2][4];
        #pragma unroll
        for (int i = 0; i < 4; i++)
            #pragma unroll
            for (int j = 0; j < 2; j++)
                #pragma unroll
                for (int q = 0; q < 4; q++) d_s[i][j][q] = 0.f;

        u32 kst = sbase + FA_K + (u32)(c & 1) * 32768;
        #pragma unroll
        for (int cc = 0; cc < 2; cc++) {
            u32 sQ_  = sbase + FA_Q + (u32)cc * 16384;
            u32 sKh_ = kst + (u32)cc * 8192;
            u32 sKl_ = sKh_ + 16384;
            #pragma unroll
            for (int kk = 0; kk < 4; kk++) {
                int kuA = kk * 2 + aKu;
                int kuB = kk * 2 + bKu;
                u32 ah[4][4], xbh[4], xbl[4];
                #pragma unroll
                for (int mi = 0; mi < 4; mi++)
                    ldsm4(ah[mi], sQ_ + aBase[mi] + ((u32)(kuA ^ aSw[mi]) << 4));
                ldsm4(xbh, sKh_ + bBaseS + ((u32)(kuB ^ bSwS) << 4));
                ldsm4(xbl, sKl_ + bBaseS + ((u32)(kuB ^ bSwS) << 4));
                #pragma unroll
                for (int mi = 0; mi < 4; mi++)
                    #pragma unroll
                    for (int nj = 0; nj < 2; nj++)
                        mma16816(d_s[mi][nj], ah[mi], &xbh[nj * 2]);
                #pragma unroll
                for (int mi = 0; mi < 4; mi++)
                    #pragma unroll
                    for (int nj = 0; nj < 2; nj++)
                        mma16816(d_s[mi][nj], ah[mi], &xbl[nj * 2]);
            }
        }

        // ---- mask + alpha + chunk row-max ----
        bool domask = (c >= nch - 2);
        #pragma unroll
        for (int mi = 0; mi < 4; mi++) {
            int rl0 = wy * 64 + mi * 16 + g;
            int grow0 = m0 + rl0, grow8 = grow0 + 8;
            float mx0 = -1e30f, mx8 = -1e30f;
            #pragma unroll
            for (int nj = 0; nj < 2; nj++) {
                #pragma unroll
                for (int e = 0; e < 2; e++) {
                    int gc = j0 + wx * 16 + nj * 8 + tg * 2 + e;
                    float v0 = d_s[mi][nj][e] * alpha;
                    float v8 = d_s[mi][nj][2 + e] * alpha;
                    if (domask) {
                        if (gc > grow0) v0 = -1e30f;
                        if (gc > grow8) v8 = -1e30f;
                    }
                    d_s[mi][nj][e] = v0; d_s[mi][nj][2 + e] = v8;
                    mx0 = fmaxf(mx0, v0); mx8 = fmaxf(mx8, v8);
                }
            }
            mx0 = fmaxf(mx0, __shfl_xor_sync(0xffffffffu, mx0, 1));
            mx0 = fmaxf(mx0, __shfl_xor_sync(0xffffffffu, mx0, 2));
            mx8 = fmaxf(mx8, __shfl_xor_sync(0xffffffffu, mx8, 1));
            mx8 = fmaxf(mx8, __shfl_xor_sync(0xffffffffu, mx8, 2));
            if (tg == 0) {
                mpart[wx * 128 + rl0] = mx0;
                mpart[wx * 128 + rl0 + 8] = mx8;
            }
        }
        __syncthreads();

        if (tid < 128) {
            float mc = fmaxf(fmaxf(mpart[tid], mpart[128 + tid]),
                             fmaxf(mpart[256 + tid], mpart[384 + tid]));
            float mo = m_run[tid];
            float mn = fmaxf(mo, mc);
            fch[tid] = __expf(mo - mn);
            m_run[tid] = mn;
        }
        __syncthreads();

        #pragma unroll
        for (int mi = 0; mi < 4; mi++) {
            int rl = wy * 64 + mi * 16 + g;
            float f0 = fch[rl], f8 = fch[rl + 8];
            #pragma unroll
            for (int nj = 0; nj < 4; nj++) {
                d_o[mi][nj][0] *= f0; d_o[mi][nj][1] *= f0;
                d_o[mi][nj][2] *= f8; d_o[mi][nj][3] *= f8;
            }
        }

        // ---- P = exp(S - m), fp16 hi only, store to smem; partial sums ----
        #pragma unroll
        for (int mi = 0; mi < 4; mi++) {
            int rl0 = wy * 64 + mi * 16 + g;
            float mrow0 = m_run[rl0], mrow8 = m_run[rl0 + 8];
            float s0 = 0.f, s8 = 0.f;
            #pragma unroll
            for (int nj = 0; nj < 2; nj++) {
                float p00 = __expf(d_s[mi][nj][0] - mrow0);
                float p01 = __expf(d_s[mi][nj][1] - mrow0);
                float p80 = __expf(d_s[mi][nj][2] - mrow8);
                float p81 = __expf(d_s[mi][nj][3] - mrow8);
                s0 += p00 + p01; s8 += p80 + p81;
                int cl = wx * 16 + nj * 8 + tg * 2;
                u32 u0 = (u32)(((cl >> 3) ^ (rl0 & 7)) << 4) + (u32)((cl & 7) * 2);
                u32 u8 = (u32)(((cl >> 3) ^ ((rl0 + 8) & 7)) << 4) + (u32)((cl & 7) * 2);
                *(u32*)(dsm + FA_P + rl0 * 128 + u0) =
                    (u32)h16(p00) | ((u32)h16(p01) << 16);
                *(u32*)(dsm + FA_P + (rl0 + 8) * 128 + u8) =
                    (u32)h16(p80) | ((u32)h16(p81) << 16);
            }
            s0 += __shfl_xor_sync(0xffffffffu, s0, 1);
            s0 += __shfl_xor_sync(0xffffffffu, s0, 2);
            s8 += __shfl_xor_sync(0xffffffffu, s8, 1);
            s8 += __shfl_xor_sync(0xffffffffu, s8, 2);
            if (tg == 0) {
                lpart[wx * 128 + rl0] = s0;
                lpart[wx * 128 + rl0 + 8] = s8;
            }
        }

        if (hasNext) CP_WAIT1(); else CP_WAIT0();
        __syncthreads();

        if (tid < 128) {
            float sum = lpart[tid] + lpart[128 + tid] + lpart[256 + tid] + lpart[384 + tid];
            l_run[tid] = l_run[tid] * fch[tid] + sum;
        }

        // ---- O += Ph @ (Vh+Vl) (2 terms) ----
        u32 sP = sbase + FA_P;
        u32 sVh = sbase + FA_V, sVl = sVh + 16384;
        #pragma unroll
        for (int kk = 0; kk < 4; kk++) {
            int kuA = kk * 2 + aKu;
            int kuB = kk * 2 + bKu;
            u32 ah[4][4], xbh[2][4], xbl[2][4];
            #pragma unroll
            for (int mi = 0; mi < 4; mi++)
                ldsm4(ah[mi], sP + aBase[mi] + ((u32)(kuA ^ aSw[mi]) << 4));
            #pragma unroll
            for (int p = 0; p < 2; p++)
                ldsm4(xbh[p], sVh + bBaseV[p] + ((u32)(kuB ^ bSwV[p]) << 4));
            #pragma unroll
            for (int p = 0; p < 2; p++)
                ldsm4(xbl[p], sVl + bBaseV[p] + ((u32)(kuB ^ bSwV[p]) << 4));
            #pragma unroll
            for (int mi = 0; mi < 4; mi++)
                #pragma unroll
                for (int nj = 0; nj < 4; nj++)
                    mma16816(d_o[mi][nj], ah[mi], &xbh[nj >> 1][(nj & 1) * 2]);
            #pragma unroll
            for (int mi = 0; mi < 4; mi++)
                #pragma unroll
                for (int nj = 0; nj < 4; nj++)
                    mma16816(d_o[mi][nj], ah[mi], &xbl[nj >> 1][(nj & 1) * 2]);
        }
        __syncthreads();
    }

    // epilogue: divide by l, fp16-truncate, store AO
    #pragma unroll
    for (int mi = 0; mi < 4; mi++) {
        int rl = wy * 64 + mi * 16 + g;
        float i0 = 1.0f / l_run[rl];
        float i8 = 1.0f / l_run[rl + 8];
        #pragma unroll
        for (int nj = 0; nj < 4; nj++) {
            int cc = wx * 32 + nj * 8 + tg * 2;
            long o0 = ((long)b * S_ + m0 + rl) * D_ + h * HD + cc;
            long o1 = o0 + 8L * D_;
            *(u32*)&Ao[o0] = (u32)h16(d_o[mi][nj][0] * i0)
                           | ((u32)h16(d_o[mi][nj][1] * i0) << 16);
            *(u32*)&Ao[o1] = (u32)h16(d_o[mi][nj][2] * i8)
                           | ((u32)h16(d_o[mi][nj][3] * i8) << 16);
        }
    }
}

// ---------------------------------------------------------------------------
__global__ void conv_split(const float* __restrict__ in, u16* __restrict__ oh,
                           u16* __restrict__ ol, long n)
{
    long i = blockIdx.x * 256L + threadIdx.x;
    if (i < n) split2(in[i], oh[i], ol[i]);
}

__global__ void tsplit(const float* __restrict__ in, u16* __restrict__ oh,
                       u16* __restrict__ ol, int ldin, int ldout,
                       long sInB, long sInH, long sOutZ, int Hc)
{
    __shared__ float t[32][33];
    int z = blockIdx.z, bb = z / Hc, hh = z - bb * Hc;
    const float* ip = in + bb * sInB + (long)hh * sInH;
    int c0 = blockIdx.x * 32, r0 = blockIdx.y * 32;
    #pragma unroll
    for (int i = 0; i < 4; i++)
        t[threadIdx.y + i * 8][threadIdx.x] =
            ip[(long)(r0 + threadIdx.y + i * 8) * ldin + c0 + threadIdx.x];
    __syncthreads();
    #pragma unroll
    for (int i = 0; i < 4; i++) {
        int orow = c0 + threadIdx.y + i * 8;
        int oc = r0 + threadIdx.x;
        float v = t[threadIdx.x][threadIdx.y + i * 8];
        long o = z * sOutZ + (long)orow * ldout + oc;
        split2(v, oh[o], ol[o]);
    }
}

// ---------------------------------------------------------------------------
extern "C" void kernel_launch(void* const* d_in, const int* in_sizes, int n_in,
                              void* d_out, int out_size)
{
    const float* x  = (const float*)d_in[0];
    const float* fc = (const float*)d_in[1];
    const float* fs = (const float*)d_in[2];
    const float* qw = (const float*)d_in[3];
    const float* qb = (const float*)d_in[4];
    const float* kw = (const float*)d_in[5];
    const float* kb = (const float*)d_in[6];
    const float* vw = (const float*)d_in[7];
    const float* vb = (const float*)d_in[8];
    const float* ow = (const float*)d_in[9];
    const int*   sp = (const int*)d_in[10];
    float* out = (float*)d_out;

    float *v;
    u16 *xh, *xl, *qwth, *qwtl, *kwth, *kwtl, *vwth, *vwtl, *owth, *owtl;
    u16 *qh, *kh, *kl, *vth, *vtl, *ao;
    cudaGetSymbolAddress((void**)&v, g_v);
    cudaGetSymbolAddress((void**)&xh, g_xh);   cudaGetSymbolAddress((void**)&xl, g_xl);
    cudaGetSymbolAddress((void**)&qwth, g_qwt_h); cudaGetSymbolAddress((void**)&qwtl, g_qwt_l);
    cudaGetSymbolAddress((void**)&kwth, g_kwt_h); cudaGetSymbolAddress((void**)&kwtl, g_kwt_l);
    cudaGetSymbolAddress((void**)&vwth, g_vwt_h); cudaGetSymbolAddress((void**)&vwtl, g_vwt_l);
    cudaGetSymbolAddress((void**)&owth, g_owt_h); cudaGetSymbolAddress((void**)&owtl, g_owt_l);
    cudaGetSymbolAddress((void**)&qh, g_qh);
    cudaGetSymbolAddress((void**)&kh, g_kh);   cudaGetSymbolAddress((void**)&kl, g_kl);
    cudaGetSymbolAddress((void**)&vth, g_vth); cudaGetSymbolAddress((void**)&vtl, g_vtl);
    cudaGetSymbolAddress((void**)&ao, g_ao);

    const int SM3 = 2 * (32768 + 2 * 256 * 128);   // 196608
    const int SM2 = 2 * (16384 + 2 * 256 * 128);   // 163840
    cudaFuncSetAttribute((const void*)qkv_gemm,
                         cudaFuncAttributeMaxDynamicSharedMemorySize, SM3);
    cudaFuncSetAttribute((const void*)oproj_gemm,
                         cudaFuncAttributeMaxDynamicSharedMemorySize, SM2);
    cudaFuncSetAttribute((const void*)fa_fused,
                         cudaFuncAttributeMaxDynamicSharedMemorySize, FA_SMEM);

    // 1) split-convert activations and weights (weights transposed to [N,K])
    conv_split<<<(unsigned)(((long)MR * D_ + 255) / 256), 256>>>(x, xh, xl, (long)MR * D_);
    dim3 tb(32, 8);
    tsplit<<<dim3(128, 128, 1), tb>>>(qw, qwth, qwtl, D_, D_, 0, 0, 0, 1);
    tsplit<<<dim3(32, 128, 1), tb>>>(kw, kwth, kwtl, 1024, D_, 0, 0, 0, 1);
    tsplit<<<dim3(32, 128, 1), tb>>>(vw, vwth, vwtl, 1024, D_, 0, 0, 0, 1);
    tsplit<<<dim3(128, 128, 1), tb>>>(ow, owth, owtl, D_, D_, 0, 0, 0, 1);

    // 2) merged Q/K/V projections (Q 2-term hi-out; K 3-term split; V 2-term)
    qkv_gemm<<<dim3(24, 32), 256, SM3>>>(
        xh, xl, qwth, qwtl, qb, kwth, kwtl, kb, vwth, vwtl, vb,
        qh, kh, kl, v, fc, fs, sp);
    // transpose+split V -> [b,h,d,s]
    tsplit<<<dim3(4, 64, B_ * HKV), tb>>>(v, vth, vtl, 1024, S_,
        (long)S_ * 1024, (long)HD, (long)HD * S_, HKV);

    // 3) fused attention (2-term S, 2-term PV) -> fp16 AO in [b,s,h*128+d]
    fa_fused<<<dim3(16, B_ * HQ), 256, FA_SMEM>>>(
        qh, kh, kl, vth, vtl, ao, 0.08838834764831845f);

    // 4) out = AO @ ow (2-term)
    oproj_gemm<<<dim3(16, 32), 256, SM2>>>(ao, owth, owtl, out);
}

// round 11
// speedup vs baseline: 6.6588x; 1.4787x over previous
#include <cuda_runtime.h>
#include <cuda_fp16.h>

typedef unsigned short u16;
typedef unsigned int   u32;

#define B_   2
#define S_   2048
#define D_   4096
#define HQ   32
#define HKV  8
#define HD   128
#define GRP  4
#define MR   (B_*S_)   // 4096

// ---------------- scratch (__device__ globals; no runtime allocation) -------
__device__ float g_v[(size_t)MR*HKV*HD];             // fp32 V (pre-transpose)

__device__ u16 g_x16[(size_t)MR*D_];                 // fp16 x
__device__ u16 g_qwt_h[(size_t)D_*D_];               // [N,K] fp16 hi
__device__ u16 g_kwt_h[(size_t)1024*D_],   g_kwt_l[(size_t)1024*D_];
__device__ u16 g_vwt_h[(size_t)1024*D_],   g_vwt_l[(size_t)1024*D_];
__device__ u16 g_owt_h[(size_t)D_*D_];
__device__ u16 g_qh[(size_t)MR*D_];                  // rope'd Q fp16
__device__ u16 g_kh[(size_t)MR*HKV*HD];              // rope'd K fp16
__device__ u16 g_vth[(size_t)B_*HKV*HD*S_],g_vtl[(size_t)B_*HKV*HD*S_];   // V^T split
__device__ u16 g_ao[(size_t)MR*D_];                  // fp16 attn out

// ---------------------------------------------------------------------------
__device__ __forceinline__ void split2(float v, u16& h, u16& l) {
    __half hb = __float2half_rn(v);
    float r = v - __half2float(hb);
    h = __half_as_ushort(hb);
    l = __half_as_ushort(__float2half_rn(r));
}
__device__ __forceinline__ u16 h16(float v) {
    return __half_as_ushort(__float2half_rn(v));
}

__device__ __forceinline__ u32 smem_u32(const void* p) {
    u32 a;
    asm("{ .reg .u64 t; cvta.to.shared.u64 t, %1; cvt.u32.u64 %0, t; }" : "=r"(a) : "l"(p));
    return a;
}

__device__ __forceinline__ void cp16(u32 sdst, const void* gsrc) {
    asm volatile("cp.async.cg.shared.global [%0], [%1], 16;\n" :: "r"(sdst), "l"(gsrc));
}
#define CP_COMMIT()  asm volatile("cp.async.commit_group;" ::: "memory")
#define CP_WAIT2()   asm volatile("cp.async.wait_group 2;" ::: "memory")
#define CP_WAIT1()   asm volatile("cp.async.wait_group 1;" ::: "memory")
#define CP_WAIT0()   asm volatile("cp.async.wait_group 0;" ::: "memory")

__device__ __forceinline__ void ldsm4(u32* r, u32 addr) {
    asm volatile("ldmatrix.sync.aligned.m8n8.x4.shared.b16 {%0,%1,%2,%3}, [%4];"
        : "=r"(r[0]), "=r"(r[1]), "=r"(r[2]), "=r"(r[3]) : "r"(addr));
}

__device__ __forceinline__ void mma16816(float* d, const u32* a, const u32* b) {
    asm volatile(
        "mma.sync.aligned.m16n8k16.row.col.f32.f16.f16.f32 "
        "{%0,%1,%2,%3}, {%4,%5,%6,%7}, {%8,%9}, {%0,%1,%2,%3};\n"
        : "+f"(d[0]), "+f"(d[1]), "+f"(d[2]), "+f"(d[3])
        : "r"(a[0]), "r"(a[1]), "r"(a[2]), "r"(a[3]), "r"(b[0]), "r"(b[1]));
}

// ---------------------------------------------------------------------------
// GEMM mainloop, single fp16 A. BLO=true: d += A@(Bh+Bl)^T ; false: A@Bh^T.
// 128 x 256 CTA tile, BK=64, 2-stage cp.async, SW128 swizzle.
// ---------------------------------------------------------------------------
template<bool BLO>
__device__ __forceinline__ void gemm_core2(
    u32 sbase,
    const u16* __restrict__ Ap,
    const u16* __restrict__ Bph, const u16* __restrict__ Bpl,
    int lda, int ldb, int m0, int n0, int K,
    float (&d)[4][8][4])
{
    constexpr int NT = 256, NJ = 8;
    constexpr int STG = 16384 + (BLO ? 2 : 1) * NT * 128;

    int tid = threadIdx.x, wid = tid >> 5, lane = tid & 31;
    int wx = wid & 3, wy = wid >> 2;

    int aRow = ((lane >> 3) & 1) * 8 + (lane & 7);
    int aKu  = lane >> 4;
    u32 aBase[4]; int aSw[4];
    #pragma unroll
    for (int mi = 0; mi < 4; mi++) {
        int r = wy * 64 + mi * 16 + aRow;
        aBase[mi] = (u32)(r * 128); aSw[mi] = r & 7;
    }
    int bRow = (lane >> 4) * 8 + (lane & 7);
    int bKu  = (lane >> 3) & 1;
    u32 bBase[NJ / 2]; int bSw[NJ / 2];
    #pragma unroll
    for (int p = 0; p < NJ / 2; p++) {
        int r = wx * 64 + p * 16 + bRow;
        bBase[p] = (u32)(r * 128); bSw[p] = r & 7;
    }

    int nch = K >> 6;

    auto prefetch = [&](int c, int s) {
        u32 st = sbase + s * STG;
        int k0 = c << 6;
        constexpr int TOT = (128 + (BLO ? 2 : 1) * NT) * 8;
        #pragma unroll
        for (int u0 = 0; u0 < TOT; u0 += 256) {
            int u = u0 + tid;
            int row, c16;
            const u16* gp;
            u32 abase;
            if (u0 < 1024) {
                row = (u >> 3) & 127; c16 = u & 7;
                gp = Ap + (long)(m0 + row) * lda + k0 + c16 * 8;
                abase = st;
            } else {
                int v = u - 1024;
                row = (v >> 3) & (NT - 1); c16 = v & 7;
                bool lo = BLO && (v >= NT * 8);
                gp = (lo ? Bpl : Bph) + (long)(n0 + row) * ldb + k0 + c16 * 8;
                abase = st + 16384u + (lo ? (u32)(NT * 128) : 0u);
            }
            u32 so = abase + (u32)(row * 128) + ((u32)(c16 ^ (row & 7)) << 4);
            cp16(so, gp);
        }
    };

    prefetch(0, 0);
    CP_COMMIT();

    for (int c = 0; c < nch; c++) {
        if (c + 1 < nch) { prefetch(c + 1, (c + 1) & 1); CP_COMMIT(); CP_WAIT1(); }
        else             { CP_WAIT0(); }
        __syncthreads();

        u32 st = sbase + (c & 1) * STG;
        u32 sA_ = st, sBh_ = st + 16384, sBl_ = st + 16384 + NT * 128;

        #pragma unroll
        for (int kk = 0; kk < 4; kk++) {
            int kuA = kk * 2 + aKu;
            int kuB = kk * 2 + bKu;
            u32 ah[4][4], xbh[NJ / 2][4];
            #pragma unroll
            for (int mi = 0; mi < 4; mi++)
                ldsm4(ah[mi], sA_ + aBase[mi] + ((u32)(kuA ^ aSw[mi]) << 4));
            #pragma unroll
            for (int p = 0; p < NJ / 2; p++)
                ldsm4(xbh[p], sBh_ + bBase[p] + ((u32)(kuB ^ bSw[p]) << 4));
            #pragma unroll
            for (int mi = 0; mi < 4; mi++)
                #pragma unroll
                for (int nj = 0; nj < NJ; nj++)
                    mma16816(d[mi][nj], ah[mi], &xbh[nj >> 1][(nj & 1) * 2]);
            if (BLO) {
                u32 xbl[NJ / 2][4];
                #pragma unroll
                for (int p = 0; p < NJ / 2; p++)
                    ldsm4(xbl[p], sBl_ + bBase[p] + ((u32)(kuB ^ bSw[p]) << 4));
                #pragma unroll
                for (int mi = 0; mi < 4; mi++)
                    #pragma unroll
                    for (int nj = 0; nj < NJ; nj++)
                        mma16816(d[mi][nj], ah[mi], &xbl[nj >> 1][(nj & 1) * 2]);
            }
        }
        __syncthreads();
    }
}

// ---------------------------------------------------------------------------
// Merged Q/K/V projection. Q: 1-term. K: 2-term. V: 2-term.
// Q/K: bias + RoPE + fp16 out. V: bias + fp32 out.
// ---------------------------------------------------------------------------
__global__ __launch_bounds__(256, 1)
void qkv_gemm(const u16* __restrict__ x16,
              const u16* __restrict__ qwth, const float* __restrict__ qb,
              const u16* __restrict__ kwth, const u16* __restrict__ kwtl, const float* __restrict__ kb,
              const u16* __restrict__ vwth, const u16* __restrict__ vwtl, const float* __restrict__ vb,
              u16* __restrict__ qh, u16* __restrict__ kh,
              float* __restrict__ vf,
              const float* __restrict__ fc, const float* __restrict__ fs,
              const int* __restrict__ sp)
{
    extern __shared__ __align__(16) char dsm[];
    int nt = blockIdx.x, m0 = blockIdx.y * 128;

    const u16 *Bph = nullptr, *Bpl = nullptr; const float* bias;
    u16* Ch = nullptr; float* Cf = nullptr;
    int ldc, n0; bool blo;
    if (nt < 16)      { Bph = qwth;              bias = qb; Ch = qh; ldc = 4096; n0 = nt * 256;       blo = false; }
    else if (nt < 20) { Bph = kwth; Bpl = kwtl;  bias = kb; Ch = kh; ldc = 1024; n0 = (nt - 16) * 256; blo = true; }
    else              { Bph = vwth; Bpl = vwtl;  bias = vb; Cf = vf; ldc = 1024; n0 = (nt - 20) * 256; blo = true; }

    float d[4][8][4];
    #pragma unroll
    for (int i = 0; i < 4; i++)
        #pragma unroll
        for (int j = 0; j < 8; j++)
            #pragma unroll
            for (int q = 0; q < 4; q++) d[i][j][q] = 0.f;

    if (blo) gemm_core2<true >(smem_u32(dsm), x16, Bph, Bpl, D_, D_, m0, n0, D_, d);
    else     gemm_core2<false>(smem_u32(dsm), x16, Bph, Bpl, D_, D_, m0, n0, D_, d);

    int tid = threadIdx.x, wid = tid >> 5, lane = tid & 31;
    int wx = wid & 3, wy = wid >> 2;
    int g = lane >> 2, tg = lane & 3;
    int sp0 = *sp;

    #pragma unroll
    for (int mi = 0; mi < 4; mi++) {
        #pragma unroll
        for (int nj = 0; nj < 8; nj++) {
            int r = m0 + wy * 64 + mi * 16 + g;
            int c = n0 + wx * 64 + nj * 8 + tg * 2;
            float b0 = bias[c], b1 = bias[c + 1];
            float v0 = d[mi][nj][0] + b0, v1 = d[mi][nj][1] + b1;
            float v2 = d[mi][nj][2] + b0, v3 = d[mi][nj][3] + b1;
            long o0 = (long)r * ldc + c;
            long o1 = o0 + 8L * ldc;
            if (Cf) {
                *(float2*)&Cf[o0] = make_float2(v0, v1);
                *(float2*)&Cf[o1] = make_float2(v2, v3);
            } else {
                int i_ = (c & 127) >> 1;
                int s0 = (r & (S_ - 1)) + sp0;
                int s8 = ((r + 8) & (S_ - 1)) + sp0;
                float c0f = fc[s0 * 64 + i_], s0f = fs[s0 * 64 + i_];
                float c8f = fc[s8 * 64 + i_], s8f = fs[s8 * 64 + i_];
                float r0 = v0 * c0f - v1 * s0f, r1 = v0 * s0f + v1 * c0f;
                float r2 = v2 * c8f - v3 * s8f, r3 = v2 * s8f + v3 * c8f;
                *(u32*)&Ch[o0] = (u32)h16(r0) | ((u32)h16(r1) << 16);
                *(u32*)&Ch[o1] = (u32)h16(r2) | ((u32)h16(r3) << 16);
            }
        }
    }
}

// ---------------------------------------------------------------------------
// Output projection: out = AO(fp16) @ owh^T, 1-term. fp32 out.
// ---------------------------------------------------------------------------
__global__ __launch_bounds__(256, 1)
void oproj_gemm(const u16* __restrict__ Ap,
                const u16* __restrict__ Bgh,
                float* __restrict__ Cf)
{
    extern __shared__ __align__(16) char dsm[];
    int m0 = blockIdx.y * 128, n0 = blockIdx.x * 256;

    float d[4][8][4];
    #pragma unroll
    for (int i = 0; i < 4; i++)
        #pragma unroll
        for (int j = 0; j < 8; j++)
            #pragma unroll
            for (int q = 0; q < 4; q++) d[i][j][q] = 0.f;

    gemm_core2<false>(smem_u32(dsm), Ap, Bgh, nullptr, D_, D_, m0, n0, D_, d);

    int tid = threadIdx.x, wid = tid >> 5, lane = tid & 31;
    int wx = wid & 3, wy = wid >> 2;
    int g = lane >> 2, tg = lane & 3;

    #pragma unroll
    for (int mi = 0; mi < 4; mi++) {
        #pragma unroll
        for (int nj = 0; nj < 8; nj++) {
            int r = m0 + wy * 64 + mi * 16 + g;
            int c = n0 + wx * 64 + nj * 8 + tg * 2;
            long o0 = (long)r * D_ + c;
            long o1 = o0 + 8L * D_;
            *(float2*)&Cf[o0] = make_float2(d[mi][nj][0], d[mi][nj][1]);
            *(float2*)&Cf[o1] = make_float2(d[mi][nj][2], d[mi][nj][3]);
        }
    }
}

// ---------------------------------------------------------------------------
// Fused FlashAttention: S = alpha*Qh@Kh^T (1-term), online softmax,
// O = Ph@(Vh+Vl) (2-term).
// ---------------------------------------------------------------------------
#define FA_Q    0                   // 32 KB (2 cc x 16 KB)
#define FA_K    32768               // 2 stages x 16 KB
#define FA_V    65536               // VH 16K, VL 16K
#define FA_P    98304               // PH 16K
#define FA_ST   114688
#define FA_SMEM (114688 + 5632)

__global__ __launch_bounds__(256, 1)
void fa_fused(const u16* __restrict__ Qh,
              const u16* __restrict__ Kh,
              const u16* __restrict__ Vth, const u16* __restrict__ Vtl,
              u16* __restrict__ Ao, float alpha)
{
    extern __shared__ __align__(16) char dsm[];
    u32 sbase = smem_u32(dsm);
    float* m_run = (float*)(dsm + FA_ST);
    float* l_run = m_run + 128;
    float* fch   = m_run + 256;
    float* mpart = m_run + 384;
    float* lpart = m_run + 896;

    int m0 = (int)(gridDim.x - 1 - blockIdx.x) * 128;
    int z = blockIdx.y, b = z / HQ, h = z - b * HQ;

    const u16* Qph = Qh + ((long)b * S_ + m0) * D_ + h * HD;
    const u16* Kph = Kh + (long)b * S_ * 1024 + (h / GRP) * HD;
    const u16* Vph = Vth + ((long)b * HKV + (h / GRP)) * (long)HD * S_;
    const u16* Vpl = Vtl + ((long)b * HKV + (h / GRP)) * (long)HD * S_;

    int tid = threadIdx.x, wid = tid >> 5, lane = tid & 31;
    int wx = wid & 3, wy = wid >> 2;
    int g = lane >> 2, tg = lane & 3;

    if (tid < 128) { m_run[tid] = -1e30f; l_run[tid] = 0.f; }

    int aRow = ((lane >> 3) & 1) * 8 + (lane & 7);
    int aKu  = lane >> 4;
    u32 aBase[4]; int aSw[4];
    #pragma unroll
    for (int mi = 0; mi < 4; mi++) {
        int rr = wy * 64 + mi * 16 + aRow;
        aBase[mi] = (u32)(rr * 128); aSw[mi] = rr & 7;
    }
    int bRow = (lane >> 4) * 8 + (lane & 7);
    int bKu  = (lane >> 3) & 1;
    u32 bBaseS = (u32)((wx * 16 + bRow) * 128); int bSwS = bRow & 7;
    u32 bBaseV[2]; int bSwV[2];
    #pragma unroll
    for (int p = 0; p < 2; p++) {
        int rr = wx * 32 + p * 16 + bRow;
        bBaseV[p] = (u32)(rr * 128); bSwV[p] = rr & 7;
    }

    float d_o[4][4][4];
    #pragma unroll
    for (int i = 0; i < 4; i++)
        #pragma unroll
        for (int j = 0; j < 4; j++)
            #pragma unroll
            for (int q = 0; q < 4; q++) d_o[i][j][q] = 0.f;

    int nch = (m0 + 128) >> 6;

    auto qfetch = [&]() {
        #pragma unroll
        for (int u0 = 0; u0 < 2048; u0 += 256) {
            int u = u0 + tid;
            int cc = u >> 10, v = u & 1023;
            int row = v >> 3, c16 = v & 7;
            const u16* gp = Qph + (long)row * D_ + cc * 64 + c16 * 8;
            u32 so = sbase + FA_Q + (u32)cc * 16384
                   + (u32)(row * 128) + ((u32)(c16 ^ (row & 7)) << 4);
            cp16(so, gp);
        }
    };
    auto kfetch = [&](int c, int s) {
        int j0 = c << 6;
        #pragma unroll
        for (int u0 = 0; u0 < 1024; u0 += 256) {
            int u = u0 + tid;
            int cc = u >> 9, v = u & 511;
            int row = v >> 3, c16 = v & 7;
            const u16* gp = Kph + (long)(j0 + row) * 1024 + cc * 64 + c16 * 8;
            u32 so = sbase + FA_K + (u32)s * 16384 + (u32)cc * 8192
                   + (u32)(row * 128) + ((u32)(c16 ^ (row & 7)) << 4);
            cp16(so, gp);
        }
    };
    auto vfetch = [&](int c) {
        int j0 = c << 6;
        #pragma unroll
        for (int u0 = 0; u0 < 2048; u0 += 256) {
            int u = u0 + tid;
            bool lo = u >= 1024;
            int v = u & 1023, row = v >> 3, c16 = v & 7;
            const u16* gp = (lo ? Vpl : Vph) + (long)row * S_ + j0 + c16 * 8;
            u32 so = sbase + FA_V + (lo ? 16384u : 0u)
                   + (u32)(row * 128) + ((u32)(c16 ^ (row & 7)) << 4);
            cp16(so, gp);
        }
    };

    qfetch();
    CP_COMMIT();
    kfetch(0, 0);
    CP_COMMIT();

    for (int c = 0; c < nch; c++) {
        int j0 = c << 6;
        bool hasNext = (c + 1 < nch);

        vfetch(c); CP_COMMIT();
        if (hasNext) { kfetch(c + 1, (c + 1) & 1); CP_COMMIT(); }

        if (hasNext) CP_WAIT2(); else CP_WAIT1();
        __syncthreads();

        // ---- S = Qh @ Kh^T (1 term) ----
        float d_s[4][2][4];
        #pragma unroll
        for (int i = 0; i < 4; i++)
            #pragma unroll
            for (int j = 0; j < 2; j++)
                #pragma unroll
                for (int q = 0; q < 4; q++) d_s[i][j][q] = 0.f;

        u32 kst = sbase + FA_K + (u32)(c & 1) * 16384;
        #pragma unroll
        for (int cc = 0; cc < 2; cc++) {
            u32 sQ_ = sbase + FA_Q + (u32)cc * 16384;
            u32 sK_ = kst + (u32)cc * 8192;
            #pragma unroll
            for (int kk = 0; kk < 4; kk++) {
                int kuA = kk * 2 + aKu;
                int kuB = kk * 2 + bKu;
                u32 ah[4][4], xb[4];
                #pragma unroll
                for (int mi = 0; mi < 4; mi++)
                    ldsm4(ah[mi], sQ_ + aBase[mi] + ((u32)(kuA ^ aSw[mi]) << 4));
                ldsm4(xb, sK_ + bBaseS + ((u32)(kuB ^ bSwS) << 4));
                #pragma unroll
                for (int mi = 0; mi < 4; mi++)
                    #pragma unroll
                    for (int nj = 0; nj < 2; nj++)
                        mma16816(d_s[mi][nj], ah[mi], &xb[nj * 2]);
            }
        }

        // ---- mask + alpha + chunk row-max ----
        bool domask = (c >= nch - 2);
        #pragma unroll
        for (int mi = 0; mi < 4; mi++) {
            int rl0 = wy * 64 + mi * 16 + g;
            int grow0 = m0 + rl0, grow8 = grow0 + 8;
            float mx0 = -1e30f, mx8 = -1e30f;
            #pragma unroll
            for (int nj = 0; nj < 2; nj++) {
                #pragma unroll
                for (int e = 0; e < 2; e++) {
                    int gc = j0 + wx * 16 + nj * 8 + tg * 2 + e;
                    float v0 = d_s[mi][nj][e] * alpha;
                    float v8 = d_s[mi][nj][2 + e] * alpha;
                    if (domask) {
                        if (gc > grow0) v0 = -1e30f;
                        if (gc > grow8) v8 = -1e30f;
                    }
                    d_s[mi][nj][e] = v0; d_s[mi][nj][2 + e] = v8;
                    mx0 = fmaxf(mx0, v0); mx8 = fmaxf(mx8, v8);
                }
            }
            mx0 = fmaxf(mx0, __shfl_xor_sync(0xffffffffu, mx0, 1));
            mx0 = fmaxf(mx0, __shfl_xor_sync(0xffffffffu, mx0, 2));
            mx8 = fmaxf(mx8, __shfl_xor_sync(0xffffffffu, mx8, 1));
            mx8 = fmaxf(mx8, __shfl_xor_sync(0xffffffffu, mx8, 2));
            if (tg == 0) {
                mpart[wx * 128 + rl0] = mx0;
                mpart[wx * 128 + rl0 + 8] = mx8;
            }
        }
        __syncthreads();

        if (tid < 128) {
            float mc = fmaxf(fmaxf(mpart[tid], mpart[128 + tid]),
                             fmaxf(mpart[256 + tid], mpart[384 + tid]));
            float mo = m_run[tid];
            float mn = fmaxf(mo, mc);
            fch[tid] = __expf(mo - mn);
            m_run[tid] = mn;
        }
        __syncthreads();

        #pragma unroll
        for (int mi = 0; mi < 4; mi++) {
            int rl = wy * 64 + mi * 16 + g;
            float f0 = fch[rl], f8 = fch[rl + 8];
            #pragma unroll
            for (int nj = 0; nj < 4; nj++) {
                d_o[mi][nj][0] *= f0; d_o[mi][nj][1] *= f0;
                d_o[mi][nj][2] *= f8; d_o[mi][nj][3] *= f8;
            }
        }

        // ---- P = exp(S - m), fp16, store to smem; partial sums ----
        #pragma unroll
        for (int mi = 0; mi < 4; mi++) {
            int rl0 = wy * 64 + mi * 16 + g;
            float mrow0 = m_run[rl0], mrow8 = m_run[rl0 + 8];
            float s0 = 0.f, s8 = 0.f;
            #pragma unroll
            for (int nj = 0; nj < 2; nj++) {
                float p00 = __expf(d_s[mi][nj][0] - mrow0);
                float p01 = __expf(d_s[mi][nj][1] - mrow0);
                float p80 = __expf(d_s[mi][nj][2] - mrow8);
                float p81 = __expf(d_s[mi][nj][3] - mrow8);
                s0 += p00 + p01; s8 += p80 + p81;
                int cl = wx * 16 + nj * 8 + tg * 2;
                u32 u0 = (u32)(((cl >> 3) ^ (rl0 & 7)) << 4) + (u32)((cl & 7) * 2);
                u32 u8 = (u32)(((cl >> 3) ^ ((rl0 + 8) & 7)) << 4) + (u32)((cl & 7) * 2);
                *(u32*)(dsm + FA_P + rl0 * 128 + u0) =
                    (u32)h16(p00) | ((u32)h16(p01) << 16);
                *(u32*)(dsm + FA_P + (rl0 + 8) * 128 + u8) =
                    (u32)h16(p80) | ((u32)h16(p81) << 16);
            }
            s0 += __shfl_xor_sync(0xffffffffu, s0, 1);
            s0 += __shfl_xor_sync(0xffffffffu, s0, 2);
            s8 += __shfl_xor_sync(0xffffffffu, s8, 1);
            s8 += __shfl_xor_sync(0xffffffffu, s8, 2);
            if (tg == 0) {
                lpart[wx * 128 + rl0] = s0;
                lpart[wx * 128 + rl0 + 8] = s8;
            }
        }

        if (hasNext) CP_WAIT1(); else CP_WAIT0();
        __syncthreads();

        if (tid < 128) {
            float sum = lpart[tid] + lpart[128 + tid] + lpart[256 + tid] + lpart[384 + tid];
            l_run[tid] = l_run[tid] * fch[tid] + sum;
        }

        // ---- O += Ph @ (Vh+Vl) (2 terms) ----
        u32 sP = sbase + FA_P;
        u32 sVh = sbase + FA_V, sVl = sVh + 16384;
        #pragma unroll
        for (int kk = 0; kk < 4; kk++) {
            int kuA = kk * 2 + aKu;
            int kuB = kk * 2 + bKu;
            u32 ah[4][4], xbh[2][4], xbl[2][4];
            #pragma unroll
            for (int mi = 0; mi < 4; mi++)
                ldsm4(ah[mi], sP + aBase[mi] + ((u32)(kuA ^ aSw[mi]) << 4));
            #pragma unroll
            for (int p = 0; p < 2; p++)
                ldsm4(xbh[p], sVh + bBaseV[p] + ((u32)(kuB ^ bSwV[p]) << 4));
            #pragma unroll
            for (int p = 0; p < 2; p++)
                ldsm4(xbl[p], sVl + bBaseV[p] + ((u32)(kuB ^ bSwV[p]) << 4));
            #pragma unroll
            for (int mi = 0; mi < 4; mi++)
                #pragma unroll
                for (int nj = 0; nj < 4; nj++)
                    mma16816(d_o[mi][nj], ah[mi], &xbh[nj >> 1][(nj & 1) * 2]);
            #pragma unroll
            for (int mi = 0; mi < 4; mi++)
                #pragma unroll
                for (int nj = 0; nj < 4; nj++)
                    mma16816(d_o[mi][nj], ah[mi], &xbl[nj >> 1][(nj & 1) * 2]);
        }
        __syncthreads();
    }

    // epilogue: divide by l, fp16-truncate, store AO
    #pragma unroll
    for (int mi = 0; mi < 4; mi++) {
        int rl = wy * 64 + mi * 16 + g;
        float i0 = 1.0f / l_run[rl];
        float i8 = 1.0f / l_run[rl + 8];
        #pragma unroll
        for (int nj = 0; nj < 4; nj++) {
            int cc = wx * 32 + nj * 8 + tg * 2;
            long o0 = ((long)b * S_ + m0 + rl) * D_ + h * HD + cc;
            long o1 = o0 + 8L * D_;
            *(u32*)&Ao[o0] = (u32)h16(d_o[mi][nj][0] * i0)
                           | ((u32)h16(d_o[mi][nj][1] * i0) << 16);
            *(u32*)&Ao[o1] = (u32)h16(d_o[mi][nj][2] * i8)
                           | ((u32)h16(d_o[mi][nj][3] * i8) << 16);
        }
    }
}

// ---------------------------------------------------------------------------
__global__ void conv_h(const float* __restrict__ in, u16* __restrict__ oh, long n)
{
    long i = blockIdx.x * 256L + threadIdx.x;
    if (i < n) oh[i] = h16(in[i]);
}

// fp32 [R,C] -> transposed fp16 [C,R]; WLO: also write lo residual array
__global__ void tsplit(const float* __restrict__ in, u16* __restrict__ oh,
                       u16* __restrict__ ol, int ldin, int ldout,
                       long sInB, long sInH, long sOutZ, int Hc, int writeLo)
{
    __shared__ float t[32][33];
    int z = blockIdx.z, bb = z / Hc, hh = z - bb * Hc;
    const float* ip = in + bb * sInB + (long)hh * sInH;
    int c0 = blockIdx.x * 32, r0 = blockIdx.y * 32;
    #pragma unroll
    for (int i = 0; i < 4; i++)
        t[threadIdx.y + i * 8][threadIdx.x] =
            ip[(long)(r0 + threadIdx.y + i * 8) * ldin + c0 + threadIdx.x];
    __syncthreads();
    #pragma unroll
    for (int i = 0; i < 4; i++) {
        int orow = c0 + threadIdx.y + i * 8;
        int oc = r0 + threadIdx.x;
        float v = t[threadIdx.x][threadIdx.y + i * 8];
        long o = z * sOutZ + (long)orow * ldout + oc;
        if (writeLo) {
            u16 hh2, ll;
            split2(v, hh2, ll);
            oh[o] = hh2; ol[o] = ll;
        } else {
            oh[o] = h16(v);
        }
    }
}

// ---------------------------------------------------------------------------
extern "C" void kernel_launch(void* const* d_in, const int* in_sizes, int n_in,
                              void* d_out, int out_size)
{
    const float* x  = (const float*)d_in[0];
    const float* fc = (const float*)d_in[1];
    const float* fs = (const float*)d_in[2];
    const float* qw = (const float*)d_in[3];
    const float* qb = (const float*)d_in[4];
    const float* kw = (const float*)d_in[5];
    const float* kb = (const float*)d_in[6];
    const float* vw = (const float*)d_in[7];
    const float* vb = (const float*)d_in[8];
    const float* ow = (const float*)d_in[9];
    const int*   sp = (const int*)d_in[10];
    float* out = (float*)d_out;

    float *v;
    u16 *x16, *qwth, *kwth, *kwtl, *vwth, *vwtl, *owth;
    u16 *qh, *kh, *vth, *vtl, *ao;
    cudaGetSymbolAddress((void**)&v, g_v);
    cudaGetSymbolAddress((void**)&x16, g_x16);
    cudaGetSymbolAddress((void**)&qwth, g_qwt_h);
    cudaGetSymbolAddress((void**)&kwth, g_kwt_h); cudaGetSymbolAddress((void**)&kwtl, g_kwt_l);
    cudaGetSymbolAddress((void**)&vwth, g_vwt_h); cudaGetSymbolAddress((void**)&vwtl, g_vwt_l);
    cudaGetSymbolAddress((void**)&owth, g_owt_h);
    cudaGetSymbolAddress((void**)&qh, g_qh);
    cudaGetSymbolAddress((void**)&kh, g_kh);
    cudaGetSymbolAddress((void**)&vth, g_vth); cudaGetSymbolAddress((void**)&vtl, g_vtl);
    cudaGetSymbolAddress((void**)&ao, g_ao);

    const int SM_QKV = 2 * (16384 + 2 * 256 * 128);   // 163840 (BLO=true stages)
    const int SM_O   = 2 * (16384 + 1 * 256 * 128);   // 98304
    cudaFuncSetAttribute((const void*)qkv_gemm,
                         cudaFuncAttributeMaxDynamicSharedMemorySize, SM_QKV);
    cudaFuncSetAttribute((const void*)oproj_gemm,
                         cudaFuncAttributeMaxDynamicSharedMemorySize, SM_O);
    cudaFuncSetAttribute((const void*)fa_fused,
                         cudaFuncAttributeMaxDynamicSharedMemorySize, FA_SMEM);

    // 1) converts: x -> fp16; weights transposed to [N,K] (Q/O hi-only)
    conv_h<<<(unsigned)(((long)MR * D_ + 255) / 256), 256>>>(x, x16, (long)MR * D_);
    dim3 tb(32, 8);
    tsplit<<<dim3(128, 128, 1), tb>>>(qw, qwth, nullptr, D_, D_, 0, 0, 0, 1, 0);
    tsplit<<<dim3(32, 128, 1), tb>>>(kw, kwth, kwtl, 1024, D_, 0, 0, 0, 1, 1);
    tsplit<<<dim3(32, 128, 1), tb>>>(vw, vwth, vwtl, 1024, D_, 0, 0, 0, 1, 1);
    tsplit<<<dim3(128, 128, 1), tb>>>(ow, owth, nullptr, D_, D_, 0, 0, 0, 1, 0);

    // 2) merged Q/K/V projections (Q 1-term; K/V 2-term; RoPE for Q/K)
    qkv_gemm<<<dim3(24, 32), 256, SM_QKV>>>(
        x16, qwth, qb, kwth, kwtl, kb, vwth, vwtl, vb,
        qh, kh, v, fc, fs, sp);
    // transpose+split V -> [b,h,d,s]
    tsplit<<<dim3(4, 64, B_ * HKV), tb>>>(v, vth, vtl, 1024, S_,
        (long)S_ * 1024, (long)HD, (long)HD * S_, HKV, 1);

    // 3) fused attention (1-term S, 2-term PV) -> fp16 AO in [b,s,h*128+d]
    fa_fused<<<dim3(16, B_ * HQ), 256, FA_SMEM>>>(
        qh, kh, vth, vtl, ao, 0.08838834764831845f);

    // 4) out = AO @ ow (1-term)
    oproj_gemm<<<dim3(16, 32), 256, SM_O>>>(ao, owth, out);
}

// round 12
// speedup vs baseline: 7.2039x; 1.0819x over previous
#include <cuda_runtime.h>
#include <cuda_fp16.h>

typedef unsigned short u16;
typedef unsigned int   u32;

#define B_   2
#define S_   2048
#define D_   4096
#define HQ   32
#define HKV  8
#define HD   128
#define GRP  4
#define MR   (B_*S_)   // 4096

// ---------------- scratch (__device__ globals; no runtime allocation) -------
__device__ float g_v[(size_t)MR*HKV*HD];             // fp32 V (pre-transpose)

__device__ u16 g_x16[(size_t)MR*D_];                 // fp16 x
__device__ u16 g_qwt_h[(size_t)D_*D_];               // [N,K] fp16
__device__ u16 g_kwt_h[(size_t)1024*D_],   g_kwt_l[(size_t)1024*D_];
__device__ u16 g_vwt_h[(size_t)1024*D_];
__device__ u16 g_owt_h[(size_t)D_*D_];
__device__ u16 g_qh[(size_t)MR*D_];                  // rope'd Q fp16
__device__ u16 g_kh[(size_t)MR*HKV*HD];              // rope'd K fp16
__device__ u16 g_vth[(size_t)B_*HKV*HD*S_];          // V^T fp16 [b,h,d,s]
__device__ u16 g_ao[(size_t)MR*D_];                  // fp16 attn out

// ---------------------------------------------------------------------------
__device__ __forceinline__ void split2(float v, u16& h, u16& l) {
    __half hb = __float2half_rn(v);
    float r = v - __half2float(hb);
    h = __half_as_ushort(hb);
    l = __half_as_ushort(__float2half_rn(r));
}
__device__ __forceinline__ u16 h16(float v) {
    return __half_as_ushort(__float2half_rn(v));
}

__device__ __forceinline__ u32 smem_u32(const void* p) {
    u32 a;
    asm("{ .reg .u64 t; cvta.to.shared.u64 t, %1; cvt.u32.u64 %0, t; }" : "=r"(a) : "l"(p));
    return a;
}

__device__ __forceinline__ void cp16(u32 sdst, const void* gsrc) {
    asm volatile("cp.async.cg.shared.global [%0], [%1], 16;\n" :: "r"(sdst), "l"(gsrc));
}
#define CP_COMMIT()  asm volatile("cp.async.commit_group;" ::: "memory")
#define CP_WAIT2()   asm volatile("cp.async.wait_group 2;" ::: "memory")
#define CP_WAIT1()   asm volatile("cp.async.wait_group 1;" ::: "memory")
#define CP_WAIT0()   asm volatile("cp.async.wait_group 0;" ::: "memory")

__device__ __forceinline__ void ldsm4(u32* r, u32 addr) {
    asm volatile("ldmatrix.sync.aligned.m8n8.x4.shared.b16 {%0,%1,%2,%3}, [%4];"
        : "=r"(r[0]), "=r"(r[1]), "=r"(r[2]), "=r"(r[3]) : "r"(addr));
}

__device__ __forceinline__ void mma16816(float* d, const u32* a, const u32* b) {
    asm volatile(
        "mma.sync.aligned.m16n8k16.row.col.f32.f16.f16.f32 "
        "{%0,%1,%2,%3}, {%4,%5,%6,%7}, {%8,%9}, {%0,%1,%2,%3};\n"
        : "+f"(d[0]), "+f"(d[1]), "+f"(d[2]), "+f"(d[3])
        : "r"(a[0]), "r"(a[1]), "r"(a[2]), "r"(a[3]), "r"(b[0]), "r"(b[1]));
}

// ---------------------------------------------------------------------------
// GEMM mainloop, single fp16 A. BLO=true: d += A@(Bh+Bl)^T ; false: A@Bh^T.
// 128 x 256 CTA tile, BK=64, 2-stage cp.async, SW128 swizzle.
// ---------------------------------------------------------------------------
template<bool BLO>
__device__ __forceinline__ void gemm_core2(
    u32 sbase,
    const u16* __restrict__ Ap,
    const u16* __restrict__ Bph, const u16* __restrict__ Bpl,
    int lda, int ldb, int m0, int n0, int K,
    float (&d)[4][8][4])
{
    constexpr int NT = 256, NJ = 8;
    constexpr int STG = 16384 + (BLO ? 2 : 1) * NT * 128;

    int tid = threadIdx.x, wid = tid >> 5, lane = tid & 31;
    int wx = wid & 3, wy = wid >> 2;

    int aRow = ((lane >> 3) & 1) * 8 + (lane & 7);
    int aKu  = lane >> 4;
    u32 aBase[4]; int aSw[4];
    #pragma unroll
    for (int mi = 0; mi < 4; mi++) {
        int r = wy * 64 + mi * 16 + aRow;
        aBase[mi] = (u32)(r * 128); aSw[mi] = r & 7;
    }
    int bRow = (lane >> 4) * 8 + (lane & 7);
    int bKu  = (lane >> 3) & 1;
    u32 bBase[NJ / 2]; int bSw[NJ / 2];
    #pragma unroll
    for (int p = 0; p < NJ / 2; p++) {
        int r = wx * 64 + p * 16 + bRow;
        bBase[p] = (u32)(r * 128); bSw[p] = r & 7;
    }

    int nch = K >> 6;

    auto prefetch = [&](int c, int s) {
        u32 st = sbase + s * STG;
        int k0 = c << 6;
        constexpr int TOT = (128 + (BLO ? 2 : 1) * NT) * 8;
        #pragma unroll
        for (int u0 = 0; u0 < TOT; u0 += 256) {
            int u = u0 + tid;
            int row, c16;
            const u16* gp;
            u32 abase;
            if (u0 < 1024) {
                row = (u >> 3) & 127; c16 = u & 7;
                gp = Ap + (long)(m0 + row) * lda + k0 + c16 * 8;
                abase = st;
            } else {
                int v = u - 1024;
                row = (v >> 3) & (NT - 1); c16 = v & 7;
                bool lo = BLO && (v >= NT * 8);
                gp = (lo ? Bpl : Bph) + (long)(n0 + row) * ldb + k0 + c16 * 8;
                abase = st + 16384u + (lo ? (u32)(NT * 128) : 0u);
            }
            u32 so = abase + (u32)(row * 128) + ((u32)(c16 ^ (row & 7)) << 4);
            cp16(so, gp);
        }
    };

    prefetch(0, 0);
    CP_COMMIT();

    for (int c = 0; c < nch; c++) {
        if (c + 1 < nch) { prefetch(c + 1, (c + 1) & 1); CP_COMMIT(); CP_WAIT1(); }
        else             { CP_WAIT0(); }
        __syncthreads();

        u32 st = sbase + (c & 1) * STG;
        u32 sA_ = st, sBh_ = st + 16384, sBl_ = st + 16384 + NT * 128;

        #pragma unroll
        for (int kk = 0; kk < 4; kk++) {
            int kuA = kk * 2 + aKu;
            int kuB = kk * 2 + bKu;
            u32 ah[4][4], xbh[NJ / 2][4];
            #pragma unroll
            for (int mi = 0; mi < 4; mi++)
                ldsm4(ah[mi], sA_ + aBase[mi] + ((u32)(kuA ^ aSw[mi]) << 4));
            #pragma unroll
            for (int p = 0; p < NJ / 2; p++)
                ldsm4(xbh[p], sBh_ + bBase[p] + ((u32)(kuB ^ bSw[p]) << 4));
            #pragma unroll
            for (int mi = 0; mi < 4; mi++)
                #pragma unroll
                for (int nj = 0; nj < NJ; nj++)
                    mma16816(d[mi][nj], ah[mi], &xbh[nj >> 1][(nj & 1) * 2]);
            if (BLO) {
                u32 xbl[NJ / 2][4];
                #pragma unroll
                for (int p = 0; p < NJ / 2; p++)
                    ldsm4(xbl[p], sBl_ + bBase[p] + ((u32)(kuB ^ bSw[p]) << 4));
                #pragma unroll
                for (int mi = 0; mi < 4; mi++)
                    #pragma unroll
                    for (int nj = 0; nj < NJ; nj++)
                        mma16816(d[mi][nj], ah[mi], &xbl[nj >> 1][(nj & 1) * 2]);
            }
        }
        __syncthreads();
    }
}

// ---------------------------------------------------------------------------
// Merged Q/K/V projection. Q: 1-term. K: 2-term. V: 1-term.
// Q/K: bias + RoPE + fp16 out. V: bias + fp32 out.
// ---------------------------------------------------------------------------
__global__ __launch_bounds__(256, 1)
void qkv_gemm(const u16* __restrict__ x16,
              const u16* __restrict__ qwth, const float* __restrict__ qb,
              const u16* __restrict__ kwth, const u16* __restrict__ kwtl, const float* __restrict__ kb,
              const u16* __restrict__ vwth, const float* __restrict__ vb,
              u16* __restrict__ qh, u16* __restrict__ kh,
              float* __restrict__ vf,
              const float* __restrict__ fc, const float* __restrict__ fs,
              const int* __restrict__ sp)
{
    extern __shared__ __align__(16) char dsm[];
    int nt = blockIdx.x, m0 = blockIdx.y * 128;

    const u16 *Bph = nullptr, *Bpl = nullptr; const float* bias;
    u16* Ch = nullptr; float* Cf = nullptr;
    int ldc, n0; bool blo;
    if (nt < 16)      { Bph = qwth;             bias = qb; Ch = qh; ldc = 4096; n0 = nt * 256;        blo = false; }
    else if (nt < 20) { Bph = kwth; Bpl = kwtl; bias = kb; Ch = kh; ldc = 1024; n0 = (nt - 16) * 256; blo = true;  }
    else              { Bph = vwth;             bias = vb; Cf = vf; ldc = 1024; n0 = (nt - 20) * 256; blo = false; }

    float d[4][8][4];
    #pragma unroll
    for (int i = 0; i < 4; i++)
        #pragma unroll
        for (int j = 0; j < 8; j++)
            #pragma unroll
            for (int q = 0; q < 4; q++) d[i][j][q] = 0.f;

    if (blo) gemm_core2<true >(smem_u32(dsm), x16, Bph, Bpl, D_, D_, m0, n0, D_, d);
    else     gemm_core2<false>(smem_u32(dsm), x16, Bph, Bpl, D_, D_, m0, n0, D_, d);

    int tid = threadIdx.x, wid = tid >> 5, lane = tid & 31;
    int wx = wid & 3, wy = wid >> 2;
    int g = lane >> 2, tg = lane & 3;
    int sp0 = *sp;

    #pragma unroll
    for (int mi = 0; mi < 4; mi++) {
        #pragma unroll
        for (int nj = 0; nj < 8; nj++) {
            int r = m0 + wy * 64 + mi * 16 + g;
            int c = n0 + wx * 64 + nj * 8 + tg * 2;
            float b0 = bias[c], b1 = bias[c + 1];
            float v0 = d[mi][nj][0] + b0, v1 = d[mi][nj][1] + b1;
            float v2 = d[mi][nj][2] + b0, v3 = d[mi][nj][3] + b1;
            long o0 = (long)r * ldc + c;
            long o1 = o0 + 8L * ldc;
            if (Cf) {
                *(float2*)&Cf[o0] = make_float2(v0, v1);
                *(float2*)&Cf[o1] = make_float2(v2, v3);
            } else {
                int i_ = (c & 127) >> 1;
                int s0 = (r & (S_ - 1)) + sp0;
                int s8 = ((r + 8) & (S_ - 1)) + sp0;
                float c0f = fc[s0 * 64 + i_], s0f = fs[s0 * 64 + i_];
                float c8f = fc[s8 * 64 + i_], s8f = fs[s8 * 64 + i_];
                float r0 = v0 * c0f - v1 * s0f, r1 = v0 * s0f + v1 * c0f;
                float r2 = v2 * c8f - v3 * s8f, r3 = v2 * s8f + v3 * c8f;
                *(u32*)&Ch[o0] = (u32)h16(r0) | ((u32)h16(r1) << 16);
                *(u32*)&Ch[o1] = (u32)h16(r2) | ((u32)h16(r3) << 16);
            }
        }
    }
}

// ---------------------------------------------------------------------------
// Output projection: out = AO(fp16) @ owh^T, 1-term. fp32 out.
// ---------------------------------------------------------------------------
__global__ __launch_bounds__(256, 1)
void oproj_gemm(const u16* __restrict__ Ap,
                const u16* __restrict__ Bgh,
                float* __restrict__ Cf)
{
    extern __shared__ __align__(16) char dsm[];
    int m0 = blockIdx.y * 128, n0 = blockIdx.x * 256;

    float d[4][8][4];
    #pragma unroll
    for (int i = 0; i < 4; i++)
        #pragma unroll
        for (int j = 0; j < 8; j++)
            #pragma unroll
            for (int q = 0; q < 4; q++) d[i][j][q] = 0.f;

    gemm_core2<false>(smem_u32(dsm), Ap, Bgh, nullptr, D_, D_, m0, n0, D_, d);

    int tid = threadIdx.x, wid = tid >> 5, lane = tid & 31;
    int wx = wid & 3, wy = wid >> 2;
    int g = lane >> 2, tg = lane & 3;

    #pragma unroll
    for (int mi = 0; mi < 4; mi++) {
        #pragma unroll
        for (int nj = 0; nj < 8; nj++) {
            int r = m0 + wy * 64 + mi * 16 + g;
            int c = n0 + wx * 64 + nj * 8 + tg * 2;
            long o0 = (long)r * D_ + c;
            long o1 = o0 + 8L * D_;
            *(float2*)&Cf[o0] = make_float2(d[mi][nj][0], d[mi][nj][1]);
            *(float2*)&Cf[o1] = make_float2(d[mi][nj][2], d[mi][nj][3]);
        }
    }
}

// ---------------------------------------------------------------------------
// Fused FlashAttention: S = alpha*Qh@Kh^T (1-term), online softmax,
// O = Ph@Vh (1-term). ~102 KB smem -> 2 CTAs/SM.
// ---------------------------------------------------------------------------
#define FA_Q    0                   // 32 KB (2 cc x 16 KB)
#define FA_K    32768               // 2 stages x 16 KB
#define FA_V    65536               // 16 KB
#define FA_P    81920               // 16 KB
#define FA_ST   98304
#define FA_SMEM (98304 + 5632)

__global__ __launch_bounds__(256)
void fa_fused(const u16* __restrict__ Qh,
              const u16* __restrict__ Kh,
              const u16* __restrict__ Vth,
              u16* __restrict__ Ao, float alpha)
{
    extern __shared__ __align__(16) char dsm[];
    u32 sbase = smem_u32(dsm);
    float* m_run = (float*)(dsm + FA_ST);
    float* l_run = m_run + 128;
    float* fch   = m_run + 256;
    float* mpart = m_run + 384;
    float* lpart = m_run + 896;

    int m0 = (int)(gridDim.x - 1 - blockIdx.x) * 128;
    int z = blockIdx.y, b = z / HQ, h = z - b * HQ;

    const u16* Qph = Qh + ((long)b * S_ + m0) * D_ + h * HD;
    const u16* Kph = Kh + (long)b * S_ * 1024 + (h / GRP) * HD;
    const u16* Vph = Vth + ((long)b * HKV + (h / GRP)) * (long)HD * S_;

    int tid = threadIdx.x, wid = tid >> 5, lane = tid & 31;
    int wx = wid & 3, wy = wid >> 2;
    int g = lane >> 2, tg = lane & 3;

    if (tid < 128) { m_run[tid] = -1e30f; l_run[tid] = 0.f; }

    int aRow = ((lane >> 3) & 1) * 8 + (lane & 7);
    int aKu  = lane >> 4;
    u32 aBase[4]; int aSw[4];
    #pragma unroll
    for (int mi = 0; mi < 4; mi++) {
        int rr = wy * 64 + mi * 16 + aRow;
        aBase[mi] = (u32)(rr * 128); aSw[mi] = rr & 7;
    }
    int bRow = (lane >> 4) * 8 + (lane & 7);
    int bKu  = (lane >> 3) & 1;
    u32 bBaseS = (u32)((wx * 16 + bRow) * 128); int bSwS = bRow & 7;
    u32 bBaseV[2]; int bSwV[2];
    #pragma unroll
    for (int p = 0; p < 2; p++) {
        int rr = wx * 32 + p * 16 + bRow;
        bBaseV[p] = (u32)(rr * 128); bSwV[p] = rr & 7;
    }

    float d_o[4][4][4];
    #pragma unroll
    for (int i = 0; i < 4; i++)
        #pragma unroll
        for (int j = 0; j < 4; j++)
            #pragma unroll
            for (int q = 0; q < 4; q++) d_o[i][j][q] = 0.f;

    int nch = (m0 + 128) >> 6;

    auto qfetch = [&]() {
        #pragma unroll
        for (int u0 = 0; u0 < 2048; u0 += 256) {
            int u = u0 + tid;
            int cc = u >> 10, v = u & 1023;
            int row = v >> 3, c16 = v & 7;
            const u16* gp = Qph + (long)row * D_ + cc * 64 + c16 * 8;
            u32 so = sbase + FA_Q + (u32)cc * 16384
                   + (u32)(row * 128) + ((u32)(c16 ^ (row & 7)) << 4);
            cp16(so, gp);
        }
    };
    auto kfetch = [&](int c, int s) {
        int j0 = c << 6;
        #pragma unroll
        for (int u0 = 0; u0 < 1024; u0 += 256) {
            int u = u0 + tid;
            int cc = u >> 9, v = u & 511;
            int row = v >> 3, c16 = v & 7;
            const u16* gp = Kph + (long)(j0 + row) * 1024 + cc * 64 + c16 * 8;
            u32 so = sbase + FA_K + (u32)s * 16384 + (u32)cc * 8192
                   + (u32)(row * 128) + ((u32)(c16 ^ (row & 7)) << 4);
            cp16(so, gp);
        }
    };
    auto vfetch = [&](int c) {
        int j0 = c << 6;
        #pragma unroll
        for (int u0 = 0; u0 < 1024; u0 += 256) {
            int u = u0 + tid;
            int row = u >> 3, c16 = u & 7;
            const u16* gp = Vph + (long)row * S_ + j0 + c16 * 8;
            u32 so = sbase + FA_V
                   + (u32)(row * 128) + ((u32)(c16 ^ (row & 7)) << 4);
            cp16(so, gp);
        }
    };

    qfetch();
    CP_COMMIT();
    kfetch(0, 0);
    CP_COMMIT();

    for (int c = 0; c < nch; c++) {
        int j0 = c << 6;
        bool hasNext = (c + 1 < nch);

        vfetch(c); CP_COMMIT();
        if (hasNext) { kfetch(c + 1, (c + 1) & 1); CP_COMMIT(); }

        if (hasNext) CP_WAIT2(); else CP_WAIT1();
        __syncthreads();

        // ---- S = Qh @ Kh^T (1 term) ----
        float d_s[4][2][4];
        #pragma unroll
        for (int i = 0; i < 4; i++)
            #pragma unroll
            for (int j = 0; j < 2; j++)
                #pragma unroll
                for (int q = 0; q < 4; q++) d_s[i][j][q] = 0.f;

        u32 kst = sbase + FA_K + (u32)(c & 1) * 16384;
        #pragma unroll
        for (int cc = 0; cc < 2; cc++) {
            u32 sQ_ = sbase + FA_Q + (u32)cc * 16384;
            u32 sK_ = kst + (u32)cc * 8192;
            #pragma unroll
            for (int kk = 0; kk < 4; kk++) {
                int kuA = kk * 2 + aKu;
                int kuB = kk * 2 + bKu;
                u32 ah[4][4], xb[4];
                #pragma unroll
                for (int mi = 0; mi < 4; mi++)
                    ldsm4(ah[mi], sQ_ + aBase[mi] + ((u32)(kuA ^ aSw[mi]) << 4));
                ldsm4(xb, sK_ + bBaseS + ((u32)(kuB ^ bSwS) << 4));
                #pragma unroll
                for (int mi = 0; mi < 4; mi++)
                    #pragma unroll
                    for (int nj = 0; nj < 2; nj++)
                        mma16816(d_s[mi][nj], ah[mi], &xb[nj * 2]);
            }
        }

        // ---- mask + alpha + chunk row-max ----
        bool domask = (c >= nch - 2);
        #pragma unroll
        for (int mi = 0; mi < 4; mi++) {
            int rl0 = wy * 64 + mi * 16 + g;
            int grow0 = m0 + rl0, grow8 = grow0 + 8;
            float mx0 = -1e30f, mx8 = -1e30f;
            #pragma unroll
            for (int nj = 0; nj < 2; nj++) {
                #pragma unroll
                for (int e = 0; e < 2; e++) {
                    int gc = j0 + wx * 16 + nj * 8 + tg * 2 + e;
                    float v0 = d_s[mi][nj][e] * alpha;
                    float v8 = d_s[mi][nj][2 + e] * alpha;
                    if (domask) {
                        if (gc > grow0) v0 = -1e30f;
                        if (gc > grow8) v8 = -1e30f;
                    }
                    d_s[mi][nj][e] = v0; d_s[mi][nj][2 + e] = v8;
                    mx0 = fmaxf(mx0, v0); mx8 = fmaxf(mx8, v8);
                }
            }
            mx0 = fmaxf(mx0, __shfl_xor_sync(0xffffffffu, mx0, 1));
            mx0 = fmaxf(mx0, __shfl_xor_sync(0xffffffffu, mx0, 2));
            mx8 = fmaxf(mx8, __shfl_xor_sync(0xffffffffu, mx8, 1));
            mx8 = fmaxf(mx8, __shfl_xor_sync(0xffffffffu, mx8, 2));
            if (tg == 0) {
                mpart[wx * 128 + rl0] = mx0;
                mpart[wx * 128 + rl0 + 8] = mx8;
            }
        }
        __syncthreads();

        if (tid < 128) {
            float mc = fmaxf(fmaxf(mpart[tid], mpart[128 + tid]),
                             fmaxf(mpart[256 + tid], mpart[384 + tid]));
            float mo = m_run[tid];
            float mn = fmaxf(mo, mc);
            fch[tid] = __expf(mo - mn);
            m_run[tid] = mn;
        }
        __syncthreads();

        #pragma unroll
        for (int mi = 0; mi < 4; mi++) {
            int rl = wy * 64 + mi * 16 + g;
            float f0 = fch[rl], f8 = fch[rl + 8];
            #pragma unroll
            for (int nj = 0; nj < 4; nj++) {
                d_o[mi][nj][0] *= f0; d_o[mi][nj][1] *= f0;
                d_o[mi][nj][2] *= f8; d_o[mi][nj][3] *= f8;
            }
        }

        // ---- P = exp(S - m), fp16, store to smem; partial sums ----
        #pragma unroll
        for (int mi = 0; mi < 4; mi++) {
            int rl0 = wy * 64 + mi * 16 + g;
            float mrow0 = m_run[rl0], mrow8 = m_run[rl0 + 8];
            float s0 = 0.f, s8 = 0.f;
            #pragma unroll
            for (int nj = 0; nj < 2; nj++) {
                float p00 = __expf(d_s[mi][nj][0] - mrow0);
                float p01 = __expf(d_s[mi][nj][1] - mrow0);
                float p80 = __expf(d_s[mi][nj][2] - mrow8);
                float p81 = __expf(d_s[mi][nj][3] - mrow8);
                s0 += p00 + p01; s8 += p80 + p81;
                int cl = wx * 16 + nj * 8 + tg * 2;
                u32 u0 = (u32)(((cl >> 3) ^ (rl0 & 7)) << 4) + (u32)((cl & 7) * 2);
                u32 u8 = (u32)(((cl >> 3) ^ ((rl0 + 8) & 7)) << 4) + (u32)((cl & 7) * 2);
                *(u32*)(dsm + FA_P + rl0 * 128 + u0) =
                    (u32)h16(p00) | ((u32)h16(p01) << 16);
                *(u32*)(dsm + FA_P + (rl0 + 8) * 128 + u8) =
                    (u32)h16(p80) | ((u32)h16(p81) << 16);
            }
            s0 += __shfl_xor_sync(0xffffffffu, s0, 1);
            s0 += __shfl_xor_sync(0xffffffffu, s0, 2);
            s8 += __shfl_xor_sync(0xffffffffu, s8, 1);
            s8 += __shfl_xor_sync(0xffffffffu, s8, 2);
            if (tg == 0) {
                lpart[wx * 128 + rl0] = s0;
                lpart[wx * 128 + rl0 + 8] = s8;
            }
        }

        if (hasNext) CP_WAIT1(); else CP_WAIT0();
        __syncthreads();

        if (tid < 128) {
            float sum = lpart[tid] + lpart[128 + tid] + lpart[256 + tid] + lpart[384 + tid];
            l_run[tid] = l_run[tid] * fch[tid] + sum;
        }

        // ---- O += Ph @ Vh (1 term) ----
        u32 sP = sbase + FA_P;
        u32 sV = sbase + FA_V;
        #pragma unroll
        for (int kk = 0; kk < 4; kk++) {
            int kuA = kk * 2 + aKu;
            int kuB = kk * 2 + bKu;
            u32 ah[4][4], xb[2][4];
            #pragma unroll
            for (int mi = 0; mi < 4; mi++)
                ldsm4(ah[mi], sP + aBase[mi] + ((u32)(kuA ^ aSw[mi]) << 4));
            #pragma unroll
            for (int p = 0; p < 2; p++)
                ldsm4(xb[p], sV + bBaseV[p] + ((u32)(kuB ^ bSwV[p]) << 4));
            #pragma unroll
            for (int mi = 0; mi < 4; mi++)
                #pragma unroll
                for (int nj = 0; nj < 4; nj++)
                    mma16816(d_o[mi][nj], ah[mi], &xb[nj >> 1][(nj & 1) * 2]);
        }
        __syncthreads();
    }

    // epilogue: divide by l, fp16-truncate, store AO
    #pragma unroll
    for (int mi = 0; mi < 4; mi++) {
        int rl = wy * 64 + mi * 16 + g;
        float i0 = 1.0f / l_run[rl];
        float i8 = 1.0f / l_run[rl + 8];
        #pragma unroll
        for (int nj = 0; nj < 4; nj++) {
            int cc = wx * 32 + nj * 8 + tg * 2;
            long o0 = ((long)b * S_ + m0 + rl) * D_ + h * HD + cc;
            long o1 = o0 + 8L * D_;
            *(u32*)&Ao[o0] = (u32)h16(d_o[mi][nj][0] * i0)
                           | ((u32)h16(d_o[mi][nj][1] * i0) << 16);
            *(u32*)&Ao[o1] = (u32)h16(d_o[mi][nj][2] * i8)
                           | ((u32)h16(d_o[mi][nj][3] * i8) << 16);
        }
    }
}

// ---------------------------------------------------------------------------
__global__ void conv_h(const float* __restrict__ in, u16* __restrict__ oh, long n)
{
    long i = blockIdx.x * 256L + threadIdx.x;
    if (i < n) oh[i] = h16(in[i]);
}

// fp32 [R,C] -> transposed fp16 [C,R]; writeLo: also write lo residual array
__global__ void tsplit(const float* __restrict__ in, u16* __restrict__ oh,
                       u16* __restrict__ ol, int ldin, int ldout,
                       long sInB, long sInH, long sOutZ, int Hc, int writeLo)
{
    __shared__ float t[32][33];
    int z = blockIdx.z, bb = z / Hc, hh = z - bb * Hc;
    const float* ip = in + bb * sInB + (long)hh * sInH;
    int c0 = blockIdx.x * 32, r0 = blockIdx.y * 32;
    #pragma unroll
    for (int i = 0; i < 4; i++)
        t[threadIdx.y + i * 8][threadIdx.x] =
            ip[(long)(r0 + threadIdx.y + i * 8) * ldin + c0 + threadIdx.x];
    __syncthreads();
    #pragma unroll
    for (int i = 0; i < 4; i++) {
        int orow = c0 + threadIdx.y + i * 8;
        int oc = r0 + threadIdx.x;
        float v = t[threadIdx.x][threadIdx.y + i * 8];
        long o = z * sOutZ + (long)orow * ldout + oc;
        if (writeLo) {
            u16 hh2, ll;
            split2(v, hh2, ll);
            oh[o] = hh2; ol[o] = ll;
        } else {
            oh[o] = h16(v);
        }
    }
}

// ---------------------------------------------------------------------------
extern "C" void kernel_launch(void* const* d_in, const int* in_sizes, int n_in,
                              void* d_out, int out_size)
{
    const float* x  = (const float*)d_in[0];
    const float* fc = (const float*)d_in[1];
    const float* fs = (const float*)d_in[2];
    const float* qw = (const float*)d_in[3];
    const float* qb = (const float*)d_in[4];
    const float* kw = (const float*)d_in[5];
    const float* kb = (const float*)d_in[6];
    const float* vw = (const float*)d_in[7];
    const float* vb = (const float*)d_in[8];
    const float* ow = (const float*)d_in[9];
    const int*   sp = (const int*)d_in[10];
    float* out = (float*)d_out;

    float *v;
    u16 *x16, *qwth, *kwth, *kwtl, *vwth, *owth;
    u16 *qh, *kh, *vth, *ao;
    cudaGetSymbolAddress((void**)&v, g_v);
    cudaGetSymbolAddress((void**)&x16, g_x16);
    cudaGetSymbolAddress((void**)&qwth, g_qwt_h);
    cudaGetSymbolAddress((void**)&kwth, g_kwt_h); cudaGetSymbolAddress((void**)&kwtl, g_kwt_l);
    cudaGetSymbolAddress((void**)&vwth, g_vwt_h);
    cudaGetSymbolAddress((void**)&owth, g_owt_h);
    cudaGetSymbolAddress((void**)&qh, g_qh);
    cudaGetSymbolAddress((void**)&kh, g_kh);
    cudaGetSymbolAddress((void**)&vth, g_vth);
    cudaGetSymbolAddress((void**)&ao, g_ao);

    const int SM_QKV = 2 * (16384 + 2 * 256 * 128);   // 163840 (K path stages)
    const int SM_O   = 2 * (16384 + 1 * 256 * 128);   // 98304
    cudaFuncSetAttribute((const void*)qkv_gemm,
                         cudaFuncAttributeMaxDynamicSharedMemorySize, SM_QKV);
    cudaFuncSetAttribute((const void*)oproj_gemm,
                         cudaFuncAttributeMaxDynamicSharedMemorySize, SM_O);
    cudaFuncSetAttribute((const void*)fa_fused,
                         cudaFuncAttributeMaxDynamicSharedMemorySize, FA_SMEM);

    // 1) converts: x -> fp16; weights transposed to [N,K] (K split; Q/V/O hi)
    conv_h<<<(unsigned)(((long)MR * D_ + 255) / 256), 256>>>(x, x16, (long)MR * D_);
    dim3 tb(32, 8);
    tsplit<<<dim3(128, 128, 1), tb>>>(qw, qwth, nullptr, D_, D_, 0, 0, 0, 1, 0);
    tsplit<<<dim3(32, 128, 1), tb>>>(kw, kwth, kwtl, 1024, D_, 0, 0, 0, 1, 1);
    tsplit<<<dim3(32, 128, 1), tb>>>(vw, vwth, nullptr, 1024, D_, 0, 0, 0, 1, 0);
    tsplit<<<dim3(128, 128, 1), tb>>>(ow, owth, nullptr, D_, D_, 0, 0, 0, 1, 0);

    // 2) merged Q/K/V projections (Q/V 1-term; K 2-term; RoPE for Q/K)
    qkv_gemm<<<dim3(24, 32), 256, SM_QKV>>>(
        x16, qwth, qb, kwth, kwtl, kb, vwth, vb,
        qh, kh, v, fc, fs, sp);
    // transpose V -> fp16 [b,h,d,s]
    tsplit<<<dim3(4, 64, B_ * HKV), tb>>>(v, vth, nullptr, 1024, S_,
        (long)S_ * 1024, (long)HD, (long)HD * S_, HKV, 0);

    // 3) fused attention (1-term S, 1-term PV) -> fp16 AO in [b,s,h*128+d]
    fa_fused<<<dim3(16, B_ * HQ), 256, FA_SMEM>>>(
        qh, kh, vth, ao, 0.08838834764831845f);

    // 4) out = AO @ ow (1-term)
    oproj_gemm<<<dim3(16, 32), 256, SM_O>>>(ao, owth, out);
}

// round 13
// speedup vs baseline: 7.6060x; 1.0558x over previous
#include <cuda_runtime.h>
#include <cuda_fp16.h>

typedef unsigned short u16;
typedef unsigned int   u32;

#define B_   2
#define S_   2048
#define D_   4096
#define HQ   32
#define HKV  8
#define HD   128
#define GRP  4
#define MR   (B_*S_)   // 4096

// ---------------- scratch (__device__ globals; no runtime allocation) -------
__device__ float g_v[(size_t)MR*HKV*HD];             // fp32 V (pre-transpose)

__device__ u16 g_x16[(size_t)MR*D_];                 // fp16 x
__device__ u16 g_qwt_h[(size_t)D_*D_];               // [N,K] fp16
__device__ u16 g_kwt_h[(size_t)1024*D_],   g_kwt_l[(size_t)1024*D_];
__device__ u16 g_vwt_h[(size_t)1024*D_];
__device__ u16 g_owt_h[(size_t)D_*D_];
__device__ u16 g_qh[(size_t)MR*D_];                  // rope'd Q fp16
__device__ u16 g_kh[(size_t)MR*HKV*HD];              // rope'd K fp16
__device__ u16 g_vth[(size_t)B_*HKV*HD*S_];          // V^T fp16 [b,h,d,s]
__device__ u16 g_ao[(size_t)MR*D_];                  // fp16 attn out

// ---------------------------------------------------------------------------
__device__ __forceinline__ void split2(float v, u16& h, u16& l) {
    __half hb = __float2half_rn(v);
    float r = v - __half2float(hb);
    h = __half_as_ushort(hb);
    l = __half_as_ushort(__float2half_rn(r));
}
__device__ __forceinline__ u16 h16(float v) {
    return __half_as_ushort(__float2half_rn(v));
}

__device__ __forceinline__ u32 smem_u32(const void* p) {
    u32 a;
    asm("{ .reg .u64 t; cvta.to.shared.u64 t, %1; cvt.u32.u64 %0, t; }" : "=r"(a) : "l"(p));
    return a;
}

__device__ __forceinline__ void cp16(u32 sdst, const void* gsrc) {
    asm volatile("cp.async.cg.shared.global [%0], [%1], 16;\n" :: "r"(sdst), "l"(gsrc));
}
#define CP_COMMIT()  asm volatile("cp.async.commit_group;" ::: "memory")
#define CP_WAIT2()   asm volatile("cp.async.wait_group 2;" ::: "memory")
#define CP_WAIT1()   asm volatile("cp.async.wait_group 1;" ::: "memory")
#define CP_WAIT0()   asm volatile("cp.async.wait_group 0;" ::: "memory")

__device__ __forceinline__ void ldsm4(u32* r, u32 addr) {
    asm volatile("ldmatrix.sync.aligned.m8n8.x4.shared.b16 {%0,%1,%2,%3}, [%4];"
        : "=r"(r[0]), "=r"(r[1]), "=r"(r[2]), "=r"(r[3]) : "r"(addr));
}

__device__ __forceinline__ void mma16816(float* d, const u32* a, const u32* b) {
    asm volatile(
        "mma.sync.aligned.m16n8k16.row.col.f32.f16.f16.f32 "
        "{%0,%1,%2,%3}, {%4,%5,%6,%7}, {%8,%9}, {%0,%1,%2,%3};\n"
        : "+f"(d[0]), "+f"(d[1]), "+f"(d[2]), "+f"(d[3])
        : "r"(a[0]), "r"(a[1]), "r"(a[2]), "r"(a[3]), "r"(b[0]), "r"(b[1]));
}

// ---------------------------------------------------------------------------
// GEMM mainloop, single fp16 A. BLO=true: d += A@(Bh+Bl)^T ; false: A@Bh^T.
// 128 x NT CTA tile, BK=64, 2-stage cp.async, SW128 swizzle.
// ---------------------------------------------------------------------------
template<int NT, bool BLO>
__device__ __forceinline__ void gemm_core2(
    u32 sbase,
    const u16* __restrict__ Ap,
    const u16* __restrict__ Bph, const u16* __restrict__ Bpl,
    int lda, int ldb, int m0, int n0, int K,
    float (&d)[4][NT / 32][4])
{
    constexpr int NJ = NT / 32;
    constexpr int STG = 16384 + (BLO ? 2 : 1) * NT * 128;

    int tid = threadIdx.x, wid = tid >> 5, lane = tid & 31;
    int wx = wid & 3, wy = wid >> 2;

    int aRow = ((lane >> 3) & 1) * 8 + (lane & 7);
    int aKu  = lane >> 4;
    u32 aBase[4]; int aSw[4];
    #pragma unroll
    for (int mi = 0; mi < 4; mi++) {
        int r = wy * 64 + mi * 16 + aRow;
        aBase[mi] = (u32)(r * 128); aSw[mi] = r & 7;
    }
    int bRow = (lane >> 4) * 8 + (lane & 7);
    int bKu  = (lane >> 3) & 1;
    u32 bBase[NJ / 2]; int bSw[NJ / 2];
    #pragma unroll
    for (int p = 0; p < NJ / 2; p++) {
        int r = wx * (NT / 4) + p * 16 + bRow;
        bBase[p] = (u32)(r * 128); bSw[p] = r & 7;
    }

    int nch = K >> 6;

    auto prefetch = [&](int c, int s) {
        u32 st = sbase + s * STG;
        int k0 = c << 6;
        constexpr int TOT = (128 + (BLO ? 2 : 1) * NT) * 8;
        #pragma unroll
        for (int u0 = 0; u0 < TOT; u0 += 256) {
            int u = u0 + tid;
            int row, c16;
            const u16* gp;
            u32 abase;
            if (u0 < 1024) {
                row = (u >> 3) & 127; c16 = u & 7;
                gp = Ap + (long)(m0 + row) * lda + k0 + c16 * 8;
                abase = st;
            } else {
                int v = u - 1024;
                row = (v >> 3) & (NT - 1); c16 = v & 7;
                bool lo = BLO && (v >= NT * 8);
                gp = (lo ? Bpl : Bph) + (long)(n0 + row) * ldb + k0 + c16 * 8;
                abase = st + 16384u + (lo ? (u32)(NT * 128) : 0u);
            }
            u32 so = abase + (u32)(row * 128) + ((u32)(c16 ^ (row & 7)) << 4);
            cp16(so, gp);
        }
    };

    prefetch(0, 0);
    CP_COMMIT();

    for (int c = 0; c < nch; c++) {
        if (c + 1 < nch) { prefetch(c + 1, (c + 1) & 1); CP_COMMIT(); CP_WAIT1(); }
        else             { CP_WAIT0(); }
        __syncthreads();

        u32 st = sbase + (c & 1) * STG;
        u32 sA_ = st, sBh_ = st + 16384, sBl_ = st + 16384 + NT * 128;

        #pragma unroll
        for (int kk = 0; kk < 4; kk++) {
            int kuA = kk * 2 + aKu;
            int kuB = kk * 2 + bKu;
            u32 ah[4][4], xbh[NJ / 2][4];
            #pragma unroll
            for (int mi = 0; mi < 4; mi++)
                ldsm4(ah[mi], sA_ + aBase[mi] + ((u32)(kuA ^ aSw[mi]) << 4));
            #pragma unroll
            for (int p = 0; p < NJ / 2; p++)
                ldsm4(xbh[p], sBh_ + bBase[p] + ((u32)(kuB ^ bSw[p]) << 4));
            #pragma unroll
            for (int mi = 0; mi < 4; mi++)
                #pragma unroll
                for (int nj = 0; nj < NJ; nj++)
                    mma16816(d[mi][nj], ah[mi], &xbh[nj >> 1][(nj & 1) * 2]);
            if (BLO) {
                u32 xbl[NJ / 2][4];
                #pragma unroll
                for (int p = 0; p < NJ / 2; p++)
                    ldsm4(xbl[p], sBl_ + bBase[p] + ((u32)(kuB ^ bSw[p]) << 4));
                #pragma unroll
                for (int mi = 0; mi < 4; mi++)
                    #pragma unroll
                    for (int nj = 0; nj < NJ; nj++)
                        mma16816(d[mi][nj], ah[mi], &xbl[nj >> 1][(nj & 1) * 2]);
            }
        }
        __syncthreads();
    }
}

// ---------------------------------------------------------------------------
// Merged Q/K/V projection, NT=128 tiles. Q: 1-term. K: 2-term. V: 1-term.
// Q/K: bias + RoPE + fp16 out. V: bias + fp32 out.
// grid.x: 0-31 Q tiles, 32-39 K, 40-47 V.
// ---------------------------------------------------------------------------
__global__ __launch_bounds__(256, 1)
void qkv_gemm(const u16* __restrict__ x16,
              const u16* __restrict__ qwth, const float* __restrict__ qb,
              const u16* __restrict__ kwth, const u16* __restrict__ kwtl, const float* __restrict__ kb,
              const u16* __restrict__ vwth, const float* __restrict__ vb,
              u16* __restrict__ qh, u16* __restrict__ kh,
              float* __restrict__ vf,
              const float* __restrict__ fc, const float* __restrict__ fs,
              const int* __restrict__ sp)
{
    extern __shared__ __align__(16) char dsm[];
    int nt = blockIdx.x, m0 = blockIdx.y * 128;

    const u16 *Bph = nullptr, *Bpl = nullptr; const float* bias;
    u16* Ch = nullptr; float* Cf = nullptr;
    int ldc, n0; bool blo;
    if (nt < 32)      { Bph = qwth;             bias = qb; Ch = qh; ldc = 4096; n0 = nt * 128;        blo = false; }
    else if (nt < 40) { Bph = kwth; Bpl = kwtl; bias = kb; Ch = kh; ldc = 1024; n0 = (nt - 32) * 128; blo = true;  }
    else              { Bph = vwth;             bias = vb; Cf = vf; ldc = 1024; n0 = (nt - 40) * 128; blo = false; }

    float d[4][4][4];
    #pragma unroll
    for (int i = 0; i < 4; i++)
        #pragma unroll
        for (int j = 0; j < 4; j++)
            #pragma unroll
            for (int q = 0; q < 4; q++) d[i][j][q] = 0.f;

    if (blo) gemm_core2<128, true >(smem_u32(dsm), x16, Bph, Bpl, D_, D_, m0, n0, D_, d);
    else     gemm_core2<128, false>(smem_u32(dsm), x16, Bph, Bpl, D_, D_, m0, n0, D_, d);

    int tid = threadIdx.x, wid = tid >> 5, lane = tid & 31;
    int wx = wid & 3, wy = wid >> 2;
    int g = lane >> 2, tg = lane & 3;
    int sp0 = *sp;

    #pragma unroll
    for (int mi = 0; mi < 4; mi++) {
        #pragma unroll
        for (int nj = 0; nj < 4; nj++) {
            int r = m0 + wy * 64 + mi * 16 + g;
            int c = n0 + wx * 32 + nj * 8 + tg * 2;
            float b0 = bias[c], b1 = bias[c + 1];
            float v0 = d[mi][nj][0] + b0, v1 = d[mi][nj][1] + b1;
            float v2 = d[mi][nj][2] + b0, v3 = d[mi][nj][3] + b1;
            long o0 = (long)r * ldc + c;
            long o1 = o0 + 8L * ldc;
            if (Cf) {
                *(float2*)&Cf[o0] = make_float2(v0, v1);
                *(float2*)&Cf[o1] = make_float2(v2, v3);
            } else {
                int i_ = (c & 127) >> 1;
                int s0 = (r & (S_ - 1)) + sp0;
                int s8 = ((r + 8) & (S_ - 1)) + sp0;
                float c0f = fc[s0 * 64 + i_], s0f = fs[s0 * 64 + i_];
                float c8f = fc[s8 * 64 + i_], s8f = fs[s8 * 64 + i_];
                float r0 = v0 * c0f - v1 * s0f, r1 = v0 * s0f + v1 * c0f;
                float r2 = v2 * c8f - v3 * s8f, r3 = v2 * s8f + v3 * c8f;
                *(u32*)&Ch[o0] = (u32)h16(r0) | ((u32)h16(r1) << 16);
                *(u32*)&Ch[o1] = (u32)h16(r2) | ((u32)h16(r3) << 16);
            }
        }
    }
}

// ---------------------------------------------------------------------------
// Output projection: out = AO(fp16) @ owh^T, 1-term, NT=128. fp32 out.
// ---------------------------------------------------------------------------
__global__ __launch_bounds__(256, 1)
void oproj_gemm(const u16* __restrict__ Ap,
                const u16* __restrict__ Bgh,
                float* __restrict__ Cf)
{
    extern __shared__ __align__(16) char dsm[];
    int m0 = blockIdx.y * 128, n0 = blockIdx.x * 128;

    float d[4][4][4];
    #pragma unroll
    for (int i = 0; i < 4; i++)
        #pragma unroll
        for (int j = 0; j < 4; j++)
            #pragma unroll
            for (int q = 0; q < 4; q++) d[i][j][q] = 0.f;

    gemm_core2<128, false>(smem_u32(dsm), Ap, Bgh, nullptr, D_, D_, m0, n0, D_, d);

    int tid = threadIdx.x, wid = tid >> 5, lane = tid & 31;
    int wx = wid & 3, wy = wid >> 2;
    int g = lane >> 2, tg = lane & 3;

    #pragma unroll
    for (int mi = 0; mi < 4; mi++) {
        #pragma unroll
        for (int nj = 0; nj < 4; nj++) {
            int r = m0 + wy * 64 + mi * 16 + g;
            int c = n0 + wx * 32 + nj * 8 + tg * 2;
            long o0 = (long)r * D_ + c;
            long o1 = o0 + 8L * D_;
            *(float2*)&Cf[o0] = make_float2(d[mi][nj][0], d[mi][nj][1]);
            *(float2*)&Cf[o1] = make_float2(d[mi][nj][2], d[mi][nj][3]);
        }
    }
}

// ---------------------------------------------------------------------------
// Fused FlashAttention, 128-wide K/V chunks: S = alpha*Qh@Kh^T (1-term),
// online softmax (one phase per 128 cols), O = Ph@Vh (1-term).
// Smem: Q 32K (2 d-blocks), K 2 stages x 32K (2 d-blocks each),
//       V 32K (2 s-blocks), P 32K (2 s-blocks), stats.
// ---------------------------------------------------------------------------
#define FA_Q    0
#define FA_K    32768
#define FA_V    98304
#define FA_P    131072
#define FA_ST   163840
#define FA_SMEM (163840 + 5632)

__global__ __launch_bounds__(256)
void fa_fused(const u16* __restrict__ Qh,
              const u16* __restrict__ Kh,
              const u16* __restrict__ Vth,
              u16* __restrict__ Ao, float alpha)
{
    extern __shared__ __align__(16) char dsm[];
    u32 sbase = smem_u32(dsm);
    float* m_run = (float*)(dsm + FA_ST);
    float* l_run = m_run + 128;
    float* fch   = m_run + 256;
    float* mpart = m_run + 384;
    float* lpart = m_run + 896;

    int m0 = (int)(gridDim.x - 1 - blockIdx.x) * 128;
    int z = blockIdx.y, b = z / HQ, h = z - b * HQ;

    const u16* Qph = Qh + ((long)b * S_ + m0) * D_ + h * HD;
    const u16* Kph = Kh + (long)b * S_ * 1024 + (h / GRP) * HD;
    const u16* Vph = Vth + ((long)b * HKV + (h / GRP)) * (long)HD * S_;

    int tid = threadIdx.x, wid = tid >> 5, lane = tid & 31;
    int wx = wid & 3, wy = wid >> 2;
    int g = lane >> 2, tg = lane & 3;

    if (tid < 128) { m_run[tid] = -1e30f; l_run[tid] = 0.f; }

    int aRow = ((lane >> 3) & 1) * 8 + (lane & 7);
    int aKu  = lane >> 4;
    u32 aBase[4]; int aSw[4];
    #pragma unroll
    for (int mi = 0; mi < 4; mi++) {
        int rr = wy * 64 + mi * 16 + aRow;
        aBase[mi] = (u32)(rr * 128); aSw[mi] = rr & 7;
    }
    int bRow = (lane >> 4) * 8 + (lane & 7);
    int bKu  = (lane >> 3) & 1;
    u32 bBaseN[2]; int bSwN[2];
    #pragma unroll
    for (int p = 0; p < 2; p++) {
        int rr = wx * 32 + p * 16 + bRow;
        bBaseN[p] = (u32)(rr * 128); bSwN[p] = rr & 7;
    }

    float d_o[4][4][4];
    #pragma unroll
    for (int i = 0; i < 4; i++)
        #pragma unroll
        for (int j = 0; j < 4; j++)
            #pragma unroll
            for (int q = 0; q < 4; q++) d_o[i][j][q] = 0.f;

    int nch = (m0 >> 7) + 1;      // 128-wide chunks up to and incl. diagonal

    auto qfetch = [&]() {
        #pragma unroll
        for (int u0 = 0; u0 < 2048; u0 += 256) {
            int u = u0 + tid;
            int cc = u >> 10, v = u & 1023;
            int row = v >> 3, c16 = v & 7;
            const u16* gp = Qph + (long)row * D_ + cc * 64 + c16 * 8;
            u32 so = sbase + FA_Q + (u32)cc * 16384
                   + (u32)(row * 128) + ((u32)(c16 ^ (row & 7)) << 4);
            cp16(so, gp);
        }
    };
    // 128 K rows x 128 d, 2 d-blocks of 16 KB
    auto kfetch = [&](int c, int s) {
        int j0 = c << 7;
        #pragma unroll
        for (int u0 = 0; u0 < 2048; u0 += 256) {
            int u = u0 + tid;
            int cc = u >> 10, v = u & 1023;
            int row = v >> 3, c16 = v & 7;
            const u16* gp = Kph + (long)(j0 + row) * 1024 + cc * 64 + c16 * 8;
            u32 so = sbase + FA_K + (u32)s * 32768 + (u32)cc * 16384
                   + (u32)(row * 128) + ((u32)(c16 ^ (row & 7)) << 4);
            cp16(so, gp);
        }
    };
    // V^T tile: 128 d rows x 128 s, 2 s-blocks of 16 KB
    auto vfetch = [&](int c) {
        int j0 = c << 7;
        #pragma unroll
        for (int u0 = 0; u0 < 2048; u0 += 256) {
            int u = u0 + tid;
            int cc = u >> 10, v = u & 1023;
            int row = v >> 3, c16 = v & 7;
            const u16* gp = Vph + (long)row * S_ + j0 + cc * 64 + c16 * 8;
            u32 so = sbase + FA_V + (u32)cc * 16384
                   + (u32)(row * 128) + ((u32)(c16 ^ (row & 7)) << 4);
            cp16(so, gp);
        }
    };

    qfetch();
    CP_COMMIT();
    kfetch(0, 0);
    CP_COMMIT();

    for (int c = 0; c < nch; c++) {
        int j0 = c << 7;
        bool hasNext = (c + 1 < nch);

        vfetch(c); CP_COMMIT();
        if (hasNext) { kfetch(c + 1, (c + 1) & 1); CP_COMMIT(); }

        if (hasNext) CP_WAIT2(); else CP_WAIT1();
        __syncthreads();

        // ---- S = Qh @ Kh^T (1 term, N=128) ----
        float d_s[4][4][4];
        #pragma unroll
        for (int i = 0; i < 4; i++)
            #pragma unroll
            for (int j = 0; j < 4; j++)
                #pragma unroll
                for (int q = 0; q < 4; q++) d_s[i][j][q] = 0.f;

        u32 kst = sbase + FA_K + (u32)(c & 1) * 32768;
        #pragma unroll
        for (int cc = 0; cc < 2; cc++) {
            u32 sQ_ = sbase + FA_Q + (u32)cc * 16384;
            u32 sK_ = kst + (u32)cc * 16384;
            #pragma unroll
            for (int kk = 0; kk < 4; kk++) {
                int kuA = kk * 2 + aKu;
                int kuB = kk * 2 + bKu;
                u32 ah[4][4], xb[2][4];
                #pragma unroll
                for (int mi = 0; mi < 4; mi++)
                    ldsm4(ah[mi], sQ_ + aBase[mi] + ((u32)(kuA ^ aSw[mi]) << 4));
                #pragma unroll
                for (int p = 0; p < 2; p++)
                    ldsm4(xb[p], sK_ + bBaseN[p] + ((u32)(kuB ^ bSwN[p]) << 4));
                #pragma unroll
                for (int mi = 0; mi < 4; mi++)
                    #pragma unroll
                    for (int nj = 0; nj < 4; nj++)
                        mma16816(d_s[mi][nj], ah[mi], &xb[nj >> 1][(nj & 1) * 2]);
            }
        }

        // ---- mask + alpha + chunk row-max ----
        bool domask = (c == nch - 1);
        #pragma unroll
        for (int mi = 0; mi < 4; mi++) {
            int rl0 = wy * 64 + mi * 16 + g;
            int grow0 = m0 + rl0, grow8 = grow0 + 8;
            float mx0 = -1e30f, mx8 = -1e30f;
            #pragma unroll
            for (int nj = 0; nj < 4; nj++) {
                #pragma unroll
                for (int e = 0; e < 2; e++) {
                    int gc = j0 + wx * 32 + nj * 8 + tg * 2 + e;
                    float v0 = d_s[mi][nj][e] * alpha;
                    float v8 = d_s[mi][nj][2 + e] * alpha;
                    if (domask) {
                        if (gc > grow0) v0 = -1e30f;
                        if (gc > grow8) v8 = -1e30f;
                    }
                    d_s[mi][nj][e] = v0; d_s[mi][nj][2 + e] = v8;
                    mx0 = fmaxf(mx0, v0); mx8 = fmaxf(mx8, v8);
                }
            }
            mx0 = fmaxf(mx0, __shfl_xor_sync(0xffffffffu, mx0, 1));
            mx0 = fmaxf(mx0, __shfl_xor_sync(0xffffffffu, mx0, 2));
            mx8 = fmaxf(mx8, __shfl_xor_sync(0xffffffffu, mx8, 1));
            mx8 = fmaxf(mx8, __shfl_xor_sync(0xffffffffu, mx8, 2));
            if (tg == 0) {
                mpart[wx * 128 + rl0] = mx0;
                mpart[wx * 128 + rl0 + 8] = mx8;
            }
        }
        __syncthreads();

        if (tid < 128) {
            float mc = fmaxf(fmaxf(mpart[tid], mpart[128 + tid]),
                             fmaxf(mpart[256 + tid], mpart[384 + tid]));
            float mo = m_run[tid];
            float mn = fmaxf(mo, mc);
            fch[tid] = __expf(mo - mn);
            m_run[tid] = mn;
        }
        __syncthreads();

        #pragma unroll
        for (int mi = 0; mi < 4; mi++) {
            int rl = wy * 64 + mi * 16 + g;
            float f0 = fch[rl], f8 = fch[rl + 8];
            #pragma unroll
            for (int nj = 0; nj < 4; nj++) {
                d_o[mi][nj][0] *= f0; d_o[mi][nj][1] *= f0;
                d_o[mi][nj][2] *= f8; d_o[mi][nj][3] *= f8;
            }
        }

        // ---- P = exp(S - m), fp16, store to smem (2 s-blocks); sums ----
        #pragma unroll
        for (int mi = 0; mi < 4; mi++) {
            int rl0 = wy * 64 + mi * 16 + g;
            float mrow0 = m_run[rl0], mrow8 = m_run[rl0 + 8];
            float s0 = 0.f, s8 = 0.f;
            #pragma unroll
            for (int nj = 0; nj < 4; nj++) {
                float p00 = __expf(d_s[mi][nj][0] - mrow0);
                float p01 = __expf(d_s[mi][nj][1] - mrow0);
                float p80 = __expf(d_s[mi][nj][2] - mrow8);
                float p81 = __expf(d_s[mi][nj][3] - mrow8);
                s0 += p00 + p01; s8 += p80 + p81;
                int cl = wx * 32 + nj * 8 + tg * 2;
                u32 blk = (u32)(cl >> 6) * 16384;
                int cw = cl & 63;
                u32 u0 = blk + (u32)(((cw >> 3) ^ (rl0 & 7)) << 4) + (u32)((cw & 7) * 2);
                u32 u8 = blk + (u32)(((cw >> 3) ^ ((rl0 + 8) & 7)) << 4) + (u32)((cw & 7) * 2);
                *(u32*)(dsm + FA_P + rl0 * 128 + u0) =
                    (u32)h16(p00) | ((u32)h16(p01) << 16);
                *(u32*)(dsm + FA_P + (rl0 + 8) * 128 + u8) =
                    (u32)h16(p80) | ((u32)h16(p81) << 16);
            }
            s0 += __shfl_xor_sync(0xffffffffu, s0, 1);
            s0 += __shfl_xor_sync(0xffffffffu, s0, 2);
            s8 += __shfl_xor_sync(0xffffffffu, s8, 1);
            s8 += __shfl_xor_sync(0xffffffffu, s8, 2);
            if (tg == 0) {
                lpart[wx * 128 + rl0] = s0;
                lpart[wx * 128 + rl0 + 8] = s8;
            }
        }

        if (hasNext) CP_WAIT1(); else CP_WAIT0();
        __syncthreads();

        if (tid < 128) {
            float sum = lpart[tid] + lpart[128 + tid] + lpart[256 + tid] + lpart[384 + tid];
            l_run[tid] = l_run[tid] * fch[tid] + sum;
        }

        // ---- O += Ph @ Vh (1 term, K=128 over 2 s-blocks) ----
        #pragma unroll
        for (int cc = 0; cc < 2; cc++) {
            u32 sP = sbase + FA_P + (u32)cc * 16384;
            u32 sV = sbase + FA_V + (u32)cc * 16384;
            #pragma unroll
            for (int kk = 0; kk < 4; kk++) {
                int kuA = kk * 2 + aKu;
                int kuB = kk * 2 + bKu;
                u32 ah[4][4], xb[2][4];
                #pragma unroll
                for (int mi = 0; mi < 4; mi++)
                    ldsm4(ah[mi], sP + aBase[mi] + ((u32)(kuA ^ aSw[mi]) << 4));
                #pragma unroll
                for (int p = 0; p < 2; p++)
                    ldsm4(xb[p], sV + bBaseN[p] + ((u32)(kuB ^ bSwN[p]) << 4));
                #pragma unroll
                for (int mi = 0; mi < 4; mi++)
                    #pragma unroll
                    for (int nj = 0; nj < 4; nj++)
                        mma16816(d_o[mi][nj], ah[mi], &xb[nj >> 1][(nj & 1) * 2]);
            }
        }
        __syncthreads();
    }

    // epilogue: divide by l, fp16-truncate, store AO
    #pragma unroll
    for (int mi = 0; mi < 4; mi++) {
        int rl = wy * 64 + mi * 16 + g;
        float i0 = 1.0f / l_run[rl];
        float i8 = 1.0f / l_run[rl + 8];
        #pragma unroll
        for (int nj = 0; nj < 4; nj++) {
            int cc = wx * 32 + nj * 8 + tg * 2;
            long o0 = ((long)b * S_ + m0 + rl) * D_ + h * HD + cc;
            long o1 = o0 + 8L * D_;
            *(u32*)&Ao[o0] = (u32)h16(d_o[mi][nj][0] * i0)
                           | ((u32)h16(d_o[mi][nj][1] * i0) << 16);
            *(u32*)&Ao[o1] = (u32)h16(d_o[mi][nj][2] * i8)
                           | ((u32)h16(d_o[mi][nj][3] * i8) << 16);
        }
    }
}

// ---------------------------------------------------------------------------
__global__ void conv_h(const float* __restrict__ in, u16* __restrict__ oh, long n)
{
    long i = blockIdx.x * 256L + threadIdx.x;
    if (i < n) oh[i] = h16(in[i]);
}

// fp32 [R,C] -> transposed fp16 [C,R]; writeLo: also write lo residual array
__global__ void tsplit(const float* __restrict__ in, u16* __restrict__ oh,
                       u16* __restrict__ ol, int ldin, int ldout,
                       long sInB, long sInH, long sOutZ, int Hc, int writeLo)
{
    __shared__ float t[32][33];
    int z = blockIdx.z, bb = z / Hc, hh = z - bb * Hc;
    const float* ip = in + bb * sInB + (long)hh * sInH;
    int c0 = blockIdx.x * 32, r0 = blockIdx.y * 32;
    #pragma unroll
    for (int i = 0; i < 4; i++)
        t[threadIdx.y + i * 8][threadIdx.x] =
            ip[(long)(r0 + threadIdx.y + i * 8) * ldin + c0 + threadIdx.x];
    __syncthreads();
    #pragma unroll
    for (int i = 0; i < 4; i++) {
        int orow = c0 + threadIdx.y + i * 8;
        int oc = r0 + threadIdx.x;
        float v = t[threadIdx.x][threadIdx.y + i * 8];
        long o = z * sOutZ + (long)orow * ldout + oc;
        if (writeLo) {
            u16 hh2, ll;
            split2(v, hh2, ll);
            oh[o] = hh2; ol[o] = ll;
        } else {
            oh[o] = h16(v);
        }
    }
}

// ---------------------------------------------------------------------------
extern "C" void kernel_launch(void* const* d_in, const int* in_sizes, int n_in,
                              void* d_out, int out_size)
{
    const float* x  = (const float*)d_in[0];
    const float* fc = (const float*)d_in[1];
    const float* fs = (const float*)d_in[2];
    const float* qw = (const float*)d_in[3];
    const float* qb = (const float*)d_in[4];
    const float* kw = (const float*)d_in[5];
    const float* kb = (const float*)d_in[6];
    const float* vw = (const float*)d_in[7];
    const float* vb = (const float*)d_in[8];
    const float* ow = (const float*)d_in[9];
    const int*   sp = (const int*)d_in[10];
    float* out = (float*)d_out;

    float *v;
    u16 *x16, *qwth, *kwth, *kwtl, *vwth, *owth;
    u16 *qh, *kh, *vth, *ao;
    cudaGetSymbolAddress((void**)&v, g_v);
    cudaGetSymbolAddress((void**)&x16, g_x16);
    cudaGetSymbolAddress((void**)&qwth, g_qwt_h);
    cudaGetSymbolAddress((void**)&kwth, g_kwt_h); cudaGetSymbolAddress((void**)&kwtl, g_kwt_l);
    cudaGetSymbolAddress((void**)&vwth, g_vwt_h);
    cudaGetSymbolAddress((void**)&owth, g_owt_h);
    cudaGetSymbolAddress((void**)&qh, g_qh);
    cudaGetSymbolAddress((void**)&kh, g_kh);
    cudaGetSymbolAddress((void**)&vth, g_vth);
    cudaGetSymbolAddress((void**)&ao, g_ao);

    const int SM_QKV = 2 * (16384 + 2 * 128 * 128);   // 98304 (K-path stages)
    const int SM_O   = 2 * (16384 + 1 * 128 * 128);   // 65536
    cudaFuncSetAttribute((const void*)qkv_gemm,
                         cudaFuncAttributeMaxDynamicSharedMemorySize, SM_QKV);
    cudaFuncSetAttribute((const void*)oproj_gemm,
                         cudaFuncAttributeMaxDynamicSharedMemorySize, SM_O);
    cudaFuncSetAttribute((const void*)fa_fused,
                         cudaFuncAttributeMaxDynamicSharedMemorySize, FA_SMEM);

    // 1) converts: x -> fp16; weights transposed to [N,K] (K split; Q/V/O hi)
    conv_h<<<(unsigned)(((long)MR * D_ + 255) / 256), 256>>>(x, x16, (long)MR * D_);
    dim3 tb(32, 8);
    tsplit<<<dim3(128, 128, 1), tb>>>(qw, qwth, nullptr, D_, D_, 0, 0, 0, 1, 0);
    tsplit<<<dim3(32, 128, 1), tb>>>(kw, kwth, kwtl, 1024, D_, 0, 0, 0, 1, 1);
    tsplit<<<dim3(32, 128, 1), tb>>>(vw, vwth, nullptr, 1024, D_, 0, 0, 0, 1, 0);
    tsplit<<<dim3(128, 128, 1), tb>>>(ow, owth, nullptr, D_, D_, 0, 0, 0, 1, 0);

    // 2) merged Q/K/V projections, NT=128 tiles (48 n-tiles x 32 m-tiles)
    qkv_gemm<<<dim3(48, 32), 256, SM_QKV>>>(
        x16, qwth, qb, kwth, kwtl, kb, vwth, vb,
        qh, kh, v, fc, fs, sp);
    // transpose V -> fp16 [b,h,d,s]
    tsplit<<<dim3(4, 64, B_ * HKV), tb>>>(v, vth, nullptr, 1024, S_,
        (long)S_ * 1024, (long)HD, (long)HD * S_, HKV, 0);

    // 3) fused attention (1-term S, 1-term PV, 128-wide chunks)
    fa_fused<<<dim3(16, B_ * HQ), 256, FA_SMEM>>>(
        qh, kh, vth, ao, 0.08838834764831845f);

    // 4) out = AO @ ow (1-term), NT=128
    oproj_gemm<<<dim3(32, 32), 256, SM_O>>>(ao, owth, out);
}

// round 15
// speedup vs baseline: 7.8941x; 1.0379x over previous
#include <cuda_runtime.h>
#include <cuda_fp16.h>

typedef unsigned short u16;
typedef unsigned int   u32;

#define B_   2
#define S_   2048
#define D_   4096
#define HQ   32
#define HKV  8
#define HD   128
#define GRP  4
#define MR   (B_*S_)   // 4096

// ---------------- scratch (__device__ globals; no runtime allocation) -------
__device__ float g_v[(size_t)MR*HKV*HD];             // fp32 V (pre-transpose)

__device__ u16 g_x16[(size_t)MR*D_];                 // fp16 x
__device__ u16 g_qwt_h[(size_t)D_*D_];               // [N,K] fp16
__device__ u16 g_kwt_h[(size_t)1024*D_],   g_kwt_l[(size_t)1024*D_];
__device__ u16 g_vwt_h[(size_t)1024*D_];
__device__ u16 g_owt_h[(size_t)D_*D_];
__device__ u16 g_qh[(size_t)MR*D_];                  // rope'd Q fp16
__device__ u16 g_kh[(size_t)MR*HKV*HD];              // rope'd K fp16
__device__ u16 g_vth[(size_t)B_*HKV*HD*S_];          // V^T fp16 [b,h,d,s]
__device__ u16 g_ao[(size_t)MR*D_];                  // fp16 attn out

// ---------------------------------------------------------------------------
__device__ __forceinline__ void split2(float v, u16& h, u16& l) {
    __half hb = __float2half_rn(v);
    float r = v - __half2float(hb);
    h = __half_as_ushort(hb);
    l = __half_as_ushort(__float2half_rn(r));
}
__device__ __forceinline__ u16 h16(float v) {
    return __half_as_ushort(__float2half_rn(v));
}

__device__ __forceinline__ u32 smem_u32(const void* p) {
    u32 a;
    asm("{ .reg .u64 t; cvta.to.shared.u64 t, %1; cvt.u32.u64 %0, t; }" : "=r"(a) : "l"(p));
    return a;
}

__device__ __forceinline__ void cp16(u32 sdst, const void* gsrc) {
    asm volatile("cp.async.cg.shared.global [%0], [%1], 16;\n" :: "r"(sdst), "l"(gsrc));
}
#define CP_COMMIT()  asm volatile("cp.async.commit_group;" ::: "memory")
#define CP_WAIT2()   asm volatile("cp.async.wait_group 2;" ::: "memory")
#define CP_WAIT1()   asm volatile("cp.async.wait_group 1;" ::: "memory")
#define CP_WAIT0()   asm volatile("cp.async.wait_group 0;" ::: "memory")

__device__ __forceinline__ void ldsm4(u32* r, u32 addr) {
    asm volatile("ldmatrix.sync.aligned.m8n8.x4.shared.b16 {%0,%1,%2,%3}, [%4];"
        : "=r"(r[0]), "=r"(r[1]), "=r"(r[2]), "=r"(r[3]) : "r"(addr));
}

__device__ __forceinline__ void mma16816(float* d, const u32* a, const u32* b) {
    asm volatile(
        "mma.sync.aligned.m16n8k16.row.col.f32.f16.f16.f32 "
        "{%0,%1,%2,%3}, {%4,%5,%6,%7}, {%8,%9}, {%0,%1,%2,%3};\n"
        : "+f"(d[0]), "+f"(d[1]), "+f"(d[2]), "+f"(d[3])
        : "r"(a[0]), "r"(a[1]), "r"(a[2]), "r"(a[3]), "r"(b[0]), "r"(b[1]));
}

// ---------------------------------------------------------------------------
// GEMM mainloop, single fp16 A. BLO=true: d += A@(Bh+Bl)^T ; false: A@Bh^T.
// 128 x 128 CTA tile, BK=64, 2-stage cp.async, SW128 swizzle.
// ---------------------------------------------------------------------------
template<bool BLO>
__device__ __forceinline__ void gemm_core2(
    u32 sbase,
    const u16* __restrict__ Ap,
    const u16* __restrict__ Bph, const u16* __restrict__ Bpl,
    int lda, int ldb, int m0, int n0, int K,
    float (&d)[4][4][4])
{
    constexpr int NT = 128, NJ = 4;
    constexpr int STG = 16384 + (BLO ? 2 : 1) * NT * 128;

    int tid = threadIdx.x, wid = tid >> 5, lane = tid & 31;
    int wx = wid & 3, wy = wid >> 2;

    int aRow = ((lane >> 3) & 1) * 8 + (lane & 7);
    int aKu  = lane >> 4;
    u32 aBase[4]; int aSw[4];
    #pragma unroll
    for (int mi = 0; mi < 4; mi++) {
        int r = wy * 64 + mi * 16 + aRow;
        aBase[mi] = (u32)(r * 128); aSw[mi] = r & 7;
    }
    int bRow = (lane >> 4) * 8 + (lane & 7);
    int bKu  = (lane >> 3) & 1;
    u32 bBase[NJ / 2]; int bSw[NJ / 2];
    #pragma unroll
    for (int p = 0; p < NJ / 2; p++) {
        int r = wx * 32 + p * 16 + bRow;
        bBase[p] = (u32)(r * 128); bSw[p] = r & 7;
    }

    int nch = K >> 6;

    auto prefetch = [&](int c, int s) {
        u32 st = sbase + s * STG;
        int k0 = c << 6;
        constexpr int TOT = (128 + (BLO ? 2 : 1) * NT) * 8;
        #pragma unroll
        for (int u0 = 0; u0 < TOT; u0 += 256) {
            int u = u0 + tid;
            int row, c16;
            const u16* gp;
            u32 abase;
            if (u0 < 1024) {
                row = (u >> 3) & 127; c16 = u & 7;
                gp = Ap + (long)(m0 + row) * lda + k0 + c16 * 8;
                abase = st;
            } else {
                int v = u - 1024;
                row = (v >> 3) & (NT - 1); c16 = v & 7;
                bool lo = BLO && (v >= NT * 8);
                gp = (lo ? Bpl : Bph) + (long)(n0 + row) * ldb + k0 + c16 * 8;
                abase = st + 16384u + (lo ? (u32)(NT * 128) : 0u);
            }
            u32 so = abase + (u32)(row * 128) + ((u32)(c16 ^ (row & 7)) << 4);
            cp16(so, gp);
        }
    };

    prefetch(0, 0);
    CP_COMMIT();

    for (int c = 0; c < nch; c++) {
        if (c + 1 < nch) { prefetch(c + 1, (c + 1) & 1); CP_COMMIT(); CP_WAIT1(); }
        else             { CP_WAIT0(); }
        __syncthreads();

        u32 st = sbase + (c & 1) * STG;
        u32 sA_ = st, sBh_ = st + 16384, sBl_ = st + 16384 + NT * 128;

        #pragma unroll
        for (int kk = 0; kk < 4; kk++) {
            int kuA = kk * 2 + aKu;
            int kuB = kk * 2 + bKu;
            u32 ah[4][4], xbh[NJ / 2][4];
            #pragma unroll
            for (int mi = 0; mi < 4; mi++)
                ldsm4(ah[mi], sA_ + aBase[mi] + ((u32)(kuA ^ aSw[mi]) << 4));
            #pragma unroll
            for (int p = 0; p < NJ / 2; p++)
                ldsm4(xbh[p], sBh_ + bBase[p] + ((u32)(kuB ^ bSw[p]) << 4));
            #pragma unroll
            for (int mi = 0; mi < 4; mi++)
                #pragma unroll
                for (int nj = 0; nj < NJ; nj++)
                    mma16816(d[mi][nj], ah[mi], &xbh[nj >> 1][(nj & 1) * 2]);
            if (BLO) {
                u32 xbl[NJ / 2][4];
                #pragma unroll
                for (int p = 0; p < NJ / 2; p++)
                    ldsm4(xbl[p], sBl_ + bBase[p] + ((u32)(kuB ^ bSw[p]) << 4));
                #pragma unroll
                for (int mi = 0; mi < 4; mi++)
                    #pragma unroll
                    for (int nj = 0; nj < NJ; nj++)
                        mma16816(d[mi][nj], ah[mi], &xbl[nj >> 1][(nj & 1) * 2]);
            }
        }
        __syncthreads();
    }
}

// ---------------------------------------------------------------------------
// Merged Q/K/V projection, NT=128 tiles, heavy (K 2-term) tiles first.
// grid.x: 0-7 K (2-term), 8-39 Q (1-term), 40-47 V (1-term).
// ---------------------------------------------------------------------------
__global__ __launch_bounds__(256, 1)
void qkv_gemm(const u16* __restrict__ x16,
              const u16* __restrict__ qwth, const float* __restrict__ qb,
              const u16* __restrict__ kwth, const u16* __restrict__ kwtl, const float* __restrict__ kb,
              const u16* __restrict__ vwth, const float* __restrict__ vb,
              u16* __restrict__ qh, u16* __restrict__ kh,
              float* __restrict__ vf,
              const float* __restrict__ fc, const float* __restrict__ fs,
              const int* __restrict__ sp)
{
    extern __shared__ __align__(16) char dsm[];
    int nt = blockIdx.x, m0 = blockIdx.y * 128;

    const u16 *Bph = nullptr, *Bpl = nullptr; const float* bias;
    u16* Ch = nullptr; float* Cf = nullptr;
    int ldc, n0; bool blo;
    if (nt < 8)       { Bph = kwth; Bpl = kwtl; bias = kb; Ch = kh; ldc = 1024; n0 = nt * 128;        blo = true;  }
    else if (nt < 40) { Bph = qwth;             bias = qb; Ch = qh; ldc = 4096; n0 = (nt - 8) * 128;  blo = false; }
    else              { Bph = vwth;             bias = vb; Cf = vf; ldc = 1024; n0 = (nt - 40) * 128; blo = false; }

    float d[4][4][4];
    #pragma unroll
    for (int i = 0; i < 4; i++)
        #pragma unroll
        for (int j = 0; j < 4; j++)
            #pragma unroll
            for (int q = 0; q < 4; q++) d[i][j][q] = 0.f;

    if (blo) gemm_core2<true >(smem_u32(dsm), x16, Bph, Bpl, D_, D_, m0, n0, D_, d);
    else     gemm_core2<false>(smem_u32(dsm), x16, Bph, Bpl, D_, D_, m0, n0, D_, d);

    int tid = threadIdx.x, wid = tid >> 5, lane = tid & 31;
    int wx = wid & 3, wy = wid >> 2;
    int g = lane >> 2, tg = lane & 3;
    int sp0 = *sp;

    #pragma unroll
    for (int mi = 0; mi < 4; mi++) {
        #pragma unroll
        for (int nj = 0; nj < 4; nj++) {
            int r = m0 + wy * 64 + mi * 16 + g;
            int c = n0 + wx * 32 + nj * 8 + tg * 2;
            float b0 = bias[c], b1 = bias[c + 1];
            float v0 = d[mi][nj][0] + b0, v1 = d[mi][nj][1] + b1;
            float v2 = d[mi][nj][2] + b0, v3 = d[mi][nj][3] + b1;
            long o0 = (long)r * ldc + c;
            long o1 = o0 + 8L * ldc;
            if (Cf) {
                *(float2*)&Cf[o0] = make_float2(v0, v1);
                *(float2*)&Cf[o1] = make_float2(v2, v3);
            } else {
                int i_ = (c & 127) >> 1;
                int s0 = (r & (S_ - 1)) + sp0;
                int s8 = ((r + 8) & (S_ - 1)) + sp0;
                float c0f = fc[s0 * 64 + i_], s0f = fs[s0 * 64 + i_];
                float c8f = fc[s8 * 64 + i_], s8f = fs[s8 * 64 + i_];
                float r0 = v0 * c0f - v1 * s0f, r1 = v0 * s0f + v1 * c0f;
                float r2 = v2 * c8f - v3 * s8f, r3 = v2 * s8f + v3 * c8f;
                *(u32*)&Ch[o0] = (u32)h16(r0) | ((u32)h16(r1) << 16);
                *(u32*)&Ch[o1] = (u32)h16(r2) | ((u32)h16(r3) << 16);
            }
        }
    }
}

// ---------------------------------------------------------------------------
// Output projection: out = AO(fp16) @ owh^T, 1-term, NT=128. fp32 out.
// ---------------------------------------------------------------------------
__global__ __launch_bounds__(256, 1)
void oproj_gemm(const u16* __restrict__ Ap,
                const u16* __restrict__ Bgh,
                float* __restrict__ Cf)
{
    extern __shared__ __align__(16) char dsm[];
    int m0 = blockIdx.y * 128, n0 = blockIdx.x * 128;

    float d[4][4][4];
    #pragma unroll
    for (int i = 0; i < 4; i++)
        #pragma unroll
        for (int j = 0; j < 4; j++)
            #pragma unroll
            for (int q = 0; q < 4; q++) d[i][j][q] = 0.f;

    gemm_core2<false>(smem_u32(dsm), Ap, Bgh, nullptr, D_, D_, m0, n0, D_, d);

    int tid = threadIdx.x, wid = tid >> 5, lane = tid & 31;
    int wx = wid & 3, wy = wid >> 2;
    int g = lane >> 2, tg = lane & 3;

    #pragma unroll
    for (int mi = 0; mi < 4; mi++) {
        #pragma unroll
        for (int nj = 0; nj < 4; nj++) {
            int r = m0 + wy * 64 + mi * 16 + g;
            int c = n0 + wx * 32 + nj * 8 + tg * 2;
            long o0 = (long)r * D_ + c;
            long o1 = o0 + 8L * D_;
            *(float2*)&Cf[o0] = make_float2(d[mi][nj][0], d[mi][nj][1]);
            *(float2*)&Cf[o1] = make_float2(d[mi][nj][2], d[mi][nj][3]);
        }
    }
}

// ---------------------------------------------------------------------------
// Fused FlashAttention, 128-wide K/V chunks: S = alpha*Qh@Kh^T (1-term),
// online softmax, O = Ph@Vh (1-term).
// Grid: (head, m-rank) with m-rank heavy-first -> global LPT scheduling.
// ---------------------------------------------------------------------------
#define FA_Q    0
#define FA_K    32768
#define FA_V    98304
#define FA_P    131072
#define FA_ST   163840
#define FA_SMEM (163840 + 5632)

__global__ __launch_bounds__(256)
void fa_fused(const u16* __restrict__ Qh,
              const u16* __restrict__ Kh,
              const u16* __restrict__ Vth,
              u16* __restrict__ Ao, float alpha)
{
    extern __shared__ __align__(16) char dsm[];
    u32 sbase = smem_u32(dsm);
    float* m_run = (float*)(dsm + FA_ST);
    float* l_run = m_run + 128;
    float* fch   = m_run + 256;
    float* mpart = m_run + 384;
    float* lpart = m_run + 896;

    // global LPT: first gridDim.x blocks are every head's heaviest tile
    int m0 = (int)(gridDim.y - 1 - blockIdx.y) * 128;
    int z = blockIdx.x, b = z / HQ, h = z - b * HQ;

    const u16* Qph = Qh + ((long)b * S_ + m0) * D_ + h * HD;
    const u16* Kph = Kh + (long)b * S_ * 1024 + (h / GRP) * HD;
    const u16* Vph = Vth + ((long)b * HKV + (h / GRP)) * (long)HD * S_;

    int tid = threadIdx.x, wid = tid >> 5, lane = tid & 31;
    int wx = wid & 3, wy = wid >> 2;
    int g = lane >> 2, tg = lane & 3;

    if (tid < 128) { m_run[tid] = -1e30f; l_run[tid] = 0.f; }

    int aRow = ((lane >> 3) & 1) * 8 + (lane & 7);
    int aKu  = lane >> 4;
    u32 aBase[4]; int aSw[4];
    #pragma unroll
    for (int mi = 0; mi < 4; mi++) {
        int rr = wy * 64 + mi * 16 + aRow;
        aBase[mi] = (u32)(rr * 128); aSw[mi] = rr & 7;
    }
    int bRow = (lane >> 4) * 8 + (lane & 7);
    int bKu  = (lane >> 3) & 1;
    u32 bBaseN[2]; int bSwN[2];
    #pragma unroll
    for (int p = 0; p < 2; p++) {
        int rr = wx * 32 + p * 16 + bRow;
        bBaseN[p] = (u32)(rr * 128); bSwN[p] = rr & 7;
    }

    float d_o[4][4][4];
    #pragma unroll
    for (int i = 0; i < 4; i++)
        #pragma unroll
        for (int j = 0; j < 4; j++)
            #pragma unroll
            for (int q = 0; q < 4; q++) d_o[i][j][q] = 0.f;

    int nch = (m0 >> 7) + 1;      // 128-wide chunks up to and incl. diagonal

    auto qfetch = [&]() {
        #pragma unroll
        for (int u0 = 0; u0 < 2048; u0 += 256) {
            int u = u0 + tid;
            int cc = u >> 10, v = u & 1023;
            int row = v >> 3, c16 = v & 7;
            const u16* gp = Qph + (long)row * D_ + cc * 64 + c16 * 8;
            u32 so = sbase + FA_Q + (u32)cc * 16384
                   + (u32)(row * 128) + ((u32)(c16 ^ (row & 7)) << 4);
            cp16(so, gp);
        }
    };
    auto kfetch = [&](int c, int s) {
        int j0 = c << 7;
        #pragma unroll
        for (int u0 = 0; u0 < 2048; u0 += 256) {
            int u = u0 + tid;
            int cc = u >> 10, v = u & 1023;
            int row = v >> 3, c16 = v & 7;
            const u16* gp = Kph + (long)(j0 + row) * 1024 + cc * 64 + c16 * 8;
            u32 so = sbase + FA_K + (u32)s * 32768 + (u32)cc * 16384
                   + (u32)(row * 128) + ((u32)(c16 ^ (row & 7)) << 4);
            cp16(so, gp);
        }
    };
    auto vfetch = [&](int c) {
        int j0 = c << 7;
        #pragma unroll
        for (int u0 = 0; u0 < 2048; u0 += 256) {
            int u = u0 + tid;
            int cc = u >> 10, v = u & 1023;
            int row = v >> 3, c16 = v & 7;
            const u16* gp = Vph + (long)row * S_ + j0 + cc * 64 + c16 * 8;
            u32 so = sbase + FA_V + (u32)cc * 16384
                   + (u32)(row * 128) + ((u32)(c16 ^ (row & 7)) << 4);
            cp16(so, gp);
        }
    };

    qfetch();
    CP_COMMIT();
    kfetch(0, 0);
    CP_COMMIT();

    for (int c = 0; c < nch; c++) {
        int j0 = c << 7;
        bool hasNext = (c + 1 < nch);

        vfetch(c); CP_COMMIT();
        if (hasNext) { kfetch(c + 1, (c + 1) & 1); CP_COMMIT(); }

        if (hasNext) CP_WAIT2(); else CP_WAIT1();
        __syncthreads();

        // ---- S = Qh @ Kh^T (1 term, N=128) ----
        float d_s[4][4][4];
        #pragma unroll
        for (int i = 0; i < 4; i++)
            #pragma unroll
            for (int j = 0; j < 4; j++)
                #pragma unroll
                for (int q = 0; q < 4; q++) d_s[i][j][q] = 0.f;

        u32 kst = sbase + FA_K + (u32)(c & 1) * 32768;
        #pragma unroll
        for (int cc = 0; cc < 2; cc++) {
            u32 sQ_ = sbase + FA_Q + (u32)cc * 16384;
            u32 sK_ = kst + (u32)cc * 16384;
            #pragma unroll
            for (int kk = 0; kk < 4; kk++) {
                int kuA = kk * 2 + aKu;
                int kuB = kk * 2 + bKu;
                u32 ah[4][4], xb[2][4];
                #pragma unroll
                for (int mi = 0; mi < 4; mi++)
                    ldsm4(ah[mi], sQ_ + aBase[mi] + ((u32)(kuA ^ aSw[mi]) << 4));
                #pragma unroll
                for (int p = 0; p < 2; p++)
                    ldsm4(xb[p], sK_ + bBaseN[p] + ((u32)(kuB ^ bSwN[p]) << 4));
                #pragma unroll
                for (int mi = 0; mi < 4; mi++)
                    #pragma unroll
                    for (int nj = 0; nj < 4; nj++)
                        mma16816(d_s[mi][nj], ah[mi], &xb[nj >> 1][(nj & 1) * 2]);
            }
        }

        // ---- mask + alpha + chunk row-max ----
        bool domask = (c == nch - 1);
        #pragma unroll
        for (int mi = 0; mi < 4; mi++) {
            int rl0 = wy * 64 + mi * 16 + g;
            int grow0 = m0 + rl0, grow8 = grow0 + 8;
            float mx0 = -1e30f, mx8 = -1e30f;
            #pragma unroll
            for (int nj = 0; nj < 4; nj++) {
                #pragma unroll
                for (int e = 0; e < 2; e++) {
                    int gc = j0 + wx * 32 + nj * 8 + tg * 2 + e;
                    float v0 = d_s[mi][nj][e] * alpha;
                    float v8 = d_s[mi][nj][2 + e] * alpha;
                    if (domask) {
                        if (gc > grow0) v0 = -1e30f;
                        if (gc > grow8) v8 = -1e30f;
                    }
                    d_s[mi][nj][e] = v0; d_s[mi][nj][2 + e] = v8;
                    mx0 = fmaxf(mx0, v0); mx8 = fmaxf(mx8, v8);
                }
            }
            mx0 = fmaxf(mx0, __shfl_xor_sync(0xffffffffu, mx0, 1));
            mx0 = fmaxf(mx0, __shfl_xor_sync(0xffffffffu, mx0, 2));
            mx8 = fmaxf(mx8, __shfl_xor_sync(0xffffffffu, mx8, 1));
            mx8 = fmaxf(mx8, __shfl_xor_sync(0xffffffffu, mx8, 2));
            if (tg == 0) {
                mpart[wx * 128 + rl0] = mx0;
                mpart[wx * 128 + rl0 + 8] = mx8;
            }
        }
        __syncthreads();

        if (tid < 128) {
            float mc = fmaxf(fmaxf(mpart[tid], mpart[128 + tid]),
                             fmaxf(mpart[256 + tid], mpart[384 + tid]));
            float mo = m_run[tid];
            float mn = fmaxf(mo, mc);
            fch[tid] = __expf(mo - mn);
            m_run[tid] = mn;
        }
        __syncthreads();

        #pragma unroll
        for (int mi = 0; mi < 4; mi++) {
            int rl = wy * 64 + mi * 16 + g;
            float f0 = fch[rl], f8 = fch[rl + 8];
            #pragma unroll
            for (int nj = 0; nj < 4; nj++) {
                d_o[mi][nj][0] *= f0; d_o[mi][nj][1] *= f0;
                d_o[mi][nj][2] *= f8; d_o[mi][nj][3] *= f8;
            }
        }

        // ---- P = exp(S - m), fp16, store to smem (2 s-blocks); sums ----
        #pragma unroll
        for (int mi = 0; mi < 4; mi++) {
            int rl0 = wy * 64 + mi * 16 + g;
            float mrow0 = m_run[rl0], mrow8 = m_run[rl0 + 8];
            float s0 = 0.f, s8 = 0.f;
            #pragma unroll
            for (int nj = 0; nj < 4; nj++) {
                float p00 = __expf(d_s[mi][nj][0] - mrow0);
                float p01 = __expf(d_s[mi][nj][1] - mrow0);
                float p80 = __expf(d_s[mi][nj][2] - mrow8);
                float p81 = __expf(d_s[mi][nj][3] - mrow8);
                s0 += p00 + p01; s8 += p80 + p81;
                int cl = wx * 32 + nj * 8 + tg * 2;
                u32 blk = (u32)(cl >> 6) * 16384;
                int cw = cl & 63;
                u32 u0 = blk + (u32)(((cw >> 3) ^ (rl0 & 7)) << 4) + (u32)((cw & 7) * 2);
                u32 u8 = blk + (u32)(((cw >> 3) ^ ((rl0 + 8) & 7)) << 4) + (u32)((cw & 7) * 2);
                *(u32*)(dsm + FA_P + rl0 * 128 + u0) =
                    (u32)h16(p00) | ((u32)h16(p01) << 16);
                *(u32*)(dsm + FA_P + (rl0 + 8) * 128 + u8) =
                    (u32)h16(p80) | ((u32)h16(p81) << 16);
            }
            s0 += __shfl_xor_sync(0xffffffffu, s0, 1);
            s0 += __shfl_xor_sync(0xffffffffu, s0, 2);
            s8 += __shfl_xor_sync(0xffffffffu, s8, 1);
            s8 += __shfl_xor_sync(0xffffffffu, s8, 2);
            if (tg == 0) {
                lpart[wx * 128 + rl0] = s0;
                lpart[wx * 128 + rl0 + 8] = s8;
            }
        }

        if (hasNext) CP_WAIT1(); else CP_WAIT0();
        __syncthreads();

        if (tid < 128) {
            float sum = lpart[tid] + lpart[128 + tid] + lpart[256 + tid] + lpart[384 + tid];
            l_run[tid] = l_run[tid] * fch[tid] + sum;
        }

        // ---- O += Ph @ Vh (1 term, K=128 over 2 s-blocks) ----
        #pragma unroll
        for (int cc = 0; cc < 2; cc++) {
            u32 sP = sbase + FA_P + (u32)cc * 16384;
            u32 sV = sbase + FA_V + (u32)cc * 16384;
            #pragma unroll
            for (int kk = 0; kk < 4; kk++) {
                int kuA = kk * 2 + aKu;
                int kuB = kk * 2 + bKu;
                u32 ah[4][4], xb[2][4];
                #pragma unroll
                for (int mi = 0; mi < 4; mi++)
                    ldsm4(ah[mi], sP + aBase[mi] + ((u32)(kuA ^ aSw[mi]) << 4));
                #pragma unroll
                for (int p = 0; p < 2; p++)
                    ldsm4(xb[p], sV + bBaseN[p] + ((u32)(kuB ^ bSwN[p]) << 4));
                #pragma unroll
                for (int mi = 0; mi < 4; mi++)
                    #pragma unroll
                    for (int nj = 0; nj < 4; nj++)
                        mma16816(d_o[mi][nj], ah[mi], &xb[nj >> 1][(nj & 1) * 2]);
            }
        }
        __syncthreads();
    }

    // epilogue: divide by l, fp16-truncate, store AO
    #pragma unroll
    for (int mi = 0; mi < 4; mi++) {
        int rl = wy * 64 + mi * 16 + g;
        float i0 = 1.0f / l_run[rl];
        float i8 = 1.0f / l_run[rl + 8];
        #pragma unroll
        for (int nj = 0; nj < 4; nj++) {
            int cc = wx * 32 + nj * 8 + tg * 2;
            long o0 = ((long)b * S_ + m0 + rl) * D_ + h * HD + cc;
            long o1 = o0 + 8L * D_;
            *(u32*)&Ao[o0] = (u32)h16(d_o[mi][nj][0] * i0)
                           | ((u32)h16(d_o[mi][nj][1] * i0) << 16);
            *(u32*)&Ao[o1] = (u32)h16(d_o[mi][nj][2] * i8)
                           | ((u32)h16(d_o[mi][nj][3] * i8) << 16);
        }
    }
}

// ---------------------------------------------------------------------------
__global__ void conv_h(const float* __restrict__ in, u16* __restrict__ oh, long n)
{
    long i = blockIdx.x * 256L + threadIdx.x;
    if (i < n) oh[i] = h16(in[i]);
}

// fp32 [R,C] -> transposed fp16 [C,R]; writeLo: also write lo residual array
__global__ void tsplit(const float* __restrict__ in, u16* __restrict__ oh,
                       u16* __restrict__ ol, int ldin, int ldout,
                       long sInB, long sInH, long sOutZ, int Hc, int writeLo)
{
    __shared__ float t[32][33];
    int z = blockIdx.z, bb = z / Hc, hh = z - bb * Hc;
    const float* ip = in + bb * sInB + (long)hh * sInH;
    int c0 = blockIdx.x * 32, r0 = blockIdx.y * 32;
    #pragma unroll
    for (int i = 0; i < 4; i++)
        t[threadIdx.y + i * 8][threadIdx.x] =
            ip[(long)(r0 + threadIdx.y + i * 8) * ldin + c0 + threadIdx.x];
    __syncthreads();
    #pragma unroll
    for (int i = 0; i < 4; i++) {
        int orow = c0 + threadIdx.y + i * 8;
        int oc = r0 + threadIdx.x;
        float v = t[threadIdx.x][threadIdx.y + i * 8];
        long o = z * sOutZ + (long)orow * ldout + oc;
        if (writeLo) {
            u16 hh2, ll;
            split2(v, hh2, ll);
            oh[o] = hh2; ol[o] = ll;
        } else {
            oh[o] = h16(v);
        }
    }
}

// ---------------------------------------------------------------------------
extern "C" void kernel_launch(void* const* d_in, const int* in_sizes, int n_in,
                              void* d_out, int out_size)
{
    const float* x  = (const float*)d_in[0];
    const float* fc = (const float*)d_in[1];
    const float* fs = (const float*)d_in[2];
    const float* qw = (const float*)d_in[3];
    const float* qb = (const float*)d_in[4];
    const float* kw = (const float*)d_in[5];
    const float* kb = (const float*)d_in[6];
    const float* vw = (const float*)d_in[7];
    const float* vb = (const float*)d_in[8];
    const float* ow = (const float*)d_in[9];
    const int*   sp = (const int*)d_in[10];
    float* out = (float*)d_out;

    float *v;
    u16 *x16, *qwth, *kwth, *kwtl, *vwth, *owth;
    u16 *qh, *kh, *vth, *ao;
    cudaGetSymbolAddress((void**)&v, g_v);
    cudaGetSymbolAddress((void**)&x16, g_x16);
    cudaGetSymbolAddress((void**)&qwth, g_qwt_h);
    cudaGetSymbolAddress((void**)&kwth, g_kwt_h); cudaGetSymbolAddress((void**)&kwtl, g_kwt_l);
    cudaGetSymbolAddress((void**)&vwth, g_vwt_h);
    cudaGetSymbolAddress((void**)&owth, g_owt_h);
    cudaGetSymbolAddress((void**)&qh, g_qh);
    cudaGetSymbolAddress((void**)&kh, g_kh);
    cudaGetSymbolAddress((void**)&vth, g_vth);
    cudaGetSymbolAddress((void**)&ao, g_ao);

    const int SM_QKV = 2 * (16384 + 2 * 128 * 128);   // 98304 (K-path stages)
    const int SM_O   = 2 * (16384 + 1 * 128 * 128);   // 65536
    cudaFuncSetAttribute((const void*)qkv_gemm,
                         cudaFuncAttributeMaxDynamicSharedMemorySize, SM_QKV);
    cudaFuncSetAttribute((const void*)oproj_gemm,
                         cudaFuncAttributeMaxDynamicSharedMemorySize, SM_O);
    cudaFuncSetAttribute((const void*)fa_fused,
                         cudaFuncAttributeMaxDynamicSharedMemorySize, FA_SMEM);

    // 1) converts: x -> fp16; weights transposed to [N,K] (K split; Q/V/O hi)
    conv_h<<<(unsigned)(((long)MR * D_ + 255) / 256), 256>>>(x, x16, (long)MR * D_);
    dim3 tb(32, 8);
    tsplit<<<dim3(128, 128, 1), tb>>>(qw, qwth, nullptr, D_, D_, 0, 0, 0, 1, 0);
    tsplit<<<dim3(32, 128, 1), tb>>>(kw, kwth, kwtl, 1024, D_, 0, 0, 0, 1, 1);
    tsplit<<<dim3(32, 128, 1), tb>>>(vw, vwth, nullptr, 1024, D_, 0, 0, 0, 1, 0);
    tsplit<<<dim3(128, 128, 1), tb>>>(ow, owth, nullptr, D_, D_, 0, 0, 0, 1, 0);

    // 2) merged Q/K/V projections (K heavy tiles first; Q/V 1-term)
    qkv_gemm<<<dim3(48, 32), 256, SM_QKV>>>(
        x16, qwth, qb, kwth, kwtl, kb, vwth, vb,
        qh, kh, v, fc, fs, sp);
    // transpose V -> fp16 [b,h,d,s]
    tsplit<<<dim3(4, 64, B_ * HKV), tb>>>(v, vth, nullptr, 1024, S_,
        (long)S_ * 1024, (long)HD, (long)HD * S_, HKV, 0);

    // 3) fused attention, grid (head, m-rank) = global LPT heavy-first
    fa_fused<<<dim3(B_ * HQ, 16), 256, FA_SMEM>>>(
        qh, kh, vth, ao, 0.08838834764831845f);

    // 4) out = AO @ ow (1-term), NT=128
    oproj_gemm<<<dim3(32, 32), 256, SM_O>>>(ao, owth, out);
}

// round 16
// speedup vs baseline: 8.0855x; 1.0242x over previous
#include <cuda_runtime.h>
#include <cuda_fp16.h>

typedef unsigned short u16;
typedef unsigned int   u32;

#define B_   2
#define S_   2048
#define D_   4096
#define HQ   32
#define HKV  8
#define HD   128
#define GRP  4
#define MR   (B_*S_)   // 4096

// ---------------- scratch (__device__ globals; no runtime allocation) -------
__device__ u16 g_x16[(size_t)MR*D_];                 // fp16 x
__device__ u16 g_qwt_h[(size_t)D_*D_];               // [N,K] fp16
__device__ u16 g_kwt_h[(size_t)1024*D_],   g_kwt_l[(size_t)1024*D_];
__device__ u16 g_owt_h[(size_t)D_*D_];
__device__ u16 g_vwt_h[(size_t)1024*D_];
__device__ u16 g_qh[(size_t)MR*D_];                  // rope'd Q fp16
__device__ u16 g_kh[(size_t)MR*HKV*HD];              // rope'd K fp16
__device__ u16 g_vth[(size_t)B_*HKV*HD*S_];          // V^T fp16 [b,h,d,s]
__device__ u16 g_ao[(size_t)MR*D_];                  // fp16 attn out

// ---------------------------------------------------------------------------
__device__ __forceinline__ void split2(float v, u16& h, u16& l) {
    __half hb = __float2half_rn(v);
    float r = v - __half2float(hb);
    h = __half_as_ushort(hb);
    l = __half_as_ushort(__float2half_rn(r));
}
__device__ __forceinline__ u16 h16(float v) {
    return __half_as_ushort(__float2half_rn(v));
}

__device__ __forceinline__ u32 smem_u32(const void* p) {
    u32 a;
    asm("{ .reg .u64 t; cvta.to.shared.u64 t, %1; cvt.u32.u64 %0, t; }" : "=r"(a) : "l"(p));
    return a;
}

__device__ __forceinline__ void cp16(u32 sdst, const void* gsrc) {
    asm volatile("cp.async.cg.shared.global [%0], [%1], 16;\n" :: "r"(sdst), "l"(gsrc));
}
#define CP_COMMIT()  asm volatile("cp.async.commit_group;" ::: "memory")
#define CP_WAIT2()   asm volatile("cp.async.wait_group 2;" ::: "memory")
#define CP_WAIT1()   asm volatile("cp.async.wait_group 1;" ::: "memory")
#define CP_WAIT0()   asm volatile("cp.async.wait_group 0;" ::: "memory")

__device__ __forceinline__ void ldsm4(u32* r, u32 addr) {
    asm volatile("ldmatrix.sync.aligned.m8n8.x4.shared.b16 {%0,%1,%2,%3}, [%4];"
        : "=r"(r[0]), "=r"(r[1]), "=r"(r[2]), "=r"(r[3]) : "r"(addr));
}

__device__ __forceinline__ void mma16816(float* d, const u32* a, const u32* b) {
    asm volatile(
        "mma.sync.aligned.m16n8k16.row.col.f32.f16.f16.f32 "
        "{%0,%1,%2,%3}, {%4,%5,%6,%7}, {%8,%9}, {%0,%1,%2,%3};\n"
        : "+f"(d[0]), "+f"(d[1]), "+f"(d[2]), "+f"(d[3])
        : "r"(a[0]), "r"(a[1]), "r"(a[2]), "r"(a[3]), "r"(b[0]), "r"(b[1]));
}

// ---------------------------------------------------------------------------
// GEMM mainloop, single fp16 A. BLO=true: d += A@(Bh+Bl)^T ; false: A@Bh^T.
// 128 x 128 CTA tile, BK=64, 2-stage cp.async, SW128 swizzle.
// ---------------------------------------------------------------------------
template<bool BLO>
__device__ __forceinline__ void gemm_core2(
    u32 sbase,
    const u16* __restrict__ Ap,
    const u16* __restrict__ Bph, const u16* __restrict__ Bpl,
    int lda, int ldb, int m0, int n0, int K,
    float (&d)[4][4][4])
{
    constexpr int NT = 128, NJ = 4;
    constexpr int STG = 16384 + (BLO ? 2 : 1) * NT * 128;

    int tid = threadIdx.x, wid = tid >> 5, lane = tid & 31;
    int wx = wid & 3, wy = wid >> 2;

    int aRow = ((lane >> 3) & 1) * 8 + (lane & 7);
    int aKu  = lane >> 4;
    u32 aBase[4]; int aSw[4];
    #pragma unroll
    for (int mi = 0; mi < 4; mi++) {
        int r = wy * 64 + mi * 16 + aRow;
        aBase[mi] = (u32)(r * 128); aSw[mi] = r & 7;
    }
    int bRow = (lane >> 4) * 8 + (lane & 7);
    int bKu  = (lane >> 3) & 1;
    u32 bBase[NJ / 2]; int bSw[NJ / 2];
    #pragma unroll
    for (int p = 0; p < NJ / 2; p++) {
        int r = wx * 32 + p * 16 + bRow;
        bBase[p] = (u32)(r * 128); bSw[p] = r & 7;
    }

    int nch = K >> 6;

    auto prefetch = [&](int c, int s) {
        u32 st = sbase + s * STG;
        int k0 = c << 6;
        constexpr int TOT = (128 + (BLO ? 2 : 1) * NT) * 8;
        #pragma unroll
        for (int u0 = 0; u0 < TOT; u0 += 256) {
            int u = u0 + tid;
            int row, c16;
            const u16* gp;
            u32 abase;
            if (u0 < 1024) {
                row = (u >> 3) & 127; c16 = u & 7;
                gp = Ap + (long)(m0 + row) * lda + k0 + c16 * 8;
                abase = st;
            } else {
                int v = u - 1024;
                row = (v >> 3) & (NT - 1); c16 = v & 7;
                bool lo = BLO && (v >= NT * 8);
                gp = (lo ? Bpl : Bph) + (long)(n0 + row) * ldb + k0 + c16 * 8;
                abase = st + 16384u + (lo ? (u32)(NT * 128) : 0u);
            }
            u32 so = abase + (u32)(row * 128) + ((u32)(c16 ^ (row & 7)) << 4);
            cp16(so, gp);
        }
    };

    prefetch(0, 0);
    CP_COMMIT();

    for (int c = 0; c < nch; c++) {
        if (c + 1 < nch) { prefetch(c + 1, (c + 1) & 1); CP_COMMIT(); CP_WAIT1(); }
        else             { CP_WAIT0(); }
        __syncthreads();

        u32 st = sbase + (c & 1) * STG;
        u32 sA_ = st, sBh_ = st + 16384, sBl_ = st + 16384 + NT * 128;

        #pragma unroll
        for (int kk = 0; kk < 4; kk++) {
            int kuA = kk * 2 + aKu;
            int kuB = kk * 2 + bKu;
            u32 ah[4][4], xbh[NJ / 2][4];
            #pragma unroll
            for (int mi = 0; mi < 4; mi++)
                ldsm4(ah[mi], sA_ + aBase[mi] + ((u32)(kuA ^ aSw[mi]) << 4));
            #pragma unroll
            for (int p = 0; p < NJ / 2; p++)
                ldsm4(xbh[p], sBh_ + bBase[p] + ((u32)(kuB ^ bSw[p]) << 4));
            #pragma unroll
            for (int mi = 0; mi < 4; mi++)
                #pragma unroll
                for (int nj = 0; nj < NJ; nj++)
                    mma16816(d[mi][nj], ah[mi], &xbh[nj >> 1][(nj & 1) * 2]);
            if (BLO) {
                u32 xbl[NJ / 2][4];
                #pragma unroll
                for (int p = 0; p < NJ / 2; p++)
                    ldsm4(xbl[p], sBl_ + bBase[p] + ((u32)(kuB ^ bSw[p]) << 4));
                #pragma unroll
                for (int mi = 0; mi < 4; mi++)
                    #pragma unroll
                    for (int nj = 0; nj < NJ; nj++)
                        mma16816(d[mi][nj], ah[mi], &xbl[nj >> 1][(nj & 1) * 2]);
            }
        }
        __syncthreads();
    }
}

// ---------------------------------------------------------------------------
// Merged Q/K/V projection. grid.x: 0-7 K (2-term, heavy-first), 8-39 Q, 40-47 V.
// Q/K: bias + RoPE + fp16 out. V: bias + fp16 out, transposed in smem
// directly to vth [b,hv,d,s] (each V n-tile covers one KV head's 128 dims).
// ---------------------------------------------------------------------------
__global__ __launch_bounds__(256, 1)
void qkv_gemm(const u16* __restrict__ x16,
              const u16* __restrict__ qwth, const float* __restrict__ qb,
              const u16* __restrict__ kwth, const u16* __restrict__ kwtl, const float* __restrict__ kb,
              const u16* __restrict__ vwth, const float* __restrict__ vb,
              u16* __restrict__ qh, u16* __restrict__ kh,
              u16* __restrict__ vth,
              const float* __restrict__ fc, const float* __restrict__ fs,
              const int* __restrict__ sp)
{
    extern __shared__ __align__(16) char dsm[];
    int nt = blockIdx.x, m0 = blockIdx.y * 128;

    const u16 *Bph = nullptr, *Bpl = nullptr; const float* bias;
    u16* Ch = nullptr;
    int ldc = 0, n0; bool blo; bool isV = false;
    if (nt < 8)       { Bph = kwth; Bpl = kwtl; bias = kb; Ch = kh; ldc = 1024; n0 = nt * 128;        blo = true;  }
    else if (nt < 40) { Bph = qwth;             bias = qb; Ch = qh; ldc = 4096; n0 = (nt - 8) * 128;  blo = false; }
    else              { Bph = vwth;             bias = vb;          isV = true; n0 = (nt - 40) * 128; blo = false; }

    float d[4][4][4];
    #pragma unroll
    for (int i = 0; i < 4; i++)
        #pragma unroll
        for (int j = 0; j < 4; j++)
            #pragma unroll
            for (int q = 0; q < 4; q++) d[i][j][q] = 0.f;

    if (blo) gemm_core2<true >(smem_u32(dsm), x16, Bph, Bpl, D_, D_, m0, n0, D_, d);
    else     gemm_core2<false>(smem_u32(dsm), x16, Bph, Bpl, D_, D_, m0, n0, D_, d);

    int tid = threadIdx.x, wid = tid >> 5, lane = tid & 31;
    int wx = wid & 3, wy = wid >> 2;
    int g = lane >> 2, tg = lane & 3;

    if (isV) {
        // transpose in smem (U[d][s], rows padded to 136 u16) then coalesced out
        u16* U = (u16*)dsm;
        #pragma unroll
        for (int mi = 0; mi < 4; mi++) {
            int rl = wy * 64 + mi * 16 + g;
            #pragma unroll
            for (int nj = 0; nj < 4; nj++) {
                int c = n0 + wx * 32 + nj * 8 + tg * 2;
                int dd = c & 127;
                float b0 = bias[c], b1 = bias[c + 1];
                U[dd * 136 + rl]           = h16(d[mi][nj][0] + b0);
                U[(dd + 1) * 136 + rl]     = h16(d[mi][nj][1] + b1);
                U[dd * 136 + rl + 8]       = h16(d[mi][nj][2] + b0);
                U[(dd + 1) * 136 + rl + 8] = h16(d[mi][nj][3] + b1);
            }
        }
        __syncthreads();
        int bb = m0 >> 11;
        int s0 = m0 & (S_ - 1);
        int hv = n0 >> 7;
        u16* dst = vth + ((long)(bb * HKV + hv) * HD) * S_ + s0;
        #pragma unroll
        for (int i0 = 0; i0 < 2048; i0 += 256) {
            int i = i0 + tid;
            int dd = i >> 4, un = i & 15;
            uint4 val = *(uint4*)(U + dd * 136 + un * 8);
            *(uint4*)(dst + (long)dd * S_ + un * 8) = val;
        }
        return;
    }

    int sp0 = *sp;
    #pragma unroll
    for (int mi = 0; mi < 4; mi++) {
        #pragma unroll
        for (int nj = 0; nj < 4; nj++) {
            int r = m0 + wy * 64 + mi * 16 + g;
            int c = n0 + wx * 32 + nj * 8 + tg * 2;
            float b0 = bias[c], b1 = bias[c + 1];
            float v0 = d[mi][nj][0] + b0, v1 = d[mi][nj][1] + b1;
            float v2 = d[mi][nj][2] + b0, v3 = d[mi][nj][3] + b1;
            long o0 = (long)r * ldc + c;
            long o1 = o0 + 8L * ldc;
            int i_ = (c & 127) >> 1;
            int s0 = (r & (S_ - 1)) + sp0;
            int s8 = ((r + 8) & (S_ - 1)) + sp0;
            float c0f = fc[s0 * 64 + i_], s0f = fs[s0 * 64 + i_];
            float c8f = fc[s8 * 64 + i_], s8f = fs[s8 * 64 + i_];
            float r0 = v0 * c0f - v1 * s0f, r1 = v0 * s0f + v1 * c0f;
            float r2 = v2 * c8f - v3 * s8f, r3 = v2 * s8f + v3 * c8f;
            *(u32*)&Ch[o0] = (u32)h16(r0) | ((u32)h16(r1) << 16);
            *(u32*)&Ch[o1] = (u32)h16(r2) | ((u32)h16(r3) << 16);
        }
    }
}

// ---------------------------------------------------------------------------
// Output projection: out = AO(fp16) @ owh^T, 1-term, NT=128. fp32 out.
// ---------------------------------------------------------------------------
__global__ __launch_bounds__(256, 1)
void oproj_gemm(const u16* __restrict__ Ap,
                const u16* __restrict__ Bgh,
                float* __restrict__ Cf)
{
    extern __shared__ __align__(16) char dsm[];
    int m0 = blockIdx.y * 128, n0 = blockIdx.x * 128;

    float d[4][4][4];
    #pragma unroll
    for (int i = 0; i < 4; i++)
        #pragma unroll
        for (int j = 0; j < 4; j++)
            #pragma unroll
            for (int q = 0; q < 4; q++) d[i][j][q] = 0.f;

    gemm_core2<false>(smem_u32(dsm), Ap, Bgh, nullptr, D_, D_, m0, n0, D_, d);

    int tid = threadIdx.x, wid = tid >> 5, lane = tid & 31;
    int wx = wid & 3, wy = wid >> 2;
    int g = lane >> 2, tg = lane & 3;

    #pragma unroll
    for (int mi = 0; mi < 4; mi++) {
        #pragma unroll
        for (int nj = 0; nj < 4; nj++) {
            int r = m0 + wy * 64 + mi * 16 + g;
            int c = n0 + wx * 32 + nj * 8 + tg * 2;
            long o0 = (long)r * D_ + c;
            long o1 = o0 + 8L * D_;
            *(float2*)&Cf[o0] = make_float2(d[mi][nj][0], d[mi][nj][1]);
            *(float2*)&Cf[o1] = make_float2(d[mi][nj][2], d[mi][nj][3]);
        }
    }
}

// ---------------------------------------------------------------------------
// Fused FlashAttention, 64-wide chunks, 2 CTAs/SM (103.9 KB smem):
// S = alpha*Qh@Kh^T (1-term), online softmax, O = Ph@Vh (1-term).
// Grid: (head, m-rank heavy-first) -> global LPT.
// ---------------------------------------------------------------------------
#define FA_Q    0                   // 32 KB (2 cc x 16 KB)
#define FA_K    32768               // 2 stages x 16 KB
#define FA_V    65536               // 16 KB
#define FA_P    81920               // 16 KB
#define FA_ST   98304
#define FA_SMEM (98304 + 5632)

__global__ __launch_bounds__(256, 2)
void fa_fused(const u16* __restrict__ Qh,
              const u16* __restrict__ Kh,
              const u16* __restrict__ Vth,
              u16* __restrict__ Ao, float alpha)
{
    extern __shared__ __align__(16) char dsm[];
    u32 sbase = smem_u32(dsm);
    float* m_run = (float*)(dsm + FA_ST);
    float* l_run = m_run + 128;
    float* fch   = m_run + 256;
    float* mpart = m_run + 384;
    float* lpart = m_run + 896;

    int m0 = (int)(gridDim.y - 1 - blockIdx.y) * 128;     // LPT heavy-first
    int z = blockIdx.x, b = z / HQ, h = z - b * HQ;

    const u16* Qph = Qh + ((long)b * S_ + m0) * D_ + h * HD;
    const u16* Kph = Kh + (long)b * S_ * 1024 + (h / GRP) * HD;
    const u16* Vph = Vth + ((long)b * HKV + (h / GRP)) * (long)HD * S_;

    int tid = threadIdx.x, wid = tid >> 5, lane = tid & 31;
    int wx = wid & 3, wy = wid >> 2;
    int g = lane >> 2, tg = lane & 3;

    if (tid < 128) { m_run[tid] = -1e30f; l_run[tid] = 0.f; }

    int aRow = ((lane >> 3) & 1) * 8 + (lane & 7);
    int aKu  = lane >> 4;
    u32 aBase[4]; int aSw[4];
    #pragma unroll
    for (int mi = 0; mi < 4; mi++) {
        int rr = wy * 64 + mi * 16 + aRow;
        aBase[mi] = (u32)(rr * 128); aSw[mi] = rr & 7;
    }
    int bRow = (lane >> 4) * 8 + (lane & 7);
    int bKu  = (lane >> 3) & 1;
    u32 bBaseS = (u32)((wx * 16 + bRow) * 128); int bSwS = bRow & 7;
    u32 bBaseV[2]; int bSwV[2];
    #pragma unroll
    for (int p = 0; p < 2; p++) {
        int rr = wx * 32 + p * 16 + bRow;
        bBaseV[p] = (u32)(rr * 128); bSwV[p] = rr & 7;
    }

    float d_o[4][4][4];
    #pragma unroll
    for (int i = 0; i < 4; i++)
        #pragma unroll
        for (int j = 0; j < 4; j++)
            #pragma unroll
            for (int q = 0; q < 4; q++) d_o[i][j][q] = 0.f;

    int nch = (m0 + 128) >> 6;

    auto qfetch = [&]() {
        #pragma unroll
        for (int u0 = 0; u0 < 2048; u0 += 256) {
            int u = u0 + tid;
            int cc = u >> 10, v = u & 1023;
            int row = v >> 3, c16 = v & 7;
            const u16* gp = Qph + (long)row * D_ + cc * 64 + c16 * 8;
            u32 so = sbase + FA_Q + (u32)cc * 16384
                   + (u32)(row * 128) + ((u32)(c16 ^ (row & 7)) << 4);
            cp16(so, gp);
        }
    };
    auto kfetch = [&](int c, int s) {
        int j0 = c << 6;
        #pragma unroll
        for (int u0 = 0; u0 < 1024; u0 += 256) {
            int u = u0 + tid;
            int cc = u >> 9, v = u & 511;
            int row = v >> 3, c16 = v & 7;
            const u16* gp = Kph + (long)(j0 + row) * 1024 + cc * 64 + c16 * 8;
            u32 so = sbase + FA_K + (u32)s * 16384 + (u32)cc * 8192
                   + (u32)(row * 128) + ((u32)(c16 ^ (row & 7)) << 4);
            cp16(so, gp);
        }
    };
    auto vfetch = [&](int c) {
        int j0 = c << 6;
        #pragma unroll
        for (int u0 = 0; u0 < 1024; u0 += 256) {
            int u = u0 + tid;
            int row = u >> 3, c16 = u & 7;
            const u16* gp = Vph + (long)row * S_ + j0 + c16 * 8;
            u32 so = sbase + FA_V
                   + (u32)(row * 128) + ((u32)(c16 ^ (row & 7)) << 4);
            cp16(so, gp);
        }
    };

    qfetch();
    CP_COMMIT();
    kfetch(0, 0);
    CP_COMMIT();

    for (int c = 0; c < nch; c++) {
        int j0 = c << 6;
        bool hasNext = (c + 1 < nch);

        vfetch(c); CP_COMMIT();
        if (hasNext) { kfetch(c + 1, (c + 1) & 1); CP_COMMIT(); }

        if (hasNext) CP_WAIT2(); else CP_WAIT1();
        __syncthreads();

        // ---- S = Qh @ Kh^T (1 term) ----
        float d_s[4][2][4];
        #pragma unroll
        for (int i = 0; i < 4; i++)
            #pragma unroll
            for (int j = 0; j < 2; j++)
                #pragma unroll
                for (int q = 0; q < 4; q++) d_s[i][j][q] = 0.f;

        u32 kst = sbase + FA_K + (u32)(c & 1) * 16384;
        #pragma unroll
        for (int cc = 0; cc < 2; cc++) {
            u32 sQ_ = sbase + FA_Q + (u32)cc * 16384;
            u32 sK_ = kst + (u32)cc * 8192;
            #pragma unroll
            for (int kk = 0; kk < 4; kk++) {
                int kuA = kk * 2 + aKu;
                int kuB = kk * 2 + bKu;
                u32 ah[4][4], xb[4];
                #pragma unroll
                for (int mi = 0; mi < 4; mi++)
                    ldsm4(ah[mi], sQ_ + aBase[mi] + ((u32)(kuA ^ aSw[mi]) << 4));
                ldsm4(xb, sK_ + bBaseS + ((u32)(kuB ^ bSwS) << 4));
                #pragma unroll
                for (int mi = 0; mi < 4; mi++)
                    #pragma unroll
                    for (int nj = 0; nj < 2; nj++)
                        mma16816(d_s[mi][nj], ah[mi], &xb[nj * 2]);
            }
        }

        // ---- mask + alpha + chunk row-max ----
        bool domask = (c >= nch - 2);
        #pragma unroll
        for (int mi = 0; mi < 4; mi++) {
            int rl0 = wy * 64 + mi * 16 + g;
            int grow0 = m0 + rl0, grow8 = grow0 + 8;
            float mx0 = -1e30f, mx8 = -1e30f;
            #pragma unroll
            for (int nj = 0; nj < 2; nj++) {
                #pragma unroll
                for (int e = 0; e < 2; e++) {
                    int gc = j0 + wx * 16 + nj * 8 + tg * 2 + e;
                    float v0 = d_s[mi][nj][e] * alpha;
                    float v8 = d_s[mi][nj][2 + e] * alpha;
                    if (domask) {
                        if (gc > grow0) v0 = -1e30f;
                        if (gc > grow8) v8 = -1e30f;
                    }
                    d_s[mi][nj][e] = v0; d_s[mi][nj][2 + e] = v8;
                    mx0 = fmaxf(mx0, v0); mx8 = fmaxf(mx8, v8);
                }
            }
            mx0 = fmaxf(mx0, __shfl_xor_sync(0xffffffffu, mx0, 1));
            mx0 = fmaxf(mx0, __shfl_xor_sync(0xffffffffu, mx0, 2));
            mx8 = fmaxf(mx8, __shfl_xor_sync(0xffffffffu, mx8, 1));
            mx8 = fmaxf(mx8, __shfl_xor_sync(0xffffffffu, mx8, 2));
            if (tg == 0) {
                mpart[wx * 128 + rl0] = mx0;
                mpart[wx * 128 + rl0 + 8] = mx8;
            }
        }
        __syncthreads();

        if (tid < 128) {
            float mc = fmaxf(fmaxf(mpart[tid], mpart[128 + tid]),
                             fmaxf(mpart[256 + tid], mpart[384 + tid]));
            float mo = m_run[tid];
            float mn = fmaxf(mo, mc);
            fch[tid] = __expf(mo - mn);
            m_run[tid] = mn;
        }
        __syncthreads();

        #pragma unroll
        for (int mi = 0; mi < 4; mi++) {
            int rl = wy * 64 + mi * 16 + g;
            float f0 = fch[rl], f8 = fch[rl + 8];
            #pragma unroll
            for (int nj = 0; nj < 4; nj++) {
                d_o[mi][nj][0] *= f0; d_o[mi][nj][1] *= f0;
                d_o[mi][nj][2] *= f8; d_o[mi][nj][3] *= f8;
            }
        }

        // ---- P = exp(S - m), fp16, store to smem; partial sums ----
        #pragma unroll
        for (int mi = 0; mi < 4; mi++) {
            int rl0 = wy * 64 + mi * 16 + g;
            float mrow0 = m_run[rl0], mrow8 = m_run[rl0 + 8];
            float s0 = 0.f, s8 = 0.f;
            #pragma unroll
            for (int nj = 0; nj < 2; nj++) {
                float p00 = __expf(d_s[mi][nj][0] - mrow0);
                float p01 = __expf(d_s[mi][nj][1] - mrow0);
                float p80 = __expf(d_s[mi][nj][2] - mrow8);
                float p81 = __expf(d_s[mi][nj][3] - mrow8);
                s0 += p00 + p01; s8 += p80 + p81;
                int cl = wx * 16 + nj * 8 + tg * 2;
                u32 u0 = (u32)(((cl >> 3) ^ (rl0 & 7)) << 4) + (u32)((cl & 7) * 2);
                u32 u8 = (u32)(((cl >> 3) ^ ((rl0 + 8) & 7)) << 4) + (u32)((cl & 7) * 2);
                *(u32*)(dsm + FA_P + rl0 * 128 + u0) =
                    (u32)h16(p00) | ((u32)h16(p01) << 16);
                *(u32*)(dsm + FA_P + (rl0 + 8) * 128 + u8) =
                    (u32)h16(p80) | ((u32)h16(p81) << 16);
            }
            s0 += __shfl_xor_sync(0xffffffffu, s0, 1);
            s0 += __shfl_xor_sync(0xffffffffu, s0, 2);
            s8 += __shfl_xor_sync(0xffffffffu, s8, 1);
            s8 += __shfl_xor_sync(0xffffffffu, s8, 2);
            if (tg == 0) {
                lpart[wx * 128 + rl0] = s0;
                lpart[wx * 128 + rl0 + 8] = s8;
            }
        }

        if (hasNext) CP_WAIT1(); else CP_WAIT0();
        __syncthreads();

        if (tid < 128) {
            float sum = lpart[tid] + lpart[128 + tid] + lpart[256 + tid] + lpart[384 + tid];
            l_run[tid] = l_run[tid] * fch[tid] + sum;
        }

        // ---- O += Ph @ Vh (1 term) ----
        u32 sP = sbase + FA_P;
        u32 sV = sbase + FA_V;
        #pragma unroll
        for (int kk = 0; kk < 4; kk++) {
            int kuA = kk * 2 + aKu;
            int kuB = kk * 2 + bKu;
            u32 ah[4][4], xb[2][4];
            #pragma unroll
            for (int mi = 0; mi < 4; mi++)
                ldsm4(ah[mi], sP + aBase[mi] + ((u32)(kuA ^ aSw[mi]) << 4));
            #pragma unroll
            for (int p = 0; p < 2; p++)
                ldsm4(xb[p], sV + bBaseV[p] + ((u32)(kuB ^ bSwV[p]) << 4));
            #pragma unroll
            for (int mi = 0; mi < 4; mi++)
                #pragma unroll
                for (int nj = 0; nj < 4; nj++)
                    mma16816(d_o[mi][nj], ah[mi], &xb[nj >> 1][(nj & 1) * 2]);
        }
        __syncthreads();
    }

    // epilogue: divide by l, fp16-truncate, store AO
    #pragma unroll
    for (int mi = 0; mi < 4; mi++) {
        int rl = wy * 64 + mi * 16 + g;
        float i0 = 1.0f / l_run[rl];
        float i8 = 1.0f / l_run[rl + 8];
        #pragma unroll
        for (int nj = 0; nj < 4; nj++) {
            int cc = wx * 32 + nj * 8 + tg * 2;
            long o0 = ((long)b * S_ + m0 + rl) * D_ + h * HD + cc;
            long o1 = o0 + 8L * D_;
            *(u32*)&Ao[o0] = (u32)h16(d_o[mi][nj][0] * i0)
                           | ((u32)h16(d_o[mi][nj][1] * i0) << 16);
            *(u32*)&Ao[o1] = (u32)h16(d_o[mi][nj][2] * i8)
                           | ((u32)h16(d_o[mi][nj][3] * i8) << 16);
        }
    }
}

// ---------------------------------------------------------------------------
__global__ void conv_h(const float* __restrict__ in, u16* __restrict__ oh, long n)
{
    long i = blockIdx.x * 256L + threadIdx.x;
    if (i < n) oh[i] = h16(in[i]);
}

// fp32 [R,C] -> transposed fp16 [C,R]; writeLo: also write lo residual array
__global__ void tsplit(const float* __restrict__ in, u16* __restrict__ oh,
                       u16* __restrict__ ol, int ldin, int ldout, int writeLo)
{
    __shared__ float t[32][33];
    int c0 = blockIdx.x * 32, r0 = blockIdx.y * 32;
    #pragma unroll
    for (int i = 0; i < 4; i++)
        t[threadIdx.y + i * 8][threadIdx.x] =
            in[(long)(r0 + threadIdx.y + i * 8) * ldin + c0 + threadIdx.x];
    __syncthreads();
    #pragma unroll
    for (int i = 0; i < 4; i++) {
        int orow = c0 + threadIdx.y + i * 8;
        int oc = r0 + threadIdx.x;
        float v = t[threadIdx.x][threadIdx.y + i * 8];
        long o = (long)orow * ldout + oc;
        if (writeLo) {
            u16 hh2, ll;
            split2(v, hh2, ll);
            oh[o] = hh2; ol[o] = ll;
        } else {
            oh[o] = h16(v);
        }
    }
}

// ---------------------------------------------------------------------------
extern "C" void kernel_launch(void* const* d_in, const int* in_sizes, int n_in,
                              void* d_out, int out_size)
{
    const float* x  = (const float*)d_in[0];
    const float* fc = (const float*)d_in[1];
    const float* fs = (const float*)d_in[2];
    const float* qw = (const float*)d_in[3];
    const float* qb = (const float*)d_in[4];
    const float* kw = (const float*)d_in[5];
    const float* kb = (const float*)d_in[6];
    const float* vw = (const float*)d_in[7];
    const float* vb = (const float*)d_in[8];
    const float* ow = (const float*)d_in[9];
    const int*   sp = (const int*)d_in[10];
    float* out = (float*)d_out;

    u16 *x16, *qwth, *kwth, *kwtl, *vwth, *owth;
    u16 *qh, *kh, *vth, *ao;
    cudaGetSymbolAddress((void**)&x16, g_x16);
    cudaGetSymbolAddress((void**)&qwth, g_qwt_h);
    cudaGetSymbolAddress((void**)&kwth, g_kwt_h); cudaGetSymbolAddress((void**)&kwtl, g_kwt_l);
    cudaGetSymbolAddress((void**)&vwth, g_vwt_h);
    cudaGetSymbolAddress((void**)&owth, g_owt_h);
    cudaGetSymbolAddress((void**)&qh, g_qh);
    cudaGetSymbolAddress((void**)&kh, g_kh);
    cudaGetSymbolAddress((void**)&vth, g_vth);
    cudaGetSymbolAddress((void**)&ao, g_ao);

    const int SM_QKV = 2 * (16384 + 2 * 128 * 128);   // 98304 (K-path stages)
    const int SM_O   = 2 * (16384 + 1 * 128 * 128);   // 65536
    cudaFuncSetAttribute((const void*)qkv_gemm,
                         cudaFuncAttributeMaxDynamicSharedMemorySize, SM_QKV);
    cudaFuncSetAttribute((const void*)oproj_gemm,
                         cudaFuncAttributeMaxDynamicSharedMemorySize, SM_O);
    cudaFuncSetAttribute((const void*)fa_fused,
                         cudaFuncAttributeMaxDynamicSharedMemorySize, FA_SMEM);

    // 1) converts: x -> fp16; weights transposed to [N,K] (K split; Q/V/O hi)
    conv_h<<<(unsigned)(((long)MR * D_ + 255) / 256), 256>>>(x, x16, (long)MR * D_);
    dim3 tb(32, 8);
    tsplit<<<dim3(128, 128, 1), tb>>>(qw, qwth, nullptr, D_, D_, 0);
    tsplit<<<dim3(32, 128, 1), tb>>>(kw, kwth, kwtl, 1024, D_, 1);
    tsplit<<<dim3(32, 128, 1), tb>>>(vw, vwth, nullptr, 1024, D_, 0);
    tsplit<<<dim3(128, 128, 1), tb>>>(ow, owth, nullptr, D_, D_, 0);

    // 2) merged Q/K/V projections (V^T written directly from epilogue)
    qkv_gemm<<<dim3(48, 32), 256, SM_QKV>>>(
        x16, qwth, qb, kwth, kwtl, kb, vwth, vb,
        qh, kh, vth, fc, fs, sp);

    // 3) fused attention, 64-chunks, 2 CTAs/SM, LPT grid (head, m-rank)
    fa_fused<<<dim3(B_ * HQ, 16), 256, FA_SMEM>>>(
        qh, kh, vth, ao, 0.08838834764831845f);

    // 4) out = AO @ ow (1-term), NT=128
    oproj_gemm<<<dim3(32, 32), 256, SM_O>>>(ao, owth, out);
}